// round 6
// baseline (speedup 1.0000x reference)
#include <cuda_runtime.h>
#include <cuda_bf16.h>
#include <math.h>

#define NT 16384
#define DM 256
#define DI 512
#define DS 64
#define NH 8
#define HD 64
#define CD 640      // CONV_DIM
#define DP 1160     // D_PROJ
#define KER 4
#define NCH 256     // number of chunks
#define CQ 64       // chunk length
#define SR 68       // padded row stride for 64-col smem tiles
#define NPIN 1216   // padded N for in_proj (19*64)
#define WSTR 20     // GEMM smem row stride in uints (conflict-free for LDSM)
#define CTILE 160   // conv col chunk

// ---------------- device scratch ----------------
__device__ float g_q[NT * DM];
__device__ unsigned g_qnhi[NT * (DM / 2)];
__device__ unsigned g_qnlo[NT * (DM / 2)];
__device__ float g_Z[NT * DP];
__device__ float g_XBC[2 * NT * CD];
__device__ float g_dt[2 * NT * NH];
__device__ float g_a[2 * NT * NH];
__device__ float g_cum[2 * NH * NCH * CQ];
__device__ float g_cdec[2 * NH * NCH];
__device__ float g_S[2 * NH * NCH * HD * DS];
__device__ float g_Hp[2 * NH * NCH * HD * DS];
__device__ float g_Y[2 * NT * DI];
__device__ unsigned g_combhi[NT * (DI / 2)];
__device__ unsigned g_comblo[NT * (DI / 2)];
__device__ float g_O[NT * DM];
__device__ unsigned g_Whi[NPIN * (DM / 2)];
__device__ unsigned g_Wlo[NPIN * (DM / 2)];
__device__ unsigned long long g_keys[2 * NT];
__device__ int g_order[2 * NT];
__device__ int g_inv[2 * NT];
__device__ float g_pmin[3], g_pmax[3];

extern __shared__ float dynsmem[];

// ---------------- helpers ----------------
__device__ __forceinline__ float blockReduceSum(float v) {
    __shared__ float sh[32];
    __shared__ float tot;
    int lane = threadIdx.x & 31, wid = threadIdx.x >> 5;
    #pragma unroll
    for (int o = 16; o > 0; o >>= 1) v += __shfl_xor_sync(0xffffffffu, v, o);
    if (lane == 0) sh[wid] = v;
    __syncthreads();
    int nw = blockDim.x >> 5;
    v = (threadIdx.x < nw) ? sh[threadIdx.x] : 0.0f;
    if (wid == 0) {
        #pragma unroll
        for (int o = 16; o > 0; o >>= 1) v += __shfl_xor_sync(0xffffffffu, v, o);
        if (lane == 0) tot = v;
    }
    __syncthreads();
    return tot;
}

__device__ __forceinline__ unsigned hilbert3(unsigned a0, unsigned a1, unsigned a2) {
    unsigned x0 = a0, x1 = a1, x2 = a2;
    const unsigned M = 1u << 9;
    for (unsigned Q = M; Q > 1; Q >>= 1) {
        unsigned P = Q - 1;
        if (x0 & Q) x0 ^= P;
        {
            unsigned t = (x0 ^ x1) & P;
            if (x1 & Q) { x0 ^= P; } else { x0 ^= t; x1 ^= t; }
        }
        {
            unsigned t = (x0 ^ x2) & P;
            if (x2 & Q) { x0 ^= P; } else { x0 ^= t; x2 ^= t; }
        }
    }
    x1 ^= x0;
    x2 ^= x1;
    unsigned t = 0;
    for (unsigned Q = M; Q > 1; Q >>= 1)
        if (x2 & Q) t ^= (Q - 1);
    x0 ^= t; x1 ^= t; x2 ^= t;
    unsigned code = 0;
    for (int b = 9; b >= 0; b--) {
        code = (code << 1) | ((x0 >> b) & 1);
        code = (code << 1) | ((x1 >> b) & 1);
        code = (code << 1) | ((x2 >> b) & 1);
    }
    return code;
}

__device__ __forceinline__ void bfsplit(float x, unsigned short& hi, unsigned short& lo) {
    __nv_bfloat16 h = __float2bfloat16(x);
    __nv_bfloat16 l = __float2bfloat16(x - __bfloat162float(h));
    hi = *(unsigned short*)&h;
    lo = *(unsigned short*)&l;
}

__device__ __forceinline__ void mma_bf16(float c[4], const unsigned a[4],
                                         unsigned b0, unsigned b1) {
    asm volatile("mma.sync.aligned.m16n8k16.row.col.f32.bf16.bf16.f32 "
        "{%0,%1,%2,%3}, {%4,%5,%6,%7}, {%8,%9}, {%0,%1,%2,%3};"
        : "+f"(c[0]), "+f"(c[1]), "+f"(c[2]), "+f"(c[3])
        : "r"(a[0]), "r"(a[1]), "r"(a[2]), "r"(a[3]), "r"(b0), "r"(b1));
}

__device__ __forceinline__ void ldsm4(unsigned& r0, unsigned& r1, unsigned& r2,
                                      unsigned& r3, const unsigned* p) {
    unsigned a = (unsigned)__cvta_generic_to_shared(p);
    asm volatile("ldmatrix.sync.aligned.m8n8.x4.shared.b16 {%0,%1,%2,%3}, [%4];"
        : "=r"(r0), "=r"(r1), "=r"(r2), "=r"(r3) : "r"(a));
}

__device__ __forceinline__ void cp16(unsigned dst, const void* src) {
    asm volatile("cp.async.cg.shared.global [%0], [%1], 16;" :: "r"(dst), "l"(src));
}

// ---------------- setup kernels ----------------
__global__ void k_copy(const float* __restrict__ src) {
    int i = blockIdx.x * blockDim.x + threadIdx.x;
    if (i < NT * DM) g_q[i] = src[i];
}

__global__ void k_minmax(const float* __restrict__ pos) {
    __shared__ float smn[256][3], smx[256][3];
    float mn[3] = {1e30f, 1e30f, 1e30f}, mx[3] = {-1e30f, -1e30f, -1e30f};
    for (int r = threadIdx.x; r < NT; r += 256) {
        #pragma unroll
        for (int j = 0; j < 3; j++) {
            float v = pos[r * 3 + j];
            mn[j] = fminf(mn[j], v);
            mx[j] = fmaxf(mx[j], v);
        }
    }
    #pragma unroll
    for (int j = 0; j < 3; j++) { smn[threadIdx.x][j] = mn[j]; smx[threadIdx.x][j] = mx[j]; }
    __syncthreads();
    for (int s = 128; s > 0; s >>= 1) {
        if (threadIdx.x < s) {
            #pragma unroll
            for (int j = 0; j < 3; j++) {
                smn[threadIdx.x][j] = fminf(smn[threadIdx.x][j], smn[threadIdx.x + s][j]);
                smx[threadIdx.x][j] = fmaxf(smx[threadIdx.x][j], smx[threadIdx.x + s][j]);
            }
        }
        __syncthreads();
    }
    if (threadIdx.x == 0) {
        #pragma unroll
        for (int j = 0; j < 3; j++) { g_pmin[j] = smn[0][j]; g_pmax[j] = smx[0][j]; }
    }
}

__global__ void k_keys(const float* __restrict__ pos) {
    int idx = blockIdx.x * blockDim.x + threadIdx.x;
    if (idx >= NT) return;
    unsigned g[3];
    #pragma unroll
    for (int j = 0; j < 3; j++) {
        float denom = g_pmax[j] - g_pmin[j] + 1e-6f;
        float v = ((pos[idx * 3 + j] - g_pmin[j]) / denom) * 1023.0f;
        v = fminf(fmaxf(v, 0.0f), 1023.0f);
        g[j] = (unsigned)(int)v;
    }
    unsigned c0 = hilbert3(g[0], g[1], g[2]);
    unsigned c1 = hilbert3(g[1], g[0], g[2]);
    g_keys[idx]      = (((unsigned long long)c0) << 14) | (unsigned long long)idx;
    g_keys[NT + idx] = (((unsigned long long)c1) << 14) | (unsigned long long)idx;
}

#define SADDR(i) ((i) + ((i) >> 4))

__global__ void k_sort() {
    unsigned long long* s = (unsigned long long*)dynsmem;
    unsigned long long* keys = g_keys + blockIdx.x * NT;
    int t = threadIdx.x;
    for (int i = t; i < NT; i += 1024) s[SADDR(i)] = keys[i];
    __syncthreads();

    int base = t * 16;
    unsigned long long v[16];
    #pragma unroll
    for (int r = 0; r < 16; r++) v[r] = s[SADDR(base + r)];

    // k = 2..16 entirely in registers
    #pragma unroll
    for (int k = 2; k <= 16; k <<= 1) {
        #pragma unroll
        for (int j = k >> 1; j > 0; j >>= 1) {
            #pragma unroll
            for (int r = 0; r < 16; r++) {
                int rr = r ^ j;
                if (rr > r) {
                    bool up = (((base + r) & k) == 0);
                    unsigned long long a = v[r], b = v[rr];
                    if ((a > b) == up) { v[r] = b; v[rr] = a; }
                }
            }
        }
    }

    // k = 32..512: j passes all intra-warp (j=16*jp, jp<=16) -> shfl, no smem
    #pragma unroll
    for (int k = 32; k <= 512; k <<= 1) {
        bool up = ((base & k) == 0);
        for (int jp = k >> 5; jp >= 1; jp >>= 1) {
            bool lower = ((t & jp) == 0);
            bool take_min = (lower == up);
            #pragma unroll
            for (int r = 0; r < 16; r++) {
                unsigned long long other = __shfl_xor_sync(0xffffffffu, v[r], jp);
                bool mine_gt = v[r] > other;
                v[r] = (take_min == mine_gt) ? other : v[r];
            }
        }
        #pragma unroll
        for (int j = 8; j > 0; j >>= 1) {
            #pragma unroll
            for (int r = 0; r < 16; r++) {
                int rr = r ^ j;
                if (rr > r) {
                    unsigned long long a = v[r], b = v[rr];
                    if ((a > b) == up) { v[r] = b; v[rr] = a; }
                }
            }
        }
    }

    // k = 1024..16384: smem only for j >= 512
    for (int k = 1024; k <= NT; k <<= 1) {
        #pragma unroll
        for (int r = 0; r < 16; r++) s[SADDR(base + r)] = v[r];
        __syncthreads();
        for (int j = k >> 1; j >= 512; j >>= 1) {
            for (int i = t; i < NT; i += 1024) {
                int ixj = i ^ j;
                if (ixj > i) {
                    unsigned long long a = s[SADDR(i)], b = s[SADDR(ixj)];
                    bool up2 = ((i & k) == 0);
                    if ((a > b) == up2) { s[SADDR(i)] = b; s[SADDR(ixj)] = a; }
                }
            }
            __syncthreads();
        }
        #pragma unroll
        for (int r = 0; r < 16; r++) v[r] = s[SADDR(base + r)];
        bool up = ((base & k) == 0);
        for (int jp = 16; jp >= 1; jp >>= 1) {
            bool lower = ((t & jp) == 0);
            bool take_min = (lower == up);
            #pragma unroll
            for (int r = 0; r < 16; r++) {
                unsigned long long other = __shfl_xor_sync(0xffffffffu, v[r], jp);
                bool mine_gt = v[r] > other;
                v[r] = (take_min == mine_gt) ? other : v[r];
            }
        }
        #pragma unroll
        for (int j = 8; j > 0; j >>= 1) {
            #pragma unroll
            for (int r = 0; r < 16; r++) {
                int rr = r ^ j;
                if (rr > r) {
                    unsigned long long a = v[r], b = v[rr];
                    if ((a > b) == up) { v[r] = b; v[rr] = a; }
                }
            }
        }
    }

    #pragma unroll
    for (int r = 0; r < 16; r++) s[SADDR(base + r)] = v[r];
    __syncthreads();
    for (int i = t; i < NT; i += 1024) keys[i] = s[SADDR(i)];
}

__global__ void k_order() {
    int i = blockIdx.x * blockDim.x + threadIdx.x;
    if (i >= 2 * NT) return;
    int b = i / NT;
    int idx = (int)(g_keys[i] & 0x3FFFULL);
    g_order[i] = idx;
    g_inv[b * NT + idx] = i - b * NT;
}

__global__ void k_ln256(const float* __restrict__ w, const float* __restrict__ bias) {
    int r = blockIdx.x, t = threadIdx.x;
    float2 v = *(const float2*)(g_q + r * DM + 2 * t);
    float mean = blockReduceSum(v.x + v.y) * (1.0f / DM);
    float x0 = v.x - mean, x1 = v.y - mean;
    float var = blockReduceSum(x0 * x0 + x1 * x1) * (1.0f / DM);
    float rs = rsqrtf(var + 1e-5f);
    float r0 = x0 * rs * w[2 * t] + bias[2 * t];
    float r1 = x1 * rs * w[2 * t + 1] + bias[2 * t + 1];
    unsigned short h0, l0, h1, l1;
    bfsplit(r0, h0, l0);
    bfsplit(r1, h1, l1);
    g_qnhi[r * (DM / 2) + t] = (unsigned)h0 | ((unsigned)h1 << 16);
    g_qnlo[r * (DM / 2) + t] = (unsigned)l0 | ((unsigned)l1 << 16);
}

__global__ void k_splitW(const float* __restrict__ src, int K, int N, int NP) {
    int idx = blockIdx.x * blockDim.x + threadIdx.x;
    if (idx >= (K / 2) * NP) return;
    int kp = idx / NP, n = idx - kp * NP;
    float w0 = (n < N) ? src[(size_t)(2 * kp) * N + n] : 0.0f;
    float w1 = (n < N) ? src[(size_t)(2 * kp + 1) * N + n] : 0.0f;
    unsigned short h0, l0, h1, l1;
    bfsplit(w0, h0, l0);
    bfsplit(w1, h1, l1);
    g_Whi[(size_t)n * (K / 2) + kp] = (unsigned)h0 | ((unsigned)h1 << 16);
    g_Wlo[(size_t)n * (K / 2) + kp] = (unsigned)l0 | ((unsigned)l1 << 16);
}

// ---------------- bf16x3 tensor-core GEMM with ldmatrix ----------------
__device__ __forceinline__ void gemm_load_bf(
    const unsigned* __restrict__ Ahi, const unsigned* __restrict__ Alo, int K2,
    const unsigned* __restrict__ Bhi, const unsigned* __restrict__ Blo,
    int m0, int n0, int kt, unsigned* sAh, unsigned* sAl,
    unsigned* sBh, unsigned* sBl, int tid) {
    int kp0 = kt * 16;
    int r = tid >> 1, cu = (tid & 1) * 8;
    const unsigned* pah = Ahi + (size_t)(m0 + r) * K2 + kp0 + cu;
    const unsigned* pal = Alo + (size_t)(m0 + r) * K2 + kp0 + cu;
    unsigned dah = (unsigned)__cvta_generic_to_shared(sAh + r * WSTR + cu);
    unsigned dal = (unsigned)__cvta_generic_to_shared(sAl + r * WSTR + cu);
    cp16(dah, pah); cp16(dah + 16, pah + 4);
    cp16(dal, pal); cp16(dal + 16, pal + 4);
    int n = tid >> 2, cb = (tid & 3) * 4;
    cp16((unsigned)__cvta_generic_to_shared(sBh + n * WSTR + cb),
         Bhi + (size_t)(n0 + n) * K2 + kp0 + cb);
    cp16((unsigned)__cvta_generic_to_shared(sBl + n * WSTR + cb),
         Blo + (size_t)(n0 + n) * K2 + kp0 + cb);
}

__global__ __launch_bounds__(256) void k_gemm_bf(int M, int N, int K,
        const unsigned* __restrict__ Ahi, const unsigned* __restrict__ Alo,
        float* __restrict__ C, int ldc) {
    const unsigned* Bhi = g_Whi;
    const unsigned* Blo = g_Wlo;
    unsigned* sm = (unsigned*)dynsmem;
    const int ASZ = 128 * WSTR, BSZ = 64 * WSTR;
    const int STG = 2 * ASZ + 2 * BSZ;

    int m0 = blockIdx.y * 128, n0 = blockIdx.x * 64;
    int tid = threadIdx.x;
    int wid = tid >> 5, lane = tid & 31;
    int wm = (wid & 3) * 32, wn = (wid >> 2) * 32;
    int g = lane >> 2, tg = lane & 3;
    int lrow = lane & 15, lk = (lane >> 4) * 4;
    int K2 = K >> 1;
    int KT = K / 32;

    float acc[2][4][4];
    #pragma unroll
    for (int a = 0; a < 2; a++)
        #pragma unroll
        for (int b = 0; b < 4; b++)
            #pragma unroll
            for (int c = 0; c < 4; c++) acc[a][b][c] = 0.0f;

    gemm_load_bf(Ahi, Alo, K2, Bhi, Blo, m0, n0, 0,
                 sm, sm + ASZ, sm + 2 * ASZ, sm + 2 * ASZ + BSZ, tid);
    asm volatile("cp.async.commit_group;");

    for (int kt = 0; kt < KT; kt++) {
        int st = kt & 1;
        if (kt + 1 < KT) {
            int ns = st ^ 1;
            unsigned* b0 = sm + ns * STG;
            gemm_load_bf(Ahi, Alo, K2, Bhi, Blo, m0, n0, kt + 1,
                         b0, b0 + ASZ, b0 + 2 * ASZ, b0 + 2 * ASZ + BSZ, tid);
            asm volatile("cp.async.commit_group;");
            asm volatile("cp.async.wait_group 1;");
        } else {
            asm volatile("cp.async.wait_group 0;");
        }
        __syncthreads();
        unsigned* sAhi = sm + st * STG;
        unsigned* sAlo = sAhi + ASZ;
        unsigned* sBhi = sAhi + 2 * ASZ;
        unsigned* sBlo = sBhi + BSZ;
        #pragma unroll
        for (int kk2 = 0; kk2 < 16; kk2 += 8) {
            unsigned ahi[2][4], alo[2][4], bhi[4][2], blo[4][2];
            #pragma unroll
            for (int mi = 0; mi < 2; mi++) {
                const unsigned* pa = sAhi + (wm + mi * 16 + lrow) * WSTR + kk2 + lk;
                ldsm4(ahi[mi][0], ahi[mi][1], ahi[mi][2], ahi[mi][3], pa);
                const unsigned* pl = sAlo + (wm + mi * 16 + lrow) * WSTR + kk2 + lk;
                ldsm4(alo[mi][0], alo[mi][1], alo[mi][2], alo[mi][3], pl);
            }
            #pragma unroll
            for (int njp = 0; njp < 2; njp++) {
                const unsigned* pb = sBhi + (wn + njp * 16 + lrow) * WSTR + kk2 + lk;
                ldsm4(bhi[2 * njp][0], bhi[2 * njp + 1][0],
                      bhi[2 * njp][1], bhi[2 * njp + 1][1], pb);
                const unsigned* pbl = sBlo + (wn + njp * 16 + lrow) * WSTR + kk2 + lk;
                ldsm4(blo[2 * njp][0], blo[2 * njp + 1][0],
                      blo[2 * njp][1], blo[2 * njp + 1][1], pbl);
            }
            #pragma unroll
            for (int mi = 0; mi < 2; mi++)
                #pragma unroll
                for (int nj = 0; nj < 4; nj++) {
                    mma_bf16(acc[mi][nj], ahi[mi], bhi[nj][0], bhi[nj][1]);
                    mma_bf16(acc[mi][nj], ahi[mi], blo[nj][0], blo[nj][1]);
                    mma_bf16(acc[mi][nj], alo[mi], bhi[nj][0], bhi[nj][1]);
                }
        }
        __syncthreads();
    }
    #pragma unroll
    for (int mi = 0; mi < 2; mi++)
        #pragma unroll
        for (int nj = 0; nj < 4; nj++) {
            int row = m0 + wm + mi * 16 + g;
            int col = n0 + wn + nj * 8 + tg * 2;
            if (col + 1 < N) {
                *(float2*)(C + (size_t)row * ldc + col) =
                    make_float2(acc[mi][nj][0], acc[mi][nj][1]);
                *(float2*)(C + (size_t)(row + 8) * ldc + col) =
                    make_float2(acc[mi][nj][2], acc[mi][nj][3]);
            } else if (col < N) {
                C[(size_t)row * ldc + col] = acc[mi][nj][0];
                C[(size_t)(row + 8) * ldc + col] = acc[mi][nj][2];
            }
        }
}

// ---------------- tiled conv + dt ----------------
__global__ __launch_bounds__(256) void k_conv2(const float* __restrict__ cw,
                                               const float* __restrict__ cb) {
    float* sZ  = dynsmem;                     // (64+3) x CTILE
    float* scw = sZ + 67 * CTILE;             // CTILE x 4
    float* scb = scw + CTILE * 4;             // CTILE
    int*   stok = (int*)(scb + CTILE);        // 67
    int r0 = blockIdx.x * 64, cc = blockIdx.y * CTILE, b = blockIdx.z;
    int tid = threadIdx.x;
    if (tid < 67) {
        int rr = r0 - 3 + tid;
        stok[tid] = (rr >= 0) ? g_order[b * NT + rr] : -1;
    }
    for (int idx = tid; idx < CTILE * 4; idx += 256)
        scw[idx] = cw[(cc + (idx >> 2)) * KER + (idx & 3)];
    for (int idx = tid; idx < CTILE; idx += 256)
        scb[idx] = cb[cc + idx];
    __syncthreads();
    for (int idx = tid; idx < 67 * CTILE; idx += 256) {
        int row = idx / CTILE, col = idx - row * CTILE;
        int t = stok[row];
        sZ[idx] = (t >= 0) ? g_Z[(size_t)t * DP + DI + cc + col] : 0.0f;
    }
    __syncthreads();
    for (int idx = tid; idx < 64 * CTILE; idx += 256) {
        int row = idx / CTILE, col = idx - row * CTILE;
        float acc = scb[col];
        #pragma unroll
        for (int k = 0; k < KER; k++)
            acc += scw[col * 4 + k] * sZ[(row + k) * CTILE + col];
        float s = acc / (1.0f + __expf(-acc));
        g_XBC[(size_t)(b * NT + r0 + row) * CD + cc + col] = s;
    }
}

__global__ void k_dt(const float* __restrict__ dtb, const float* __restrict__ alog) {
    int i = blockIdx.x * blockDim.x + threadIdx.x;
    if (i >= 2 * NT * NH) return;
    int b = i / (NT * NH);
    int rem = i - b * NT * NH;
    int r = rem / NH, h = rem - r * NH;
    int t = g_order[b * NT + r];
    float x = g_Z[(size_t)t * DP + DI + CD + h] + dtb[h];
    float sp = fmaxf(x, 0.0f) + log1pf(expf(-fabsf(x)));
    float A = -expf(alog[h]);
    g_dt[i] = sp;
    g_a[i] = sp * A;
}

// ---------------- chunked scan ----------------
__global__ __launch_bounds__(256) void k_scan1() {
    int c = blockIdx.x, h = blockIdx.y, b = blockIdx.z;
    __shared__ float sX[CQ * SR], sB[CQ * SR];
    __shared__ float scum[CQ], sw[CQ];
    int r0 = c * CQ, tid = threadIdx.x;
    for (int idx = tid; idx < CQ * 64; idx += 256) {
        int j = idx >> 6, p = idx & 63;
        sX[j * SR + p] = g_XBC[(size_t)(b * NT + r0 + j) * CD + h * HD + p];
        sB[j * SR + p] = g_XBC[(size_t)(b * NT + r0 + j) * CD + DI + p];
    }
    if (tid < CQ) scum[tid] = g_a[(size_t)(b * NT + r0 + tid) * NH + h];
    __syncthreads();
    if (tid < CQ) {
        float x = scum[tid];
        #pragma unroll
        for (int o = 1; o < 32; o <<= 1) {
            float y = __shfl_up_sync(0xffffffffu, x, o);
            if ((tid & 31) >= o) x += y;
        }
        scum[tid] = x;
    }
    __syncthreads();
    if (tid >= 32 && tid < CQ) scum[tid] += scum[31];
    __syncthreads();
    float slast = scum[CQ - 1];
    if (tid < CQ) {
        sw[tid] = __expf(slast - scum[tid]) * g_dt[(size_t)(b * NT + r0 + tid) * NH + h];
        g_cum[((b * NH + h) * NCH + c) * CQ + tid] = scum[tid];
    }
    if (tid == 0) g_cdec[(b * NH + h) * NCH + c] = __expf(slast);
    __syncthreads();
    int p0 = (tid & 15) * 4, s0 = (tid >> 4) * 4;
    float acc[4][4] = {};
    for (int j = 0; j < CQ; j++) {
        float4 xv = *(float4*)&sX[j * SR + p0];
        float4 bv = *(float4*)&sB[j * SR + s0];
        float w = sw[j];
        float wx[4] = {xv.x * w, xv.y * w, xv.z * w, xv.w * w};
        float bb[4] = {bv.x, bv.y, bv.z, bv.w};
        #pragma unroll
        for (int pi = 0; pi < 4; pi++)
            #pragma unroll
            for (int si = 0; si < 4; si++) acc[pi][si] += wx[pi] * bb[si];
    }
    size_t base = ((size_t)((b * NH + h) * NCH + c) * HD) * DS;
    #pragma unroll
    for (int pi = 0; pi < 4; pi++)
        *(float4*)&g_S[base + (size_t)(p0 + pi) * DS + s0] =
            make_float4(acc[pi][0], acc[pi][1], acc[pi][2], acc[pi][3]);
}

__global__ void k_scan2() {
    __shared__ float scd[NCH];
    int bh = blockIdx.x >> 4;
    int e = ((blockIdx.x & 15) << 8) + threadIdx.x;
    if (threadIdx.x < NCH) scd[threadIdx.x] = g_cdec[bh * NCH + threadIdx.x];
    __syncthreads();
    const size_t stride = HD * DS;
    size_t off = (size_t)bh * NCH * stride + e;
    float H = 0.0f;
    float s_next = g_S[off];
    for (int c = 0; c < NCH; c++) {
        float s_cur = s_next;
        if (c + 1 < NCH) s_next = g_S[off + stride];
        g_Hp[off] = H;
        H = scd[c] * H + s_cur;
        off += stride;
    }
}

__global__ __launch_bounds__(256) void k_scan3(const float* __restrict__ Dv) {
    int c = blockIdx.x, b = blockIdx.y;
    int r0 = c * CQ, tid = threadIdx.x;
    float* sB  = dynsmem;
    float* sC  = sB  + CQ * SR;
    float* sD0 = sC  + CQ * SR;
    float* sX  = sD0 + CQ * SR;
    float* sH  = sX  + CQ * SR;
    float* sG  = sH  + CQ * SR;
    float* scum = sG + CQ * SR;
    float* sdt  = scum + CQ;
    float* seY  = sdt + CQ;

    for (int idx = tid; idx < CQ * 64; idx += 256) {
        int j = idx >> 6, s = idx & 63;
        sB[j * SR + s] = g_XBC[(size_t)(b * NT + r0 + j) * CD + DI + s];
        sC[j * SR + s] = g_XBC[(size_t)(b * NT + r0 + j) * CD + DI + DS + s];
    }
    __syncthreads();
    int i0 = (tid >> 4) * 4, j0 = (tid & 15) * 4;
    {
        float acc[4][4] = {};
        for (int sc = 0; sc < 64; sc += 4) {
            float4 Cr[4], Br[4];
            #pragma unroll
            for (int r = 0; r < 4; r++) Cr[r] = *(float4*)&sC[(i0 + r) * SR + sc];
            #pragma unroll
            for (int q = 0; q < 4; q++) Br[q] = *(float4*)&sB[(j0 + q) * SR + sc];
            #pragma unroll
            for (int r = 0; r < 4; r++) {
                float cr[4] = {Cr[r].x, Cr[r].y, Cr[r].z, Cr[r].w};
                #pragma unroll
                for (int q = 0; q < 4; q++) {
                    acc[r][q] += cr[0] * Br[q].x + cr[1] * Br[q].y +
                                 cr[2] * Br[q].z + cr[3] * Br[q].w;
                }
            }
        }
        #pragma unroll
        for (int r = 0; r < 4; r++)
            *(float4*)&sD0[(i0 + r) * SR + j0] =
                make_float4(acc[r][0], acc[r][1], acc[r][2], acc[r][3]);
    }
    __syncthreads();

    for (int h = 0; h < NH; h++) {
        for (int idx = tid; idx < CQ * 64; idx += 256) {
            int j = idx >> 6, p = idx & 63;
            sX[j * SR + p] = g_XBC[(size_t)(b * NT + r0 + j) * CD + h * HD + p];
            sH[j * SR + p] = g_Hp[((size_t)((b * NH + h) * NCH + c) * HD) * DS + idx];
        }
        if (tid < CQ) {
            float cu = g_cum[((b * NH + h) * NCH + c) * CQ + tid];
            scum[tid] = cu;
            sdt[tid] = g_dt[(size_t)(b * NT + r0 + tid) * NH + h];
            seY[tid] = __expf(cu);
        }
        __syncthreads();
        {
            #pragma unroll
            for (int r = 0; r < 4; r++) {
                float4 d = *(float4*)&sD0[(i0 + r) * SR + j0];
                float dd[4] = {d.x, d.y, d.z, d.w};
                float gv[4];
                int i = i0 + r;
                float ci = scum[i];
                #pragma unroll
                for (int q = 0; q < 4; q++) {
                    int j = j0 + q;
                    gv[q] = (j <= i) ? __expf(ci - scum[j]) * sdt[j] * dd[q] : 0.0f;
                }
                *(float4*)&sG[(i0 + r) * SR + j0] = make_float4(gv[0], gv[1], gv[2], gv[3]);
            }
        }
        __syncthreads();
        int p0 = j0;
        float acc[4][4] = {};
        for (int sc = 0; sc < 64; sc += 4) {
            float4 Cr[4], Hc[4];
            #pragma unroll
            for (int r = 0; r < 4; r++) Cr[r] = *(float4*)&sC[(i0 + r) * SR + sc];
            #pragma unroll
            for (int q = 0; q < 4; q++) Hc[q] = *(float4*)&sH[(p0 + q) * SR + sc];
            #pragma unroll
            for (int r = 0; r < 4; r++) {
                float cr[4] = {Cr[r].x, Cr[r].y, Cr[r].z, Cr[r].w};
                #pragma unroll
                for (int q = 0; q < 4; q++) {
                    acc[r][q] += cr[0] * Hc[q].x + cr[1] * Hc[q].y +
                                 cr[2] * Hc[q].z + cr[3] * Hc[q].w;
                }
            }
        }
        #pragma unroll
        for (int r = 0; r < 4; r++) {
            float e = seY[i0 + r];
            #pragma unroll
            for (int q = 0; q < 4; q++) acc[r][q] *= e;
        }
        for (int jc = 0; jc < 64; jc += 4) {
            float G4[4][4];
            #pragma unroll
            for (int r = 0; r < 4; r++) {
                float4 t = *(float4*)&sG[(i0 + r) * SR + jc];
                G4[r][0] = t.x; G4[r][1] = t.y; G4[r][2] = t.z; G4[r][3] = t.w;
            }
            #pragma unroll
            for (int q = 0; q < 4; q++) {
                float4 xv = *(float4*)&sX[(jc + q) * SR + p0];
                float xb[4] = {xv.x, xv.y, xv.z, xv.w};
                #pragma unroll
                for (int r = 0; r < 4; r++) {
                    float gq = G4[r][q];
                    #pragma unroll
                    for (int cc = 0; cc < 4; cc++) acc[r][cc] += gq * xb[cc];
                }
            }
        }
        float Dh = Dv[h];
        #pragma unroll
        for (int r = 0; r < 4; r++) {
            float4 xi = *(float4*)&sX[(i0 + r) * SR + p0];
            float4 yv = make_float4(acc[r][0] + Dh * xi.x, acc[r][1] + Dh * xi.y,
                                    acc[r][2] + Dh * xi.z, acc[r][3] + Dh * xi.w);
            *(float4*)&g_Y[(size_t)(b * NT + r0 + i0 + r) * DI + h * HD + p0] = yv;
        }
        __syncthreads();
    }
}

// ---------------- epilogue ----------------
__global__ void k_postnorm(const float* __restrict__ nw) {
    int r = blockIdx.x, b = blockIdx.y, tid = threadIdx.x;
    int t = g_order[b * NT + r];
    float v0, v1, ss;
    {
        float y0 = g_Y[(size_t)(b * NT + r) * DI + tid];
        float g0 = g_Z[(size_t)t * DP + tid];
        v0 = y0 * (g0 / (1.0f + __expf(-g0)));
        float y1 = g_Y[(size_t)(b * NT + r) * DI + tid + 256];
        float g1 = g_Z[(size_t)t * DP + tid + 256];
        v1 = y1 * (g1 / (1.0f + __expf(-g1)));
        ss = v0 * v0 + v1 * v1;
    }
    ss = blockReduceSum(ss);
    float rr = rsqrtf(ss * (1.0f / DI) + 1e-5f);
    g_Y[(size_t)(b * NT + r) * DI + tid]       = v0 * rr * nw[tid];
    g_Y[(size_t)(b * NT + r) * DI + tid + 256] = v1 * rr * nw[tid + 256];
}

__global__ void k_combine() {
    int t = blockIdx.x, c = threadIdx.x;
    int r0 = g_inv[t], r1 = g_inv[NT + t];
    float2 a = *(const float2*)(g_Y + (size_t)r0 * DI + 2 * c);
    float2 bq = *(const float2*)(g_Y + (size_t)(NT + r1) * DI + 2 * c);
    float v0 = 0.5f * (a.x + bq.x);
    float v1 = 0.5f * (a.y + bq.y);
    unsigned short h0, l0, h1, l1;
    bfsplit(v0, h0, l0);
    bfsplit(v1, h1, l1);
    g_combhi[(size_t)t * (DI / 2) + c] = (unsigned)h0 | ((unsigned)h1 << 16);
    g_comblo[(size_t)t * (DI / 2) + c] = (unsigned)l0 | ((unsigned)l1 << 16);
}

__global__ void k_final(const float* __restrict__ w, const float* __restrict__ bias,
                        float* __restrict__ dout) {
    int r = blockIdx.x, c = threadIdx.x;
    float v = g_q[r * DM + c] + g_O[r * DM + c];
    float mean = blockReduceSum(v) * (1.0f / DM);
    float xc = v - mean;
    float var = blockReduceSum(xc * xc) * (1.0f / DM);
    float res = xc * rsqrtf(var + 1e-5f) * w[c] + bias[c];
    g_q[r * DM + c] = res;
    if (dout) dout[r * DM + c] = res;
}

// ---------------- launcher ----------------
extern "C" void kernel_launch(void* const* d_in, const int* in_sizes, int n_in,
                              void* d_out, int out_size) {
    (void)in_sizes; (void)n_in; (void)out_size;
    const float* query = (const float*)d_in[0];
    const float* pos   = (const float*)d_in[1];
    const float* pre_w = (const float*)d_in[2];
    const float* pre_b = (const float*)d_in[3];
    const float* fin_w = (const float*)d_in[4];
    const float* fin_b = (const float*)d_in[5];

    const int SORT_SMEM = (NT + NT / 16) * 8;
    const int GEMM_SMEM = 2 * (2 * 128 * WSTR + 2 * 64 * WSTR) * 4;
    const int SCAN3_SMEM = (6 * CQ * SR + 3 * CQ) * 4;
    const int CONV_SMEM = (67 * CTILE + CTILE * 4 + CTILE) * 4 + 68 * 4;
    cudaFuncSetAttribute(k_sort, cudaFuncAttributeMaxDynamicSharedMemorySize, SORT_SMEM);
    cudaFuncSetAttribute(k_gemm_bf, cudaFuncAttributeMaxDynamicSharedMemorySize, GEMM_SMEM);
    cudaFuncSetAttribute(k_scan3, cudaFuncAttributeMaxDynamicSharedMemorySize, SCAN3_SMEM);
    cudaFuncSetAttribute(k_conv2, cudaFuncAttributeMaxDynamicSharedMemorySize, CONV_SMEM);

    unsigned *p_qnhi, *p_qnlo, *p_combhi, *p_comblo;
    float *p_Z, *p_O;
    cudaGetSymbolAddress((void**)&p_qnhi, g_qnhi);
    cudaGetSymbolAddress((void**)&p_qnlo, g_qnlo);
    cudaGetSymbolAddress((void**)&p_combhi, g_combhi);
    cudaGetSymbolAddress((void**)&p_comblo, g_comblo);
    cudaGetSymbolAddress((void**)&p_Z, g_Z);
    cudaGetSymbolAddress((void**)&p_O, g_O);

    k_copy<<<(NT * DM + 255) / 256, 256>>>(query);
    k_minmax<<<1, 256>>>(pos);
    k_keys<<<(NT + 255) / 256, 256>>>(pos);
    k_sort<<<2, 1024, SORT_SMEM>>>();
    k_order<<<(2 * NT + 255) / 256, 256>>>();

    for (int L = 0; L < 2; L++) {
        const float* Win  = (const float*)d_in[6 + 8 * L];
        const float* cw   = (const float*)d_in[7 + 8 * L];
        const float* cb   = (const float*)d_in[8 + 8 * L];
        const float* dtb  = (const float*)d_in[9 + 8 * L];
        const float* alog = (const float*)d_in[10 + 8 * L];
        const float* Dv   = (const float*)d_in[11 + 8 * L];
        const float* nw   = (const float*)d_in[12 + 8 * L];
        const float* Wout = (const float*)d_in[13 + 8 * L];

        k_ln256<<<NT, 128>>>(pre_w, pre_b);
        k_splitW<<<((DM / 2) * NPIN + 255) / 256, 256>>>(Win, DM, DP, NPIN);
        k_gemm_bf<<<dim3(NPIN / 64, NT / 128), 256, GEMM_SMEM>>>(
            NT, DP, DM, p_qnhi, p_qnlo, p_Z, DP);
        k_conv2<<<dim3(NT / 64, CD / CTILE, 2), 256, CONV_SMEM>>>(cw, cb);
        k_dt<<<(2 * NT * NH + 255) / 256, 256>>>(dtb, alog);
        k_scan1<<<dim3(NCH, NH, 2), 256>>>();
        k_scan2<<<256, 256>>>();
        k_scan3<<<dim3(NCH, 2), 256, SCAN3_SMEM>>>(Dv);
        k_postnorm<<<dim3(NT, 2), 256>>>(nw);
        k_combine<<<NT, 256>>>();
        k_splitW<<<((DI / 2) * DM + 255) / 256, 256>>>(Wout, DI, DM, DM);
        k_gemm_bf<<<dim3(DM / 64, NT / 128), 256, GEMM_SMEM>>>(
            NT, DM, DI, p_combhi, p_comblo, p_O, DM);
        k_final<<<NT, 256>>>(fin_w, fin_b, (L == 1) ? (float*)d_out : nullptr);
    }
}

// round 7
// speedup vs baseline: 1.3797x; 1.3797x over previous
#include <cuda_runtime.h>
#include <cuda_bf16.h>
#include <math.h>

#define NT 16384
#define DM 256
#define DI 512
#define DS 64
#define NH 8
#define HD 64
#define CD 640      // CONV_DIM
#define DP 1160     // D_PROJ
#define KER 4
#define NCH 256     // number of chunks
#define CQ 64       // chunk length
#define SR 68       // padded row stride for 64-col smem tiles
#define NPIN 1216   // padded N for in_proj (19*64)
#define WSTR 20     // GEMM smem row stride in uints

// ---------------- device scratch ----------------
__device__ float g_q[NT * DM];
__device__ unsigned g_qnhi[NT * (DM / 2)];
__device__ unsigned g_qnlo[NT * (DM / 2)];
__device__ float g_Z[NT * DP];
__device__ float g_XBC[2 * NT * CD];
__device__ float g_dt[2 * NT * NH];
__device__ float g_a[2 * NT * NH];
__device__ float g_cum[2 * NH * NCH * CQ];
__device__ float g_cdec[2 * NH * NCH];
__device__ float g_S[2 * NH * NCH * HD * DS];
__device__ float g_Hp[2 * NH * NCH * HD * DS];
__device__ float g_Y[2 * NT * DI];
__device__ unsigned g_combhi[NT * (DI / 2)];
__device__ unsigned g_comblo[NT * (DI / 2)];
__device__ float g_O[NT * DM];
__device__ unsigned g_Whi[NPIN * (DM / 2)];
__device__ unsigned g_Wlo[NPIN * (DM / 2)];
__device__ unsigned long long g_keys[2 * NT];
__device__ int g_order[2 * NT];
__device__ int g_inv[2 * NT];
__device__ float g_pmin[3], g_pmax[3];

extern __shared__ float dynsmem[];

// ---------------- helpers ----------------
__device__ __forceinline__ float blockReduceSum(float v) {
    __shared__ float sh[32];
    __shared__ float tot;
    int lane = threadIdx.x & 31, wid = threadIdx.x >> 5;
    #pragma unroll
    for (int o = 16; o > 0; o >>= 1) v += __shfl_xor_sync(0xffffffffu, v, o);
    if (lane == 0) sh[wid] = v;
    __syncthreads();
    int nw = blockDim.x >> 5;
    v = (threadIdx.x < nw) ? sh[threadIdx.x] : 0.0f;
    if (wid == 0) {
        #pragma unroll
        for (int o = 16; o > 0; o >>= 1) v += __shfl_xor_sync(0xffffffffu, v, o);
        if (lane == 0) tot = v;
    }
    __syncthreads();
    return tot;
}

__device__ __forceinline__ unsigned hilbert3(unsigned a0, unsigned a1, unsigned a2) {
    unsigned x0 = a0, x1 = a1, x2 = a2;
    const unsigned M = 1u << 9;
    for (unsigned Q = M; Q > 1; Q >>= 1) {
        unsigned P = Q - 1;
        if (x0 & Q) x0 ^= P;
        {
            unsigned t = (x0 ^ x1) & P;
            if (x1 & Q) { x0 ^= P; } else { x0 ^= t; x1 ^= t; }
        }
        {
            unsigned t = (x0 ^ x2) & P;
            if (x2 & Q) { x0 ^= P; } else { x0 ^= t; x2 ^= t; }
        }
    }
    x1 ^= x0;
    x2 ^= x1;
    unsigned t = 0;
    for (unsigned Q = M; Q > 1; Q >>= 1)
        if (x2 & Q) t ^= (Q - 1);
    x0 ^= t; x1 ^= t; x2 ^= t;
    unsigned code = 0;
    for (int b = 9; b >= 0; b--) {
        code = (code << 1) | ((x0 >> b) & 1);
        code = (code << 1) | ((x1 >> b) & 1);
        code = (code << 1) | ((x2 >> b) & 1);
    }
    return code;
}

__device__ __forceinline__ void bfsplit(float x, unsigned short& hi, unsigned short& lo) {
    __nv_bfloat16 h = __float2bfloat16(x);
    __nv_bfloat16 l = __float2bfloat16(x - __bfloat162float(h));
    hi = *(unsigned short*)&h;
    lo = *(unsigned short*)&l;
}

__device__ __forceinline__ void mma_bf16(float c[4], const unsigned a[4],
                                         unsigned b0, unsigned b1) {
    asm volatile("mma.sync.aligned.m16n8k16.row.col.f32.bf16.bf16.f32 "
        "{%0,%1,%2,%3}, {%4,%5,%6,%7}, {%8,%9}, {%0,%1,%2,%3};"
        : "+f"(c[0]), "+f"(c[1]), "+f"(c[2]), "+f"(c[3])
        : "r"(a[0]), "r"(a[1]), "r"(a[2]), "r"(a[3]), "r"(b0), "r"(b1));
}

__device__ __forceinline__ void cp16(unsigned dst, const void* src) {
    asm volatile("cp.async.cg.shared.global [%0], [%1], 16;" :: "r"(dst), "l"(src));
}

// ---------------- setup kernels ----------------
__global__ void k_minmax(const float* __restrict__ pos) {
    __shared__ float smn[256][3], smx[256][3];
    float mn[3] = {1e30f, 1e30f, 1e30f}, mx[3] = {-1e30f, -1e30f, -1e30f};
    for (int r = threadIdx.x; r < NT; r += 256) {
        #pragma unroll
        for (int j = 0; j < 3; j++) {
            float v = pos[r * 3 + j];
            mn[j] = fminf(mn[j], v);
            mx[j] = fmaxf(mx[j], v);
        }
    }
    #pragma unroll
    for (int j = 0; j < 3; j++) { smn[threadIdx.x][j] = mn[j]; smx[threadIdx.x][j] = mx[j]; }
    __syncthreads();
    for (int s = 128; s > 0; s >>= 1) {
        if (threadIdx.x < s) {
            #pragma unroll
            for (int j = 0; j < 3; j++) {
                smn[threadIdx.x][j] = fminf(smn[threadIdx.x][j], smn[threadIdx.x + s][j]);
                smx[threadIdx.x][j] = fmaxf(smx[threadIdx.x][j], smx[threadIdx.x + s][j]);
            }
        }
        __syncthreads();
    }
    if (threadIdx.x == 0) {
        #pragma unroll
        for (int j = 0; j < 3; j++) { g_pmin[j] = smn[0][j]; g_pmax[j] = smx[0][j]; }
    }
}

__global__ void k_keys(const float* __restrict__ pos) {
    int idx = blockIdx.x * blockDim.x + threadIdx.x;
    if (idx >= NT) return;
    unsigned g[3];
    #pragma unroll
    for (int j = 0; j < 3; j++) {
        float denom = g_pmax[j] - g_pmin[j] + 1e-6f;
        float v = ((pos[idx * 3 + j] - g_pmin[j]) / denom) * 1023.0f;
        v = fminf(fmaxf(v, 0.0f), 1023.0f);
        g[j] = (unsigned)(int)v;
    }
    unsigned c0 = hilbert3(g[0], g[1], g[2]);
    unsigned c1 = hilbert3(g[1], g[0], g[2]);
    g_keys[idx]      = (((unsigned long long)c0) << 14) | (unsigned long long)idx;
    g_keys[NT + idx] = (((unsigned long long)c1) << 14) | (unsigned long long)idx;
}

#define SADDR(i) ((i) + ((i) >> 4))

__global__ void k_sort() {
    unsigned long long* s = (unsigned long long*)dynsmem;
    unsigned long long* keys = g_keys + blockIdx.x * NT;
    int t = threadIdx.x;
    for (int i = t; i < NT; i += 1024) s[SADDR(i)] = keys[i];
    __syncthreads();

    int base = t * 16;
    unsigned long long v[16];
    #pragma unroll
    for (int r = 0; r < 16; r++) v[r] = s[SADDR(base + r)];
    #pragma unroll
    for (int k = 2; k <= 16; k <<= 1) {
        #pragma unroll
        for (int j = k >> 1; j > 0; j >>= 1) {
            #pragma unroll
            for (int r = 0; r < 16; r++) {
                int rr = r ^ j;
                if (rr > r) {
                    bool up = (((base + r) & k) == 0);
                    unsigned long long a = v[r], b = v[rr];
                    if ((a > b) == up) { v[r] = b; v[rr] = a; }
                }
            }
        }
    }
    #pragma unroll
    for (int r = 0; r < 16; r++) s[SADDR(base + r)] = v[r];
    __syncthreads();

    for (int k = 32; k <= NT; k <<= 1) {
        for (int j = k >> 1; j >= 16; j >>= 1) {
            for (int i = t; i < NT; i += 1024) {
                int ixj = i ^ j;
                if (ixj > i) {
                    unsigned long long a = s[SADDR(i)], b = s[SADDR(ixj)];
                    bool up = ((i & k) == 0);
                    if ((a > b) == up) { s[SADDR(i)] = b; s[SADDR(ixj)] = a; }
                }
            }
            __syncthreads();
        }
        #pragma unroll
        for (int r = 0; r < 16; r++) v[r] = s[SADDR(base + r)];
        bool up = ((base & k) == 0);
        #pragma unroll
        for (int j = 8; j > 0; j >>= 1) {
            #pragma unroll
            for (int r = 0; r < 16; r++) {
                int rr = r ^ j;
                if (rr > r) {
                    unsigned long long a = v[r], b = v[rr];
                    if ((a > b) == up) { v[r] = b; v[rr] = a; }
                }
            }
        }
        #pragma unroll
        for (int r = 0; r < 16; r++) s[SADDR(base + r)] = v[r];
        __syncthreads();
    }
    for (int i = t; i < NT; i += 1024) keys[i] = s[SADDR(i)];
}

__global__ void k_order() {
    int i = blockIdx.x * blockDim.x + threadIdx.x;
    if (i >= 2 * NT) return;
    int b = i / NT;
    int idx = (int)(g_keys[i] & 0x3FFFULL);
    g_order[i] = idx;
    g_inv[b * NT + idx] = i - b * NT;
}

// LN from src pointer -> packed bf16 hi/lo (128 threads, 2 cols each)
__global__ void k_ln256(const float* __restrict__ src,
                        const float* __restrict__ w, const float* __restrict__ bias) {
    int r = blockIdx.x, t = threadIdx.x;
    float2 v = *(const float2*)(src + (size_t)r * DM + 2 * t);
    float mean = blockReduceSum(v.x + v.y) * (1.0f / DM);
    float x0 = v.x - mean, x1 = v.y - mean;
    float var = blockReduceSum(x0 * x0 + x1 * x1) * (1.0f / DM);
    float rs = rsqrtf(var + 1e-5f);
    float r0 = x0 * rs * w[2 * t] + bias[2 * t];
    float r1 = x1 * rs * w[2 * t + 1] + bias[2 * t + 1];
    unsigned short h0, l0, h1, l1;
    bfsplit(r0, h0, l0);
    bfsplit(r1, h1, l1);
    g_qnhi[r * (DM / 2) + t] = (unsigned)h0 | ((unsigned)h1 << 16);
    g_qnlo[r * (DM / 2) + t] = (unsigned)l0 | ((unsigned)l1 << 16);
}

__global__ void k_splitW(const float* __restrict__ src, int K, int N, int NP) {
    int idx = blockIdx.x * blockDim.x + threadIdx.x;
    if (idx >= (K / 2) * NP) return;
    int kp = idx / NP, n = idx - kp * NP;
    float w0 = (n < N) ? src[(size_t)(2 * kp) * N + n] : 0.0f;
    float w1 = (n < N) ? src[(size_t)(2 * kp + 1) * N + n] : 0.0f;
    unsigned short h0, l0, h1, l1;
    bfsplit(w0, h0, l0);
    bfsplit(w1, h1, l1);
    g_Whi[(size_t)n * (K / 2) + kp] = (unsigned)h0 | ((unsigned)h1 << 16);
    g_Wlo[(size_t)n * (K / 2) + kp] = (unsigned)l0 | ((unsigned)l1 << 16);
}

// ---------------- bf16x3 tensor-core GEMM (R4-proven scalar-LDS version) ----------------
__device__ __forceinline__ void gemm_load_bf(
    const unsigned* __restrict__ Ahi, const unsigned* __restrict__ Alo, int K2,
    const unsigned* __restrict__ Bhi, const unsigned* __restrict__ Blo,
    int m0, int n0, int kt, unsigned* sAh, unsigned* sAl,
    unsigned* sBh, unsigned* sBl, int tid) {
    int kp0 = kt * 16;
    int r = tid >> 1, cu = (tid & 1) * 8;
    const unsigned* pah = Ahi + (size_t)(m0 + r) * K2 + kp0 + cu;
    const unsigned* pal = Alo + (size_t)(m0 + r) * K2 + kp0 + cu;
    unsigned dah = (unsigned)__cvta_generic_to_shared(sAh + r * WSTR + cu);
    unsigned dal = (unsigned)__cvta_generic_to_shared(sAl + r * WSTR + cu);
    cp16(dah, pah); cp16(dah + 16, pah + 4);
    cp16(dal, pal); cp16(dal + 16, pal + 4);
    int n = tid >> 2, cb = (tid & 3) * 4;
    cp16((unsigned)__cvta_generic_to_shared(sBh + n * WSTR + cb),
         Bhi + (size_t)(n0 + n) * K2 + kp0 + cb);
    cp16((unsigned)__cvta_generic_to_shared(sBl + n * WSTR + cb),
         Blo + (size_t)(n0 + n) * K2 + kp0 + cb);
}

__global__ __launch_bounds__(256) void k_gemm_bf(int M, int N, int K,
        const unsigned* __restrict__ Ahi, const unsigned* __restrict__ Alo,
        float* __restrict__ C, int ldc) {
    const unsigned* Bhi = g_Whi;
    const unsigned* Blo = g_Wlo;
    unsigned* sm = (unsigned*)dynsmem;
    const int ASZ = 128 * WSTR, BSZ = 64 * WSTR;
    const int STG = 2 * ASZ + 2 * BSZ;

    int m0 = blockIdx.y * 128, n0 = blockIdx.x * 64;
    int tid = threadIdx.x;
    int wid = tid >> 5, lane = tid & 31;
    int wm = (wid & 3) * 32, wn = (wid >> 2) * 32;
    int g = lane >> 2, tg = lane & 3;
    int K2 = K >> 1;
    int KT = K / 32;

    float acc[2][4][4];
    #pragma unroll
    for (int a = 0; a < 2; a++)
        #pragma unroll
        for (int b = 0; b < 4; b++)
            #pragma unroll
            for (int c = 0; c < 4; c++) acc[a][b][c] = 0.0f;

    gemm_load_bf(Ahi, Alo, K2, Bhi, Blo, m0, n0, 0,
                 sm, sm + ASZ, sm + 2 * ASZ, sm + 2 * ASZ + BSZ, tid);
    asm volatile("cp.async.commit_group;");

    for (int kt = 0; kt < KT; kt++) {
        int st = kt & 1;
        if (kt + 1 < KT) {
            int ns = st ^ 1;
            unsigned* b0 = sm + ns * STG;
            gemm_load_bf(Ahi, Alo, K2, Bhi, Blo, m0, n0, kt + 1,
                         b0, b0 + ASZ, b0 + 2 * ASZ, b0 + 2 * ASZ + BSZ, tid);
            asm volatile("cp.async.commit_group;");
            asm volatile("cp.async.wait_group 1;");
        } else {
            asm volatile("cp.async.wait_group 0;");
        }
        __syncthreads();
        unsigned* sAhi = sm + st * STG;
        unsigned* sAlo = sAhi + ASZ;
        unsigned* sBhi = sAhi + 2 * ASZ;
        unsigned* sBlo = sBhi + BSZ;
        #pragma unroll
        for (int kk2 = 0; kk2 < 16; kk2 += 8) {
            unsigned ahi[2][4], alo[2][4], bhi[4][2], blo[4][2];
            #pragma unroll
            for (int mi = 0; mi < 2; mi++) {
                int ra = (wm + mi * 16 + g) * WSTR;
                int rb = (wm + mi * 16 + g + 8) * WSTR;
                ahi[mi][0] = sAhi[ra + kk2 + tg];
                ahi[mi][1] = sAhi[rb + kk2 + tg];
                ahi[mi][2] = sAhi[ra + kk2 + 4 + tg];
                ahi[mi][3] = sAhi[rb + kk2 + 4 + tg];
                alo[mi][0] = sAlo[ra + kk2 + tg];
                alo[mi][1] = sAlo[rb + kk2 + tg];
                alo[mi][2] = sAlo[ra + kk2 + 4 + tg];
                alo[mi][3] = sAlo[rb + kk2 + 4 + tg];
            }
            #pragma unroll
            for (int nj = 0; nj < 4; nj++) {
                int rn = (wn + nj * 8 + g) * WSTR;
                bhi[nj][0] = sBhi[rn + kk2 + tg];
                bhi[nj][1] = sBhi[rn + kk2 + 4 + tg];
                blo[nj][0] = sBlo[rn + kk2 + tg];
                blo[nj][1] = sBlo[rn + kk2 + 4 + tg];
            }
            #pragma unroll
            for (int mi = 0; mi < 2; mi++)
                #pragma unroll
                for (int nj = 0; nj < 4; nj++) {
                    mma_bf16(acc[mi][nj], ahi[mi], bhi[nj][0], bhi[nj][1]);
                    mma_bf16(acc[mi][nj], ahi[mi], blo[nj][0], blo[nj][1]);
                    mma_bf16(acc[mi][nj], alo[mi], bhi[nj][0], bhi[nj][1]);
                }
        }
        __syncthreads();
    }
    #pragma unroll
    for (int mi = 0; mi < 2; mi++)
        #pragma unroll
        for (int nj = 0; nj < 4; nj++) {
            int row = m0 + wm + mi * 16 + g;
            int col = n0 + wn + nj * 8 + tg * 2;
            if (col + 1 < N) {
                *(float2*)(C + (size_t)row * ldc + col) =
                    make_float2(acc[mi][nj][0], acc[mi][nj][1]);
                *(float2*)(C + (size_t)(row + 8) * ldc + col) =
                    make_float2(acc[mi][nj][2], acc[mi][nj][3]);
            } else if (col < N) {
                C[(size_t)row * ldc + col] = acc[mi][nj][0];
                C[(size_t)(row + 8) * ldc + col] = acc[mi][nj][2];
            }
        }
}

// ---------------- conv + dt (R4 versions) ----------------
__global__ void k_conv(const float* __restrict__ cw, const float* __restrict__ cb) {
    int r = blockIdx.x, b = blockIdx.y;
    __shared__ int tok[KER];
    if (threadIdx.x < KER) {
        int rr = r - (KER - 1) + threadIdx.x;
        tok[threadIdx.x] = (rr >= 0) ? g_order[b * NT + rr] : -1;
    }
    __syncthreads();
    for (int c = threadIdx.x; c < CD; c += blockDim.x) {
        float acc = cb[c];
        #pragma unroll
        for (int k = 0; k < KER; k++) {
            int t = tok[k];
            if (t >= 0) acc += cw[c * KER + k] * g_Z[(size_t)t * DP + DI + c];
        }
        float s = acc / (1.0f + __expf(-acc));
        g_XBC[(size_t)(b * NT + r) * CD + c] = s;
    }
}

__global__ void k_dt(const float* __restrict__ dtb, const float* __restrict__ alog) {
    int i = blockIdx.x * blockDim.x + threadIdx.x;
    if (i >= 2 * NT * NH) return;
    int b = i / (NT * NH);
    int rem = i - b * NT * NH;
    int r = rem / NH, h = rem - r * NH;
    int t = g_order[b * NT + r];
    float x = g_Z[(size_t)t * DP + DI + CD + h] + dtb[h];
    float sp = fmaxf(x, 0.0f) + log1pf(expf(-fabsf(x)));
    float A = -expf(alog[h]);
    g_dt[i] = sp;
    g_a[i] = sp * A;
}

// ---------------- chunked scan ----------------
__global__ __launch_bounds__(256) void k_scan1() {
    int c = blockIdx.x, h = blockIdx.y, b = blockIdx.z;
    __shared__ float sX[CQ * SR], sB[CQ * SR];
    __shared__ float scum[CQ], sw[CQ];
    int r0 = c * CQ, tid = threadIdx.x;
    for (int idx = tid; idx < CQ * 64; idx += 256) {
        int j = idx >> 6, p = idx & 63;
        sX[j * SR + p] = g_XBC[(size_t)(b * NT + r0 + j) * CD + h * HD + p];
        sB[j * SR + p] = g_XBC[(size_t)(b * NT + r0 + j) * CD + DI + p];
    }
    if (tid < CQ) scum[tid] = g_a[(size_t)(b * NT + r0 + tid) * NH + h];
    __syncthreads();
    if (tid < CQ) {
        float x = scum[tid];
        #pragma unroll
        for (int o = 1; o < 32; o <<= 1) {
            float y = __shfl_up_sync(0xffffffffu, x, o);
            if ((tid & 31) >= o) x += y;
        }
        scum[tid] = x;
    }
    __syncthreads();
    if (tid >= 32 && tid < CQ) scum[tid] += scum[31];
    __syncthreads();
    float slast = scum[CQ - 1];
    if (tid < CQ) {
        sw[tid] = __expf(slast - scum[tid]) * g_dt[(size_t)(b * NT + r0 + tid) * NH + h];
        g_cum[((b * NH + h) * NCH + c) * CQ + tid] = scum[tid];
    }
    if (tid == 0) g_cdec[(b * NH + h) * NCH + c] = __expf(slast);
    __syncthreads();
    int p0 = (tid & 15) * 4, s0 = (tid >> 4) * 4;
    float acc[4][4] = {};
    for (int j = 0; j < CQ; j++) {
        float4 xv = *(float4*)&sX[j * SR + p0];
        float4 bv = *(float4*)&sB[j * SR + s0];
        float w = sw[j];
        float wx[4] = {xv.x * w, xv.y * w, xv.z * w, xv.w * w};
        float bb[4] = {bv.x, bv.y, bv.z, bv.w};
        #pragma unroll
        for (int pi = 0; pi < 4; pi++)
            #pragma unroll
            for (int si = 0; si < 4; si++) acc[pi][si] += wx[pi] * bb[si];
    }
    size_t base = ((size_t)((b * NH + h) * NCH + c) * HD) * DS;
    #pragma unroll
    for (int pi = 0; pi < 4; pi++)
        *(float4*)&g_S[base + (size_t)(p0 + pi) * DS + s0] =
            make_float4(acc[pi][0], acc[pi][1], acc[pi][2], acc[pi][3]);
}

__global__ void k_scan2() {
    __shared__ float scd[NCH];
    int bh = blockIdx.x >> 4;
    int e = ((blockIdx.x & 15) << 8) + threadIdx.x;
    if (threadIdx.x < NCH) scd[threadIdx.x] = g_cdec[bh * NCH + threadIdx.x];
    __syncthreads();
    float H = 0.0f;
    for (int c = 0; c < NCH; c++) {
        size_t off = ((size_t)(bh * NCH + c)) * (HD * DS) + e;
        float s = g_S[off];
        g_Hp[off] = H;
        H = scd[c] * H + s;
    }
}

__global__ __launch_bounds__(256) void k_scan3(const float* __restrict__ Dv) {
    int c = blockIdx.x, b = blockIdx.y;
    int r0 = c * CQ, tid = threadIdx.x;
    float* sB  = dynsmem;
    float* sC  = sB  + CQ * SR;
    float* sD0 = sC  + CQ * SR;
    float* sX  = sD0 + CQ * SR;
    float* sH  = sX  + CQ * SR;
    float* sG  = sH  + CQ * SR;
    float* scum = sG + CQ * SR;
    float* sdt  = scum + CQ;
    float* seY  = sdt + CQ;

    for (int idx = tid; idx < CQ * 64; idx += 256) {
        int j = idx >> 6, s = idx & 63;
        sB[j * SR + s] = g_XBC[(size_t)(b * NT + r0 + j) * CD + DI + s];
        sC[j * SR + s] = g_XBC[(size_t)(b * NT + r0 + j) * CD + DI + DS + s];
    }
    __syncthreads();
    int i0 = (tid >> 4) * 4, j0 = (tid & 15) * 4;
    {
        float acc[4][4] = {};
        for (int sc = 0; sc < 64; sc += 4) {
            float4 Cr[4], Br[4];
            #pragma unroll
            for (int r = 0; r < 4; r++) Cr[r] = *(float4*)&sC[(i0 + r) * SR + sc];
            #pragma unroll
            for (int q = 0; q < 4; q++) Br[q] = *(float4*)&sB[(j0 + q) * SR + sc];
            #pragma unroll
            for (int r = 0; r < 4; r++) {
                float cr[4] = {Cr[r].x, Cr[r].y, Cr[r].z, Cr[r].w};
                #pragma unroll
                for (int q = 0; q < 4; q++) {
                    acc[r][q] += cr[0] * Br[q].x + cr[1] * Br[q].y +
                                 cr[2] * Br[q].z + cr[3] * Br[q].w;
                }
            }
        }
        #pragma unroll
        for (int r = 0; r < 4; r++)
            *(float4*)&sD0[(i0 + r) * SR + j0] =
                make_float4(acc[r][0], acc[r][1], acc[r][2], acc[r][3]);
    }
    __syncthreads();

    for (int h = 0; h < NH; h++) {
        for (int idx = tid; idx < CQ * 64; idx += 256) {
            int j = idx >> 6, p = idx & 63;
            sX[j * SR + p] = g_XBC[(size_t)(b * NT + r0 + j) * CD + h * HD + p];
            sH[j * SR + p] = g_Hp[((size_t)((b * NH + h) * NCH + c) * HD) * DS + idx];
        }
        if (tid < CQ) {
            float cu = g_cum[((b * NH + h) * NCH + c) * CQ + tid];
            scum[tid] = cu;
            sdt[tid] = g_dt[(size_t)(b * NT + r0 + tid) * NH + h];
            seY[tid] = __expf(cu);
        }
        __syncthreads();
        {
            #pragma unroll
            for (int r = 0; r < 4; r++) {
                float4 d = *(float4*)&sD0[(i0 + r) * SR + j0];
                float dd[4] = {d.x, d.y, d.z, d.w};
                float gv[4];
                int i = i0 + r;
                float ci = scum[i];
                #pragma unroll
                for (int q = 0; q < 4; q++) {
                    int j = j0 + q;
                    gv[q] = (j <= i) ? __expf(ci - scum[j]) * sdt[j] * dd[q] : 0.0f;
                }
                *(float4*)&sG[(i0 + r) * SR + j0] = make_float4(gv[0], gv[1], gv[2], gv[3]);
            }
        }
        __syncthreads();
        int p0 = j0;
        float acc[4][4] = {};
        for (int sc = 0; sc < 64; sc += 4) {
            float4 Cr[4], Hc[4];
            #pragma unroll
            for (int r = 0; r < 4; r++) Cr[r] = *(float4*)&sC[(i0 + r) * SR + sc];
            #pragma unroll
            for (int q = 0; q < 4; q++) Hc[q] = *(float4*)&sH[(p0 + q) * SR + sc];
            #pragma unroll
            for (int r = 0; r < 4; r++) {
                float cr[4] = {Cr[r].x, Cr[r].y, Cr[r].z, Cr[r].w};
                #pragma unroll
                for (int q = 0; q < 4; q++) {
                    acc[r][q] += cr[0] * Hc[q].x + cr[1] * Hc[q].y +
                                 cr[2] * Hc[q].z + cr[3] * Hc[q].w;
                }
            }
        }
        #pragma unroll
        for (int r = 0; r < 4; r++) {
            float e = seY[i0 + r];
            #pragma unroll
            for (int q = 0; q < 4; q++) acc[r][q] *= e;
        }
        for (int jc = 0; jc < 64; jc += 4) {
            float G4[4][4];
            #pragma unroll
            for (int r = 0; r < 4; r++) {
                float4 t = *(float4*)&sG[(i0 + r) * SR + jc];
                G4[r][0] = t.x; G4[r][1] = t.y; G4[r][2] = t.z; G4[r][3] = t.w;
            }
            #pragma unroll
            for (int q = 0; q < 4; q++) {
                float4 xv = *(float4*)&sX[(jc + q) * SR + p0];
                float xb[4] = {xv.x, xv.y, xv.z, xv.w};
                #pragma unroll
                for (int r = 0; r < 4; r++) {
                    float gq = G4[r][q];
                    #pragma unroll
                    for (int cc = 0; cc < 4; cc++) acc[r][cc] += gq * xb[cc];
                }
            }
        }
        float Dh = Dv[h];
        #pragma unroll
        for (int r = 0; r < 4; r++) {
            float4 xi = *(float4*)&sX[(i0 + r) * SR + p0];
            float4 yv = make_float4(acc[r][0] + Dh * xi.x, acc[r][1] + Dh * xi.y,
                                    acc[r][2] + Dh * xi.z, acc[r][3] + Dh * xi.w);
            *(float4*)&g_Y[(size_t)(b * NT + r0 + i0 + r) * DI + h * HD + p0] = yv;
        }
        __syncthreads();
    }
}

// ---------------- epilogue ----------------
__global__ void k_postnorm(const float* __restrict__ nw) {
    int r = blockIdx.x, b = blockIdx.y, tid = threadIdx.x;
    int t = g_order[b * NT + r];
    float v0, v1, ss;
    {
        float y0 = g_Y[(size_t)(b * NT + r) * DI + tid];
        float g0 = g_Z[(size_t)t * DP + tid];
        v0 = y0 * (g0 / (1.0f + __expf(-g0)));
        float y1 = g_Y[(size_t)(b * NT + r) * DI + tid + 256];
        float g1 = g_Z[(size_t)t * DP + tid + 256];
        v1 = y1 * (g1 / (1.0f + __expf(-g1)));
        ss = v0 * v0 + v1 * v1;
    }
    ss = blockReduceSum(ss);
    float rr = rsqrtf(ss * (1.0f / DI) + 1e-5f);
    g_Y[(size_t)(b * NT + r) * DI + tid]       = v0 * rr * nw[tid];
    g_Y[(size_t)(b * NT + r) * DI + tid + 256] = v1 * rr * nw[tid + 256];
}

__global__ void k_combine() {
    int t = blockIdx.x, c = threadIdx.x;
    int r0 = g_inv[t], r1 = g_inv[NT + t];
    float2 a = *(const float2*)(g_Y + (size_t)r0 * DI + 2 * c);
    float2 bq = *(const float2*)(g_Y + (size_t)(NT + r1) * DI + 2 * c);
    float v0 = 0.5f * (a.x + bq.x);
    float v1 = 0.5f * (a.y + bq.y);
    unsigned short h0, l0, h1, l1;
    bfsplit(v0, h0, l0);
    bfsplit(v1, h1, l1);
    g_combhi[(size_t)t * (DI / 2) + c] = (unsigned)h0 | ((unsigned)h1 << 16);
    g_comblo[(size_t)t * (DI / 2) + c] = (unsigned)l0 | ((unsigned)l1 << 16);
}

// final LN; residual read from res pointer (query for L0, g_q for L1)
__global__ void k_final(const float* __restrict__ res,
                        const float* __restrict__ w, const float* __restrict__ bias,
                        float* __restrict__ dout) {
    int r = blockIdx.x, c = threadIdx.x;
    float v = res[(size_t)r * DM + c] + g_O[r * DM + c];
    float mean = blockReduceSum(v) * (1.0f / DM);
    float xc = v - mean;
    float var = blockReduceSum(xc * xc) * (1.0f / DM);
    float result = xc * rsqrtf(var + 1e-5f) * w[c] + bias[c];
    g_q[r * DM + c] = result;
    if (dout) dout[r * DM + c] = result;
}

// ---------------- launcher ----------------
extern "C" void kernel_launch(void* const* d_in, const int* in_sizes, int n_in,
                              void* d_out, int out_size) {
    (void)in_sizes; (void)n_in; (void)out_size;
    const float* query = (const float*)d_in[0];
    const float* pos   = (const float*)d_in[1];
    const float* pre_w = (const float*)d_in[2];
    const float* pre_b = (const float*)d_in[3];
    const float* fin_w = (const float*)d_in[4];
    const float* fin_b = (const float*)d_in[5];

    const int SORT_SMEM = (NT + NT / 16) * 8;
    const int GEMM_SMEM = 2 * (2 * 128 * WSTR + 2 * 64 * WSTR) * 4;
    const int SCAN3_SMEM = (6 * CQ * SR + 3 * CQ) * 4;
    cudaFuncSetAttribute(k_sort, cudaFuncAttributeMaxDynamicSharedMemorySize, SORT_SMEM);
    cudaFuncSetAttribute(k_gemm_bf, cudaFuncAttributeMaxDynamicSharedMemorySize, GEMM_SMEM);
    cudaFuncSetAttribute(k_scan3, cudaFuncAttributeMaxDynamicSharedMemorySize, SCAN3_SMEM);

    unsigned *p_qnhi, *p_qnlo, *p_combhi, *p_comblo;
    float *p_Z, *p_O, *p_q;
    cudaGetSymbolAddress((void**)&p_qnhi, g_qnhi);
    cudaGetSymbolAddress((void**)&p_qnlo, g_qnlo);
    cudaGetSymbolAddress((void**)&p_combhi, g_combhi);
    cudaGetSymbolAddress((void**)&p_comblo, g_comblo);
    cudaGetSymbolAddress((void**)&p_Z, g_Z);
    cudaGetSymbolAddress((void**)&p_O, g_O);
    cudaGetSymbolAddress((void**)&p_q, g_q);

    k_minmax<<<1, 256>>>(pos);
    k_keys<<<(NT + 255) / 256, 256>>>(pos);
    k_sort<<<2, 1024, SORT_SMEM>>>();
    k_order<<<(2 * NT + 255) / 256, 256>>>();

    for (int L = 0; L < 2; L++) {
        const float* Win  = (const float*)d_in[6 + 8 * L];
        const float* cw   = (const float*)d_in[7 + 8 * L];
        const float* cb   = (const float*)d_in[8 + 8 * L];
        const float* dtb  = (const float*)d_in[9 + 8 * L];
        const float* alog = (const float*)d_in[10 + 8 * L];
        const float* Dv   = (const float*)d_in[11 + 8 * L];
        const float* nw   = (const float*)d_in[12 + 8 * L];
        const float* Wout = (const float*)d_in[13 + 8 * L];
        const float* src  = (L == 0) ? query : p_q;

        k_ln256<<<NT, 128>>>(src, pre_w, pre_b);
        k_splitW<<<((DM / 2) * NPIN + 255) / 256, 256>>>(Win, DM, DP, NPIN);
        k_gemm_bf<<<dim3(NPIN / 64, NT / 128), 256, GEMM_SMEM>>>(
            NT, DP, DM, p_qnhi, p_qnlo, p_Z, DP);
        k_conv<<<dim3(NT, 2), 256>>>(cw, cb);
        k_dt<<<(2 * NT * NH + 255) / 256, 256>>>(dtb, alog);
        k_scan1<<<dim3(NCH, NH, 2), 256>>>();
        k_scan2<<<256, 256>>>();
        k_scan3<<<dim3(NCH, 2), 256, SCAN3_SMEM>>>(Dv);
        k_postnorm<<<dim3(NT, 2), 256>>>(nw);
        k_combine<<<NT, 256>>>();
        k_splitW<<<((DI / 2) * DM + 255) / 256, 256>>>(Wout, DI, DM, DM);
        k_gemm_bf<<<dim3(DM / 64, NT / 128), 256, GEMM_SMEM>>>(
            NT, DM, DI, p_combhi, p_comblo, p_O, DM);
        k_final<<<NT, 256>>>(src, fin_w, fin_b, (L == 1) ? (float*)d_out : nullptr);
    }
}

// round 8
// speedup vs baseline: 1.4348x; 1.0399x over previous
#include <cuda_runtime.h>
#include <cuda_bf16.h>
#include <math.h>

#define NT 16384
#define DM 256
#define DI 512
#define DS 64
#define NH 8
#define HD 64
#define CD 640      // CONV_DIM
#define DP 1160     // D_PROJ
#define KER 4
#define NCH 256     // number of chunks
#define CQ 64       // chunk length
#define SR 68       // padded row stride for 64-col smem tiles (16B-aligned rows)
#define NPIN 1216   // padded N for in_proj (19*64)
#define WSTR 20     // GEMM smem row stride in uints

// ---------------- device scratch ----------------
__device__ float g_q[NT * DM];
__device__ unsigned g_qnhi[NT * (DM / 2)];
__device__ unsigned g_qnlo[NT * (DM / 2)];
__device__ float g_Z[NT * DP];
__device__ float g_XBC[2 * NT * CD];
__device__ float g_dt[2 * NT * NH];
__device__ float g_a[2 * NT * NH];
__device__ float g_cum[2 * NH * NCH * CQ];
__device__ float g_cdec[2 * NH * NCH];
__device__ float g_S[2 * NH * NCH * HD * DS];
__device__ float g_Hp[2 * NH * NCH * HD * DS];
__device__ float g_Y[2 * NT * DI];
__device__ unsigned g_combhi[NT * (DI / 2)];
__device__ unsigned g_comblo[NT * (DI / 2)];
__device__ float g_O[NT * DM];
__device__ unsigned g_Whi[NPIN * (DM / 2)];
__device__ unsigned g_Wlo[NPIN * (DM / 2)];
__device__ unsigned long long g_keys[2 * NT];
__device__ int g_order[2 * NT];
__device__ int g_inv[2 * NT];
__device__ float g_pmin[3], g_pmax[3];

extern __shared__ float dynsmem[];

// ---------------- helpers ----------------
__device__ __forceinline__ float blockReduceSum(float v) {
    __shared__ float sh[32];
    __shared__ float tot;
    int lane = threadIdx.x & 31, wid = threadIdx.x >> 5;
    #pragma unroll
    for (int o = 16; o > 0; o >>= 1) v += __shfl_xor_sync(0xffffffffu, v, o);
    if (lane == 0) sh[wid] = v;
    __syncthreads();
    int nw = blockDim.x >> 5;
    v = (threadIdx.x < nw) ? sh[threadIdx.x] : 0.0f;
    if (wid == 0) {
        #pragma unroll
        for (int o = 16; o > 0; o >>= 1) v += __shfl_xor_sync(0xffffffffu, v, o);
        if (lane == 0) tot = v;
    }
    __syncthreads();
    return tot;
}

__device__ __forceinline__ unsigned hilbert3(unsigned a0, unsigned a1, unsigned a2) {
    unsigned x0 = a0, x1 = a1, x2 = a2;
    const unsigned M = 1u << 9;
    for (unsigned Q = M; Q > 1; Q >>= 1) {
        unsigned P = Q - 1;
        if (x0 & Q) x0 ^= P;
        {
            unsigned t = (x0 ^ x1) & P;
            if (x1 & Q) { x0 ^= P; } else { x0 ^= t; x1 ^= t; }
        }
        {
            unsigned t = (x0 ^ x2) & P;
            if (x2 & Q) { x0 ^= P; } else { x0 ^= t; x2 ^= t; }
        }
    }
    x1 ^= x0;
    x2 ^= x1;
    unsigned t = 0;
    for (unsigned Q = M; Q > 1; Q >>= 1)
        if (x2 & Q) t ^= (Q - 1);
    x0 ^= t; x1 ^= t; x2 ^= t;
    unsigned code = 0;
    for (int b = 9; b >= 0; b--) {
        code = (code << 1) | ((x0 >> b) & 1);
        code = (code << 1) | ((x1 >> b) & 1);
        code = (code << 1) | ((x2 >> b) & 1);
    }
    return code;
}

__device__ __forceinline__ void bfsplit(float x, unsigned short& hi, unsigned short& lo) {
    __nv_bfloat16 h = __float2bfloat16(x);
    __nv_bfloat16 l = __float2bfloat16(x - __bfloat162float(h));
    hi = *(unsigned short*)&h;
    lo = *(unsigned short*)&l;
}

__device__ __forceinline__ void mma_bf16(float c[4], const unsigned a[4],
                                         unsigned b0, unsigned b1) {
    asm volatile("mma.sync.aligned.m16n8k16.row.col.f32.bf16.bf16.f32 "
        "{%0,%1,%2,%3}, {%4,%5,%6,%7}, {%8,%9}, {%0,%1,%2,%3};"
        : "+f"(c[0]), "+f"(c[1]), "+f"(c[2]), "+f"(c[3])
        : "r"(a[0]), "r"(a[1]), "r"(a[2]), "r"(a[3]), "r"(b0), "r"(b1));
}

__device__ __forceinline__ void cp16(unsigned dst, const void* src) {
    asm volatile("cp.async.cg.shared.global [%0], [%1], 16;" :: "r"(dst), "l"(src));
}

// ---- packed f32x2 FMA (sm_103a FFMA2) ----
__device__ __forceinline__ void fma2(unsigned long long& c, unsigned long long a,
                                     unsigned long long b) {
    asm("fma.rn.f32x2 %0, %1, %2, %0;" : "+l"(c) : "l"(a), "l"(b));
}
__device__ __forceinline__ unsigned long long bcast2(float x) {
    unsigned long long r;
    unsigned u = __float_as_uint(x);
    asm("mov.b64 %0, {%1, %2};" : "=l"(r) : "r"(u), "r"(u));
    return r;
}
__device__ __forceinline__ unsigned long long packf2(float a, float b) {
    unsigned long long r;
    asm("mov.b64 %0, {%1, %2};" : "=l"(r) : "r"(__float_as_uint(a)), "r"(__float_as_uint(b)));
    return r;
}
__device__ __forceinline__ float2 unpack2(unsigned long long v) {
    unsigned lo, hi;
    asm("mov.b64 {%0, %1}, %2;" : "=r"(lo), "=r"(hi) : "l"(v));
    return make_float2(__uint_as_float(lo), __uint_as_float(hi));
}

// ---------------- setup kernels ----------------
__global__ void k_minmax(const float* __restrict__ pos) {
    __shared__ float smn[256][3], smx[256][3];
    float mn[3] = {1e30f, 1e30f, 1e30f}, mx[3] = {-1e30f, -1e30f, -1e30f};
    for (int r = threadIdx.x; r < NT; r += 256) {
        #pragma unroll
        for (int j = 0; j < 3; j++) {
            float v = pos[r * 3 + j];
            mn[j] = fminf(mn[j], v);
            mx[j] = fmaxf(mx[j], v);
        }
    }
    #pragma unroll
    for (int j = 0; j < 3; j++) { smn[threadIdx.x][j] = mn[j]; smx[threadIdx.x][j] = mx[j]; }
    __syncthreads();
    for (int s = 128; s > 0; s >>= 1) {
        if (threadIdx.x < s) {
            #pragma unroll
            for (int j = 0; j < 3; j++) {
                smn[threadIdx.x][j] = fminf(smn[threadIdx.x][j], smn[threadIdx.x + s][j]);
                smx[threadIdx.x][j] = fmaxf(smx[threadIdx.x][j], smx[threadIdx.x + s][j]);
            }
        }
        __syncthreads();
    }
    if (threadIdx.x == 0) {
        #pragma unroll
        for (int j = 0; j < 3; j++) { g_pmin[j] = smn[0][j]; g_pmax[j] = smx[0][j]; }
    }
}

__global__ void k_keys(const float* __restrict__ pos) {
    int idx = blockIdx.x * blockDim.x + threadIdx.x;
    if (idx >= NT) return;
    unsigned g[3];
    #pragma unroll
    for (int j = 0; j < 3; j++) {
        float denom = g_pmax[j] - g_pmin[j] + 1e-6f;
        float v = ((pos[idx * 3 + j] - g_pmin[j]) / denom) * 1023.0f;
        v = fminf(fmaxf(v, 0.0f), 1023.0f);
        g[j] = (unsigned)(int)v;
    }
    unsigned c0 = hilbert3(g[0], g[1], g[2]);
    unsigned c1 = hilbert3(g[1], g[0], g[2]);
    g_keys[idx]      = (((unsigned long long)c0) << 14) | (unsigned long long)idx;
    g_keys[NT + idx] = (((unsigned long long)c1) << 14) | (unsigned long long)idx;
}

#define SADDR(i) ((i) + ((i) >> 4))

__global__ void k_sort() {
    unsigned long long* s = (unsigned long long*)dynsmem;
    unsigned long long* keys = g_keys + blockIdx.x * NT;
    int t = threadIdx.x;
    for (int i = t; i < NT; i += 1024) s[SADDR(i)] = keys[i];
    __syncthreads();

    int base = t * 16;
    unsigned long long v[16];
    #pragma unroll
    for (int r = 0; r < 16; r++) v[r] = s[SADDR(base + r)];
    #pragma unroll
    for (int k = 2; k <= 16; k <<= 1) {
        #pragma unroll
        for (int j = k >> 1; j > 0; j >>= 1) {
            #pragma unroll
            for (int r = 0; r < 16; r++) {
                int rr = r ^ j;
                if (rr > r) {
                    bool up = (((base + r) & k) == 0);
                    unsigned long long a = v[r], b = v[rr];
                    if ((a > b) == up) { v[r] = b; v[rr] = a; }
                }
            }
        }
    }
    #pragma unroll
    for (int r = 0; r < 16; r++) s[SADDR(base + r)] = v[r];
    __syncthreads();

    for (int k = 32; k <= NT; k <<= 1) {
        for (int j = k >> 1; j >= 16; j >>= 1) {
            for (int i = t; i < NT; i += 1024) {
                int ixj = i ^ j;
                if (ixj > i) {
                    unsigned long long a = s[SADDR(i)], b = s[SADDR(ixj)];
                    bool up = ((i & k) == 0);
                    if ((a > b) == up) { s[SADDR(i)] = b; s[SADDR(ixj)] = a; }
                }
            }
            __syncthreads();
        }
        #pragma unroll
        for (int r = 0; r < 16; r++) v[r] = s[SADDR(base + r)];
        bool up = ((base & k) == 0);
        #pragma unroll
        for (int j = 8; j > 0; j >>= 1) {
            #pragma unroll
            for (int r = 0; r < 16; r++) {
                int rr = r ^ j;
                if (rr > r) {
                    unsigned long long a = v[r], b = v[rr];
                    if ((a > b) == up) { v[r] = b; v[rr] = a; }
                }
            }
        }
        #pragma unroll
        for (int r = 0; r < 16; r++) s[SADDR(base + r)] = v[r];
        __syncthreads();
    }
    for (int i = t; i < NT; i += 1024) keys[i] = s[SADDR(i)];
}

__global__ void k_order() {
    int i = blockIdx.x * blockDim.x + threadIdx.x;
    if (i >= 2 * NT) return;
    int b = i / NT;
    int idx = (int)(g_keys[i] & 0x3FFFULL);
    g_order[i] = idx;
    g_inv[b * NT + idx] = i - b * NT;
}

__global__ void k_ln256(const float* __restrict__ src,
                        const float* __restrict__ w, const float* __restrict__ bias) {
    int r = blockIdx.x, t = threadIdx.x;
    float2 v = *(const float2*)(src + (size_t)r * DM + 2 * t);
    float mean = blockReduceSum(v.x + v.y) * (1.0f / DM);
    float x0 = v.x - mean, x1 = v.y - mean;
    float var = blockReduceSum(x0 * x0 + x1 * x1) * (1.0f / DM);
    float rs = rsqrtf(var + 1e-5f);
    float r0 = x0 * rs * w[2 * t] + bias[2 * t];
    float r1 = x1 * rs * w[2 * t + 1] + bias[2 * t + 1];
    unsigned short h0, l0, h1, l1;
    bfsplit(r0, h0, l0);
    bfsplit(r1, h1, l1);
    g_qnhi[r * (DM / 2) + t] = (unsigned)h0 | ((unsigned)h1 << 16);
    g_qnlo[r * (DM / 2) + t] = (unsigned)l0 | ((unsigned)l1 << 16);
}

__global__ void k_splitW(const float* __restrict__ src, int K, int N, int NP) {
    int idx = blockIdx.x * blockDim.x + threadIdx.x;
    if (idx >= (K / 2) * NP) return;
    int kp = idx / NP, n = idx - kp * NP;
    float w0 = (n < N) ? src[(size_t)(2 * kp) * N + n] : 0.0f;
    float w1 = (n < N) ? src[(size_t)(2 * kp + 1) * N + n] : 0.0f;
    unsigned short h0, l0, h1, l1;
    bfsplit(w0, h0, l0);
    bfsplit(w1, h1, l1);
    g_Whi[(size_t)n * (K / 2) + kp] = (unsigned)h0 | ((unsigned)h1 << 16);
    g_Wlo[(size_t)n * (K / 2) + kp] = (unsigned)l0 | ((unsigned)l1 << 16);
}

// ---------------- bf16x3 tensor-core GEMM (R4-proven) ----------------
__device__ __forceinline__ void gemm_load_bf(
    const unsigned* __restrict__ Ahi, const unsigned* __restrict__ Alo, int K2,
    const unsigned* __restrict__ Bhi, const unsigned* __restrict__ Blo,
    int m0, int n0, int kt, unsigned* sAh, unsigned* sAl,
    unsigned* sBh, unsigned* sBl, int tid) {
    int kp0 = kt * 16;
    int r = tid >> 1, cu = (tid & 1) * 8;
    const unsigned* pah = Ahi + (size_t)(m0 + r) * K2 + kp0 + cu;
    const unsigned* pal = Alo + (size_t)(m0 + r) * K2 + kp0 + cu;
    unsigned dah = (unsigned)__cvta_generic_to_shared(sAh + r * WSTR + cu);
    unsigned dal = (unsigned)__cvta_generic_to_shared(sAl + r * WSTR + cu);
    cp16(dah, pah); cp16(dah + 16, pah + 4);
    cp16(dal, pal); cp16(dal + 16, pal + 4);
    int n = tid >> 2, cb = (tid & 3) * 4;
    cp16((unsigned)__cvta_generic_to_shared(sBh + n * WSTR + cb),
         Bhi + (size_t)(n0 + n) * K2 + kp0 + cb);
    cp16((unsigned)__cvta_generic_to_shared(sBl + n * WSTR + cb),
         Blo + (size_t)(n0 + n) * K2 + kp0 + cb);
}

__global__ __launch_bounds__(256) void k_gemm_bf(int M, int N, int K,
        const unsigned* __restrict__ Ahi, const unsigned* __restrict__ Alo,
        float* __restrict__ C, int ldc) {
    const unsigned* Bhi = g_Whi;
    const unsigned* Blo = g_Wlo;
    unsigned* sm = (unsigned*)dynsmem;
    const int ASZ = 128 * WSTR, BSZ = 64 * WSTR;
    const int STG = 2 * ASZ + 2 * BSZ;

    int m0 = blockIdx.y * 128, n0 = blockIdx.x * 64;
    int tid = threadIdx.x;
    int wid = tid >> 5, lane = tid & 31;
    int wm = (wid & 3) * 32, wn = (wid >> 2) * 32;
    int g = lane >> 2, tg = lane & 3;
    int K2 = K >> 1;
    int KT = K / 32;

    float acc[2][4][4];
    #pragma unroll
    for (int a = 0; a < 2; a++)
        #pragma unroll
        for (int b = 0; b < 4; b++)
            #pragma unroll
            for (int c = 0; c < 4; c++) acc[a][b][c] = 0.0f;

    gemm_load_bf(Ahi, Alo, K2, Bhi, Blo, m0, n0, 0,
                 sm, sm + ASZ, sm + 2 * ASZ, sm + 2 * ASZ + BSZ, tid);
    asm volatile("cp.async.commit_group;");

    for (int kt = 0; kt < KT; kt++) {
        int st = kt & 1;
        if (kt + 1 < KT) {
            int ns = st ^ 1;
            unsigned* b0 = sm + ns * STG;
            gemm_load_bf(Ahi, Alo, K2, Bhi, Blo, m0, n0, kt + 1,
                         b0, b0 + ASZ, b0 + 2 * ASZ, b0 + 2 * ASZ + BSZ, tid);
            asm volatile("cp.async.commit_group;");
            asm volatile("cp.async.wait_group 1;");
        } else {
            asm volatile("cp.async.wait_group 0;");
        }
        __syncthreads();
        unsigned* sAhi = sm + st * STG;
        unsigned* sAlo = sAhi + ASZ;
        unsigned* sBhi = sAhi + 2 * ASZ;
        unsigned* sBlo = sBhi + BSZ;
        #pragma unroll
        for (int kk2 = 0; kk2 < 16; kk2 += 8) {
            unsigned ahi[2][4], alo[2][4], bhi[4][2], blo[4][2];
            #pragma unroll
            for (int mi = 0; mi < 2; mi++) {
                int ra = (wm + mi * 16 + g) * WSTR;
                int rb = (wm + mi * 16 + g + 8) * WSTR;
                ahi[mi][0] = sAhi[ra + kk2 + tg];
                ahi[mi][1] = sAhi[rb + kk2 + tg];
                ahi[mi][2] = sAhi[ra + kk2 + 4 + tg];
                ahi[mi][3] = sAhi[rb + kk2 + 4 + tg];
                alo[mi][0] = sAlo[ra + kk2 + tg];
                alo[mi][1] = sAlo[rb + kk2 + tg];
                alo[mi][2] = sAlo[ra + kk2 + 4 + tg];
                alo[mi][3] = sAlo[rb + kk2 + 4 + tg];
            }
            #pragma unroll
            for (int nj = 0; nj < 4; nj++) {
                int rn = (wn + nj * 8 + g) * WSTR;
                bhi[nj][0] = sBhi[rn + kk2 + tg];
                bhi[nj][1] = sBhi[rn + kk2 + 4 + tg];
                blo[nj][0] = sBlo[rn + kk2 + tg];
                blo[nj][1] = sBlo[rn + kk2 + 4 + tg];
            }
            #pragma unroll
            for (int mi = 0; mi < 2; mi++)
                #pragma unroll
                for (int nj = 0; nj < 4; nj++) {
                    mma_bf16(acc[mi][nj], ahi[mi], bhi[nj][0], bhi[nj][1]);
                    mma_bf16(acc[mi][nj], ahi[mi], blo[nj][0], blo[nj][1]);
                    mma_bf16(acc[mi][nj], alo[mi], bhi[nj][0], bhi[nj][1]);
                }
        }
        __syncthreads();
    }
    #pragma unroll
    for (int mi = 0; mi < 2; mi++)
        #pragma unroll
        for (int nj = 0; nj < 4; nj++) {
            int row = m0 + wm + mi * 16 + g;
            int col = n0 + wn + nj * 8 + tg * 2;
            if (col + 1 < N) {
                *(float2*)(C + (size_t)row * ldc + col) =
                    make_float2(acc[mi][nj][0], acc[mi][nj][1]);
                *(float2*)(C + (size_t)(row + 8) * ldc + col) =
                    make_float2(acc[mi][nj][2], acc[mi][nj][3]);
            } else if (col < N) {
                C[(size_t)row * ldc + col] = acc[mi][nj][0];
                C[(size_t)(row + 8) * ldc + col] = acc[mi][nj][2];
            }
        }
}

// ---------------- conv + dt ----------------
__global__ void k_conv(const float* __restrict__ cw, const float* __restrict__ cb) {
    int r = blockIdx.x, b = blockIdx.y;
    __shared__ int tok[KER];
    if (threadIdx.x < KER) {
        int rr = r - (KER - 1) + threadIdx.x;
        tok[threadIdx.x] = (rr >= 0) ? g_order[b * NT + rr] : -1;
    }
    __syncthreads();
    for (int c = threadIdx.x; c < CD; c += blockDim.x) {
        float acc = cb[c];
        #pragma unroll
        for (int k = 0; k < KER; k++) {
            int t = tok[k];
            if (t >= 0) acc += cw[c * KER + k] * g_Z[(size_t)t * DP + DI + c];
        }
        float s = acc / (1.0f + __expf(-acc));
        g_XBC[(size_t)(b * NT + r) * CD + c] = s;
    }
}

__global__ void k_dt(const float* __restrict__ dtb, const float* __restrict__ alog) {
    int i = blockIdx.x * blockDim.x + threadIdx.x;
    if (i >= 2 * NT * NH) return;
    int b = i / (NT * NH);
    int rem = i - b * NT * NH;
    int r = rem / NH, h = rem - r * NH;
    int t = g_order[b * NT + r];
    float x = g_Z[(size_t)t * DP + DI + CD + h] + dtb[h];
    float sp = fmaxf(x, 0.0f) + log1pf(expf(-fabsf(x)));
    float A = -expf(alog[h]);
    g_dt[i] = sp;
    g_a[i] = sp * A;
}

// ---------------- chunked scan (f32x2-packed math) ----------------
__global__ __launch_bounds__(256) void k_scan1() {
    int c = blockIdx.x, h = blockIdx.y, b = blockIdx.z;
    __shared__ float sX[CQ * SR], sB[CQ * SR];
    __shared__ float scum[CQ], sw[CQ];
    int r0 = c * CQ, tid = threadIdx.x;
    for (int idx = tid; idx < CQ * 64; idx += 256) {
        int j = idx >> 6, p = idx & 63;
        sX[j * SR + p] = g_XBC[(size_t)(b * NT + r0 + j) * CD + h * HD + p];
        sB[j * SR + p] = g_XBC[(size_t)(b * NT + r0 + j) * CD + DI + p];
    }
    if (tid < CQ) scum[tid] = g_a[(size_t)(b * NT + r0 + tid) * NH + h];
    __syncthreads();
    if (tid < CQ) {
        float x = scum[tid];
        #pragma unroll
        for (int o = 1; o < 32; o <<= 1) {
            float y = __shfl_up_sync(0xffffffffu, x, o);
            if ((tid & 31) >= o) x += y;
        }
        scum[tid] = x;
    }
    __syncthreads();
    if (tid >= 32 && tid < CQ) scum[tid] += scum[31];
    __syncthreads();
    float slast = scum[CQ - 1];
    if (tid < CQ) {
        sw[tid] = __expf(slast - scum[tid]) * g_dt[(size_t)(b * NT + r0 + tid) * NH + h];
        g_cum[((b * NH + h) * NCH + c) * CQ + tid] = scum[tid];
    }
    if (tid == 0) g_cdec[(b * NH + h) * NCH + c] = __expf(slast);
    __syncthreads();
    int p0 = (tid & 15) * 4, s0 = (tid >> 4) * 4;
    unsigned long long acc2[4][2] = {};
    for (int j = 0; j < CQ; j++) {
        float4 xv = *(float4*)&sX[j * SR + p0];
        ulonglong2 b2 = *(const ulonglong2*)&sB[j * SR + s0];
        float w = sw[j];
        float wx[4] = {xv.x * w, xv.y * w, xv.z * w, xv.w * w};
        #pragma unroll
        for (int pi = 0; pi < 4; pi++) {
            unsigned long long w2 = bcast2(wx[pi]);
            fma2(acc2[pi][0], w2, b2.x);
            fma2(acc2[pi][1], w2, b2.y);
        }
    }
    size_t base = ((size_t)((b * NH + h) * NCH + c) * HD) * DS;
    #pragma unroll
    for (int pi = 0; pi < 4; pi++) {
        float2 a01 = unpack2(acc2[pi][0]);
        float2 a23 = unpack2(acc2[pi][1]);
        *(float4*)&g_S[base + (size_t)(p0 + pi) * DS + s0] =
            make_float4(a01.x, a01.y, a23.x, a23.y);
    }
}

__global__ void k_scan2() {
    __shared__ float scd[NCH];
    int bh = blockIdx.x >> 4;
    int e = ((blockIdx.x & 15) << 8) + threadIdx.x;
    if (threadIdx.x < NCH) scd[threadIdx.x] = g_cdec[bh * NCH + threadIdx.x];
    __syncthreads();
    float H = 0.0f;
    for (int c = 0; c < NCH; c++) {
        size_t off = ((size_t)(bh * NCH + c)) * (HD * DS) + e;
        float s = g_S[off];
        g_Hp[off] = H;
        H = scd[c] * H + s;
    }
}

__global__ __launch_bounds__(256) void k_scan3(const float* __restrict__ Dv) {
    int c = blockIdx.x, b = blockIdx.y;
    int r0 = c * CQ, tid = threadIdx.x;
    float* sB  = dynsmem;
    float* sC  = sB  + CQ * SR;
    float* sD0 = sC  + CQ * SR;
    float* sX  = sD0 + CQ * SR;
    float* sH  = sX  + CQ * SR;
    float* sG  = sH  + CQ * SR;
    float* scum = sG + CQ * SR;
    float* sdt  = scum + CQ;
    float* seY  = sdt + CQ;

    for (int idx = tid; idx < CQ * 64; idx += 256) {
        int j = idx >> 6, s = idx & 63;
        sB[j * SR + s] = g_XBC[(size_t)(b * NT + r0 + j) * CD + DI + s];
        sC[j * SR + s] = g_XBC[(size_t)(b * NT + r0 + j) * CD + DI + DS + s];
    }
    __syncthreads();
    int i0 = (tid >> 4) * 4, j0 = (tid & 15) * 4;
    // D0 = C @ B^T (packed over the s dimension)
    {
        unsigned long long acc2[4][4] = {};
        for (int sc = 0; sc < 64; sc += 4) {
            ulonglong2 Cr[4], Br[4];
            #pragma unroll
            for (int r = 0; r < 4; r++) Cr[r] = *(const ulonglong2*)&sC[(i0 + r) * SR + sc];
            #pragma unroll
            for (int q = 0; q < 4; q++) Br[q] = *(const ulonglong2*)&sB[(j0 + q) * SR + sc];
            #pragma unroll
            for (int r = 0; r < 4; r++)
                #pragma unroll
                for (int q = 0; q < 4; q++) {
                    fma2(acc2[r][q], Cr[r].x, Br[q].x);
                    fma2(acc2[r][q], Cr[r].y, Br[q].y);
                }
        }
        #pragma unroll
        for (int r = 0; r < 4; r++) {
            float dv[4];
            #pragma unroll
            for (int q = 0; q < 4; q++) {
                float2 p = unpack2(acc2[r][q]);
                dv[q] = p.x + p.y;
            }
            *(float4*)&sD0[(i0 + r) * SR + j0] = make_float4(dv[0], dv[1], dv[2], dv[3]);
        }
    }
    __syncthreads();

    for (int h = 0; h < NH; h++) {
        for (int idx = tid; idx < CQ * 64; idx += 256) {
            int j = idx >> 6, p = idx & 63;
            sX[j * SR + p] = g_XBC[(size_t)(b * NT + r0 + j) * CD + h * HD + p];
            sH[j * SR + p] = g_Hp[((size_t)((b * NH + h) * NCH + c) * HD) * DS + idx];
        }
        if (tid < CQ) {
            float cu = g_cum[((b * NH + h) * NCH + c) * CQ + tid];
            scum[tid] = cu;
            sdt[tid] = g_dt[(size_t)(b * NT + r0 + tid) * NH + h];
            seY[tid] = __expf(cu);
        }
        __syncthreads();
        {
            #pragma unroll
            for (int r = 0; r < 4; r++) {
                float4 d = *(float4*)&sD0[(i0 + r) * SR + j0];
                float dd[4] = {d.x, d.y, d.z, d.w};
                float gv[4];
                int i = i0 + r;
                float ci = scum[i];
                #pragma unroll
                for (int q = 0; q < 4; q++) {
                    int j = j0 + q;
                    gv[q] = (j <= i) ? __expf(ci - scum[j]) * sdt[j] * dd[q] : 0.0f;
                }
                *(float4*)&sG[(i0 + r) * SR + j0] = make_float4(gv[0], gv[1], gv[2], gv[3]);
            }
        }
        __syncthreads();
        int p0 = j0;
        // CH phase: acc[r][q] = sum_s C[i0+r][s] * H[p0+q][s]   (packed over s)
        float acc[4][4];
        {
            unsigned long long acc2[4][4] = {};
            for (int sc = 0; sc < 64; sc += 4) {
                ulonglong2 Cr[4], Hc[4];
                #pragma unroll
                for (int r = 0; r < 4; r++) Cr[r] = *(const ulonglong2*)&sC[(i0 + r) * SR + sc];
                #pragma unroll
                for (int q = 0; q < 4; q++) Hc[q] = *(const ulonglong2*)&sH[(p0 + q) * SR + sc];
                #pragma unroll
                for (int r = 0; r < 4; r++)
                    #pragma unroll
                    for (int q = 0; q < 4; q++) {
                        fma2(acc2[r][q], Cr[r].x, Hc[q].x);
                        fma2(acc2[r][q], Cr[r].y, Hc[q].y);
                    }
            }
            #pragma unroll
            for (int r = 0; r < 4; r++) {
                float e = seY[i0 + r];
                #pragma unroll
                for (int q = 0; q < 4; q++) {
                    float2 p = unpack2(acc2[r][q]);
                    acc[r][q] = e * (p.x + p.y);
                }
            }
        }
        // repack accumulators along the p dimension for GX phase
        unsigned long long accq[4][2];
        #pragma unroll
        for (int r = 0; r < 4; r++) {
            accq[r][0] = packf2(acc[r][0], acc[r][1]);
            accq[r][1] = packf2(acc[r][2], acc[r][3]);
        }
        // GX phase: accq[r] += G[i0+r][j] * X[j][p0..p0+3]  (packed over p)
        for (int jc = 0; jc < 64; jc += 4) {
            float G4[4][4];
            #pragma unroll
            for (int r = 0; r < 4; r++) {
                float4 t = *(float4*)&sG[(i0 + r) * SR + jc];
                G4[r][0] = t.x; G4[r][1] = t.y; G4[r][2] = t.z; G4[r][3] = t.w;
            }
            #pragma unroll
            for (int q = 0; q < 4; q++) {
                ulonglong2 x2 = *(const ulonglong2*)&sX[(jc + q) * SR + p0];
                #pragma unroll
                for (int r = 0; r < 4; r++) {
                    unsigned long long g2 = bcast2(G4[r][q]);
                    fma2(accq[r][0], g2, x2.x);
                    fma2(accq[r][1], g2, x2.y);
                }
            }
        }
        // D*x + store
        unsigned long long D2 = bcast2(Dv[h]);
        #pragma unroll
        for (int r = 0; r < 4; r++) {
            ulonglong2 xi2 = *(const ulonglong2*)&sX[(i0 + r) * SR + p0];
            fma2(accq[r][0], D2, xi2.x);
            fma2(accq[r][1], D2, xi2.y);
            float2 y01 = unpack2(accq[r][0]);
            float2 y23 = unpack2(accq[r][1]);
            *(float4*)&g_Y[(size_t)(b * NT + r0 + i0 + r) * DI + h * HD + p0] =
                make_float4(y01.x, y01.y, y23.x, y23.y);
        }
        __syncthreads();
    }
}

// ---------------- epilogue ----------------
__global__ void k_postnorm(const float* __restrict__ nw) {
    int r = blockIdx.x, b = blockIdx.y, tid = threadIdx.x;
    int t = g_order[b * NT + r];
    float v0, v1, ss;
    {
        float y0 = g_Y[(size_t)(b * NT + r) * DI + tid];
        float g0 = g_Z[(size_t)t * DP + tid];
        v0 = y0 * (g0 / (1.0f + __expf(-g0)));
        float y1 = g_Y[(size_t)(b * NT + r) * DI + tid + 256];
        float g1 = g_Z[(size_t)t * DP + tid + 256];
        v1 = y1 * (g1 / (1.0f + __expf(-g1)));
        ss = v0 * v0 + v1 * v1;
    }
    ss = blockReduceSum(ss);
    float rr = rsqrtf(ss * (1.0f / DI) + 1e-5f);
    g_Y[(size_t)(b * NT + r) * DI + tid]       = v0 * rr * nw[tid];
    g_Y[(size_t)(b * NT + r) * DI + tid + 256] = v1 * rr * nw[tid + 256];
}

__global__ void k_combine() {
    int t = blockIdx.x, c = threadIdx.x;
    int r0 = g_inv[t], r1 = g_inv[NT + t];
    float2 a = *(const float2*)(g_Y + (size_t)r0 * DI + 2 * c);
    float2 bq = *(const float2*)(g_Y + (size_t)(NT + r1) * DI + 2 * c);
    float v0 = 0.5f * (a.x + bq.x);
    float v1 = 0.5f * (a.y + bq.y);
    unsigned short h0, l0, h1, l1;
    bfsplit(v0, h0, l0);
    bfsplit(v1, h1, l1);
    g_combhi[(size_t)t * (DI / 2) + c] = (unsigned)h0 | ((unsigned)h1 << 16);
    g_comblo[(size_t)t * (DI / 2) + c] = (unsigned)l0 | ((unsigned)l1 << 16);
}

__global__ void k_final(const float* __restrict__ res,
                        const float* __restrict__ w, const float* __restrict__ bias,
                        float* __restrict__ dout) {
    int r = blockIdx.x, c = threadIdx.x;
    float v = res[(size_t)r * DM + c] + g_O[r * DM + c];
    float mean = blockReduceSum(v) * (1.0f / DM);
    float xc = v - mean;
    float var = blockReduceSum(xc * xc) * (1.0f / DM);
    float result = xc * rsqrtf(var + 1e-5f) * w[c] + bias[c];
    g_q[r * DM + c] = result;
    if (dout) dout[r * DM + c] = result;
}

// ---------------- launcher ----------------
extern "C" void kernel_launch(void* const* d_in, const int* in_sizes, int n_in,
                              void* d_out, int out_size) {
    (void)in_sizes; (void)n_in; (void)out_size;
    const float* query = (const float*)d_in[0];
    const float* pos   = (const float*)d_in[1];
    const float* pre_w = (const float*)d_in[2];
    const float* pre_b = (const float*)d_in[3];
    const float* fin_w = (const float*)d_in[4];
    const float* fin_b = (const float*)d_in[5];

    const int SORT_SMEM = (NT + NT / 16) * 8;
    const int GEMM_SMEM = 2 * (2 * 128 * WSTR + 2 * 64 * WSTR) * 4;
    const int SCAN3_SMEM = (6 * CQ * SR + 3 * CQ) * 4;
    cudaFuncSetAttribute(k_sort, cudaFuncAttributeMaxDynamicSharedMemorySize, SORT_SMEM);
    cudaFuncSetAttribute(k_gemm_bf, cudaFuncAttributeMaxDynamicSharedMemorySize, GEMM_SMEM);
    cudaFuncSetAttribute(k_scan3, cudaFuncAttributeMaxDynamicSharedMemorySize, SCAN3_SMEM);

    unsigned *p_qnhi, *p_qnlo, *p_combhi, *p_comblo;
    float *p_Z, *p_O, *p_q;
    cudaGetSymbolAddress((void**)&p_qnhi, g_qnhi);
    cudaGetSymbolAddress((void**)&p_qnlo, g_qnlo);
    cudaGetSymbolAddress((void**)&p_combhi, g_combhi);
    cudaGetSymbolAddress((void**)&p_comblo, g_comblo);
    cudaGetSymbolAddress((void**)&p_Z, g_Z);
    cudaGetSymbolAddress((void**)&p_O, g_O);
    cudaGetSymbolAddress((void**)&p_q, g_q);

    k_minmax<<<1, 256>>>(pos);
    k_keys<<<(NT + 255) / 256, 256>>>(pos);
    k_sort<<<2, 1024, SORT_SMEM>>>();
    k_order<<<(2 * NT + 255) / 256, 256>>>();

    for (int L = 0; L < 2; L++) {
        const float* Win  = (const float*)d_in[6 + 8 * L];
        const float* cw   = (const float*)d_in[7 + 8 * L];
        const float* cb   = (const float*)d_in[8 + 8 * L];
        const float* dtb  = (const float*)d_in[9 + 8 * L];
        const float* alog = (const float*)d_in[10 + 8 * L];
        const float* Dv   = (const float*)d_in[11 + 8 * L];
        const float* nw   = (const float*)d_in[12 + 8 * L];
        const float* Wout = (const float*)d_in[13 + 8 * L];
        const float* src  = (L == 0) ? query : p_q;

        k_ln256<<<NT, 128>>>(src, pre_w, pre_b);
        k_splitW<<<((DM / 2) * NPIN + 255) / 256, 256>>>(Win, DM, DP, NPIN);
        k_gemm_bf<<<dim3(NPIN / 64, NT / 128), 256, GEMM_SMEM>>>(
            NT, DP, DM, p_qnhi, p_qnlo, p_Z, DP);
        k_conv<<<dim3(NT, 2), 256>>>(cw, cb);
        k_dt<<<(2 * NT * NH + 255) / 256, 256>>>(dtb, alog);
        k_scan1<<<dim3(NCH, NH, 2), 256>>>();
        k_scan2<<<256, 256>>>();
        k_scan3<<<dim3(NCH, 2), 256, SCAN3_SMEM>>>(Dv);
        k_postnorm<<<dim3(NT, 2), 256>>>(nw);
        k_combine<<<NT, 256>>>();
        k_splitW<<<((DI / 2) * DM + 255) / 256, 256>>>(Wout, DI, DM, DM);
        k_gemm_bf<<<dim3(DM / 64, NT / 128), 256, GEMM_SMEM>>>(
            NT, DM, DI, p_combhi, p_comblo, p_O, DM);
        k_final<<<NT, 256>>>(src, fin_w, fin_b, (L == 1) ? (float*)d_out : nullptr);
    }
}

// round 10
// speedup vs baseline: 1.5008x; 1.0459x over previous
#include <cuda_runtime.h>
#include <cuda_bf16.h>
#include <math.h>

#define NT 16384
#define DM 256
#define DI 512
#define DS 64
#define NH 8
#define HD 64
#define CD 640      // CONV_DIM
#define DP 1160     // D_PROJ
#define KER 4
#define NCH 256     // number of chunks
#define CQ 64       // chunk length
#define SR 68       // padded row stride for 64-col smem tiles
#define NPIN 1216   // padded N for in_proj (19*64)
#define WSTR 20     // GEMM smem row stride in uints
#define CTILE 160   // conv col chunk

// ---------------- device scratch ----------------
__device__ float g_q[NT * DM];
__device__ unsigned g_qnhi[NT * (DM / 2)];
__device__ unsigned g_qnlo[NT * (DM / 2)];
__device__ float g_Z[NT * DP];
__device__ float g_XBC[2 * NT * CD];
__device__ float g_dt[2 * NT * NH];
__device__ float g_a[2 * NT * NH];
__device__ float g_cum[2 * NH * NCH * CQ];
__device__ float g_cdec[2 * NH * NCH];
__device__ float g_S[2 * NH * NCH * HD * DS];
__device__ float g_Hp[2 * NH * NCH * HD * DS];
__device__ float g_Y[2 * NT * DI];
__device__ unsigned g_combhi[NT * (DI / 2)];
__device__ unsigned g_comblo[NT * (DI / 2)];
__device__ float g_O[NT * DM];
__device__ unsigned g_Whi[NPIN * (DM / 2)];
__device__ unsigned g_Wlo[NPIN * (DM / 2)];
__device__ unsigned long long g_keys[2 * NT];
__device__ int g_order[2 * NT];
__device__ int g_inv[2 * NT];
__device__ float g_pmin[3], g_pmax[3];

extern __shared__ float dynsmem[];

// ---------------- helpers ----------------
__device__ __forceinline__ float blockReduceSum(float v) {
    __shared__ float sh[32];
    __shared__ float tot;
    int lane = threadIdx.x & 31, wid = threadIdx.x >> 5;
    #pragma unroll
    for (int o = 16; o > 0; o >>= 1) v += __shfl_xor_sync(0xffffffffu, v, o);
    if (lane == 0) sh[wid] = v;
    __syncthreads();
    int nw = blockDim.x >> 5;
    v = (threadIdx.x < nw) ? sh[threadIdx.x] : 0.0f;
    if (wid == 0) {
        #pragma unroll
        for (int o = 16; o > 0; o >>= 1) v += __shfl_xor_sync(0xffffffffu, v, o);
        if (lane == 0) tot = v;
    }
    __syncthreads();
    return tot;
}

__device__ __forceinline__ unsigned hilbert3(unsigned a0, unsigned a1, unsigned a2) {
    unsigned x0 = a0, x1 = a1, x2 = a2;
    const unsigned M = 1u << 9;
    for (unsigned Q = M; Q > 1; Q >>= 1) {
        unsigned P = Q - 1;
        if (x0 & Q) x0 ^= P;
        {
            unsigned t = (x0 ^ x1) & P;
            if (x1 & Q) { x0 ^= P; } else { x0 ^= t; x1 ^= t; }
        }
        {
            unsigned t = (x0 ^ x2) & P;
            if (x2 & Q) { x0 ^= P; } else { x0 ^= t; x2 ^= t; }
        }
    }
    x1 ^= x0;
    x2 ^= x1;
    unsigned t = 0;
    for (unsigned Q = M; Q > 1; Q >>= 1)
        if (x2 & Q) t ^= (Q - 1);
    x0 ^= t; x1 ^= t; x2 ^= t;
    unsigned code = 0;
    for (int b = 9; b >= 0; b--) {
        code = (code << 1) | ((x0 >> b) & 1);
        code = (code << 1) | ((x1 >> b) & 1);
        code = (code << 1) | ((x2 >> b) & 1);
    }
    return code;
}

__device__ __forceinline__ void bfsplit(float x, unsigned short& hi, unsigned short& lo) {
    __nv_bfloat16 h = __float2bfloat16(x);
    __nv_bfloat16 l = __float2bfloat16(x - __bfloat162float(h));
    hi = *(unsigned short*)&h;
    lo = *(unsigned short*)&l;
}

__device__ __forceinline__ void mma_bf16(float c[4], const unsigned a[4],
                                         unsigned b0, unsigned b1) {
    asm volatile("mma.sync.aligned.m16n8k16.row.col.f32.bf16.bf16.f32 "
        "{%0,%1,%2,%3}, {%4,%5,%6,%7}, {%8,%9}, {%0,%1,%2,%3};"
        : "+f"(c[0]), "+f"(c[1]), "+f"(c[2]), "+f"(c[3])
        : "r"(a[0]), "r"(a[1]), "r"(a[2]), "r"(a[3]), "r"(b0), "r"(b1));
}

__device__ __forceinline__ void cp16(unsigned dst, const void* src) {
    asm volatile("cp.async.cg.shared.global [%0], [%1], 16;" :: "r"(dst), "l"(src));
}

// ---- packed f32x2 FMA ----
__device__ __forceinline__ void fma2(unsigned long long& c, unsigned long long a,
                                     unsigned long long b) {
    asm("fma.rn.f32x2 %0, %1, %2, %0;" : "+l"(c) : "l"(a), "l"(b));
}
__device__ __forceinline__ unsigned long long bcast2(float x) {
    unsigned long long r;
    unsigned u = __float_as_uint(x);
    asm("mov.b64 %0, {%1, %2};" : "=l"(r) : "r"(u), "r"(u));
    return r;
}
__device__ __forceinline__ unsigned long long packf2(float a, float b) {
    unsigned long long r;
    asm("mov.b64 %0, {%1, %2};" : "=l"(r) : "r"(__float_as_uint(a)), "r"(__float_as_uint(b)));
    return r;
}
__device__ __forceinline__ float2 unpack2(unsigned long long v) {
    unsigned lo, hi;
    asm("mov.b64 {%0, %1}, %2;" : "=r"(lo), "=r"(hi) : "l"(v));
    return make_float2(__uint_as_float(lo), __uint_as_float(hi));
}

// ---------------- setup kernels ----------------
__global__ void k_minmax(const float* __restrict__ pos) {
    __shared__ float smn[256][3], smx[256][3];
    float mn[3] = {1e30f, 1e30f, 1e30f}, mx[3] = {-1e30f, -1e30f, -1e30f};
    for (int r = threadIdx.x; r < NT; r += 256) {
        #pragma unroll
        for (int j = 0; j < 3; j++) {
            float v = pos[r * 3 + j];
            mn[j] = fminf(mn[j], v);
            mx[j] = fmaxf(mx[j], v);
        }
    }
    #pragma unroll
    for (int j = 0; j < 3; j++) { smn[threadIdx.x][j] = mn[j]; smx[threadIdx.x][j] = mx[j]; }
    __syncthreads();
    for (int s = 128; s > 0; s >>= 1) {
        if (threadIdx.x < s) {
            #pragma unroll
            for (int j = 0; j < 3; j++) {
                smn[threadIdx.x][j] = fminf(smn[threadIdx.x][j], smn[threadIdx.x + s][j]);
                smx[threadIdx.x][j] = fmaxf(smx[threadIdx.x][j], smx[threadIdx.x + s][j]);
            }
        }
        __syncthreads();
    }
    if (threadIdx.x == 0) {
        #pragma unroll
        for (int j = 0; j < 3; j++) { g_pmin[j] = smn[0][j]; g_pmax[j] = smx[0][j]; }
    }
}

__global__ void k_keys(const float* __restrict__ pos) {
    int idx = blockIdx.x * blockDim.x + threadIdx.x;
    if (idx >= NT) return;
    unsigned g[3];
    #pragma unroll
    for (int j = 0; j < 3; j++) {
        float denom = g_pmax[j] - g_pmin[j] + 1e-6f;
        float v = ((pos[idx * 3 + j] - g_pmin[j]) / denom) * 1023.0f;
        v = fminf(fmaxf(v, 0.0f), 1023.0f);
        g[j] = (unsigned)(int)v;
    }
    unsigned c0 = hilbert3(g[0], g[1], g[2]);
    unsigned c1 = hilbert3(g[1], g[0], g[2]);
    g_keys[idx]      = (((unsigned long long)c0) << 14) | (unsigned long long)idx;
    g_keys[NT + idx] = (((unsigned long long)c1) << 14) | (unsigned long long)idx;
}

#define SADDR(i) ((i) + ((i) >> 4))

__global__ void k_sort() {
    unsigned long long* s = (unsigned long long*)dynsmem;
    unsigned long long* keys = g_keys + blockIdx.x * NT;
    int t = threadIdx.x;
    for (int i = t; i < NT; i += 1024) s[SADDR(i)] = keys[i];
    __syncthreads();

    int base = t * 16;
    unsigned long long v[16];
    #pragma unroll
    for (int r = 0; r < 16; r++) v[r] = s[SADDR(base + r)];
    #pragma unroll
    for (int k = 2; k <= 16; k <<= 1) {
        #pragma unroll
        for (int j = k >> 1; j > 0; j >>= 1) {
            #pragma unroll
            for (int r = 0; r < 16; r++) {
                int rr = r ^ j;
                if (rr > r) {
                    bool up = (((base + r) & k) == 0);
                    unsigned long long a = v[r], b = v[rr];
                    if ((a > b) == up) { v[r] = b; v[rr] = a; }
                }
            }
        }
    }
    #pragma unroll
    for (int r = 0; r < 16; r++) s[SADDR(base + r)] = v[r];
    __syncthreads();

    for (int k = 32; k <= NT; k <<= 1) {
        for (int j = k >> 1; j >= 16; j >>= 1) {
            for (int i = t; i < NT; i += 1024) {
                int ixj = i ^ j;
                if (ixj > i) {
                    unsigned long long a = s[SADDR(i)], b = s[SADDR(ixj)];
                    bool up = ((i & k) == 0);
                    if ((a > b) == up) { s[SADDR(i)] = b; s[SADDR(ixj)] = a; }
                }
            }
            __syncthreads();
        }
        #pragma unroll
        for (int r = 0; r < 16; r++) v[r] = s[SADDR(base + r)];
        bool up = ((base & k) == 0);
        #pragma unroll
        for (int j = 8; j > 0; j >>= 1) {
            #pragma unroll
            for (int r = 0; r < 16; r++) {
                int rr = r ^ j;
                if (rr > r) {
                    unsigned long long a = v[r], b = v[rr];
                    if ((a > b) == up) { v[r] = b; v[rr] = a; }
                }
            }
        }
        #pragma unroll
        for (int r = 0; r < 16; r++) s[SADDR(base + r)] = v[r];
        __syncthreads();
    }
    for (int i = t; i < NT; i += 1024) keys[i] = s[SADDR(i)];
}

__global__ void k_order() {
    int i = blockIdx.x * blockDim.x + threadIdx.x;
    if (i >= 2 * NT) return;
    int b = i / NT;
    int idx = (int)(g_keys[i] & 0x3FFFULL);
    g_order[i] = idx;
    g_inv[b * NT + idx] = i - b * NT;
}

__global__ void k_ln256(const float* __restrict__ src,
                        const float* __restrict__ w, const float* __restrict__ bias) {
    int r = blockIdx.x, t = threadIdx.x;
    float2 v = *(const float2*)(src + (size_t)r * DM + 2 * t);
    float mean = blockReduceSum(v.x + v.y) * (1.0f / DM);
    float x0 = v.x - mean, x1 = v.y - mean;
    float var = blockReduceSum(x0 * x0 + x1 * x1) * (1.0f / DM);
    float rs = rsqrtf(var + 1e-5f);
    float r0 = x0 * rs * w[2 * t] + bias[2 * t];
    float r1 = x1 * rs * w[2 * t + 1] + bias[2 * t + 1];
    unsigned short h0, l0, h1, l1;
    bfsplit(r0, h0, l0);
    bfsplit(r1, h1, l1);
    g_qnhi[r * (DM / 2) + t] = (unsigned)h0 | ((unsigned)h1 << 16);
    g_qnlo[r * (DM / 2) + t] = (unsigned)l0 | ((unsigned)l1 << 16);
}

__global__ void k_splitW(const float* __restrict__ src, int K, int N, int NP) {
    int idx = blockIdx.x * blockDim.x + threadIdx.x;
    if (idx >= (K / 2) * NP) return;
    int kp = idx / NP, n = idx - kp * NP;
    float w0 = (n < N) ? src[(size_t)(2 * kp) * N + n] : 0.0f;
    float w1 = (n < N) ? src[(size_t)(2 * kp + 1) * N + n] : 0.0f;
    unsigned short h0, l0, h1, l1;
    bfsplit(w0, h0, l0);
    bfsplit(w1, h1, l1);
    g_Whi[(size_t)n * (K / 2) + kp] = (unsigned)h0 | ((unsigned)h1 << 16);
    g_Wlo[(size_t)n * (K / 2) + kp] = (unsigned)l0 | ((unsigned)l1 << 16);
}

// ---------------- bf16x3 tensor-core GEMM (R4/R7-proven) ----------------
__device__ __forceinline__ void gemm_load_bf(
    const unsigned* __restrict__ Ahi, const unsigned* __restrict__ Alo, int K2,
    const unsigned* __restrict__ Bhi, const unsigned* __restrict__ Blo,
    int m0, int n0, int kt, unsigned* sAh, unsigned* sAl,
    unsigned* sBh, unsigned* sBl, int tid) {
    int kp0 = kt * 16;
    int r = tid >> 1, cu = (tid & 1) * 8;
    const unsigned* pah = Ahi + (size_t)(m0 + r) * K2 + kp0 + cu;
    const unsigned* pal = Alo + (size_t)(m0 + r) * K2 + kp0 + cu;
    unsigned dah = (unsigned)__cvta_generic_to_shared(sAh + r * WSTR + cu);
    unsigned dal = (unsigned)__cvta_generic_to_shared(sAl + r * WSTR + cu);
    cp16(dah, pah); cp16(dah + 16, pah + 4);
    cp16(dal, pal); cp16(dal + 16, pal + 4);
    int n = tid >> 2, cb = (tid & 3) * 4;
    cp16((unsigned)__cvta_generic_to_shared(sBh + n * WSTR + cb),
         Bhi + (size_t)(n0 + n) * K2 + kp0 + cb);
    cp16((unsigned)__cvta_generic_to_shared(sBl + n * WSTR + cb),
         Blo + (size_t)(n0 + n) * K2 + kp0 + cb);
}

__global__ __launch_bounds__(256) void k_gemm_bf(int M, int N, int K,
        const unsigned* __restrict__ Ahi, const unsigned* __restrict__ Alo,
        float* __restrict__ C, int ldc) {
    const unsigned* Bhi = g_Whi;
    const unsigned* Blo = g_Wlo;
    unsigned* sm = (unsigned*)dynsmem;
    const int ASZ = 128 * WSTR, BSZ = 64 * WSTR;
    const int STG = 2 * ASZ + 2 * BSZ;

    int m0 = blockIdx.y * 128, n0 = blockIdx.x * 64;
    int tid = threadIdx.x;
    int wid = tid >> 5, lane = tid & 31;
    int wm = (wid & 3) * 32, wn = (wid >> 2) * 32;
    int g = lane >> 2, tg = lane & 3;
    int K2 = K >> 1;
    int KT = K / 32;

    float acc[2][4][4];
    #pragma unroll
    for (int a = 0; a < 2; a++)
        #pragma unroll
        for (int b = 0; b < 4; b++)
            #pragma unroll
            for (int c = 0; c < 4; c++) acc[a][b][c] = 0.0f;

    gemm_load_bf(Ahi, Alo, K2, Bhi, Blo, m0, n0, 0,
                 sm, sm + ASZ, sm + 2 * ASZ, sm + 2 * ASZ + BSZ, tid);
    asm volatile("cp.async.commit_group;");

    for (int kt = 0; kt < KT; kt++) {
        int st = kt & 1;
        if (kt + 1 < KT) {
            int ns = st ^ 1;
            unsigned* b0 = sm + ns * STG;
            gemm_load_bf(Ahi, Alo, K2, Bhi, Blo, m0, n0, kt + 1,
                         b0, b0 + ASZ, b0 + 2 * ASZ, b0 + 2 * ASZ + BSZ, tid);
            asm volatile("cp.async.commit_group;");
            asm volatile("cp.async.wait_group 1;");
        } else {
            asm volatile("cp.async.wait_group 0;");
        }
        __syncthreads();
        unsigned* sAhi = sm + st * STG;
        unsigned* sAlo = sAhi + ASZ;
        unsigned* sBhi = sAhi + 2 * ASZ;
        unsigned* sBlo = sBhi + BSZ;
        #pragma unroll
        for (int kk2 = 0; kk2 < 16; kk2 += 8) {
            unsigned ahi[2][4], alo[2][4], bhi[4][2], blo[4][2];
            #pragma unroll
            for (int mi = 0; mi < 2; mi++) {
                int ra = (wm + mi * 16 + g) * WSTR;
                int rb = (wm + mi * 16 + g + 8) * WSTR;
                ahi[mi][0] = sAhi[ra + kk2 + tg];
                ahi[mi][1] = sAhi[rb + kk2 + tg];
                ahi[mi][2] = sAhi[ra + kk2 + 4 + tg];
                ahi[mi][3] = sAhi[rb + kk2 + 4 + tg];
                alo[mi][0] = sAlo[ra + kk2 + tg];
                alo[mi][1] = sAlo[rb + kk2 + tg];
                alo[mi][2] = sAlo[ra + kk2 + 4 + tg];
                alo[mi][3] = sAlo[rb + kk2 + 4 + tg];
            }
            #pragma unroll
            for (int nj = 0; nj < 4; nj++) {
                int rn = (wn + nj * 8 + g) * WSTR;
                bhi[nj][0] = sBhi[rn + kk2 + tg];
                bhi[nj][1] = sBhi[rn + kk2 + 4 + tg];
                blo[nj][0] = sBlo[rn + kk2 + tg];
                blo[nj][1] = sBlo[rn + kk2 + 4 + tg];
            }
            #pragma unroll
            for (int mi = 0; mi < 2; mi++)
                #pragma unroll
                for (int nj = 0; nj < 4; nj++) {
                    mma_bf16(acc[mi][nj], ahi[mi], bhi[nj][0], bhi[nj][1]);
                    mma_bf16(acc[mi][nj], ahi[mi], blo[nj][0], blo[nj][1]);
                    mma_bf16(acc[mi][nj], alo[mi], bhi[nj][0], bhi[nj][1]);
                }
        }
        __syncthreads();
    }
    #pragma unroll
    for (int mi = 0; mi < 2; mi++)
        #pragma unroll
        for (int nj = 0; nj < 4; nj++) {
            int row = m0 + wm + mi * 16 + g;
            int col = n0 + wn + nj * 8 + tg * 2;
            if (col + 1 < N) {
                *(float2*)(C + (size_t)row * ldc + col) =
                    make_float2(acc[mi][nj][0], acc[mi][nj][1]);
                *(float2*)(C + (size_t)(row + 8) * ldc + col) =
                    make_float2(acc[mi][nj][2], acc[mi][nj][3]);
            } else if (col < N) {
                C[(size_t)row * ldc + col] = acc[mi][nj][0];
                C[(size_t)(row + 8) * ldc + col] = acc[mi][nj][2];
            }
        }
}

// ---------------- tiled conv (single change this round) + dt ----------------
__global__ __launch_bounds__(256) void k_conv2(const float* __restrict__ cw,
                                               const float* __restrict__ cb) {
    float* sZ  = dynsmem;                     // (64+3) x CTILE
    float* scw = sZ + 67 * CTILE;             // CTILE x 4
    float* scb = scw + CTILE * 4;             // CTILE
    int*   stok = (int*)(scb + CTILE);        // 67
    int r0 = blockIdx.x * 64, cc = blockIdx.y * CTILE, b = blockIdx.z;
    int tid = threadIdx.x;
    if (tid < 67) {
        int rr = r0 - 3 + tid;
        stok[tid] = (rr >= 0) ? g_order[b * NT + rr] : -1;
    }
    for (int idx = tid; idx < CTILE * 4; idx += 256)
        scw[idx] = cw[(cc + (idx >> 2)) * KER + (idx & 3)];
    for (int idx = tid; idx < CTILE; idx += 256)
        scb[idx] = cb[cc + idx];
    __syncthreads();
    for (int idx = tid; idx < 67 * CTILE; idx += 256) {
        int row = idx / CTILE, col = idx - row * CTILE;
        int t = stok[row];
        sZ[idx] = (t >= 0) ? g_Z[(size_t)t * DP + DI + cc + col] : 0.0f;
    }
    __syncthreads();
    for (int idx = tid; idx < 64 * CTILE; idx += 256) {
        int row = idx / CTILE, col = idx - row * CTILE;
        float acc = scb[col];
        #pragma unroll
        for (int k = 0; k < KER; k++)
            acc += scw[col * 4 + k] * sZ[(row + k) * CTILE + col];
        float s = acc / (1.0f + __expf(-acc));
        g_XBC[(size_t)(b * NT + r0 + row) * CD + cc + col] = s;
    }
}

__global__ void k_dt(const float* __restrict__ dtb, const float* __restrict__ alog) {
    int i = blockIdx.x * blockDim.x + threadIdx.x;
    if (i >= 2 * NT * NH) return;
    int b = i / (NT * NH);
    int rem = i - b * NT * NH;
    int r = rem / NH, h = rem - r * NH;
    int t = g_order[b * NT + r];
    float x = g_Z[(size_t)t * DP + DI + CD + h] + dtb[h];
    float sp = fmaxf(x, 0.0f) + log1pf(expf(-fabsf(x)));
    float A = -expf(alog[h]);
    g_dt[i] = sp;
    g_a[i] = sp * A;
}

// ---------------- chunked scan (f32x2-packed math) ----------------
__global__ __launch_bounds__(256) void k_scan1() {
    int c = blockIdx.x, h = blockIdx.y, b = blockIdx.z;
    __shared__ float sX[CQ * SR], sB[CQ * SR];
    __shared__ float scum[CQ], sw[CQ];
    int r0 = c * CQ, tid = threadIdx.x;
    for (int idx = tid; idx < CQ * 64; idx += 256) {
        int j = idx >> 6, p = idx & 63;
        sX[j * SR + p] = g_XBC[(size_t)(b * NT + r0 + j) * CD + h * HD + p];
        sB[j * SR + p] = g_XBC[(size_t)(b * NT + r0 + j) * CD + DI + p];
    }
    if (tid < CQ) scum[tid] = g_a[(size_t)(b * NT + r0 + tid) * NH + h];
    __syncthreads();
    if (tid < CQ) {
        float x = scum[tid];
        #pragma unroll
        for (int o = 1; o < 32; o <<= 1) {
            float y = __shfl_up_sync(0xffffffffu, x, o);
            if ((tid & 31) >= o) x += y;
        }
        scum[tid] = x;
    }
    __syncthreads();
    if (tid >= 32 && tid < CQ) scum[tid] += scum[31];
    __syncthreads();
    float slast = scum[CQ - 1];
    if (tid < CQ) {
        sw[tid] = __expf(slast - scum[tid]) * g_dt[(size_t)(b * NT + r0 + tid) * NH + h];
        g_cum[((b * NH + h) * NCH + c) * CQ + tid] = scum[tid];
    }
    if (tid == 0) g_cdec[(b * NH + h) * NCH + c] = __expf(slast);
    __syncthreads();
    int p0 = (tid & 15) * 4, s0 = (tid >> 4) * 4;
    unsigned long long acc2[4][2] = {};
    for (int j = 0; j < CQ; j++) {
        float4 xv = *(float4*)&sX[j * SR + p0];
        ulonglong2 b2 = *(const ulonglong2*)&sB[j * SR + s0];
        float w = sw[j];
        float wx[4] = {xv.x * w, xv.y * w, xv.z * w, xv.w * w};
        #pragma unroll
        for (int pi = 0; pi < 4; pi++) {
            unsigned long long w2 = bcast2(wx[pi]);
            fma2(acc2[pi][0], w2, b2.x);
            fma2(acc2[pi][1], w2, b2.y);
        }
    }
    size_t base = ((size_t)((b * NH + h) * NCH + c) * HD) * DS;
    #pragma unroll
    for (int pi = 0; pi < 4; pi++) {
        float2 a01 = unpack2(acc2[pi][0]);
        float2 a23 = unpack2(acc2[pi][1]);
        *(float4*)&g_S[base + (size_t)(p0 + pi) * DS + s0] =
            make_float4(a01.x, a01.y, a23.x, a23.y);
    }
}

__global__ void k_scan2() {
    __shared__ float scd[NCH];
    int bh = blockIdx.x >> 4;
    int e = ((blockIdx.x & 15) << 8) + threadIdx.x;
    if (threadIdx.x < NCH) scd[threadIdx.x] = g_cdec[bh * NCH + threadIdx.x];
    __syncthreads();
    float H = 0.0f;
    for (int c = 0; c < NCH; c++) {
        size_t off = ((size_t)(bh * NCH + c)) * (HD * DS) + e;
        float s = g_S[off];
        g_Hp[off] = H;
        H = scd[c] * H + s;
    }
}

__global__ __launch_bounds__(256) void k_scan3(const float* __restrict__ Dv) {
    int c = blockIdx.x, b = blockIdx.y;
    int r0 = c * CQ, tid = threadIdx.x;
    float* sB  = dynsmem;
    float* sC  = sB  + CQ * SR;
    float* sD0 = sC  + CQ * SR;
    float* sX  = sD0 + CQ * SR;
    float* sH  = sX  + CQ * SR;
    float* sG  = sH  + CQ * SR;
    float* scum = sG + CQ * SR;
    float* sdt  = scum + CQ;
    float* seY  = sdt + CQ;

    for (int idx = tid; idx < CQ * 64; idx += 256) {
        int j = idx >> 6, s = idx & 63;
        sB[j * SR + s] = g_XBC[(size_t)(b * NT + r0 + j) * CD + DI + s];
        sC[j * SR + s] = g_XBC[(size_t)(b * NT + r0 + j) * CD + DI + DS + s];
    }
    __syncthreads();
    int i0 = (tid >> 4) * 4, j0 = (tid & 15) * 4;
    {
        unsigned long long acc2[4][4] = {};
        for (int sc = 0; sc < 64; sc += 4) {
            ulonglong2 Cr[4], Br[4];
            #pragma unroll
            for (int r = 0; r < 4; r++) Cr[r] = *(const ulonglong2*)&sC[(i0 + r) * SR + sc];
            #pragma unroll
            for (int q = 0; q < 4; q++) Br[q] = *(const ulonglong2*)&sB[(j0 + q) * SR + sc];
            #pragma unroll
            for (int r = 0; r < 4; r++)
                #pragma unroll
                for (int q = 0; q < 4; q++) {
                    fma2(acc2[r][q], Cr[r].x, Br[q].x);
                    fma2(acc2[r][q], Cr[r].y, Br[q].y);
                }
        }
        #pragma unroll
        for (int r = 0; r < 4; r++) {
            float dv[4];
            #pragma unroll
            for (int q = 0; q < 4; q++) {
                float2 p = unpack2(acc2[r][q]);
                dv[q] = p.x + p.y;
            }
            *(float4*)&sD0[(i0 + r) * SR + j0] = make_float4(dv[0], dv[1], dv[2], dv[3]);
        }
    }
    __syncthreads();

    for (int h = 0; h < NH; h++) {
        for (int idx = tid; idx < CQ * 64; idx += 256) {
            int j = idx >> 6, p = idx & 63;
            sX[j * SR + p] = g_XBC[(size_t)(b * NT + r0 + j) * CD + h * HD + p];
            sH[j * SR + p] = g_Hp[((size_t)((b * NH + h) * NCH + c) * HD) * DS + idx];
        }
        if (tid < CQ) {
            float cu = g_cum[((b * NH + h) * NCH + c) * CQ + tid];
            scum[tid] = cu;
            sdt[tid] = g_dt[(size_t)(b * NT + r0 + tid) * NH + h];
            seY[tid] = __expf(cu);
        }
        __syncthreads();
        {
            #pragma unroll
            for (int r = 0; r < 4; r++) {
                float4 d = *(float4*)&sD0[(i0 + r) * SR + j0];
                float dd[4] = {d.x, d.y, d.z, d.w};
                float gv[4];
                int i = i0 + r;
                float ci = scum[i];
                #pragma unroll
                for (int q = 0; q < 4; q++) {
                    int j = j0 + q;
                    gv[q] = (j <= i) ? __expf(ci - scum[j]) * sdt[j] * dd[q] : 0.0f;
                }
                *(float4*)&sG[(i0 + r) * SR + j0] = make_float4(gv[0], gv[1], gv[2], gv[3]);
            }
        }
        __syncthreads();
        int p0 = j0;
        float acc[4][4];
        {
            unsigned long long acc2[4][4] = {};
            for (int sc = 0; sc < 64; sc += 4) {
                ulonglong2 Cr[4], Hc[4];
                #pragma unroll
                for (int r = 0; r < 4; r++) Cr[r] = *(const ulonglong2*)&sC[(i0 + r) * SR + sc];
                #pragma unroll
                for (int q = 0; q < 4; q++) Hc[q] = *(const ulonglong2*)&sH[(p0 + q) * SR + sc];
                #pragma unroll
                for (int r = 0; r < 4; r++)
                    #pragma unroll
                    for (int q = 0; q < 4; q++) {
                        fma2(acc2[r][q], Cr[r].x, Hc[q].x);
                        fma2(acc2[r][q], Cr[r].y, Hc[q].y);
                    }
            }
            #pragma unroll
            for (int r = 0; r < 4; r++) {
                float e = seY[i0 + r];
                #pragma unroll
                for (int q = 0; q < 4; q++) {
                    float2 p = unpack2(acc2[r][q]);
                    acc[r][q] = e * (p.x + p.y);
                }
            }
        }
        unsigned long long accq[4][2];
        #pragma unroll
        for (int r = 0; r < 4; r++) {
            accq[r][0] = packf2(acc[r][0], acc[r][1]);
            accq[r][1] = packf2(acc[r][2], acc[r][3]);
        }
        for (int jc = 0; jc < 64; jc += 4) {
            float G4[4][4];
            #pragma unroll
            for (int r = 0; r < 4; r++) {
                float4 t = *(float4*)&sG[(i0 + r) * SR + jc];
                G4[r][0] = t.x; G4[r][1] = t.y; G4[r][2] = t.z; G4[r][3] = t.w;
            }
            #pragma unroll
            for (int q = 0; q < 4; q++) {
                ulonglong2 x2 = *(const ulonglong2*)&sX[(jc + q) * SR + p0];
                #pragma unroll
                for (int r = 0; r < 4; r++) {
                    unsigned long long g2 = bcast2(G4[r][q]);
                    fma2(accq[r][0], g2, x2.x);
                    fma2(accq[r][1], g2, x2.y);
                }
            }
        }
        unsigned long long D2 = bcast2(Dv[h]);
        #pragma unroll
        for (int r = 0; r < 4; r++) {
            ulonglong2 xi2 = *(const ulonglong2*)&sX[(i0 + r) * SR + p0];
            fma2(accq[r][0], D2, xi2.x);
            fma2(accq[r][1], D2, xi2.y);
            float2 y01 = unpack2(accq[r][0]);
            float2 y23 = unpack2(accq[r][1]);
            *(float4*)&g_Y[(size_t)(b * NT + r0 + i0 + r) * DI + h * HD + p0] =
                make_float4(y01.x, y01.y, y23.x, y23.y);
        }
        __syncthreads();
    }
}

// ---------------- epilogue ----------------
__global__ void k_postnorm(const float* __restrict__ nw) {
    int r = blockIdx.x, b = blockIdx.y, tid = threadIdx.x;
    int t = g_order[b * NT + r];
    float v0, v1, ss;
    {
        float y0 = g_Y[(size_t)(b * NT + r) * DI + tid];
        float g0 = g_Z[(size_t)t * DP + tid];
        v0 = y0 * (g0 / (1.0f + __expf(-g0)));
        float y1 = g_Y[(size_t)(b * NT + r) * DI + tid + 256];
        float g1 = g_Z[(size_t)t * DP + tid + 256];
        v1 = y1 * (g1 / (1.0f + __expf(-g1)));
        ss = v0 * v0 + v1 * v1;
    }
    ss = blockReduceSum(ss);
    float rr = rsqrtf(ss * (1.0f / DI) + 1e-5f);
    g_Y[(size_t)(b * NT + r) * DI + tid]       = v0 * rr * nw[tid];
    g_Y[(size_t)(b * NT + r) * DI + tid + 256] = v1 * rr * nw[tid + 256];
}

__global__ void k_combine() {
    int t = blockIdx.x, c = threadIdx.x;
    int r0 = g_inv[t], r1 = g_inv[NT + t];
    float2 a = *(const float2*)(g_Y + (size_t)r0 * DI + 2 * c);
    float2 bq = *(const float2*)(g_Y + (size_t)(NT + r1) * DI + 2 * c);
    float v0 = 0.5f * (a.x + bq.x);
    float v1 = 0.5f * (a.y + bq.y);
    unsigned short h0, l0, h1, l1;
    bfsplit(v0, h0, l0);
    bfsplit(v1, h1, l1);
    g_combhi[(size_t)t * (DI / 2) + c] = (unsigned)h0 | ((unsigned)h1 << 16);
    g_comblo[(size_t)t * (DI / 2) + c] = (unsigned)l0 | ((unsigned)l1 << 16);
}

__global__ void k_final(const float* __restrict__ res,
                        const float* __restrict__ w, const float* __restrict__ bias,
                        float* __restrict__ dout) {
    int r = blockIdx.x, c = threadIdx.x;
    float v = res[(size_t)r * DM + c] + g_O[r * DM + c];
    float mean = blockReduceSum(v) * (1.0f / DM);
    float xc = v - mean;
    float var = blockReduceSum(xc * xc) * (1.0f / DM);
    float result = xc * rsqrtf(var + 1e-5f) * w[c] + bias[c];
    g_q[r * DM + c] = result;
    if (dout) dout[r * DM + c] = result;
}

// ---------------- launcher ----------------
extern "C" void kernel_launch(void* const* d_in, const int* in_sizes, int n_in,
                              void* d_out, int out_size) {
    (void)in_sizes; (void)n_in; (void)out_size;
    const float* query = (const float*)d_in[0];
    const float* pos   = (const float*)d_in[1];
    const float* pre_w = (const float*)d_in[2];
    const float* pre_b = (const float*)d_in[3];
    const float* fin_w = (const float*)d_in[4];
    const float* fin_b = (const float*)d_in[5];

    const int SORT_SMEM = (NT + NT / 16) * 8;
    const int GEMM_SMEM = 2 * (2 * 128 * WSTR + 2 * 64 * WSTR) * 4;
    const int SCAN3_SMEM = (6 * CQ * SR + 3 * CQ) * 4;
    const int CONV_SMEM = (67 * CTILE + CTILE * 4 + CTILE) * 4 + 68 * 4;
    cudaFuncSetAttribute(k_sort, cudaFuncAttributeMaxDynamicSharedMemorySize, SORT_SMEM);
    cudaFuncSetAttribute(k_gemm_bf, cudaFuncAttributeMaxDynamicSharedMemorySize, GEMM_SMEM);
    cudaFuncSetAttribute(k_scan3, cudaFuncAttributeMaxDynamicSharedMemorySize, SCAN3_SMEM);
    cudaFuncSetAttribute(k_conv2, cudaFuncAttributeMaxDynamicSharedMemorySize, CONV_SMEM);

    unsigned *p_qnhi, *p_qnlo, *p_combhi, *p_comblo;
    float *p_Z, *p_O, *p_q;
    cudaGetSymbolAddress((void**)&p_qnhi, g_qnhi);
    cudaGetSymbolAddress((void**)&p_qnlo, g_qnlo);
    cudaGetSymbolAddress((void**)&p_combhi, g_combhi);
    cudaGetSymbolAddress((void**)&p_comblo, g_comblo);
    cudaGetSymbolAddress((void**)&p_Z, g_Z);
    cudaGetSymbolAddress((void**)&p_O, g_O);
    cudaGetSymbolAddress((void**)&p_q, g_q);

    k_minmax<<<1, 256>>>(pos);
    k_keys<<<(NT + 255) / 256, 256>>>(pos);
    k_sort<<<2, 1024, SORT_SMEM>>>();
    k_order<<<(2 * NT + 255) / 256, 256>>>();

    for (int L = 0; L < 2; L++) {
        const float* Win  = (const float*)d_in[6 + 8 * L];
        const float* cw   = (const float*)d_in[7 + 8 * L];
        const float* cb   = (const float*)d_in[8 + 8 * L];
        const float* dtb  = (const float*)d_in[9 + 8 * L];
        const float* alog = (const float*)d_in[10 + 8 * L];
        const float* Dv   = (const float*)d_in[11 + 8 * L];
        const float* nw   = (const float*)d_in[12 + 8 * L];
        const float* Wout = (const float*)d_in[13 + 8 * L];
        const float* src  = (L == 0) ? query : p_q;

        k_ln256<<<NT, 128>>>(src, pre_w, pre_b);
        k_splitW<<<((DM / 2) * NPIN + 255) / 256, 256>>>(Win, DM, DP, NPIN);
        k_gemm_bf<<<dim3(NPIN / 64, NT / 128), 256, GEMM_SMEM>>>(
            NT, DP, DM, p_qnhi, p_qnlo, p_Z, DP);
        k_conv2<<<dim3(NT / 64, CD / CTILE, 2), 256, CONV_SMEM>>>(cw, cb);
        k_dt<<<(2 * NT * NH + 255) / 256, 256>>>(dtb, alog);
        k_scan1<<<dim3(NCH, NH, 2), 256>>>();
        k_scan2<<<256, 256>>>();
        k_scan3<<<dim3(NCH, 2), 256, SCAN3_SMEM>>>(Dv);
        k_postnorm<<<dim3(NT, 2), 256>>>(nw);
        k_combine<<<NT, 256>>>();
        k_splitW<<<((DI / 2) * DM + 255) / 256, 256>>>(Wout, DI, DM, DM);
        k_gemm_bf<<<dim3(DM / 64, NT / 128), 256, GEMM_SMEM>>>(
            NT, DM, DI, p_combhi, p_comblo, p_O, DM);
        k_final<<<NT, 256>>>(src, fin_w, fin_b, (L == 1) ? (float*)d_out : nullptr);
    }
}

// round 11
// speedup vs baseline: 1.5334x; 1.0217x over previous
#include <cuda_runtime.h>
#include <cuda_bf16.h>
#include <math.h>

#define NT 16384
#define DM 256
#define DI 512
#define DS 64
#define NH 8
#define HD 64
#define CD 640      // CONV_DIM
#define DP 1160     // D_PROJ
#define KER 4
#define NCH 256     // number of chunks
#define CQ 64      // chunk length
#define SR 68       // padded row stride for 64-col smem tiles
#define NPIN 1216   // padded N for in_proj (19*64)
#define WSTR 20     // GEMM smem row stride in uints
#define CTILE 160   // conv col chunk
#define SEG 2048    // sort segment

// ---------------- device scratch ----------------
__device__ float g_q[NT * DM];
__device__ unsigned g_qnhi[NT * (DM / 2)];
__device__ unsigned g_qnlo[NT * (DM / 2)];
__device__ float g_Z[NT * DP];
__device__ float g_XBC[2 * NT * CD];
__device__ float g_dt[2 * NT * NH];
__device__ float g_a[2 * NT * NH];
__device__ float g_cum[2 * NH * NCH * CQ];
__device__ float g_cdec[2 * NH * NCH];
__device__ float g_S[2 * NH * NCH * HD * DS];
__device__ float g_Hp[2 * NH * NCH * HD * DS];
__device__ float g_Y[2 * NT * DI];
__device__ unsigned g_combhi[NT * (DI / 2)];
__device__ unsigned g_comblo[NT * (DI / 2)];
__device__ float g_O[NT * DM];
__device__ unsigned g_Whi[NPIN * (DM / 2)];
__device__ unsigned g_Wlo[NPIN * (DM / 2)];
__device__ unsigned long long g_keys[2 * NT];
__device__ int g_order[2 * NT];
__device__ int g_inv[2 * NT];
__device__ float g_pmin[3], g_pmax[3];

extern __shared__ float dynsmem[];

// ---------------- helpers ----------------
__device__ __forceinline__ float blockReduceSum(float v) {
    __shared__ float sh[32];
    __shared__ float tot;
    int lane = threadIdx.x & 31, wid = threadIdx.x >> 5;
    #pragma unroll
    for (int o = 16; o > 0; o >>= 1) v += __shfl_xor_sync(0xffffffffu, v, o);
    if (lane == 0) sh[wid] = v;
    __syncthreads();
    int nw = blockDim.x >> 5;
    v = (threadIdx.x < nw) ? sh[threadIdx.x] : 0.0f;
    if (wid == 0) {
        #pragma unroll
        for (int o = 16; o > 0; o >>= 1) v += __shfl_xor_sync(0xffffffffu, v, o);
        if (lane == 0) tot = v;
    }
    __syncthreads();
    return tot;
}

__device__ __forceinline__ unsigned hilbert3(unsigned a0, unsigned a1, unsigned a2) {
    unsigned x0 = a0, x1 = a1, x2 = a2;
    const unsigned M = 1u << 9;
    for (unsigned Q = M; Q > 1; Q >>= 1) {
        unsigned P = Q - 1;
        if (x0 & Q) x0 ^= P;
        {
            unsigned t = (x0 ^ x1) & P;
            if (x1 & Q) { x0 ^= P; } else { x0 ^= t; x1 ^= t; }
        }
        {
            unsigned t = (x0 ^ x2) & P;
            if (x2 & Q) { x0 ^= P; } else { x0 ^= t; x2 ^= t; }
        }
    }
    x1 ^= x0;
    x2 ^= x1;
    unsigned t = 0;
    for (unsigned Q = M; Q > 1; Q >>= 1)
        if (x2 & Q) t ^= (Q - 1);
    x0 ^= t; x1 ^= t; x2 ^= t;
    unsigned code = 0;
    for (int b = 9; b >= 0; b--) {
        code = (code << 1) | ((x0 >> b) & 1);
        code = (code << 1) | ((x1 >> b) & 1);
        code = (code << 1) | ((x2 >> b) & 1);
    }
    return code;
}

__device__ __forceinline__ void bfsplit(float x, unsigned short& hi, unsigned short& lo) {
    __nv_bfloat16 h = __float2bfloat16(x);
    __nv_bfloat16 l = __float2bfloat16(x - __bfloat162float(h));
    hi = *(unsigned short*)&h;
    lo = *(unsigned short*)&l;
}

__device__ __forceinline__ void mma_bf16(float c[4], const unsigned a[4],
                                         unsigned b0, unsigned b1) {
    asm volatile("mma.sync.aligned.m16n8k16.row.col.f32.bf16.bf16.f32 "
        "{%0,%1,%2,%3}, {%4,%5,%6,%7}, {%8,%9}, {%0,%1,%2,%3};"
        : "+f"(c[0]), "+f"(c[1]), "+f"(c[2]), "+f"(c[3])
        : "r"(a[0]), "r"(a[1]), "r"(a[2]), "r"(a[3]), "r"(b0), "r"(b1));
}

__device__ __forceinline__ void cp16(unsigned dst, const void* src) {
    asm volatile("cp.async.cg.shared.global [%0], [%1], 16;" :: "r"(dst), "l"(src));
}

// ---- packed f32x2 FMA ----
__device__ __forceinline__ void fma2(unsigned long long& c, unsigned long long a,
                                     unsigned long long b) {
    asm("fma.rn.f32x2 %0, %1, %2, %0;" : "+l"(c) : "l"(a), "l"(b));
}
__device__ __forceinline__ unsigned long long bcast2(float x) {
    unsigned long long r;
    unsigned u = __float_as_uint(x);
    asm("mov.b64 %0, {%1, %2};" : "=l"(r) : "r"(u), "r"(u));
    return r;
}
__device__ __forceinline__ unsigned long long packf2(float a, float b) {
    unsigned long long r;
    asm("mov.b64 %0, {%1, %2};" : "=l"(r) : "r"(__float_as_uint(a)), "r"(__float_as_uint(b)));
    return r;
}
__device__ __forceinline__ float2 unpack2(unsigned long long v) {
    unsigned lo, hi;
    asm("mov.b64 {%0, %1}, %2;" : "=r"(lo), "=r"(hi) : "l"(v));
    return make_float2(__uint_as_float(lo), __uint_as_float(hi));
}

// ---------------- setup kernels ----------------
__global__ void k_minmax(const float* __restrict__ pos) {
    __shared__ float smn[256][3], smx[256][3];
    float mn[3] = {1e30f, 1e30f, 1e30f}, mx[3] = {-1e30f, -1e30f, -1e30f};
    for (int r = threadIdx.x; r < NT; r += 256) {
        #pragma unroll
        for (int j = 0; j < 3; j++) {
            float v = pos[r * 3 + j];
            mn[j] = fminf(mn[j], v);
            mx[j] = fmaxf(mx[j], v);
        }
    }
    #pragma unroll
    for (int j = 0; j < 3; j++) { smn[threadIdx.x][j] = mn[j]; smx[threadIdx.x][j] = mx[j]; }
    __syncthreads();
    for (int s = 128; s > 0; s >>= 1) {
        if (threadIdx.x < s) {
            #pragma unroll
            for (int j = 0; j < 3; j++) {
                smn[threadIdx.x][j] = fminf(smn[threadIdx.x][j], smn[threadIdx.x + s][j]);
                smx[threadIdx.x][j] = fmaxf(smx[threadIdx.x][j], smx[threadIdx.x + s][j]);
            }
        }
        __syncthreads();
    }
    if (threadIdx.x == 0) {
        #pragma unroll
        for (int j = 0; j < 3; j++) { g_pmin[j] = smn[0][j]; g_pmax[j] = smx[0][j]; }
    }
}

__global__ void k_keys(const float* __restrict__ pos) {
    int idx = blockIdx.x * blockDim.x + threadIdx.x;
    if (idx >= NT) return;
    unsigned g[3];
    #pragma unroll
    for (int j = 0; j < 3; j++) {
        float denom = g_pmax[j] - g_pmin[j] + 1e-6f;
        float v = ((pos[idx * 3 + j] - g_pmin[j]) / denom) * 1023.0f;
        v = fminf(fmaxf(v, 0.0f), 1023.0f);
        g[j] = (unsigned)(int)v;
    }
    unsigned c0 = hilbert3(g[0], g[1], g[2]);
    unsigned c1 = hilbert3(g[1], g[0], g[2]);
    g_keys[idx]      = (((unsigned long long)c0) << 14) | (unsigned long long)idx;
    g_keys[NT + idx] = (((unsigned long long)c1) << 14) | (unsigned long long)idx;
}

#define SADDR(i) ((i) + ((i) >> 4))

// Phase A: fully sort each 2048-segment, direction = segment parity
__global__ void k_sort_init() {
    __shared__ unsigned long long s[SEG + SEG / 16];
    int seg = blockIdx.x, b = blockIdx.y;
    unsigned long long* keys = g_keys + b * NT + seg * SEG;
    bool upg = ((seg & 1) == 0);
    int t = threadIdx.x;  // 128 threads
    for (int i = t; i < SEG; i += 128) s[SADDR(i)] = keys[i];
    __syncthreads();

    int base = t * 16;
    unsigned long long v[16];
    #pragma unroll
    for (int r = 0; r < 16; r++) v[r] = s[SADDR(base + r)];
    #pragma unroll
    for (int k = 2; k <= 16; k <<= 1) {
        #pragma unroll
        for (int j = k >> 1; j > 0; j >>= 1) {
            #pragma unroll
            for (int r = 0; r < 16; r++) {
                int rr = r ^ j;
                if (rr > r) {
                    bool up = ((((base + r) & k) == 0) == upg);
                    unsigned long long a = v[r], c = v[rr];
                    if ((a > c) == up) { v[r] = c; v[rr] = a; }
                }
            }
        }
    }
    #pragma unroll
    for (int r = 0; r < 16; r++) s[SADDR(base + r)] = v[r];
    __syncthreads();

    for (int k = 32; k <= SEG; k <<= 1) {
        for (int j = k >> 1; j >= 16; j >>= 1) {
            for (int i = t; i < SEG; i += 128) {
                int ixj = i ^ j;
                if (ixj > i) {
                    unsigned long long a = s[SADDR(i)], c = s[SADDR(ixj)];
                    bool up = (((i & k) == 0) == upg);
                    if ((a > c) == up) { s[SADDR(i)] = c; s[SADDR(ixj)] = a; }
                }
            }
            __syncthreads();
        }
        #pragma unroll
        for (int r = 0; r < 16; r++) v[r] = s[SADDR(base + r)];
        bool up = (((base & k) == 0) == upg);
        #pragma unroll
        for (int j = 8; j > 0; j >>= 1) {
            #pragma unroll
            for (int r = 0; r < 16; r++) {
                int rr = r ^ j;
                if (rr > r) {
                    unsigned long long a = v[r], c = v[rr];
                    if ((a > c) == up) { v[r] = c; v[rr] = a; }
                }
            }
        }
        #pragma unroll
        for (int r = 0; r < 16; r++) s[SADDR(base + r)] = v[r];
        __syncthreads();
    }
    for (int i = t; i < SEG; i += 128) keys[i] = s[SADDR(i)];
}

// Global compare-exchange pass (j >= SEG)
__global__ void k_sort_gpass(int k, int j) {
    int p = blockIdx.x * blockDim.x + threadIdx.x;  // 0..NT/2-1 pairs
    int b = blockIdx.y;
    int low = p & (j - 1);
    int i = ((p & ~(j - 1)) << 1) | low;
    unsigned long long* keys = g_keys + b * NT;
    unsigned long long a = keys[i], c = keys[i + j];
    bool up = ((i & k) == 0);
    if ((a > c) == up) { keys[i] = c; keys[i + j] = a; }
}

// Local merge for round k: j = 1024..1 inside each segment (direction constant)
__global__ void k_sort_local(int k) {
    __shared__ unsigned long long s[SEG + SEG / 16];
    int seg = blockIdx.x, b = blockIdx.y;
    unsigned long long* keys = g_keys + b * NT + seg * SEG;
    bool up = (((seg * SEG) & k) == 0);
    int t = threadIdx.x;
    for (int i = t; i < SEG; i += 128) s[SADDR(i)] = keys[i];
    __syncthreads();
    for (int j = SEG / 2; j >= 16; j >>= 1) {
        for (int i = t; i < SEG; i += 128) {
            int ixj = i ^ j;
            if (ixj > i) {
                unsigned long long a = s[SADDR(i)], c = s[SADDR(ixj)];
                if ((a > c) == up) { s[SADDR(i)] = c; s[SADDR(ixj)] = a; }
            }
        }
        __syncthreads();
    }
    int base = t * 16;
    unsigned long long v[16];
    #pragma unroll
    for (int r = 0; r < 16; r++) v[r] = s[SADDR(base + r)];
    #pragma unroll
    for (int j = 8; j > 0; j >>= 1) {
        #pragma unroll
        for (int r = 0; r < 16; r++) {
            int rr = r ^ j;
            if (rr > r) {
                unsigned long long a = v[r], c = v[rr];
                if ((a > c) == up) { v[r] = c; v[rr] = a; }
            }
        }
    }
    #pragma unroll
    for (int r = 0; r < 16; r++) s[SADDR(base + r)] = v[r];
    __syncthreads();
    for (int i = t; i < SEG; i += 128) keys[i] = s[SADDR(i)];
}

__global__ void k_order() {
    int i = blockIdx.x * blockDim.x + threadIdx.x;
    if (i >= 2 * NT) return;
    int b = i / NT;
    int idx = (int)(g_keys[i] & 0x3FFFULL);
    g_order[i] = idx;
    g_inv[b * NT + idx] = i - b * NT;
}

__global__ void k_ln256(const float* __restrict__ src,
                        const float* __restrict__ w, const float* __restrict__ bias) {
    int r = blockIdx.x, t = threadIdx.x;
    float2 v = *(const float2*)(src + (size_t)r * DM + 2 * t);
    float mean = blockReduceSum(v.x + v.y) * (1.0f / DM);
    float x0 = v.x - mean, x1 = v.y - mean;
    float var = blockReduceSum(x0 * x0 + x1 * x1) * (1.0f / DM);
    float rs = rsqrtf(var + 1e-5f);
    float r0 = x0 * rs * w[2 * t] + bias[2 * t];
    float r1 = x1 * rs * w[2 * t + 1] + bias[2 * t + 1];
    unsigned short h0, l0, h1, l1;
    bfsplit(r0, h0, l0);
    bfsplit(r1, h1, l1);
    g_qnhi[r * (DM / 2) + t] = (unsigned)h0 | ((unsigned)h1 << 16);
    g_qnlo[r * (DM / 2) + t] = (unsigned)l0 | ((unsigned)l1 << 16);
}

__global__ void k_splitW(const float* __restrict__ src, int K, int N, int NP) {
    int idx = blockIdx.x * blockDim.x + threadIdx.x;
    if (idx >= (K / 2) * NP) return;
    int kp = idx / NP, n = idx - kp * NP;
    float w0 = (n < N) ? src[(size_t)(2 * kp) * N + n] : 0.0f;
    float w1 = (n < N) ? src[(size_t)(2 * kp + 1) * N + n] : 0.0f;
    unsigned short h0, l0, h1, l1;
    bfsplit(w0, h0, l0);
    bfsplit(w1, h1, l1);
    g_Whi[(size_t)n * (K / 2) + kp] = (unsigned)h0 | ((unsigned)h1 << 16);
    g_Wlo[(size_t)n * (K / 2) + kp] = (unsigned)l0 | ((unsigned)l1 << 16);
}

// ---------------- bf16x3 tensor-core GEMM (R4/R7-proven) ----------------
__device__ __forceinline__ void gemm_load_bf(
    const unsigned* __restrict__ Ahi, const unsigned* __restrict__ Alo, int K2,
    const unsigned* __restrict__ Bhi, const unsigned* __restrict__ Blo,
    int m0, int n0, int kt, unsigned* sAh, unsigned* sAl,
    unsigned* sBh, unsigned* sBl, int tid) {
    int kp0 = kt * 16;
    int r = tid >> 1, cu = (tid & 1) * 8;
    const unsigned* pah = Ahi + (size_t)(m0 + r) * K2 + kp0 + cu;
    const unsigned* pal = Alo + (size_t)(m0 + r) * K2 + kp0 + cu;
    unsigned dah = (unsigned)__cvta_generic_to_shared(sAh + r * WSTR + cu);
    unsigned dal = (unsigned)__cvta_generic_to_shared(sAl + r * WSTR + cu);
    cp16(dah, pah); cp16(dah + 16, pah + 4);
    cp16(dal, pal); cp16(dal + 16, pal + 4);
    int n = tid >> 2, cb = (tid & 3) * 4;
    cp16((unsigned)__cvta_generic_to_shared(sBh + n * WSTR + cb),
         Bhi + (size_t)(n0 + n) * K2 + kp0 + cb);
    cp16((unsigned)__cvta_generic_to_shared(sBl + n * WSTR + cb),
         Blo + (size_t)(n0 + n) * K2 + kp0 + cb);
}

__global__ __launch_bounds__(256) void k_gemm_bf(int M, int N, int K,
        const unsigned* __restrict__ Ahi, const unsigned* __restrict__ Alo,
        float* __restrict__ C, int ldc) {
    const unsigned* Bhi = g_Whi;
    const unsigned* Blo = g_Wlo;
    unsigned* sm = (unsigned*)dynsmem;
    const int ASZ = 128 * WSTR, BSZ = 64 * WSTR;
    const int STG = 2 * ASZ + 2 * BSZ;

    int m0 = blockIdx.y * 128, n0 = blockIdx.x * 64;
    int tid = threadIdx.x;
    int wid = tid >> 5, lane = tid & 31;
    int wm = (wid & 3) * 32, wn = (wid >> 2) * 32;
    int g = lane >> 2, tg = lane & 3;
    int K2 = K >> 1;
    int KT = K / 32;

    float acc[2][4][4];
    #pragma unroll
    for (int a = 0; a < 2; a++)
        #pragma unroll
        for (int b = 0; b < 4; b++)
            #pragma unroll
            for (int c = 0; c < 4; c++) acc[a][b][c] = 0.0f;

    gemm_load_bf(Ahi, Alo, K2, Bhi, Blo, m0, n0, 0,
                 sm, sm + ASZ, sm + 2 * ASZ, sm + 2 * ASZ + BSZ, tid);
    asm volatile("cp.async.commit_group;");

    for (int kt = 0; kt < KT; kt++) {
        int st = kt & 1;
        if (kt + 1 < KT) {
            int ns = st ^ 1;
            unsigned* b0 = sm + ns * STG;
            gemm_load_bf(Ahi, Alo, K2, Bhi, Blo, m0, n0, kt + 1,
                         b0, b0 + ASZ, b0 + 2 * ASZ, b0 + 2 * ASZ + BSZ, tid);
            asm volatile("cp.async.commit_group;");
            asm volatile("cp.async.wait_group 1;");
        } else {
            asm volatile("cp.async.wait_group 0;");
        }
        __syncthreads();
        unsigned* sAhi = sm + st * STG;
        unsigned* sAlo = sAhi + ASZ;
        unsigned* sBhi = sAhi + 2 * ASZ;
        unsigned* sBlo = sBhi + BSZ;
        #pragma unroll
        for (int kk2 = 0; kk2 < 16; kk2 += 8) {
            unsigned ahi[2][4], alo[2][4], bhi[4][2], blo[4][2];
            #pragma unroll
            for (int mi = 0; mi < 2; mi++) {
                int ra = (wm + mi * 16 + g) * WSTR;
                int rb = (wm + mi * 16 + g + 8) * WSTR;
                ahi[mi][0] = sAhi[ra + kk2 + tg];
                ahi[mi][1] = sAhi[rb + kk2 + tg];
                ahi[mi][2] = sAhi[ra + kk2 + 4 + tg];
                ahi[mi][3] = sAhi[rb + kk2 + 4 + tg];
                alo[mi][0] = sAlo[ra + kk2 + tg];
                alo[mi][1] = sAlo[rb + kk2 + tg];
                alo[mi][2] = sAlo[ra + kk2 + 4 + tg];
                alo[mi][3] = sAlo[rb + kk2 + 4 + tg];
            }
            #pragma unroll
            for (int nj = 0; nj < 4; nj++) {
                int rn = (wn + nj * 8 + g) * WSTR;
                bhi[nj][0] = sBhi[rn + kk2 + tg];
                bhi[nj][1] = sBhi[rn + kk2 + 4 + tg];
                blo[nj][0] = sBlo[rn + kk2 + tg];
                blo[nj][1] = sBlo[rn + kk2 + 4 + tg];
            }
            #pragma unroll
            for (int mi = 0; mi < 2; mi++)
                #pragma unroll
                for (int nj = 0; nj < 4; nj++) {
                    mma_bf16(acc[mi][nj], ahi[mi], bhi[nj][0], bhi[nj][1]);
                    mma_bf16(acc[mi][nj], ahi[mi], blo[nj][0], blo[nj][1]);
                    mma_bf16(acc[mi][nj], alo[mi], bhi[nj][0], bhi[nj][1]);
                }
        }
        __syncthreads();
    }
    #pragma unroll
    for (int mi = 0; mi < 2; mi++)
        #pragma unroll
        for (int nj = 0; nj < 4; nj++) {
            int row = m0 + wm + mi * 16 + g;
            int col = n0 + wn + nj * 8 + tg * 2;
            if (col + 1 < N) {
                *(float2*)(C + (size_t)row * ldc + col) =
                    make_float2(acc[mi][nj][0], acc[mi][nj][1]);
                *(float2*)(C + (size_t)(row + 8) * ldc + col) =
                    make_float2(acc[mi][nj][2], acc[mi][nj][3]);
            } else if (col < N) {
                C[(size_t)row * ldc + col] = acc[mi][nj][0];
                C[(size_t)(row + 8) * ldc + col] = acc[mi][nj][2];
            }
        }
}

// ---------------- tiled conv + dt ----------------
__global__ __launch_bounds__(256) void k_conv2(const float* __restrict__ cw,
                                               const float* __restrict__ cb) {
    float* sZ  = dynsmem;                     // (64+3) x CTILE
    float* scw = sZ + 67 * CTILE;             // CTILE x 4
    float* scb = scw + CTILE * 4;             // CTILE
    int*   stok = (int*)(scb + CTILE);        // 67
    int r0 = blockIdx.x * 64, cc = blockIdx.y * CTILE, b = blockIdx.z;
    int tid = threadIdx.x;
    if (tid < 67) {
        int rr = r0 - 3 + tid;
        stok[tid] = (rr >= 0) ? g_order[b * NT + rr] : -1;
    }
    for (int idx = tid; idx < CTILE * 4; idx += 256)
        scw[idx] = cw[(cc + (idx >> 2)) * KER + (idx & 3)];
    for (int idx = tid; idx < CTILE; idx += 256)
        scb[idx] = cb[cc + idx];
    __syncthreads();
    for (int idx = tid; idx < 67 * CTILE; idx += 256) {
        int row = idx / CTILE, col = idx - row * CTILE;
        int t = stok[row];
        sZ[idx] = (t >= 0) ? g_Z[(size_t)t * DP + DI + cc + col] : 0.0f;
    }
    __syncthreads();
    for (int idx = tid; idx < 64 * CTILE; idx += 256) {
        int row = idx / CTILE, col = idx - row * CTILE;
        float acc = scb[col];
        #pragma unroll
        for (int k = 0; k < KER; k++)
            acc += scw[col * 4 + k] * sZ[(row + k) * CTILE + col];
        float s = acc / (1.0f + __expf(-acc));
        g_XBC[(size_t)(b * NT + r0 + row) * CD + cc + col] = s;
    }
}

__global__ void k_dt(const float* __restrict__ dtb, const float* __restrict__ alog) {
    int i = blockIdx.x * blockDim.x + threadIdx.x;
    if (i >= 2 * NT * NH) return;
    int b = i / (NT * NH);
    int rem = i - b * NT * NH;
    int r = rem / NH, h = rem - r * NH;
    int t = g_order[b * NT + r];
    float x = g_Z[(size_t)t * DP + DI + CD + h] + dtb[h];
    float sp = fmaxf(x, 0.0f) + log1pf(expf(-fabsf(x)));
    float A = -expf(alog[h]);
    g_dt[i] = sp;
    g_a[i] = sp * A;
}

// ---------------- chunked scan (f32x2-packed math) ----------------
__global__ __launch_bounds__(256) void k_scan1() {
    int c = blockIdx.x, h = blockIdx.y, b = blockIdx.z;
    __shared__ float sX[CQ * SR], sB[CQ * SR];
    __shared__ float scum[CQ], sw[CQ];
    int r0 = c * CQ, tid = threadIdx.x;
    for (int idx = tid; idx < CQ * 64; idx += 256) {
        int j = idx >> 6, p = idx & 63;
        sX[j * SR + p] = g_XBC[(size_t)(b * NT + r0 + j) * CD + h * HD + p];
        sB[j * SR + p] = g_XBC[(size_t)(b * NT + r0 + j) * CD + DI + p];
    }
    if (tid < CQ) scum[tid] = g_a[(size_t)(b * NT + r0 + tid) * NH + h];
    __syncthreads();
    if (tid < CQ) {
        float x = scum[tid];
        #pragma unroll
        for (int o = 1; o < 32; o <<= 1) {
            float y = __shfl_up_sync(0xffffffffu, x, o);
            if ((tid & 31) >= o) x += y;
        }
        scum[tid] = x;
    }
    __syncthreads();
    if (tid >= 32 && tid < CQ) scum[tid] += scum[31];
    __syncthreads();
    float slast = scum[CQ - 1];
    if (tid < CQ) {
        sw[tid] = __expf(slast - scum[tid]) * g_dt[(size_t)(b * NT + r0 + tid) * NH + h];
        g_cum[((b * NH + h) * NCH + c) * CQ + tid] = scum[tid];
    }
    if (tid == 0) g_cdec[(b * NH + h) * NCH + c] = __expf(slast);
    __syncthreads();
    int p0 = (tid & 15) * 4, s0 = (tid >> 4) * 4;
    unsigned long long acc2[4][2] = {};
    for (int j = 0; j < CQ; j++) {
        float4 xv = *(float4*)&sX[j * SR + p0];
        ulonglong2 b2 = *(const ulonglong2*)&sB[j * SR + s0];
        float w = sw[j];
        float wx[4] = {xv.x * w, xv.y * w, xv.z * w, xv.w * w};
        #pragma unroll
        for (int pi = 0; pi < 4; pi++) {
            unsigned long long w2 = bcast2(wx[pi]);
            fma2(acc2[pi][0], w2, b2.x);
            fma2(acc2[pi][1], w2, b2.y);
        }
    }
    size_t base = ((size_t)((b * NH + h) * NCH + c) * HD) * DS;
    #pragma unroll
    for (int pi = 0; pi < 4; pi++) {
        float2 a01 = unpack2(acc2[pi][0]);
        float2 a23 = unpack2(acc2[pi][1]);
        *(float4*)&g_S[base + (size_t)(p0 + pi) * DS + s0] =
            make_float4(a01.x, a01.y, a23.x, a23.y);
    }
}

__global__ void k_scan2() {
    __shared__ float scd[NCH];
    int bh = blockIdx.x >> 4;
    int e = ((blockIdx.x & 15) << 8) + threadIdx.x;
    if (threadIdx.x < NCH) scd[threadIdx.x] = g_cdec[bh * NCH + threadIdx.x];
    __syncthreads();
    float H = 0.0f;
    for (int c = 0; c < NCH; c++) {
        size_t off = ((size_t)(bh * NCH + c)) * (HD * DS) + e;
        float s = g_S[off];
        g_Hp[off] = H;
        H = scd[c] * H + s;
    }
}

__global__ __launch_bounds__(256) void k_scan3(const float* __restrict__ Dv) {
    int c = blockIdx.x, b = blockIdx.y;
    int r0 = c * CQ, tid = threadIdx.x;
    float* sB  = dynsmem;
    float* sC  = sB  + CQ * SR;
    float* sD0 = sC  + CQ * SR;
    float* sX  = sD0 + CQ * SR;
    float* sH  = sX  + CQ * SR;
    float* sG  = sH  + CQ * SR;
    float* scum = sG + CQ * SR;
    float* sdt  = scum + CQ;
    float* seY  = sdt + CQ;

    for (int idx = tid; idx < CQ * 64; idx += 256) {
        int j = idx >> 6, s = idx & 63;
        sB[j * SR + s] = g_XBC[(size_t)(b * NT + r0 + j) * CD + DI + s];
        sC[j * SR + s] = g_XBC[(size_t)(b * NT + r0 + j) * CD + DI + DS + s];
    }
    __syncthreads();
    int i0 = (tid >> 4) * 4, j0 = (tid & 15) * 4;
    {
        unsigned long long acc2[4][4] = {};
        for (int sc = 0; sc < 64; sc += 4) {
            ulonglong2 Cr[4], Br[4];
            #pragma unroll
            for (int r = 0; r < 4; r++) Cr[r] = *(const ulonglong2*)&sC[(i0 + r) * SR + sc];
            #pragma unroll
            for (int q = 0; q < 4; q++) Br[q] = *(const ulonglong2*)&sB[(j0 + q) * SR + sc];
            #pragma unroll
            for (int r = 0; r < 4; r++)
                #pragma unroll
                for (int q = 0; q < 4; q++) {
                    fma2(acc2[r][q], Cr[r].x, Br[q].x);
                    fma2(acc2[r][q], Cr[r].y, Br[q].y);
                }
        }
        #pragma unroll
        for (int r = 0; r < 4; r++) {
            float dv[4];
            #pragma unroll
            for (int q = 0; q < 4; q++) {
                float2 p = unpack2(acc2[r][q]);
                dv[q] = p.x + p.y;
            }
            *(float4*)&sD0[(i0 + r) * SR + j0] = make_float4(dv[0], dv[1], dv[2], dv[3]);
        }
    }
    __syncthreads();

    for (int h = 0; h < NH; h++) {
        for (int idx = tid; idx < CQ * 64; idx += 256) {
            int j = idx >> 6, p = idx & 63;
            sX[j * SR + p] = g_XBC[(size_t)(b * NT + r0 + j) * CD + h * HD + p];
            sH[j * SR + p] = g_Hp[((size_t)((b * NH + h) * NCH + c) * HD) * DS + idx];
        }
        if (tid < CQ) {
            float cu = g_cum[((b * NH + h) * NCH + c) * CQ + tid];
            scum[tid] = cu;
            sdt[tid] = g_dt[(size_t)(b * NT + r0 + tid) * NH + h];
            seY[tid] = __expf(cu);
        }
        __syncthreads();
        {
            #pragma unroll
            for (int r = 0; r < 4; r++) {
                float4 d = *(float4*)&sD0[(i0 + r) * SR + j0];
                float dd[4] = {d.x, d.y, d.z, d.w};
                float gv[4];
                int i = i0 + r;
                float ci = scum[i];
                #pragma unroll
                for (int q = 0; q < 4; q++) {
                    int j = j0 + q;
                    gv[q] = (j <= i) ? __expf(ci - scum[j]) * sdt[j] * dd[q] : 0.0f;
                }
                *(float4*)&sG[(i0 + r) * SR + j0] = make_float4(gv[0], gv[1], gv[2], gv[3]);
            }
        }
        __syncthreads();
        int p0 = j0;
        float acc[4][4];
        {
            unsigned long long acc2[4][4] = {};
            for (int sc = 0; sc < 64; sc += 4) {
                ulonglong2 Cr[4], Hc[4];
                #pragma unroll
                for (int r = 0; r < 4; r++) Cr[r] = *(const ulonglong2*)&sC[(i0 + r) * SR + sc];
                #pragma unroll
                for (int q = 0; q < 4; q++) Hc[q] = *(const ulonglong2*)&sH[(p0 + q) * SR + sc];
                #pragma unroll
                for (int r = 0; r < 4; r++)
                    #pragma unroll
                    for (int q = 0; q < 4; q++) {
                        fma2(acc2[r][q], Cr[r].x, Hc[q].x);
                        fma2(acc2[r][q], Cr[r].y, Hc[q].y);
                    }
            }
            #pragma unroll
            for (int r = 0; r < 4; r++) {
                float e = seY[i0 + r];
                #pragma unroll
                for (int q = 0; q < 4; q++) {
                    float2 p = unpack2(acc2[r][q]);
                    acc[r][q] = e * (p.x + p.y);
                }
            }
        }
        unsigned long long accq[4][2];
        #pragma unroll
        for (int r = 0; r < 4; r++) {
            accq[r][0] = packf2(acc[r][0], acc[r][1]);
            accq[r][1] = packf2(acc[r][2], acc[r][3]);
        }
        for (int jc = 0; jc < 64; jc += 4) {
            float G4[4][4];
            #pragma unroll
            for (int r = 0; r < 4; r++) {
                float4 t = *(float4*)&sG[(i0 + r) * SR + jc];
                G4[r][0] = t.x; G4[r][1] = t.y; G4[r][2] = t.z; G4[r][3] = t.w;
            }
            #pragma unroll
            for (int q = 0; q < 4; q++) {
                ulonglong2 x2 = *(const ulonglong2*)&sX[(jc + q) * SR + p0];
                #pragma unroll
                for (int r = 0; r < 4; r++) {
                    unsigned long long g2 = bcast2(G4[r][q]);
                    fma2(accq[r][0], g2, x2.x);
                    fma2(accq[r][1], g2, x2.y);
                }
            }
        }
        unsigned long long D2 = bcast2(Dv[h]);
        #pragma unroll
        for (int r = 0; r < 4; r++) {
            ulonglong2 xi2 = *(const ulonglong2*)&sX[(i0 + r) * SR + p0];
            fma2(accq[r][0], D2, xi2.x);
            fma2(accq[r][1], D2, xi2.y);
            float2 y01 = unpack2(accq[r][0]);
            float2 y23 = unpack2(accq[r][1]);
            *(float4*)&g_Y[(size_t)(b * NT + r0 + i0 + r) * DI + h * HD + p0] =
                make_float4(y01.x, y01.y, y23.x, y23.y);
        }
        __syncthreads();
    }
}

// ---------------- epilogue ----------------
__global__ void k_postnorm(const float* __restrict__ nw) {
    int r = blockIdx.x, b = blockIdx.y, tid = threadIdx.x;
    int t = g_order[b * NT + r];
    float v0, v1, ss;
    {
        float y0 = g_Y[(size_t)(b * NT + r) * DI + tid];
        float g0 = g_Z[(size_t)t * DP + tid];
        v0 = y0 * (g0 / (1.0f + __expf(-g0)));
        float y1 = g_Y[(size_t)(b * NT + r) * DI + tid + 256];
        float g1 = g_Z[(size_t)t * DP + tid + 256];
        v1 = y1 * (g1 / (1.0f + __expf(-g1)));
        ss = v0 * v0 + v1 * v1;
    }
    ss = blockReduceSum(ss);
    float rr = rsqrtf(ss * (1.0f / DI) + 1e-5f);
    g_Y[(size_t)(b * NT + r) * DI + tid]       = v0 * rr * nw[tid];
    g_Y[(size_t)(b * NT + r) * DI + tid + 256] = v1 * rr * nw[tid + 256];
}

__global__ void k_combine() {
    int t = blockIdx.x, c = threadIdx.x;
    int r0 = g_inv[t], r1 = g_inv[NT + t];
    float2 a = *(const float2*)(g_Y + (size_t)r0 * DI + 2 * c);
    float2 bq = *(const float2*)(g_Y + (size_t)(NT + r1) * DI + 2 * c);
    float v0 = 0.5f * (a.x + bq.x);
    float v1 = 0.5f * (a.y + bq.y);
    unsigned short h0, l0, h1, l1;
    bfsplit(v0, h0, l0);
    bfsplit(v1, h1, l1);
    g_combhi[(size_t)t * (DI / 2) + c] = (unsigned)h0 | ((unsigned)h1 << 16);
    g_comblo[(size_t)t * (DI / 2) + c] = (unsigned)l0 | ((unsigned)l1 << 16);
}

__global__ void k_final(const float* __restrict__ res,
                        const float* __restrict__ w, const float* __restrict__ bias,
                        float* __restrict__ dout) {
    int r = blockIdx.x, c = threadIdx.x;
    float v = res[(size_t)r * DM + c] + g_O[r * DM + c];
    float mean = blockReduceSum(v) * (1.0f / DM);
    float xc = v - mean;
    float var = blockReduceSum(xc * xc) * (1.0f / DM);
    float result = xc * rsqrtf(var + 1e-5f) * w[c] + bias[c];
    g_q[r * DM + c] = result;
    if (dout) dout[r * DM + c] = result;
}

// ---------------- launcher ----------------
extern "C" void kernel_launch(void* const* d_in, const int* in_sizes, int n_in,
                              void* d_out, int out_size) {
    (void)in_sizes; (void)n_in; (void)out_size;
    const float* query = (const float*)d_in[0];
    const float* pos   = (const float*)d_in[1];
    const float* pre_w = (const float*)d_in[2];
    const float* pre_b = (const float*)d_in[3];
    const float* fin_w = (const float*)d_in[4];
    const float* fin_b = (const float*)d_in[5];

    const int GEMM_SMEM = 2 * (2 * 128 * WSTR + 2 * 64 * WSTR) * 4;
    const int SCAN3_SMEM = (6 * CQ * SR + 3 * CQ) * 4;
    const int CONV_SMEM = (67 * CTILE + CTILE * 4 + CTILE) * 4 + 68 * 4;
    cudaFuncSetAttribute(k_gemm_bf, cudaFuncAttributeMaxDynamicSharedMemorySize, GEMM_SMEM);
    cudaFuncSetAttribute(k_scan3, cudaFuncAttributeMaxDynamicSharedMemorySize, SCAN3_SMEM);
    cudaFuncSetAttribute(k_conv2, cudaFuncAttributeMaxDynamicSharedMemorySize, CONV_SMEM);

    unsigned *p_qnhi, *p_qnlo, *p_combhi, *p_comblo;
    float *p_Z, *p_O, *p_q;
    cudaGetSymbolAddress((void**)&p_qnhi, g_qnhi);
    cudaGetSymbolAddress((void**)&p_qnlo, g_qnlo);
    cudaGetSymbolAddress((void**)&p_combhi, g_combhi);
    cudaGetSymbolAddress((void**)&p_comblo, g_comblo);
    cudaGetSymbolAddress((void**)&p_Z, g_Z);
    cudaGetSymbolAddress((void**)&p_O, g_O);
    cudaGetSymbolAddress((void**)&p_q, g_q);

    k_minmax<<<1, 256>>>(pos);
    k_keys<<<(NT + 255) / 256, 256>>>(pos);
    // multi-block bitonic sort: local init, then global+local merge rounds
    k_sort_init<<<dim3(NT / SEG, 2), 128>>>();
    for (int k = 2 * SEG; k <= NT; k <<= 1) {
        for (int j = k >> 1; j >= SEG; j >>= 1)
            k_sort_gpass<<<dim3(NT / 2 / 256, 2), 256>>>(k, j);
        k_sort_local<<<dim3(NT / SEG, 2), 128>>>(k);
    }
    k_order<<<(2 * NT + 255) / 256, 256>>>();

    for (int L = 0; L < 2; L++) {
        const float* Win  = (const float*)d_in[6 + 8 * L];
        const float* cw   = (const float*)d_in[7 + 8 * L];
        const float* cb   = (const float*)d_in[8 + 8 * L];
        const float* dtb  = (const float*)d_in[9 + 8 * L];
        const float* alog = (const float*)d_in[10 + 8 * L];
        const float* Dv   = (const float*)d_in[11 + 8 * L];
        const float* nw   = (const float*)d_in[12 + 8 * L];
        const float* Wout = (const float*)d_in[13 + 8 * L];
        const float* src  = (L == 0) ? query : p_q;

        k_ln256<<<NT, 128>>>(src, pre_w, pre_b);
        k_splitW<<<((DM / 2) * NPIN + 255) / 256, 256>>>(Win, DM, DP, NPIN);
        k_gemm_bf<<<dim3(NPIN / 64, NT / 128), 256, GEMM_SMEM>>>(
            NT, DP, DM, p_qnhi, p_qnlo, p_Z, DP);
        k_conv2<<<dim3(NT / 64, CD / CTILE, 2), 256, CONV_SMEM>>>(cw, cb);
        k_dt<<<(2 * NT * NH + 255) / 256, 256>>>(dtb, alog);
        k_scan1<<<dim3(NCH, NH, 2), 256>>>();
        k_scan2<<<256, 256>>>();
        k_scan3<<<dim3(NCH, 2), 256, SCAN3_SMEM>>>(Dv);
        k_postnorm<<<dim3(NT, 2), 256>>>(nw);
        k_combine<<<NT, 256>>>();
        k_splitW<<<((DI / 2) * DM + 255) / 256, 256>>>(Wout, DI, DM, DM);
        k_gemm_bf<<<dim3(DM / 64, NT / 128), 256, GEMM_SMEM>>>(
            NT, DM, DI, p_combhi, p_comblo, p_O, DM);
        k_final<<<NT, 256>>>(src, fin_w, fin_b, (L == 1) ? (float*)d_out : nullptr);
    }
}

// round 12
// speedup vs baseline: 1.5591x; 1.0168x over previous
#include <cuda_runtime.h>
#include <cuda_bf16.h>
#include <math.h>

#define NT 16384
#define DM 256
#define DI 512
#define DS 64
#define NH 8
#define HD 64
#define CD 640      // CONV_DIM
#define DP 1160     // D_PROJ
#define KER 4
#define NCH 256     // number of chunks
#define CQ 64       // chunk length
#define SR 68       // padded row stride for 64-col smem tiles
#define NPIN 1216   // padded N for in_proj (19*64)
#define WSTR 20     // GEMM smem row stride in uints
#define CTILE 160   // conv col chunk
#define SEG 2048    // sort segment

// ---------------- device scratch ----------------
__device__ float g_q[NT * DM];
__device__ unsigned g_qnhi[NT * (DM / 2)];
__device__ unsigned g_qnlo[NT * (DM / 2)];
__device__ float g_Z[NT * DP];
__device__ float g_XBC[2 * NT * CD];
__device__ float g_dt[2 * NT * NH];
__device__ float g_a[2 * NT * NH];
__device__ float g_cum[2 * NH * NCH * CQ];
__device__ float g_cdec[2 * NH * NCH];
__device__ float g_S[2 * NH * NCH * HD * DS];
__device__ float g_Hp[2 * NH * NCH * HD * DS];
__device__ float g_Y[2 * NT * DI];
__device__ unsigned g_combhi[NT * (DI / 2)];
__device__ unsigned g_comblo[NT * (DI / 2)];
__device__ float g_O[NT * DM];
__device__ unsigned g_Whi[NPIN * (DM / 2)];
__device__ unsigned g_Wlo[NPIN * (DM / 2)];
__device__ unsigned long long g_keys[2 * NT];
__device__ int g_order[2 * NT];
__device__ int g_inv[2 * NT];
__device__ float g_pmin[3], g_pmax[3];

extern __shared__ float dynsmem[];

// ---------------- helpers ----------------
__device__ __forceinline__ float blockReduceSum(float v) {
    __shared__ float sh[32];
    __shared__ float tot;
    int lane = threadIdx.x & 31, wid = threadIdx.x >> 5;
    #pragma unroll
    for (int o = 16; o > 0; o >>= 1) v += __shfl_xor_sync(0xffffffffu, v, o);
    if (lane == 0) sh[wid] = v;
    __syncthreads();
    int nw = blockDim.x >> 5;
    v = (threadIdx.x < nw) ? sh[threadIdx.x] : 0.0f;
    if (wid == 0) {
        #pragma unroll
        for (int o = 16; o > 0; o >>= 1) v += __shfl_xor_sync(0xffffffffu, v, o);
        if (lane == 0) tot = v;
    }
    __syncthreads();
    return tot;
}

__device__ __forceinline__ unsigned hilbert3(unsigned a0, unsigned a1, unsigned a2) {
    unsigned x0 = a0, x1 = a1, x2 = a2;
    const unsigned M = 1u << 9;
    for (unsigned Q = M; Q > 1; Q >>= 1) {
        unsigned P = Q - 1;
        if (x0 & Q) x0 ^= P;
        {
            unsigned t = (x0 ^ x1) & P;
            if (x1 & Q) { x0 ^= P; } else { x0 ^= t; x1 ^= t; }
        }
        {
            unsigned t = (x0 ^ x2) & P;
            if (x2 & Q) { x0 ^= P; } else { x0 ^= t; x2 ^= t; }
        }
    }
    x1 ^= x0;
    x2 ^= x1;
    unsigned t = 0;
    for (unsigned Q = M; Q > 1; Q >>= 1)
        if (x2 & Q) t ^= (Q - 1);
    x0 ^= t; x1 ^= t; x2 ^= t;
    unsigned code = 0;
    for (int b = 9; b >= 0; b--) {
        code = (code << 1) | ((x0 >> b) & 1);
        code = (code << 1) | ((x1 >> b) & 1);
        code = (code << 1) | ((x2 >> b) & 1);
    }
    return code;
}

__device__ __forceinline__ void bfsplit(float x, unsigned short& hi, unsigned short& lo) {
    __nv_bfloat16 h = __float2bfloat16(x);
    __nv_bfloat16 l = __float2bfloat16(x - __bfloat162float(h));
    hi = *(unsigned short*)&h;
    lo = *(unsigned short*)&l;
}

__device__ __forceinline__ void mma_bf16(float c[4], const unsigned a[4],
                                         unsigned b0, unsigned b1) {
    asm volatile("mma.sync.aligned.m16n8k16.row.col.f32.bf16.bf16.f32 "
        "{%0,%1,%2,%3}, {%4,%5,%6,%7}, {%8,%9}, {%0,%1,%2,%3};"
        : "+f"(c[0]), "+f"(c[1]), "+f"(c[2]), "+f"(c[3])
        : "r"(a[0]), "r"(a[1]), "r"(a[2]), "r"(a[3]), "r"(b0), "r"(b1));
}

__device__ __forceinline__ void cp16(unsigned dst, const void* src) {
    asm volatile("cp.async.cg.shared.global [%0], [%1], 16;" :: "r"(dst), "l"(src));
}

// ---- packed f32x2 FMA ----
__device__ __forceinline__ void fma2(unsigned long long& c, unsigned long long a,
                                     unsigned long long b) {
    asm("fma.rn.f32x2 %0, %1, %2, %0;" : "+l"(c) : "l"(a), "l"(b));
}
__device__ __forceinline__ unsigned long long bcast2(float x) {
    unsigned long long r;
    unsigned u = __float_as_uint(x);
    asm("mov.b64 %0, {%1, %2};" : "=l"(r) : "r"(u), "r"(u));
    return r;
}
__device__ __forceinline__ unsigned long long packf2(float a, float b) {
    unsigned long long r;
    asm("mov.b64 %0, {%1, %2};" : "=l"(r) : "r"(__float_as_uint(a)), "r"(__float_as_uint(b)));
    return r;
}
__device__ __forceinline__ float2 unpack2(unsigned long long v) {
    unsigned lo, hi;
    asm("mov.b64 {%0, %1}, %2;" : "=r"(lo), "=r"(hi) : "l"(v));
    return make_float2(__uint_as_float(lo), __uint_as_float(hi));
}

// ---------------- setup kernels ----------------
__global__ void k_minmax(const float* __restrict__ pos) {
    __shared__ float smn[256][3], smx[256][3];
    float mn[3] = {1e30f, 1e30f, 1e30f}, mx[3] = {-1e30f, -1e30f, -1e30f};
    for (int r = threadIdx.x; r < NT; r += 256) {
        #pragma unroll
        for (int j = 0; j < 3; j++) {
            float v = pos[r * 3 + j];
            mn[j] = fminf(mn[j], v);
            mx[j] = fmaxf(mx[j], v);
        }
    }
    #pragma unroll
    for (int j = 0; j < 3; j++) { smn[threadIdx.x][j] = mn[j]; smx[threadIdx.x][j] = mx[j]; }
    __syncthreads();
    for (int s = 128; s > 0; s >>= 1) {
        if (threadIdx.x < s) {
            #pragma unroll
            for (int j = 0; j < 3; j++) {
                smn[threadIdx.x][j] = fminf(smn[threadIdx.x][j], smn[threadIdx.x + s][j]);
                smx[threadIdx.x][j] = fmaxf(smx[threadIdx.x][j], smx[threadIdx.x + s][j]);
            }
        }
        __syncthreads();
    }
    if (threadIdx.x == 0) {
        #pragma unroll
        for (int j = 0; j < 3; j++) { g_pmin[j] = smn[0][j]; g_pmax[j] = smx[0][j]; }
    }
}

__global__ void k_keys(const float* __restrict__ pos) {
    int idx = blockIdx.x * blockDim.x + threadIdx.x;
    if (idx >= NT) return;
    unsigned g[3];
    #pragma unroll
    for (int j = 0; j < 3; j++) {
        float denom = g_pmax[j] - g_pmin[j] + 1e-6f;
        float v = ((pos[idx * 3 + j] - g_pmin[j]) / denom) * 1023.0f;
        v = fminf(fmaxf(v, 0.0f), 1023.0f);
        g[j] = (unsigned)(int)v;
    }
    unsigned c0 = hilbert3(g[0], g[1], g[2]);
    unsigned c1 = hilbert3(g[1], g[0], g[2]);
    g_keys[idx]      = (((unsigned long long)c0) << 14) | (unsigned long long)idx;
    g_keys[NT + idx] = (((unsigned long long)c1) << 14) | (unsigned long long)idx;
}

#define SADDR(i) ((i) + ((i) >> 4))

// Phase A: fully sort each 2048-segment, direction = segment parity
__global__ void k_sort_init() {
    __shared__ unsigned long long s[SEG + SEG / 16];
    int seg = blockIdx.x, b = blockIdx.y;
    unsigned long long* keys = g_keys + b * NT + seg * SEG;
    bool upg = ((seg & 1) == 0);
    int t = threadIdx.x;  // 128 threads
    for (int i = t; i < SEG; i += 128) s[SADDR(i)] = keys[i];
    __syncthreads();

    int base = t * 16;
    unsigned long long v[16];
    #pragma unroll
    for (int r = 0; r < 16; r++) v[r] = s[SADDR(base + r)];
    #pragma unroll
    for (int k = 2; k <= 16; k <<= 1) {
        #pragma unroll
        for (int j = k >> 1; j > 0; j >>= 1) {
            #pragma unroll
            for (int r = 0; r < 16; r++) {
                int rr = r ^ j;
                if (rr > r) {
                    bool up = ((((base + r) & k) == 0) == upg);
                    unsigned long long a = v[r], c = v[rr];
                    if ((a > c) == up) { v[r] = c; v[rr] = a; }
                }
            }
        }
    }
    #pragma unroll
    for (int r = 0; r < 16; r++) s[SADDR(base + r)] = v[r];
    __syncthreads();

    for (int k = 32; k <= SEG; k <<= 1) {
        for (int j = k >> 1; j >= 16; j >>= 1) {
            for (int i = t; i < SEG; i += 128) {
                int ixj = i ^ j;
                if (ixj > i) {
                    unsigned long long a = s[SADDR(i)], c = s[SADDR(ixj)];
                    bool up = (((i & k) == 0) == upg);
                    if ((a > c) == up) { s[SADDR(i)] = c; s[SADDR(ixj)] = a; }
                }
            }
            __syncthreads();
        }
        #pragma unroll
        for (int r = 0; r < 16; r++) v[r] = s[SADDR(base + r)];
        bool up = (((base & k) == 0) == upg);
        #pragma unroll
        for (int j = 8; j > 0; j >>= 1) {
            #pragma unroll
            for (int r = 0; r < 16; r++) {
                int rr = r ^ j;
                if (rr > r) {
                    unsigned long long a = v[r], c = v[rr];
                    if ((a > c) == up) { v[r] = c; v[rr] = a; }
                }
            }
        }
        #pragma unroll
        for (int r = 0; r < 16; r++) s[SADDR(base + r)] = v[r];
        __syncthreads();
    }
    for (int i = t; i < SEG; i += 128) keys[i] = s[SADDR(i)];
}

// Global compare-exchange pass (j >= SEG)
__global__ void k_sort_gpass(int k, int j) {
    int p = blockIdx.x * blockDim.x + threadIdx.x;  // 0..NT/2-1 pairs
    int b = blockIdx.y;
    int low = p & (j - 1);
    int i = ((p & ~(j - 1)) << 1) | low;
    unsigned long long* keys = g_keys + b * NT;
    unsigned long long a = keys[i], c = keys[i + j];
    bool up = ((i & k) == 0);
    if ((a > c) == up) { keys[i] = c; keys[i + j] = a; }
}

// Local merge for round k: j = 1024..1 inside each segment (direction constant)
__global__ void k_sort_local(int k) {
    __shared__ unsigned long long s[SEG + SEG / 16];
    int seg = blockIdx.x, b = blockIdx.y;
    unsigned long long* keys = g_keys + b * NT + seg * SEG;
    bool up = (((seg * SEG) & k) == 0);
    int t = threadIdx.x;
    for (int i = t; i < SEG; i += 128) s[SADDR(i)] = keys[i];
    __syncthreads();
    for (int j = SEG / 2; j >= 16; j >>= 1) {
        for (int i = t; i < SEG; i += 128) {
            int ixj = i ^ j;
            if (ixj > i) {
                unsigned long long a = s[SADDR(i)], c = s[SADDR(ixj)];
                if ((a > c) == up) { s[SADDR(i)] = c; s[SADDR(ixj)] = a; }
            }
        }
        __syncthreads();
    }
    int base = t * 16;
    unsigned long long v[16];
    #pragma unroll
    for (int r = 0; r < 16; r++) v[r] = s[SADDR(base + r)];
    #pragma unroll
    for (int j = 8; j > 0; j >>= 1) {
        #pragma unroll
        for (int r = 0; r < 16; r++) {
            int rr = r ^ j;
            if (rr > r) {
                unsigned long long a = v[r], c = v[rr];
                if ((a > c) == up) { v[r] = c; v[rr] = a; }
            }
        }
    }
    #pragma unroll
    for (int r = 0; r < 16; r++) s[SADDR(base + r)] = v[r];
    __syncthreads();
    for (int i = t; i < SEG; i += 128) keys[i] = s[SADDR(i)];
}

__global__ void k_order() {
    int i = blockIdx.x * blockDim.x + threadIdx.x;
    if (i >= 2 * NT) return;
    int b = i / NT;
    int idx = (int)(g_keys[i] & 0x3FFFULL);
    g_order[i] = idx;
    g_inv[b * NT + idx] = i - b * NT;
}

__global__ void k_ln256(const float* __restrict__ src,
                        const float* __restrict__ w, const float* __restrict__ bias) {
    int r = blockIdx.x, t = threadIdx.x;
    float2 v = *(const float2*)(src + (size_t)r * DM + 2 * t);
    float mean = blockReduceSum(v.x + v.y) * (1.0f / DM);
    float x0 = v.x - mean, x1 = v.y - mean;
    float var = blockReduceSum(x0 * x0 + x1 * x1) * (1.0f / DM);
    float rs = rsqrtf(var + 1e-5f);
    float r0 = x0 * rs * w[2 * t] + bias[2 * t];
    float r1 = x1 * rs * w[2 * t + 1] + bias[2 * t + 1];
    unsigned short h0, l0, h1, l1;
    bfsplit(r0, h0, l0);
    bfsplit(r1, h1, l1);
    g_qnhi[r * (DM / 2) + t] = (unsigned)h0 | ((unsigned)h1 << 16);
    g_qnlo[r * (DM / 2) + t] = (unsigned)l0 | ((unsigned)l1 << 16);
}

__global__ void k_splitW(const float* __restrict__ src, int K, int N, int NP) {
    int idx = blockIdx.x * blockDim.x + threadIdx.x;
    if (idx >= (K / 2) * NP) return;
    int kp = idx / NP, n = idx - kp * NP;
    float w0 = (n < N) ? src[(size_t)(2 * kp) * N + n] : 0.0f;
    float w1 = (n < N) ? src[(size_t)(2 * kp + 1) * N + n] : 0.0f;
    unsigned short h0, l0, h1, l1;
    bfsplit(w0, h0, l0);
    bfsplit(w1, h1, l1);
    g_Whi[(size_t)n * (K / 2) + kp] = (unsigned)h0 | ((unsigned)h1 << 16);
    g_Wlo[(size_t)n * (K / 2) + kp] = (unsigned)l0 | ((unsigned)l1 << 16);
}

// ---------------- bf16x3 tensor-core GEMM (R4/R7-proven) ----------------
__device__ __forceinline__ void gemm_load_bf(
    const unsigned* __restrict__ Ahi, const unsigned* __restrict__ Alo, int K2,
    const unsigned* __restrict__ Bhi, const unsigned* __restrict__ Blo,
    int m0, int n0, int kt, unsigned* sAh, unsigned* sAl,
    unsigned* sBh, unsigned* sBl, int tid) {
    int kp0 = kt * 16;
    int r = tid >> 1, cu = (tid & 1) * 8;
    const unsigned* pah = Ahi + (size_t)(m0 + r) * K2 + kp0 + cu;
    const unsigned* pal = Alo + (size_t)(m0 + r) * K2 + kp0 + cu;
    unsigned dah = (unsigned)__cvta_generic_to_shared(sAh + r * WSTR + cu);
    unsigned dal = (unsigned)__cvta_generic_to_shared(sAl + r * WSTR + cu);
    cp16(dah, pah); cp16(dah + 16, pah + 4);
    cp16(dal, pal); cp16(dal + 16, pal + 4);
    int n = tid >> 2, cb = (tid & 3) * 4;
    cp16((unsigned)__cvta_generic_to_shared(sBh + n * WSTR + cb),
         Bhi + (size_t)(n0 + n) * K2 + kp0 + cb);
    cp16((unsigned)__cvta_generic_to_shared(sBl + n * WSTR + cb),
         Blo + (size_t)(n0 + n) * K2 + kp0 + cb);
}

__global__ __launch_bounds__(256) void k_gemm_bf(int M, int N, int K,
        const unsigned* __restrict__ Ahi, const unsigned* __restrict__ Alo,
        float* __restrict__ C, int ldc) {
    const unsigned* Bhi = g_Whi;
    const unsigned* Blo = g_Wlo;
    unsigned* sm = (unsigned*)dynsmem;
    const int ASZ = 128 * WSTR, BSZ = 64 * WSTR;
    const int STG = 2 * ASZ + 2 * BSZ;

    int m0 = blockIdx.y * 128, n0 = blockIdx.x * 64;
    int tid = threadIdx.x;
    int wid = tid >> 5, lane = tid & 31;
    int wm = (wid & 3) * 32, wn = (wid >> 2) * 32;
    int g = lane >> 2, tg = lane & 3;
    int K2 = K >> 1;
    int KT = K / 32;

    float acc[2][4][4];
    #pragma unroll
    for (int a = 0; a < 2; a++)
        #pragma unroll
        for (int b = 0; b < 4; b++)
            #pragma unroll
            for (int c = 0; c < 4; c++) acc[a][b][c] = 0.0f;

    gemm_load_bf(Ahi, Alo, K2, Bhi, Blo, m0, n0, 0,
                 sm, sm + ASZ, sm + 2 * ASZ, sm + 2 * ASZ + BSZ, tid);
    asm volatile("cp.async.commit_group;");

    for (int kt = 0; kt < KT; kt++) {
        int st = kt & 1;
        if (kt + 1 < KT) {
            int ns = st ^ 1;
            unsigned* b0 = sm + ns * STG;
            gemm_load_bf(Ahi, Alo, K2, Bhi, Blo, m0, n0, kt + 1,
                         b0, b0 + ASZ, b0 + 2 * ASZ, b0 + 2 * ASZ + BSZ, tid);
            asm volatile("cp.async.commit_group;");
            asm volatile("cp.async.wait_group 1;");
        } else {
            asm volatile("cp.async.wait_group 0;");
        }
        __syncthreads();
        unsigned* sAhi = sm + st * STG;
        unsigned* sAlo = sAhi + ASZ;
        unsigned* sBhi = sAhi + 2 * ASZ;
        unsigned* sBlo = sBhi + BSZ;
        #pragma unroll
        for (int kk2 = 0; kk2 < 16; kk2 += 8) {
            unsigned ahi[2][4], alo[2][4], bhi[4][2], blo[4][2];
            #pragma unroll
            for (int mi = 0; mi < 2; mi++) {
                int ra = (wm + mi * 16 + g) * WSTR;
                int rb = (wm + mi * 16 + g + 8) * WSTR;
                ahi[mi][0] = sAhi[ra + kk2 + tg];
                ahi[mi][1] = sAhi[rb + kk2 + tg];
                ahi[mi][2] = sAhi[ra + kk2 + 4 + tg];
                ahi[mi][3] = sAhi[rb + kk2 + 4 + tg];
                alo[mi][0] = sAlo[ra + kk2 + tg];
                alo[mi][1] = sAlo[rb + kk2 + tg];
                alo[mi][2] = sAlo[ra + kk2 + 4 + tg];
                alo[mi][3] = sAlo[rb + kk2 + 4 + tg];
            }
            #pragma unroll
            for (int nj = 0; nj < 4; nj++) {
                int rn = (wn + nj * 8 + g) * WSTR;
                bhi[nj][0] = sBhi[rn + kk2 + tg];
                bhi[nj][1] = sBhi[rn + kk2 + 4 + tg];
                blo[nj][0] = sBlo[rn + kk2 + tg];
                blo[nj][1] = sBlo[rn + kk2 + 4 + tg];
            }
            #pragma unroll
            for (int mi = 0; mi < 2; mi++)
                #pragma unroll
                for (int nj = 0; nj < 4; nj++) {
                    mma_bf16(acc[mi][nj], ahi[mi], bhi[nj][0], bhi[nj][1]);
                    mma_bf16(acc[mi][nj], ahi[mi], blo[nj][0], blo[nj][1]);
                    mma_bf16(acc[mi][nj], alo[mi], bhi[nj][0], bhi[nj][1]);
                }
        }
        __syncthreads();
    }
    #pragma unroll
    for (int mi = 0; mi < 2; mi++)
        #pragma unroll
        for (int nj = 0; nj < 4; nj++) {
            int row = m0 + wm + mi * 16 + g;
            int col = n0 + wn + nj * 8 + tg * 2;
            if (col + 1 < N) {
                *(float2*)(C + (size_t)row * ldc + col) =
                    make_float2(acc[mi][nj][0], acc[mi][nj][1]);
                *(float2*)(C + (size_t)(row + 8) * ldc + col) =
                    make_float2(acc[mi][nj][2], acc[mi][nj][3]);
            } else if (col < N) {
                C[(size_t)row * ldc + col] = acc[mi][nj][0];
                C[(size_t)(row + 8) * ldc + col] = acc[mi][nj][2];
            }
        }
}

// ---------------- tiled conv + dt ----------------
__global__ __launch_bounds__(256) void k_conv2(const float* __restrict__ cw,
                                               const float* __restrict__ cb) {
    float* sZ  = dynsmem;                     // (64+3) x CTILE
    float* scw = sZ + 67 * CTILE;             // CTILE x 4
    float* scb = scw + CTILE * 4;             // CTILE
    int*   stok = (int*)(scb + CTILE);        // 67
    int r0 = blockIdx.x * 64, cc = blockIdx.y * CTILE, b = blockIdx.z;
    int tid = threadIdx.x;
    if (tid < 67) {
        int rr = r0 - 3 + tid;
        stok[tid] = (rr >= 0) ? g_order[b * NT + rr] : -1;
    }
    for (int idx = tid; idx < CTILE * 4; idx += 256)
        scw[idx] = cw[(cc + (idx >> 2)) * KER + (idx & 3)];
    for (int idx = tid; idx < CTILE; idx += 256)
        scb[idx] = cb[cc + idx];
    __syncthreads();
    for (int idx = tid; idx < 67 * CTILE; idx += 256) {
        int row = idx / CTILE, col = idx - row * CTILE;
        int t = stok[row];
        sZ[idx] = (t >= 0) ? g_Z[(size_t)t * DP + DI + cc + col] : 0.0f;
    }
    __syncthreads();
    for (int idx = tid; idx < 64 * CTILE; idx += 256) {
        int row = idx / CTILE, col = idx - row * CTILE;
        float acc = scb[col];
        #pragma unroll
        for (int k = 0; k < KER; k++)
            acc += scw[col * 4 + k] * sZ[(row + k) * CTILE + col];
        float s = acc / (1.0f + __expf(-acc));
        g_XBC[(size_t)(b * NT + r0 + row) * CD + cc + col] = s;
    }
}

__global__ void k_dt(const float* __restrict__ dtb, const float* __restrict__ alog) {
    int i = blockIdx.x * blockDim.x + threadIdx.x;
    if (i >= 2 * NT * NH) return;
    int b = i / (NT * NH);
    int rem = i - b * NT * NH;
    int r = rem / NH, h = rem - r * NH;
    int t = g_order[b * NT + r];
    float x = g_Z[(size_t)t * DP + DI + CD + h] + dtb[h];
    float sp = fmaxf(x, 0.0f) + log1pf(expf(-fabsf(x)));
    float A = -expf(alog[h]);
    g_dt[i] = sp;
    g_a[i] = sp * A;
}

// ---------------- chunked scan (f32x2-packed math) ----------------
__global__ __launch_bounds__(256) void k_scan1() {
    int c = blockIdx.x, h = blockIdx.y, b = blockIdx.z;
    __shared__ float sX[CQ * SR], sB[CQ * SR];
    __shared__ float scum[CQ], sw[CQ];
    int r0 = c * CQ, tid = threadIdx.x;
    for (int idx = tid; idx < CQ * 64; idx += 256) {
        int j = idx >> 6, p = idx & 63;
        sX[j * SR + p] = g_XBC[(size_t)(b * NT + r0 + j) * CD + h * HD + p];
        sB[j * SR + p] = g_XBC[(size_t)(b * NT + r0 + j) * CD + DI + p];
    }
    if (tid < CQ) scum[tid] = g_a[(size_t)(b * NT + r0 + tid) * NH + h];
    __syncthreads();
    if (tid < CQ) {
        float x = scum[tid];
        #pragma unroll
        for (int o = 1; o < 32; o <<= 1) {
            float y = __shfl_up_sync(0xffffffffu, x, o);
            if ((tid & 31) >= o) x += y;
        }
        scum[tid] = x;
    }
    __syncthreads();
    if (tid >= 32 && tid < CQ) scum[tid] += scum[31];
    __syncthreads();
    float slast = scum[CQ - 1];
    if (tid < CQ) {
        sw[tid] = __expf(slast - scum[tid]) * g_dt[(size_t)(b * NT + r0 + tid) * NH + h];
        g_cum[((b * NH + h) * NCH + c) * CQ + tid] = scum[tid];
    }
    if (tid == 0) g_cdec[(b * NH + h) * NCH + c] = __expf(slast);
    __syncthreads();
    int p0 = (tid & 15) * 4, s0 = (tid >> 4) * 4;
    unsigned long long acc2[4][2] = {};
    for (int j = 0; j < CQ; j++) {
        float4 xv = *(float4*)&sX[j * SR + p0];
        ulonglong2 b2 = *(const ulonglong2*)&sB[j * SR + s0];
        float w = sw[j];
        float wx[4] = {xv.x * w, xv.y * w, xv.z * w, xv.w * w};
        #pragma unroll
        for (int pi = 0; pi < 4; pi++) {
            unsigned long long w2 = bcast2(wx[pi]);
            fma2(acc2[pi][0], w2, b2.x);
            fma2(acc2[pi][1], w2, b2.y);
        }
    }
    size_t base = ((size_t)((b * NH + h) * NCH + c) * HD) * DS;
    #pragma unroll
    for (int pi = 0; pi < 4; pi++) {
        float2 a01 = unpack2(acc2[pi][0]);
        float2 a23 = unpack2(acc2[pi][1]);
        *(float4*)&g_S[base + (size_t)(p0 + pi) * DS + s0] =
            make_float4(a01.x, a01.y, a23.x, a23.y);
    }
}

__global__ void k_scan2() {
    __shared__ float scd[NCH];
    int bh = blockIdx.x >> 4;
    int e = ((blockIdx.x & 15) << 8) + threadIdx.x;
    if (threadIdx.x < NCH) scd[threadIdx.x] = g_cdec[bh * NCH + threadIdx.x];
    __syncthreads();
    float H = 0.0f;
    for (int c = 0; c < NCH; c++) {
        size_t off = ((size_t)(bh * NCH + c)) * (HD * DS) + e;
        float s = g_S[off];
        g_Hp[off] = H;
        H = scd[c] * H + s;
    }
}

__global__ __launch_bounds__(256) void k_scan3(const float* __restrict__ Dv) {
    int c = blockIdx.x, b = blockIdx.y;
    int r0 = c * CQ, tid = threadIdx.x;
    float* sB  = dynsmem;
    float* sC  = sB  + CQ * SR;
    float* sD0 = sC  + CQ * SR;
    float* sX  = sD0 + CQ * SR;
    float* sH  = sX  + CQ * SR;
    float* sG  = sH  + CQ * SR;
    float* scum = sG + CQ * SR;
    float* sdt  = scum + CQ;
    float* seY  = sdt + CQ;

    for (int idx = tid; idx < CQ * 64; idx += 256) {
        int j = idx >> 6, s = idx & 63;
        sB[j * SR + s] = g_XBC[(size_t)(b * NT + r0 + j) * CD + DI + s];
        sC[j * SR + s] = g_XBC[(size_t)(b * NT + r0 + j) * CD + DI + DS + s];
    }
    __syncthreads();
    int i0 = (tid >> 4) * 4, j0 = (tid & 15) * 4;
    // D0 = C @ B^T: only needed for j <= i (causal); zero above-diagonal blocks
    if (j0 <= i0) {
        unsigned long long acc2[4][4] = {};
        for (int sc = 0; sc < 64; sc += 4) {
            ulonglong2 Cr[4], Br[4];
            #pragma unroll
            for (int r = 0; r < 4; r++) Cr[r] = *(const ulonglong2*)&sC[(i0 + r) * SR + sc];
            #pragma unroll
            for (int q = 0; q < 4; q++) Br[q] = *(const ulonglong2*)&sB[(j0 + q) * SR + sc];
            #pragma unroll
            for (int r = 0; r < 4; r++)
                #pragma unroll
                for (int q = 0; q < 4; q++) {
                    fma2(acc2[r][q], Cr[r].x, Br[q].x);
                    fma2(acc2[r][q], Cr[r].y, Br[q].y);
                }
        }
        #pragma unroll
        for (int r = 0; r < 4; r++) {
            float dv[4];
            #pragma unroll
            for (int q = 0; q < 4; q++) {
                float2 p = unpack2(acc2[r][q]);
                dv[q] = p.x + p.y;
            }
            *(float4*)&sD0[(i0 + r) * SR + j0] = make_float4(dv[0], dv[1], dv[2], dv[3]);
        }
    } else {
        #pragma unroll
        for (int r = 0; r < 4; r++)
            *(float4*)&sD0[(i0 + r) * SR + j0] = make_float4(0.f, 0.f, 0.f, 0.f);
    }
    __syncthreads();

    for (int h = 0; h < NH; h++) {
        for (int idx = tid; idx < CQ * 64; idx += 256) {
            int j = idx >> 6, p = idx & 63;
            sX[j * SR + p] = g_XBC[(size_t)(b * NT + r0 + j) * CD + h * HD + p];
            sH[j * SR + p] = g_Hp[((size_t)((b * NH + h) * NCH + c) * HD) * DS + idx];
        }
        if (tid < CQ) {
            float cu = g_cum[((b * NH + h) * NCH + c) * CQ + tid];
            scum[tid] = cu;
            sdt[tid] = g_dt[(size_t)(b * NT + r0 + tid) * NH + h];
            seY[tid] = __expf(cu);
        }
        __syncthreads();
        // build G (zero above diagonal; skip compute for fully-above blocks)
        if (j0 <= i0) {
            #pragma unroll
            for (int r = 0; r < 4; r++) {
                float4 d = *(float4*)&sD0[(i0 + r) * SR + j0];
                float dd[4] = {d.x, d.y, d.z, d.w};
                float gv[4];
                int i = i0 + r;
                float ci = scum[i];
                #pragma unroll
                for (int q = 0; q < 4; q++) {
                    int j = j0 + q;
                    gv[q] = (j <= i) ? __expf(ci - scum[j]) * sdt[j] * dd[q] : 0.0f;
                }
                *(float4*)&sG[(i0 + r) * SR + j0] = make_float4(gv[0], gv[1], gv[2], gv[3]);
            }
        } else {
            #pragma unroll
            for (int r = 0; r < 4; r++)
                *(float4*)&sG[(i0 + r) * SR + j0] = make_float4(0.f, 0.f, 0.f, 0.f);
        }
        __syncthreads();
        int p0 = j0;
        // CH phase: acc[r][q] = sum_s C[i0+r][s] * H[p0+q][s]
        float acc[4][4];
        {
            unsigned long long acc2[4][4] = {};
            for (int sc = 0; sc < 64; sc += 4) {
                ulonglong2 Cr[4], Hc[4];
                #pragma unroll
                for (int r = 0; r < 4; r++) Cr[r] = *(const ulonglong2*)&sC[(i0 + r) * SR + sc];
                #pragma unroll
                for (int q = 0; q < 4; q++) Hc[q] = *(const ulonglong2*)&sH[(p0 + q) * SR + sc];
                #pragma unroll
                for (int r = 0; r < 4; r++)
                    #pragma unroll
                    for (int q = 0; q < 4; q++) {
                        fma2(acc2[r][q], Cr[r].x, Hc[q].x);
                        fma2(acc2[r][q], Cr[r].y, Hc[q].y);
                    }
            }
            #pragma unroll
            for (int r = 0; r < 4; r++) {
                float e = seY[i0 + r];
                #pragma unroll
                for (int q = 0; q < 4; q++) {
                    float2 p = unpack2(acc2[r][q]);
                    acc[r][q] = e * (p.x + p.y);
                }
            }
        }
        unsigned long long accq[4][2];
        #pragma unroll
        for (int r = 0; r < 4; r++) {
            accq[r][0] = packf2(acc[r][0], acc[r][1]);
            accq[r][1] = packf2(acc[r][2], acc[r][3]);
        }
        // GX phase (causal): only jc <= i0 contributes (G zero beyond)
        for (int jc = 0; jc <= i0; jc += 4) {
            float G4[4][4];
            #pragma unroll
            for (int r = 0; r < 4; r++) {
                float4 t = *(float4*)&sG[(i0 + r) * SR + jc];
                G4[r][0] = t.x; G4[r][1] = t.y; G4[r][2] = t.z; G4[r][3] = t.w;
            }
            #pragma unroll
            for (int q = 0; q < 4; q++) {
                ulonglong2 x2 = *(const ulonglong2*)&sX[(jc + q) * SR + p0];
                #pragma unroll
                for (int r = 0; r < 4; r++) {
                    unsigned long long g2 = bcast2(G4[r][q]);
                    fma2(accq[r][0], g2, x2.x);
                    fma2(accq[r][1], g2, x2.y);
                }
            }
        }
        unsigned long long D2 = bcast2(Dv[h]);
        #pragma unroll
        for (int r = 0; r < 4; r++) {
            ulonglong2 xi2 = *(const ulonglong2*)&sX[(i0 + r) * SR + p0];
            fma2(accq[r][0], D2, xi2.x);
            fma2(accq[r][1], D2, xi2.y);
            float2 y01 = unpack2(accq[r][0]);
            float2 y23 = unpack2(accq[r][1]);
            *(float4*)&g_Y[(size_t)(b * NT + r0 + i0 + r) * DI + h * HD + p0] =
                make_float4(y01.x, y01.y, y23.x, y23.y);
        }
        __syncthreads();
    }
}

// ---------------- epilogue ----------------
__global__ void k_postnorm(const float* __restrict__ nw) {
    int r = blockIdx.x, b = blockIdx.y, tid = threadIdx.x;
    int t = g_order[b * NT + r];
    float v0, v1, ss;
    {
        float y0 = g_Y[(size_t)(b * NT + r) * DI + tid];
        float g0 = g_Z[(size_t)t * DP + tid];
        v0 = y0 * (g0 / (1.0f + __expf(-g0)));
        float y1 = g_Y[(size_t)(b * NT + r) * DI + tid + 256];
        float g1 = g_Z[(size_t)t * DP + tid + 256];
        v1 = y1 * (g1 / (1.0f + __expf(-g1)));
        ss = v0 * v0 + v1 * v1;
    }
    ss = blockReduceSum(ss);
    float rr = rsqrtf(ss * (1.0f / DI) + 1e-5f);
    g_Y[(size_t)(b * NT + r) * DI + tid]       = v0 * rr * nw[tid];
    g_Y[(size_t)(b * NT + r) * DI + tid + 256] = v1 * rr * nw[tid + 256];
}

__global__ void k_combine() {
    int t = blockIdx.x, c = threadIdx.x;
    int r0 = g_inv[t], r1 = g_inv[NT + t];
    float2 a = *(const float2*)(g_Y + (size_t)r0 * DI + 2 * c);
    float2 bq = *(const float2*)(g_Y + (size_t)(NT + r1) * DI + 2 * c);
    float v0 = 0.5f * (a.x + bq.x);
    float v1 = 0.5f * (a.y + bq.y);
    unsigned short h0, l0, h1, l1;
    bfsplit(v0, h0, l0);
    bfsplit(v1, h1, l1);
    g_combhi[(size_t)t * (DI / 2) + c] = (unsigned)h0 | ((unsigned)h1 << 16);
    g_comblo[(size_t)t * (DI / 2) + c] = (unsigned)l0 | ((unsigned)l1 << 16);
}

__global__ void k_final(const float* __restrict__ res,
                        const float* __restrict__ w, const float* __restrict__ bias,
                        float* __restrict__ dout) {
    int r = blockIdx.x, c = threadIdx.x;
    float v = res[(size_t)r * DM + c] + g_O[r * DM + c];
    float mean = blockReduceSum(v) * (1.0f / DM);
    float xc = v - mean;
    float var = blockReduceSum(xc * xc) * (1.0f / DM);
    float result = xc * rsqrtf(var + 1e-5f) * w[c] + bias[c];
    g_q[r * DM + c] = result;
    if (dout) dout[r * DM + c] = result;
}

// ---------------- launcher ----------------
extern "C" void kernel_launch(void* const* d_in, const int* in_sizes, int n_in,
                              void* d_out, int out_size) {
    (void)in_sizes; (void)n_in; (void)out_size;
    const float* query = (const float*)d_in[0];
    const float* pos   = (const float*)d_in[1];
    const float* pre_w = (const float*)d_in[2];
    const float* pre_b = (const float*)d_in[3];
    const float* fin_w = (const float*)d_in[4];
    const float* fin_b = (const float*)d_in[5];

    const int GEMM_SMEM = 2 * (2 * 128 * WSTR + 2 * 64 * WSTR) * 4;
    const int SCAN3_SMEM = (6 * CQ * SR + 3 * CQ) * 4;
    const int CONV_SMEM = (67 * CTILE + CTILE * 4 + CTILE) * 4 + 68 * 4;
    cudaFuncSetAttribute(k_gemm_bf, cudaFuncAttributeMaxDynamicSharedMemorySize, GEMM_SMEM);
    cudaFuncSetAttribute(k_scan3, cudaFuncAttributeMaxDynamicSharedMemorySize, SCAN3_SMEM);
    cudaFuncSetAttribute(k_conv2, cudaFuncAttributeMaxDynamicSharedMemorySize, CONV_SMEM);

    unsigned *p_qnhi, *p_qnlo, *p_combhi, *p_comblo;
    float *p_Z, *p_O, *p_q;
    cudaGetSymbolAddress((void**)&p_qnhi, g_qnhi);
    cudaGetSymbolAddress((void**)&p_qnlo, g_qnlo);
    cudaGetSymbolAddress((void**)&p_combhi, g_combhi);
    cudaGetSymbolAddress((void**)&p_comblo, g_comblo);
    cudaGetSymbolAddress((void**)&p_Z, g_Z);
    cudaGetSymbolAddress((void**)&p_O, g_O);
    cudaGetSymbolAddress((void**)&p_q, g_q);

    k_minmax<<<1, 256>>>(pos);
    k_keys<<<(NT + 255) / 256, 256>>>(pos);
    k_sort_init<<<dim3(NT / SEG, 2), 128>>>();
    for (int k = 2 * SEG; k <= NT; k <<= 1) {
        for (int j = k >> 1; j >= SEG; j >>= 1)
            k_sort_gpass<<<dim3(NT / 2 / 256, 2), 256>>>(k, j);
        k_sort_local<<<dim3(NT / SEG, 2), 128>>>(k);
    }
    k_order<<<(2 * NT + 255) / 256, 256>>>();

    for (int L = 0; L < 2; L++) {
        const float* Win  = (const float*)d_in[6 + 8 * L];
        const float* cw   = (const float*)d_in[7 + 8 * L];
        const float* cb   = (const float*)d_in[8 + 8 * L];
        const float* dtb  = (const float*)d_in[9 + 8 * L];
        const float* alog = (const float*)d_in[10 + 8 * L];
        const float* Dv   = (const float*)d_in[11 + 8 * L];
        const float* nw   = (const float*)d_in[12 + 8 * L];
        const float* Wout = (const float*)d_in[13 + 8 * L];
        const float* src  = (L == 0) ? query : p_q;

        k_ln256<<<NT, 128>>>(src, pre_w, pre_b);
        k_splitW<<<((DM / 2) * NPIN + 255) / 256, 256>>>(Win, DM, DP, NPIN);
        k_gemm_bf<<<dim3(NPIN / 64, NT / 128), 256, GEMM_SMEM>>>(
            NT, DP, DM, p_qnhi, p_qnlo, p_Z, DP);
        k_conv2<<<dim3(NT / 64, CD / CTILE, 2), 256, CONV_SMEM>>>(cw, cb);
        k_dt<<<(2 * NT * NH + 255) / 256, 256>>>(dtb, alog);
        k_scan1<<<dim3(NCH, NH, 2), 256>>>();
        k_scan2<<<256, 256>>>();
        k_scan3<<<dim3(NCH, 2), 256, SCAN3_SMEM>>>(Dv);
        k_postnorm<<<dim3(NT, 2), 256>>>(nw);
        k_combine<<<NT, 256>>>();
        k_splitW<<<((DI / 2) * DM + 255) / 256, 256>>>(Wout, DI, DM, DM);
        k_gemm_bf<<<dim3(DM / 64, NT / 128), 256, GEMM_SMEM>>>(
            NT, DM, DI, p_combhi, p_comblo, p_O, DM);
        k_final<<<NT, 256>>>(src, fin_w, fin_b, (L == 1) ? (float*)d_out : nullptr);
    }
}

// round 13
// speedup vs baseline: 1.5694x; 1.0066x over previous
#include <cuda_runtime.h>
#include <cuda_bf16.h>
#include <math.h>

#define NT 16384
#define DM 256
#define DI 512
#define DS 64
#define NH 8
#define HD 64
#define CD 640      // CONV_DIM
#define DP 1160     // D_PROJ
#define KER 4
#define NCH 256     // number of chunks
#define CQ 64       // chunk length
#define SR 68       // padded row stride for 64-col smem tiles
#define NPIN 1216   // padded N for in_proj (19*64)
#define WSTR 20     // GEMM smem row stride in uints
#define CTILE 160   // conv col chunk
#define SEG 2048    // sort segment

// ---------------- device scratch ----------------
__device__ float g_q[NT * DM];
__device__ unsigned g_qnhi[NT * (DM / 2)];
__device__ unsigned g_qnlo[NT * (DM / 2)];
__device__ float g_Z[NT * DP];
__device__ float g_XBC[2 * NT * CD];
__device__ float g_dt[2 * NT * NH];
__device__ float g_a[2 * NT * NH];
__device__ float g_cum[2 * NH * NCH * CQ];
__device__ float g_cdec[2 * NH * NCH];
__device__ float g_S[2 * NH * NCH * HD * DS];
__device__ float g_Hp[2 * NH * NCH * HD * DS];
__device__ float g_Y[2 * NT * DI];
__device__ unsigned g_combhi[NT * (DI / 2)];
__device__ unsigned g_comblo[NT * (DI / 2)];
__device__ float g_O[NT * DM];
__device__ unsigned g_Whi[NPIN * (DM / 2)];
__device__ unsigned g_Wlo[NPIN * (DM / 2)];
__device__ unsigned long long g_keys[2 * NT];
__device__ int g_order[2 * NT];
__device__ int g_inv[2 * NT];
__device__ float g_pmin[3], g_pmax[3];

extern __shared__ float dynsmem[];

// ---------------- helpers ----------------
__device__ __forceinline__ float blockReduceSum(float v) {
    __shared__ float sh[32];
    __shared__ float tot;
    int lane = threadIdx.x & 31, wid = threadIdx.x >> 5;
    #pragma unroll
    for (int o = 16; o > 0; o >>= 1) v += __shfl_xor_sync(0xffffffffu, v, o);
    if (lane == 0) sh[wid] = v;
    __syncthreads();
    int nw = blockDim.x >> 5;
    v = (threadIdx.x < nw) ? sh[threadIdx.x] : 0.0f;
    if (wid == 0) {
        #pragma unroll
        for (int o = 16; o > 0; o >>= 1) v += __shfl_xor_sync(0xffffffffu, v, o);
        if (lane == 0) tot = v;
    }
    __syncthreads();
    return tot;
}

__device__ __forceinline__ unsigned hilbert3(unsigned a0, unsigned a1, unsigned a2) {
    unsigned x0 = a0, x1 = a1, x2 = a2;
    const unsigned M = 1u << 9;
    for (unsigned Q = M; Q > 1; Q >>= 1) {
        unsigned P = Q - 1;
        if (x0 & Q) x0 ^= P;
        {
            unsigned t = (x0 ^ x1) & P;
            if (x1 & Q) { x0 ^= P; } else { x0 ^= t; x1 ^= t; }
        }
        {
            unsigned t = (x0 ^ x2) & P;
            if (x2 & Q) { x0 ^= P; } else { x0 ^= t; x2 ^= t; }
        }
    }
    x1 ^= x0;
    x2 ^= x1;
    unsigned t = 0;
    for (unsigned Q = M; Q > 1; Q >>= 1)
        if (x2 & Q) t ^= (Q - 1);
    x0 ^= t; x1 ^= t; x2 ^= t;
    unsigned code = 0;
    for (int b = 9; b >= 0; b--) {
        code = (code << 1) | ((x0 >> b) & 1);
        code = (code << 1) | ((x1 >> b) & 1);
        code = (code << 1) | ((x2 >> b) & 1);
    }
    return code;
}

__device__ __forceinline__ void bfsplit(float x, unsigned short& hi, unsigned short& lo) {
    __nv_bfloat16 h = __float2bfloat16(x);
    __nv_bfloat16 l = __float2bfloat16(x - __bfloat162float(h));
    hi = *(unsigned short*)&h;
    lo = *(unsigned short*)&l;
}

__device__ __forceinline__ void mma_bf16(float c[4], const unsigned a[4],
                                         unsigned b0, unsigned b1) {
    asm volatile("mma.sync.aligned.m16n8k16.row.col.f32.bf16.bf16.f32 "
        "{%0,%1,%2,%3}, {%4,%5,%6,%7}, {%8,%9}, {%0,%1,%2,%3};"
        : "+f"(c[0]), "+f"(c[1]), "+f"(c[2]), "+f"(c[3])
        : "r"(a[0]), "r"(a[1]), "r"(a[2]), "r"(a[3]), "r"(b0), "r"(b1));
}

__device__ __forceinline__ void cp16(unsigned dst, const void* src) {
    asm volatile("cp.async.cg.shared.global [%0], [%1], 16;" :: "r"(dst), "l"(src));
}

// ---- packed f32x2 FMA ----
__device__ __forceinline__ void fma2(unsigned long long& c, unsigned long long a,
                                     unsigned long long b) {
    asm("fma.rn.f32x2 %0, %1, %2, %0;" : "+l"(c) : "l"(a), "l"(b));
}
__device__ __forceinline__ unsigned long long bcast2(float x) {
    unsigned long long r;
    unsigned u = __float_as_uint(x);
    asm("mov.b64 %0, {%1, %2};" : "=l"(r) : "r"(u), "r"(u));
    return r;
}
__device__ __forceinline__ unsigned long long packf2(float a, float b) {
    unsigned long long r;
    asm("mov.b64 %0, {%1, %2};" : "=l"(r) : "r"(__float_as_uint(a)), "r"(__float_as_uint(b)));
    return r;
}
__device__ __forceinline__ float2 unpack2(unsigned long long v) {
    unsigned lo, hi;
    asm("mov.b64 {%0, %1}, %2;" : "=r"(lo), "=r"(hi) : "l"(v));
    return make_float2(__uint_as_float(lo), __uint_as_float(hi));
}

// ---------------- setup kernels ----------------
__global__ void k_minmax(const float* __restrict__ pos) {
    __shared__ float smn[256][3], smx[256][3];
    float mn[3] = {1e30f, 1e30f, 1e30f}, mx[3] = {-1e30f, -1e30f, -1e30f};
    for (int r = threadIdx.x; r < NT; r += 256) {
        #pragma unroll
        for (int j = 0; j < 3; j++) {
            float v = pos[r * 3 + j];
            mn[j] = fminf(mn[j], v);
            mx[j] = fmaxf(mx[j], v);
        }
    }
    #pragma unroll
    for (int j = 0; j < 3; j++) { smn[threadIdx.x][j] = mn[j]; smx[threadIdx.x][j] = mx[j]; }
    __syncthreads();
    for (int s = 128; s > 0; s >>= 1) {
        if (threadIdx.x < s) {
            #pragma unroll
            for (int j = 0; j < 3; j++) {
                smn[threadIdx.x][j] = fminf(smn[threadIdx.x][j], smn[threadIdx.x + s][j]);
                smx[threadIdx.x][j] = fmaxf(smx[threadIdx.x][j], smx[threadIdx.x + s][j]);
            }
        }
        __syncthreads();
    }
    if (threadIdx.x == 0) {
        #pragma unroll
        for (int j = 0; j < 3; j++) { g_pmin[j] = smn[0][j]; g_pmax[j] = smx[0][j]; }
    }
}

__global__ void k_keys(const float* __restrict__ pos) {
    int idx = blockIdx.x * blockDim.x + threadIdx.x;
    if (idx >= NT) return;
    unsigned g[3];
    #pragma unroll
    for (int j = 0; j < 3; j++) {
        float denom = g_pmax[j] - g_pmin[j] + 1e-6f;
        float v = ((pos[idx * 3 + j] - g_pmin[j]) / denom) * 1023.0f;
        v = fminf(fmaxf(v, 0.0f), 1023.0f);
        g[j] = (unsigned)(int)v;
    }
    unsigned c0 = hilbert3(g[0], g[1], g[2]);
    unsigned c1 = hilbert3(g[1], g[0], g[2]);
    g_keys[idx]      = (((unsigned long long)c0) << 14) | (unsigned long long)idx;
    g_keys[NT + idx] = (((unsigned long long)c1) << 14) | (unsigned long long)idx;
}

#define SADDR(i) ((i) + ((i) >> 4))

__global__ void k_sort_init() {
    __shared__ unsigned long long s[SEG + SEG / 16];
    int seg = blockIdx.x, b = blockIdx.y;
    unsigned long long* keys = g_keys + b * NT + seg * SEG;
    bool upg = ((seg & 1) == 0);
    int t = threadIdx.x;  // 128 threads
    for (int i = t; i < SEG; i += 128) s[SADDR(i)] = keys[i];
    __syncthreads();

    int base = t * 16;
    unsigned long long v[16];
    #pragma unroll
    for (int r = 0; r < 16; r++) v[r] = s[SADDR(base + r)];
    #pragma unroll
    for (int k = 2; k <= 16; k <<= 1) {
        #pragma unroll
        for (int j = k >> 1; j > 0; j >>= 1) {
            #pragma unroll
            for (int r = 0; r < 16; r++) {
                int rr = r ^ j;
                if (rr > r) {
                    bool up = ((((base + r) & k) == 0) == upg);
                    unsigned long long a = v[r], c = v[rr];
                    if ((a > c) == up) { v[r] = c; v[rr] = a; }
                }
            }
        }
    }
    #pragma unroll
    for (int r = 0; r < 16; r++) s[SADDR(base + r)] = v[r];
    __syncthreads();

    for (int k = 32; k <= SEG; k <<= 1) {
        for (int j = k >> 1; j >= 16; j >>= 1) {
            for (int i = t; i < SEG; i += 128) {
                int ixj = i ^ j;
                if (ixj > i) {
                    unsigned long long a = s[SADDR(i)], c = s[SADDR(ixj)];
                    bool up = (((i & k) == 0) == upg);
                    if ((a > c) == up) { s[SADDR(i)] = c; s[SADDR(ixj)] = a; }
                }
            }
            __syncthreads();
        }
        #pragma unroll
        for (int r = 0; r < 16; r++) v[r] = s[SADDR(base + r)];
        bool up = (((base & k) == 0) == upg);
        #pragma unroll
        for (int j = 8; j > 0; j >>= 1) {
            #pragma unroll
            for (int r = 0; r < 16; r++) {
                int rr = r ^ j;
                if (rr > r) {
                    unsigned long long a = v[r], c = v[rr];
                    if ((a > c) == up) { v[r] = c; v[rr] = a; }
                }
            }
        }
        #pragma unroll
        for (int r = 0; r < 16; r++) s[SADDR(base + r)] = v[r];
        __syncthreads();
    }
    for (int i = t; i < SEG; i += 128) keys[i] = s[SADDR(i)];
}

__global__ void k_sort_gpass(int k, int j) {
    int p = blockIdx.x * blockDim.x + threadIdx.x;
    int b = blockIdx.y;
    int low = p & (j - 1);
    int i = ((p & ~(j - 1)) << 1) | low;
    unsigned long long* keys = g_keys + b * NT;
    unsigned long long a = keys[i], c = keys[i + j];
    bool up = ((i & k) == 0);
    if ((a > c) == up) { keys[i] = c; keys[i + j] = a; }
}

__global__ void k_sort_local(int k) {
    __shared__ unsigned long long s[SEG + SEG / 16];
    int seg = blockIdx.x, b = blockIdx.y;
    unsigned long long* keys = g_keys + b * NT + seg * SEG;
    bool up = (((seg * SEG) & k) == 0);
    int t = threadIdx.x;
    for (int i = t; i < SEG; i += 128) s[SADDR(i)] = keys[i];
    __syncthreads();
    for (int j = SEG / 2; j >= 16; j >>= 1) {
        for (int i = t; i < SEG; i += 128) {
            int ixj = i ^ j;
            if (ixj > i) {
                unsigned long long a = s[SADDR(i)], c = s[SADDR(ixj)];
                if ((a > c) == up) { s[SADDR(i)] = c; s[SADDR(ixj)] = a; }
            }
        }
        __syncthreads();
    }
    int base = t * 16;
    unsigned long long v[16];
    #pragma unroll
    for (int r = 0; r < 16; r++) v[r] = s[SADDR(base + r)];
    #pragma unroll
    for (int j = 8; j > 0; j >>= 1) {
        #pragma unroll
        for (int r = 0; r < 16; r++) {
            int rr = r ^ j;
            if (rr > r) {
                unsigned long long a = v[r], c = v[rr];
                if ((a > c) == up) { v[r] = c; v[rr] = a; }
            }
        }
    }
    #pragma unroll
    for (int r = 0; r < 16; r++) s[SADDR(base + r)] = v[r];
    __syncthreads();
    for (int i = t; i < SEG; i += 128) keys[i] = s[SADDR(i)];
}

__global__ void k_order() {
    int i = blockIdx.x * blockDim.x + threadIdx.x;
    if (i >= 2 * NT) return;
    int b = i / NT;
    int idx = (int)(g_keys[i] & 0x3FFFULL);
    g_order[i] = idx;
    g_inv[b * NT + idx] = i - b * NT;
}

__global__ void k_ln256(const float* __restrict__ src,
                        const float* __restrict__ w, const float* __restrict__ bias) {
    int r = blockIdx.x, t = threadIdx.x;
    float2 v = *(const float2*)(src + (size_t)r * DM + 2 * t);
    float mean = blockReduceSum(v.x + v.y) * (1.0f / DM);
    float x0 = v.x - mean, x1 = v.y - mean;
    float var = blockReduceSum(x0 * x0 + x1 * x1) * (1.0f / DM);
    float rs = rsqrtf(var + 1e-5f);
    float r0 = x0 * rs * w[2 * t] + bias[2 * t];
    float r1 = x1 * rs * w[2 * t + 1] + bias[2 * t + 1];
    unsigned short h0, l0, h1, l1;
    bfsplit(r0, h0, l0);
    bfsplit(r1, h1, l1);
    g_qnhi[r * (DM / 2) + t] = (unsigned)h0 | ((unsigned)h1 << 16);
    g_qnlo[r * (DM / 2) + t] = (unsigned)l0 | ((unsigned)l1 << 16);
}

__global__ void k_splitW(const float* __restrict__ src, int K, int N, int NP) {
    int idx = blockIdx.x * blockDim.x + threadIdx.x;
    if (idx >= (K / 2) * NP) return;
    int kp = idx / NP, n = idx - kp * NP;
    float w0 = (n < N) ? src[(size_t)(2 * kp) * N + n] : 0.0f;
    float w1 = (n < N) ? src[(size_t)(2 * kp + 1) * N + n] : 0.0f;
    unsigned short h0, l0, h1, l1;
    bfsplit(w0, h0, l0);
    bfsplit(w1, h1, l1);
    g_Whi[(size_t)n * (K / 2) + kp] = (unsigned)h0 | ((unsigned)h1 << 16);
    g_Wlo[(size_t)n * (K / 2) + kp] = (unsigned)l0 | ((unsigned)l1 << 16);
}

// ---------------- bf16x3 tensor-core GEMM ----------------
__device__ __forceinline__ void gemm_load_bf(
    const unsigned* __restrict__ Ahi, const unsigned* __restrict__ Alo, int K2,
    const unsigned* __restrict__ Bhi, const unsigned* __restrict__ Blo,
    int m0, int n0, int kt, unsigned* sAh, unsigned* sAl,
    unsigned* sBh, unsigned* sBl, int tid) {
    int kp0 = kt * 16;
    int r = tid >> 1, cu = (tid & 1) * 8;
    const unsigned* pah = Ahi + (size_t)(m0 + r) * K2 + kp0 + cu;
    const unsigned* pal = Alo + (size_t)(m0 + r) * K2 + kp0 + cu;
    unsigned dah = (unsigned)__cvta_generic_to_shared(sAh + r * WSTR + cu);
    unsigned dal = (unsigned)__cvta_generic_to_shared(sAl + r * WSTR + cu);
    cp16(dah, pah); cp16(dah + 16, pah + 4);
    cp16(dal, pal); cp16(dal + 16, pal + 4);
    int n = tid >> 2, cb = (tid & 3) * 4;
    cp16((unsigned)__cvta_generic_to_shared(sBh + n * WSTR + cb),
         Bhi + (size_t)(n0 + n) * K2 + kp0 + cb);
    cp16((unsigned)__cvta_generic_to_shared(sBl + n * WSTR + cb),
         Blo + (size_t)(n0 + n) * K2 + kp0 + cb);
}

__global__ __launch_bounds__(256) void k_gemm_bf(int M, int N, int K,
        const unsigned* __restrict__ Ahi, const unsigned* __restrict__ Alo,
        float* __restrict__ C, int ldc) {
    const unsigned* Bhi = g_Whi;
    const unsigned* Blo = g_Wlo;
    unsigned* sm = (unsigned*)dynsmem;
    const int ASZ = 128 * WSTR, BSZ = 64 * WSTR;
    const int STG = 2 * ASZ + 2 * BSZ;

    int m0 = blockIdx.y * 128, n0 = blockIdx.x * 64;
    int tid = threadIdx.x;
    int wid = tid >> 5, lane = tid & 31;
    int wm = (wid & 3) * 32, wn = (wid >> 2) * 32;
    int g = lane >> 2, tg = lane & 3;
    int K2 = K >> 1;
    int KT = K / 32;

    float acc[2][4][4];
    #pragma unroll
    for (int a = 0; a < 2; a++)
        #pragma unroll
        for (int b = 0; b < 4; b++)
            #pragma unroll
            for (int c = 0; c < 4; c++) acc[a][b][c] = 0.0f;

    gemm_load_bf(Ahi, Alo, K2, Bhi, Blo, m0, n0, 0,
                 sm, sm + ASZ, sm + 2 * ASZ, sm + 2 * ASZ + BSZ, tid);
    asm volatile("cp.async.commit_group;");

    for (int kt = 0; kt < KT; kt++) {
        int st = kt & 1;
        if (kt + 1 < KT) {
            int ns = st ^ 1;
            unsigned* b0 = sm + ns * STG;
            gemm_load_bf(Ahi, Alo, K2, Bhi, Blo, m0, n0, kt + 1,
                         b0, b0 + ASZ, b0 + 2 * ASZ, b0 + 2 * ASZ + BSZ, tid);
            asm volatile("cp.async.commit_group;");
            asm volatile("cp.async.wait_group 1;");
        } else {
            asm volatile("cp.async.wait_group 0;");
        }
        __syncthreads();
        unsigned* sAhi = sm + st * STG;
        unsigned* sAlo = sAhi + ASZ;
        unsigned* sBhi = sAhi + 2 * ASZ;
        unsigned* sBlo = sBhi + BSZ;
        #pragma unroll
        for (int kk2 = 0; kk2 < 16; kk2 += 8) {
            unsigned ahi[2][4], alo[2][4], bhi[4][2], blo[4][2];
            #pragma unroll
            for (int mi = 0; mi < 2; mi++) {
                int ra = (wm + mi * 16 + g) * WSTR;
                int rb = (wm + mi * 16 + g + 8) * WSTR;
                ahi[mi][0] = sAhi[ra + kk2 + tg];
                ahi[mi][1] = sAhi[rb + kk2 + tg];
                ahi[mi][2] = sAhi[ra + kk2 + 4 + tg];
                ahi[mi][3] = sAhi[rb + kk2 + 4 + tg];
                alo[mi][0] = sAlo[ra + kk2 + tg];
                alo[mi][1] = sAlo[rb + kk2 + tg];
                alo[mi][2] = sAlo[ra + kk2 + 4 + tg];
                alo[mi][3] = sAlo[rb + kk2 + 4 + tg];
            }
            #pragma unroll
            for (int nj = 0; nj < 4; nj++) {
                int rn = (wn + nj * 8 + g) * WSTR;
                bhi[nj][0] = sBhi[rn + kk2 + tg];
                bhi[nj][1] = sBhi[rn + kk2 + 4 + tg];
                blo[nj][0] = sBlo[rn + kk2 + tg];
                blo[nj][1] = sBlo[rn + kk2 + 4 + tg];
            }
            #pragma unroll
            for (int mi = 0; mi < 2; mi++)
                #pragma unroll
                for (int nj = 0; nj < 4; nj++) {
                    mma_bf16(acc[mi][nj], ahi[mi], bhi[nj][0], bhi[nj][1]);
                    mma_bf16(acc[mi][nj], ahi[mi], blo[nj][0], blo[nj][1]);
                    mma_bf16(acc[mi][nj], alo[mi], bhi[nj][0], bhi[nj][1]);
                }
        }
        __syncthreads();
    }
    #pragma unroll
    for (int mi = 0; mi < 2; mi++)
        #pragma unroll
        for (int nj = 0; nj < 4; nj++) {
            int row = m0 + wm + mi * 16 + g;
            int col = n0 + wn + nj * 8 + tg * 2;
            if (col + 1 < N) {
                *(float2*)(C + (size_t)row * ldc + col) =
                    make_float2(acc[mi][nj][0], acc[mi][nj][1]);
                *(float2*)(C + (size_t)(row + 8) * ldc + col) =
                    make_float2(acc[mi][nj][2], acc[mi][nj][3]);
            } else if (col < N) {
                C[(size_t)row * ldc + col] = acc[mi][nj][0];
                C[(size_t)(row + 8) * ldc + col] = acc[mi][nj][2];
            }
        }
}

// ---------------- tiled conv + dt ----------------
__global__ __launch_bounds__(256) void k_conv2(const float* __restrict__ cw,
                                               const float* __restrict__ cb) {
    float* sZ  = dynsmem;
    float* scw = sZ + 67 * CTILE;
    float* scb = scw + CTILE * 4;
    int*   stok = (int*)(scb + CTILE);
    int r0 = blockIdx.x * 64, cc = blockIdx.y * CTILE, b = blockIdx.z;
    int tid = threadIdx.x;
    if (tid < 67) {
        int rr = r0 - 3 + tid;
        stok[tid] = (rr >= 0) ? g_order[b * NT + rr] : -1;
    }
    for (int idx = tid; idx < CTILE * 4; idx += 256)
        scw[idx] = cw[(cc + (idx >> 2)) * KER + (idx & 3)];
    for (int idx = tid; idx < CTILE; idx += 256)
        scb[idx] = cb[cc + idx];
    __syncthreads();
    for (int idx = tid; idx < 67 * CTILE; idx += 256) {
        int row = idx / CTILE, col = idx - row * CTILE;
        int t = stok[row];
        sZ[idx] = (t >= 0) ? g_Z[(size_t)t * DP + DI + cc + col] : 0.0f;
    }
    __syncthreads();
    for (int idx = tid; idx < 64 * CTILE; idx += 256) {
        int row = idx / CTILE, col = idx - row * CTILE;
        float acc = scb[col];
        #pragma unroll
        for (int k = 0; k < KER; k++)
            acc += scw[col * 4 + k] * sZ[(row + k) * CTILE + col];
        float s = acc / (1.0f + __expf(-acc));
        g_XBC[(size_t)(b * NT + r0 + row) * CD + cc + col] = s;
    }
}

__global__ void k_dt(const float* __restrict__ dtb, const float* __restrict__ alog) {
    int i = blockIdx.x * blockDim.x + threadIdx.x;
    if (i >= 2 * NT * NH) return;
    int b = i / (NT * NH);
    int rem = i - b * NT * NH;
    int r = rem / NH, h = rem - r * NH;
    int t = g_order[b * NT + r];
    float x = g_Z[(size_t)t * DP + DI + CD + h] + dtb[h];
    float sp = fmaxf(x, 0.0f) + log1pf(expf(-fabsf(x)));
    float A = -expf(alog[h]);
    g_dt[i] = sp;
    g_a[i] = sp * A;
}

// ---------------- chunked scan ----------------
__global__ __launch_bounds__(256) void k_scan1() {
    int c = blockIdx.x, h = blockIdx.y, b = blockIdx.z;
    __shared__ float sX[CQ * SR], sB[CQ * SR];
    __shared__ float scum[CQ], sw[CQ];
    int r0 = c * CQ, tid = threadIdx.x;
    for (int idx = tid; idx < CQ * 64; idx += 256) {
        int j = idx >> 6, p = idx & 63;
        sX[j * SR + p] = g_XBC[(size_t)(b * NT + r0 + j) * CD + h * HD + p];
        sB[j * SR + p] = g_XBC[(size_t)(b * NT + r0 + j) * CD + DI + p];
    }
    if (tid < CQ) scum[tid] = g_a[(size_t)(b * NT + r0 + tid) * NH + h];
    __syncthreads();
    if (tid < CQ) {
        float x = scum[tid];
        #pragma unroll
        for (int o = 1; o < 32; o <<= 1) {
            float y = __shfl_up_sync(0xffffffffu, x, o);
            if ((tid & 31) >= o) x += y;
        }
        scum[tid] = x;
    }
    __syncthreads();
    if (tid >= 32 && tid < CQ) scum[tid] += scum[31];
    __syncthreads();
    float slast = scum[CQ - 1];
    if (tid < CQ) {
        sw[tid] = __expf(slast - scum[tid]) * g_dt[(size_t)(b * NT + r0 + tid) * NH + h];
        g_cum[((b * NH + h) * NCH + c) * CQ + tid] = scum[tid];
    }
    if (tid == 0) g_cdec[(b * NH + h) * NCH + c] = __expf(slast);
    __syncthreads();
    int p0 = (tid & 15) * 4, s0 = (tid >> 4) * 4;
    unsigned long long acc2[4][2] = {};
    for (int j = 0; j < CQ; j++) {
        float4 xv = *(float4*)&sX[j * SR + p0];
        ulonglong2 b2 = *(const ulonglong2*)&sB[j * SR + s0];
        float w = sw[j];
        float wx[4] = {xv.x * w, xv.y * w, xv.z * w, xv.w * w};
        #pragma unroll
        for (int pi = 0; pi < 4; pi++) {
            unsigned long long w2 = bcast2(wx[pi]);
            fma2(acc2[pi][0], w2, b2.x);
            fma2(acc2[pi][1], w2, b2.y);
        }
    }
    size_t base = ((size_t)((b * NH + h) * NCH + c) * HD) * DS;
    #pragma unroll
    for (int pi = 0; pi < 4; pi++) {
        float2 a01 = unpack2(acc2[pi][0]);
        float2 a23 = unpack2(acc2[pi][1]);
        *(float4*)&g_S[base + (size_t)(p0 + pi) * DS + s0] =
            make_float4(a01.x, a01.y, a23.x, a23.y);
    }
}

__global__ void k_scan2() {
    __shared__ float scd[NCH];
    int bh = blockIdx.x >> 4;
    int e = ((blockIdx.x & 15) << 8) + threadIdx.x;
    if (threadIdx.x < NCH) scd[threadIdx.x] = g_cdec[bh * NCH + threadIdx.x];
    __syncthreads();
    float H = 0.0f;
    for (int c = 0; c < NCH; c++) {
        size_t off = ((size_t)(bh * NCH + c)) * (HD * DS) + e;
        float s = g_S[off];
        g_Hp[off] = H;
        H = scd[c] * H + s;
    }
}

__global__ __launch_bounds__(256) void k_scan3(const float* __restrict__ Dv) {
    int c = blockIdx.x, b = blockIdx.y;
    int r0 = c * CQ, tid = threadIdx.x;
    float* sB  = dynsmem;
    float* sC  = sB  + CQ * SR;
    float* sD0 = sC  + CQ * SR;
    float* sX  = sD0 + CQ * SR;
    float* sH  = sX  + CQ * SR;
    float* sG  = sH  + CQ * SR;
    float* scum = sG + CQ * SR;
    float* sdt  = scum + CQ;
    float* seY  = sdt + CQ;

    for (int idx = tid; idx < CQ * 64; idx += 256) {
        int j = idx >> 6, s = idx & 63;
        sB[j * SR + s] = g_XBC[(size_t)(b * NT + r0 + j) * CD + DI + s];
        sC[j * SR + s] = g_XBC[(size_t)(b * NT + r0 + j) * CD + DI + DS + s];
    }
    __syncthreads();
    int i0 = (tid >> 4) * 4, j0 = (tid & 15) * 4;
    if (j0 <= i0) {
        unsigned long long acc2[4][4] = {};
        for (int sc = 0; sc < 64; sc += 4) {
            ulonglong2 Cr[4], Br[4];
            #pragma unroll
            for (int r = 0; r < 4; r++) Cr[r] = *(const ulonglong2*)&sC[(i0 + r) * SR + sc];
            #pragma unroll
            for (int q = 0; q < 4; q++) Br[q] = *(const ulonglong2*)&sB[(j0 + q) * SR + sc];
            #pragma unroll
            for (int r = 0; r < 4; r++)
                #pragma unroll
                for (int q = 0; q < 4; q++) {
                    fma2(acc2[r][q], Cr[r].x, Br[q].x);
                    fma2(acc2[r][q], Cr[r].y, Br[q].y);
                }
        }
        #pragma unroll
        for (int r = 0; r < 4; r++) {
            float dv[4];
            #pragma unroll
            for (int q = 0; q < 4; q++) {
                float2 p = unpack2(acc2[r][q]);
                dv[q] = p.x + p.y;
            }
            *(float4*)&sD0[(i0 + r) * SR + j0] = make_float4(dv[0], dv[1], dv[2], dv[3]);
        }
    } else {
        #pragma unroll
        for (int r = 0; r < 4; r++)
            *(float4*)&sD0[(i0 + r) * SR + j0] = make_float4(0.f, 0.f, 0.f, 0.f);
    }
    __syncthreads();

    for (int h = 0; h < NH; h++) {
        for (int idx = tid; idx < CQ * 64; idx += 256) {
            int j = idx >> 6, p = idx & 63;
            sX[j * SR + p] = g_XBC[(size_t)(b * NT + r0 + j) * CD + h * HD + p];
            sH[j * SR + p] = g_Hp[((size_t)((b * NH + h) * NCH + c) * HD) * DS + idx];
        }
        if (tid < CQ) {
            float cu = g_cum[((b * NH + h) * NCH + c) * CQ + tid];
            scum[tid] = cu;
            sdt[tid] = g_dt[(size_t)(b * NT + r0 + tid) * NH + h];
            seY[tid] = __expf(cu);
        }
        __syncthreads();
        if (j0 <= i0) {
            #pragma unroll
            for (int r = 0; r < 4; r++) {
                float4 d = *(float4*)&sD0[(i0 + r) * SR + j0];
                float dd[4] = {d.x, d.y, d.z, d.w};
                float gv[4];
                int i = i0 + r;
                float ci = scum[i];
                #pragma unroll
                for (int q = 0; q < 4; q++) {
                    int j = j0 + q;
                    gv[q] = (j <= i) ? __expf(ci - scum[j]) * sdt[j] * dd[q] : 0.0f;
                }
                *(float4*)&sG[(i0 + r) * SR + j0] = make_float4(gv[0], gv[1], gv[2], gv[3]);
            }
        } else {
            #pragma unroll
            for (int r = 0; r < 4; r++)
                *(float4*)&sG[(i0 + r) * SR + j0] = make_float4(0.f, 0.f, 0.f, 0.f);
        }
        __syncthreads();
        int p0 = j0;
        float acc[4][4];
        {
            unsigned long long acc2[4][4] = {};
            for (int sc = 0; sc < 64; sc += 4) {
                ulonglong2 Cr[4], Hc[4];
                #pragma unroll
                for (int r = 0; r < 4; r++) Cr[r] = *(const ulonglong2*)&sC[(i0 + r) * SR + sc];
                #pragma unroll
                for (int q = 0; q < 4; q++) Hc[q] = *(const ulonglong2*)&sH[(p0 + q) * SR + sc];
                #pragma unroll
                for (int r = 0; r < 4; r++)
                    #pragma unroll
                    for (int q = 0; q < 4; q++) {
                        fma2(acc2[r][q], Cr[r].x, Hc[q].x);
                        fma2(acc2[r][q], Cr[r].y, Hc[q].y);
                    }
            }
            #pragma unroll
            for (int r = 0; r < 4; r++) {
                float e = seY[i0 + r];
                #pragma unroll
                for (int q = 0; q < 4; q++) {
                    float2 p = unpack2(acc2[r][q]);
                    acc[r][q] = e * (p.x + p.y);
                }
            }
        }
        unsigned long long accq[4][2];
        #pragma unroll
        for (int r = 0; r < 4; r++) {
            accq[r][0] = packf2(acc[r][0], acc[r][1]);
            accq[r][1] = packf2(acc[r][2], acc[r][3]);
        }
        for (int jc = 0; jc <= i0; jc += 4) {
            float G4[4][4];
            #pragma unroll
            for (int r = 0; r < 4; r++) {
                float4 t = *(float4*)&sG[(i0 + r) * SR + jc];
                G4[r][0] = t.x; G4[r][1] = t.y; G4[r][2] = t.z; G4[r][3] = t.w;
            }
            #pragma unroll
            for (int q = 0; q < 4; q++) {
                ulonglong2 x2 = *(const ulonglong2*)&sX[(jc + q) * SR + p0];
                #pragma unroll
                for (int r = 0; r < 4; r++) {
                    unsigned long long g2 = bcast2(G4[r][q]);
                    fma2(accq[r][0], g2, x2.x);
                    fma2(accq[r][1], g2, x2.y);
                }
            }
        }
        unsigned long long D2 = bcast2(Dv[h]);
        #pragma unroll
        for (int r = 0; r < 4; r++) {
            ulonglong2 xi2 = *(const ulonglong2*)&sX[(i0 + r) * SR + p0];
            fma2(accq[r][0], D2, xi2.x);
            fma2(accq[r][1], D2, xi2.y);
            float2 y01 = unpack2(accq[r][0]);
            float2 y23 = unpack2(accq[r][1]);
            *(float4*)&g_Y[(size_t)(b * NT + r0 + i0 + r) * DI + h * HD + p0] =
                make_float4(y01.x, y01.y, y23.x, y23.y);
        }
        __syncthreads();
    }
}

// ---------------- epilogue ----------------
__global__ void k_postnorm(const float* __restrict__ nw) {
    int r = blockIdx.x, b = blockIdx.y, tid = threadIdx.x;
    int t = g_order[b * NT + r];
    float v0, v1, ss;
    {
        float y0 = g_Y[(size_t)(b * NT + r) * DI + tid];
        float g0 = g_Z[(size_t)t * DP + tid];
        v0 = y0 * (g0 / (1.0f + __expf(-g0)));
        float y1 = g_Y[(size_t)(b * NT + r) * DI + tid + 256];
        float g1 = g_Z[(size_t)t * DP + tid + 256];
        v1 = y1 * (g1 / (1.0f + __expf(-g1)));
        ss = v0 * v0 + v1 * v1;
    }
    ss = blockReduceSum(ss);
    float rr = rsqrtf(ss * (1.0f / DI) + 1e-5f);
    g_Y[(size_t)(b * NT + r) * DI + tid]       = v0 * rr * nw[tid];
    g_Y[(size_t)(b * NT + r) * DI + tid + 256] = v1 * rr * nw[tid + 256];
}

__global__ void k_combine() {
    int t = blockIdx.x, c = threadIdx.x;
    int r0 = g_inv[t], r1 = g_inv[NT + t];
    float2 a = *(const float2*)(g_Y + (size_t)r0 * DI + 2 * c);
    float2 bq = *(const float2*)(g_Y + (size_t)(NT + r1) * DI + 2 * c);
    float v0 = 0.5f * (a.x + bq.x);
    float v1 = 0.5f * (a.y + bq.y);
    unsigned short h0, l0, h1, l1;
    bfsplit(v0, h0, l0);
    bfsplit(v1, h1, l1);
    g_combhi[(size_t)t * (DI / 2) + c] = (unsigned)h0 | ((unsigned)h1 << 16);
    g_comblo[(size_t)t * (DI / 2) + c] = (unsigned)l0 | ((unsigned)l1 << 16);
}

__global__ void k_final(const float* __restrict__ res,
                        const float* __restrict__ w, const float* __restrict__ bias,
                        float* __restrict__ dout) {
    int r = blockIdx.x, c = threadIdx.x;
    float v = res[(size_t)r * DM + c] + g_O[r * DM + c];
    float mean = blockReduceSum(v) * (1.0f / DM);
    float xc = v - mean;
    float var = blockReduceSum(xc * xc) * (1.0f / DM);
    float result = xc * rsqrtf(var + 1e-5f) * w[c] + bias[c];
    g_q[r * DM + c] = result;
    if (dout) dout[r * DM + c] = result;
}

// ---------------- launcher ----------------
extern "C" void kernel_launch(void* const* d_in, const int* in_sizes, int n_in,
                              void* d_out, int out_size) {
    (void)in_sizes; (void)n_in; (void)out_size;
    const float* query = (const float*)d_in[0];
    const float* pos   = (const float*)d_in[1];
    const float* pre_w = (const float*)d_in[2];
    const float* pre_b = (const float*)d_in[3];
    const float* fin_w = (const float*)d_in[4];
    const float* fin_b = (const float*)d_in[5];

    const int GEMM_SMEM = 2 * (2 * 128 * WSTR + 2 * 64 * WSTR) * 4;
    const int SCAN3_SMEM = (6 * CQ * SR + 3 * CQ) * 4;
    const int CONV_SMEM = (67 * CTILE + CTILE * 4 + CTILE) * 4 + 68 * 4;
    cudaFuncSetAttribute(k_gemm_bf, cudaFuncAttributeMaxDynamicSharedMemorySize, GEMM_SMEM);
    cudaFuncSetAttribute(k_scan3, cudaFuncAttributeMaxDynamicSharedMemorySize, SCAN3_SMEM);
    cudaFuncSetAttribute(k_conv2, cudaFuncAttributeMaxDynamicSharedMemorySize, CONV_SMEM);

    unsigned *p_qnhi, *p_qnlo, *p_combhi, *p_comblo;
    float *p_Z, *p_O, *p_q;
    cudaGetSymbolAddress((void**)&p_qnhi, g_qnhi);
    cudaGetSymbolAddress((void**)&p_qnlo, g_qnlo);
    cudaGetSymbolAddress((void**)&p_combhi, g_combhi);
    cudaGetSymbolAddress((void**)&p_comblo, g_comblo);
    cudaGetSymbolAddress((void**)&p_Z, g_Z);
    cudaGetSymbolAddress((void**)&p_O, g_O);
    cudaGetSymbolAddress((void**)&p_q, g_q);

    // Fork a side stream for the L0 in-proj pipeline (independent of the sort).
    // Created fresh per call (kernel_launch is invoked only a handful of times);
    // not destroyed so captured graph references stay valid.
    cudaStream_t s1;
    cudaStreamCreateWithFlags(&s1, cudaStreamNonBlocking);
    cudaEvent_t evF, evJ;
    cudaEventCreateWithFlags(&evF, cudaEventDisableTiming);
    cudaEventCreateWithFlags(&evJ, cudaEventDisableTiming);

    const float* Win0 = (const float*)d_in[6];

    cudaEventRecord(evF, 0);
    cudaStreamWaitEvent(s1, evF, 0);
    // Branch A (side stream): L0 LN -> weight split -> in-proj GEMM
    k_ln256<<<NT, 128, 0, s1>>>(query, pre_w, pre_b);
    k_splitW<<<((DM / 2) * NPIN + 255) / 256, 256, 0, s1>>>(Win0, DM, DP, NPIN);
    k_gemm_bf<<<dim3(NPIN / 64, NT / 128), 256, GEMM_SMEM, s1>>>(
        NT, DP, DM, p_qnhi, p_qnlo, p_Z, DP);
    cudaEventRecord(evJ, s1);

    // Branch B (origin stream): sort chain
    k_minmax<<<1, 256>>>(pos);
    k_keys<<<(NT + 255) / 256, 256>>>(pos);
    k_sort_init<<<dim3(NT / SEG, 2), 128>>>();
    for (int k = 2 * SEG; k <= NT; k <<= 1) {
        for (int j = k >> 1; j >= SEG; j >>= 1)
            k_sort_gpass<<<dim3(NT / 2 / 256, 2), 256>>>(k, j);
        k_sort_local<<<dim3(NT / SEG, 2), 128>>>(k);
    }
    k_order<<<(2 * NT + 255) / 256, 256>>>();

    // Join: conv needs both g_Z (branch A) and g_order (branch B)
    cudaStreamWaitEvent(0, evJ, 0);

    for (int L = 0; L < 2; L++) {
        const float* Win  = (const float*)d_in[6 + 8 * L];
        const float* cw   = (const float*)d_in[7 + 8 * L];
        const float* cb   = (const float*)d_in[8 + 8 * L];
        const float* dtb  = (const float*)d_in[9 + 8 * L];
        const float* alog = (const float*)d_in[10 + 8 * L];
        const float* Dv   = (const float*)d_in[11 + 8 * L];
        const float* nw   = (const float*)d_in[12 + 8 * L];
        const float* Wout = (const float*)d_in[13 + 8 * L];
        const float* src  = (L == 0) ? query : p_q;

        if (L == 1) {
            k_ln256<<<NT, 128>>>(src, pre_w, pre_b);
            k_splitW<<<((DM / 2) * NPIN + 255) / 256, 256>>>(Win, DM, DP, NPIN);
            k_gemm_bf<<<dim3(NPIN / 64, NT / 128), 256, GEMM_SMEM>>>(
                NT, DP, DM, p_qnhi, p_qnlo, p_Z, DP);
        }
        k_conv2<<<dim3(NT / 64, CD / CTILE, 2), 256, CONV_SMEM>>>(cw, cb);
        k_dt<<<(2 * NT * NH + 255) / 256, 256>>>(dtb, alog);
        k_scan1<<<dim3(NCH, NH, 2), 256>>>();
        k_scan2<<<256, 256>>>();
        k_scan3<<<dim3(NCH, 2), 256, SCAN3_SMEM>>>(Dv);
        k_postnorm<<<dim3(NT, 2), 256>>>(nw);
        k_combine<<<NT, 256>>>();
        k_splitW<<<((DI / 2) * DM + 255) / 256, 256>>>(Wout, DI, DM, DM);
        k_gemm_bf<<<dim3(DM / 64, NT / 128), 256, GEMM_SMEM>>>(
            NT, DM, DI, p_combhi, p_comblo, p_O, DM);
        k_final<<<NT, 256>>>(src, fin_w, fin_b, (L == 1) ? (float*)d_out : nullptr);
    }
}

// round 14
// speedup vs baseline: 1.6456x; 1.0486x over previous
#include <cuda_runtime.h>
#include <cuda_bf16.h>
#include <math.h>

#define NT 16384
#define DM 256
#define DI 512
#define DS 64
#define NH 8
#define HD 64
#define CD 640      // CONV_DIM
#define DP 1160     // D_PROJ
#define KER 4
#define NCH 256     // number of chunks
#define CQ 64       // chunk length
#define SR 68       // padded row stride for 64-col smem tiles
#define NPIN 1216   // padded N for in_proj (19*64)
#define WSTR 20     // GEMM smem row stride in uints
#define CTILE 160   // conv col chunk
#define SEG 2048    // sort segment

// ---------------- device scratch ----------------
__device__ float g_q[NT * DM];
__device__ unsigned g_qnhi[NT * (DM / 2)];
__device__ unsigned g_qnlo[NT * (DM / 2)];
__device__ float g_Z[NT * DP];
__device__ float g_XBC[2 * NT * CD];
__device__ float g_dt[2 * NT * NH];
__device__ float g_a[2 * NT * NH];
__device__ float g_cum[2 * NH * NCH * CQ];
__device__ float g_cdec[2 * NH * NCH];
__device__ float g_S[2 * NH * NCH * HD * DS];
__device__ float g_Hp[2 * NH * NCH * HD * DS];
__device__ float g_Y[2 * NT * DI];
__device__ unsigned g_combhi[NT * (DI / 2)];
__device__ unsigned g_comblo[NT * (DI / 2)];
__device__ float g_O[NT * DM];
// per-layer pre-split weights: in-proj [layer][n][k/2], out-proj [layer][n][k/2]
__device__ unsigned g_WIhi[2 * NPIN * (DM / 2)];
__device__ unsigned g_WIlo[2 * NPIN * (DM / 2)];
__device__ unsigned g_WOhi[2 * DM * (DI / 2)];
__device__ unsigned g_WOlo[2 * DM * (DI / 2)];
__device__ unsigned long long g_keys[2 * NT];
__device__ int g_order[2 * NT];
__device__ int g_inv[2 * NT];
__device__ float g_pmin[3], g_pmax[3];

extern __shared__ float dynsmem[];

// ---------------- helpers ----------------
__device__ __forceinline__ float blockReduceSum(float v) {
    __shared__ float sh[32];
    __shared__ float tot;
    int lane = threadIdx.x & 31, wid = threadIdx.x >> 5;
    #pragma unroll
    for (int o = 16; o > 0; o >>= 1) v += __shfl_xor_sync(0xffffffffu, v, o);
    if (lane == 0) sh[wid] = v;
    __syncthreads();
    int nw = blockDim.x >> 5;
    v = (threadIdx.x < nw) ? sh[threadIdx.x] : 0.0f;
    if (wid == 0) {
        #pragma unroll
        for (int o = 16; o > 0; o >>= 1) v += __shfl_xor_sync(0xffffffffu, v, o);
        if (lane == 0) tot = v;
    }
    __syncthreads();
    return tot;
}

// dual-value block reduce (one shuffle tree for two sums)
__device__ __forceinline__ float2 blockReduceSum2(float a, float b) {
    __shared__ float sha[32], shb[32];
    __shared__ float2 tot;
    int lane = threadIdx.x & 31, wid = threadIdx.x >> 5;
    #pragma unroll
    for (int o = 16; o > 0; o >>= 1) {
        a += __shfl_xor_sync(0xffffffffu, a, o);
        b += __shfl_xor_sync(0xffffffffu, b, o);
    }
    if (lane == 0) { sha[wid] = a; shb[wid] = b; }
    __syncthreads();
    int nw = blockDim.x >> 5;
    a = (threadIdx.x < nw) ? sha[threadIdx.x] : 0.0f;
    b = (threadIdx.x < nw) ? shb[threadIdx.x] : 0.0f;
    if (wid == 0) {
        #pragma unroll
        for (int o = 16; o > 0; o >>= 1) {
            a += __shfl_xor_sync(0xffffffffu, a, o);
            b += __shfl_xor_sync(0xffffffffu, b, o);
        }
        if (lane == 0) tot = make_float2(a, b);
    }
    __syncthreads();
    return tot;
}

__device__ __forceinline__ unsigned hilbert3(unsigned a0, unsigned a1, unsigned a2) {
    unsigned x0 = a0, x1 = a1, x2 = a2;
    const unsigned M = 1u << 9;
    for (unsigned Q = M; Q > 1; Q >>= 1) {
        unsigned P = Q - 1;
        if (x0 & Q) x0 ^= P;
        {
            unsigned t = (x0 ^ x1) & P;
            if (x1 & Q) { x0 ^= P; } else { x0 ^= t; x1 ^= t; }
        }
        {
            unsigned t = (x0 ^ x2) & P;
            if (x2 & Q) { x0 ^= P; } else { x0 ^= t; x2 ^= t; }
        }
    }
    x1 ^= x0;
    x2 ^= x1;
    unsigned t = 0;
    for (unsigned Q = M; Q > 1; Q >>= 1)
        if (x2 & Q) t ^= (Q - 1);
    x0 ^= t; x1 ^= t; x2 ^= t;
    unsigned code = 0;
    for (int b = 9; b >= 0; b--) {
        code = (code << 1) | ((x0 >> b) & 1);
        code = (code << 1) | ((x1 >> b) & 1);
        code = (code << 1) | ((x2 >> b) & 1);
    }
    return code;
}

__device__ __forceinline__ void bfsplit(float x, unsigned short& hi, unsigned short& lo) {
    __nv_bfloat16 h = __float2bfloat16(x);
    __nv_bfloat16 l = __float2bfloat16(x - __bfloat162float(h));
    hi = *(unsigned short*)&h;
    lo = *(unsigned short*)&l;
}

__device__ __forceinline__ void mma_bf16(float c[4], const unsigned a[4],
                                         unsigned b0, unsigned b1) {
    asm volatile("mma.sync.aligned.m16n8k16.row.col.f32.bf16.bf16.f32 "
        "{%0,%1,%2,%3}, {%4,%5,%6,%7}, {%8,%9}, {%0,%1,%2,%3};"
        : "+f"(c[0]), "+f"(c[1]), "+f"(c[2]), "+f"(c[3])
        : "r"(a[0]), "r"(a[1]), "r"(a[2]), "r"(a[3]), "r"(b0), "r"(b1));
}

__device__ __forceinline__ void cp16(unsigned dst, const void* src) {
    asm volatile("cp.async.cg.shared.global [%0], [%1], 16;" :: "r"(dst), "l"(src));
}

// ---- packed f32x2 FMA ----
__device__ __forceinline__ void fma2(unsigned long long& c, unsigned long long a,
                                     unsigned long long b) {
    asm("fma.rn.f32x2 %0, %1, %2, %0;" : "+l"(c) : "l"(a), "l"(b));
}
__device__ __forceinline__ unsigned long long bcast2(float x) {
    unsigned long long r;
    unsigned u = __float_as_uint(x);
    asm("mov.b64 %0, {%1, %2};" : "=l"(r) : "r"(u), "r"(u));
    return r;
}
__device__ __forceinline__ unsigned long long packf2(float a, float b) {
    unsigned long long r;
    asm("mov.b64 %0, {%1, %2};" : "=l"(r) : "r"(__float_as_uint(a)), "r"(__float_as_uint(b)));
    return r;
}
__device__ __forceinline__ float2 unpack2(unsigned long long v) {
    unsigned lo, hi;
    asm("mov.b64 {%0, %1}, %2;" : "=r"(lo), "=r"(hi) : "l"(v));
    return make_float2(__uint_as_float(lo), __uint_as_float(hi));
}

// ---------------- setup kernels ----------------
__global__ void k_minmax(const float* __restrict__ pos) {
    __shared__ float smn[256][3], smx[256][3];
    float mn[3] = {1e30f, 1e30f, 1e30f}, mx[3] = {-1e30f, -1e30f, -1e30f};
    for (int r = threadIdx.x; r < NT; r += 256) {
        #pragma unroll
        for (int j = 0; j < 3; j++) {
            float v = pos[r * 3 + j];
            mn[j] = fminf(mn[j], v);
            mx[j] = fmaxf(mx[j], v);
        }
    }
    #pragma unroll
    for (int j = 0; j < 3; j++) { smn[threadIdx.x][j] = mn[j]; smx[threadIdx.x][j] = mx[j]; }
    __syncthreads();
    for (int s = 128; s > 0; s >>= 1) {
        if (threadIdx.x < s) {
            #pragma unroll
            for (int j = 0; j < 3; j++) {
                smn[threadIdx.x][j] = fminf(smn[threadIdx.x][j], smn[threadIdx.x + s][j]);
                smx[threadIdx.x][j] = fmaxf(smx[threadIdx.x][j], smx[threadIdx.x + s][j]);
            }
        }
        __syncthreads();
    }
    if (threadIdx.x == 0) {
        #pragma unroll
        for (int j = 0; j < 3; j++) { g_pmin[j] = smn[0][j]; g_pmax[j] = smx[0][j]; }
    }
}

__global__ void k_keys(const float* __restrict__ pos) {
    int idx = blockIdx.x * blockDim.x + threadIdx.x;
    if (idx >= NT) return;
    unsigned g[3];
    #pragma unroll
    for (int j = 0; j < 3; j++) {
        float denom = g_pmax[j] - g_pmin[j] + 1e-6f;
        float v = ((pos[idx * 3 + j] - g_pmin[j]) / denom) * 1023.0f;
        v = fminf(fmaxf(v, 0.0f), 1023.0f);
        g[j] = (unsigned)(int)v;
    }
    unsigned c0 = hilbert3(g[0], g[1], g[2]);
    unsigned c1 = hilbert3(g[1], g[0], g[2]);
    g_keys[idx]      = (((unsigned long long)c0) << 14) | (unsigned long long)idx;
    g_keys[NT + idx] = (((unsigned long long)c1) << 14) | (unsigned long long)idx;
}

#define SADDR(i) ((i) + ((i) >> 4))

__global__ void k_sort_init() {
    __shared__ unsigned long long s[SEG + SEG / 16];
    int seg = blockIdx.x, b = blockIdx.y;
    unsigned long long* keys = g_keys + b * NT + seg * SEG;
    bool upg = ((seg & 1) == 0);
    int t = threadIdx.x;  // 128 threads
    for (int i = t; i < SEG; i += 128) s[SADDR(i)] = keys[i];
    __syncthreads();

    int base = t * 16;
    unsigned long long v[16];
    #pragma unroll
    for (int r = 0; r < 16; r++) v[r] = s[SADDR(base + r)];
    #pragma unroll
    for (int k = 2; k <= 16; k <<= 1) {
        #pragma unroll
        for (int j = k >> 1; j > 0; j >>= 1) {
            #pragma unroll
            for (int r = 0; r < 16; r++) {
                int rr = r ^ j;
                if (rr > r) {
                    bool up = ((((base + r) & k) == 0) == upg);
                    unsigned long long a = v[r], c = v[rr];
                    if ((a > c) == up) { v[r] = c; v[rr] = a; }
                }
            }
        }
    }
    #pragma unroll
    for (int r = 0; r < 16; r++) s[SADDR(base + r)] = v[r];
    __syncthreads();

    for (int k = 32; k <= SEG; k <<= 1) {
        for (int j = k >> 1; j >= 16; j >>= 1) {
            for (int i = t; i < SEG; i += 128) {
                int ixj = i ^ j;
                if (ixj > i) {
                    unsigned long long a = s[SADDR(i)], c = s[SADDR(ixj)];
                    bool up = (((i & k) == 0) == upg);
                    if ((a > c) == up) { s[SADDR(i)] = c; s[SADDR(ixj)] = a; }
                }
            }
            __syncthreads();
        }
        #pragma unroll
        for (int r = 0; r < 16; r++) v[r] = s[SADDR(base + r)];
        bool up = (((base & k) == 0) == upg);
        #pragma unroll
        for (int j = 8; j > 0; j >>= 1) {
            #pragma unroll
            for (int r = 0; r < 16; r++) {
                int rr = r ^ j;
                if (rr > r) {
                    unsigned long long a = v[r], c = v[rr];
                    if ((a > c) == up) { v[r] = c; v[rr] = a; }
                }
            }
        }
        #pragma unroll
        for (int r = 0; r < 16; r++) s[SADDR(base + r)] = v[r];
        __syncthreads();
    }
    for (int i = t; i < SEG; i += 128) keys[i] = s[SADDR(i)];
}

__global__ void k_sort_gpass(int k, int j) {
    int p = blockIdx.x * blockDim.x + threadIdx.x;
    int b = blockIdx.y;
    int low = p & (j - 1);
    int i = ((p & ~(j - 1)) << 1) | low;
    unsigned long long* keys = g_keys + b * NT;
    unsigned long long a = keys[i], c = keys[i + j];
    bool up = ((i & k) == 0);
    if ((a > c) == up) { keys[i] = c; keys[i + j] = a; }
}

__global__ void k_sort_local(int k) {
    __shared__ unsigned long long s[SEG + SEG / 16];
    int seg = blockIdx.x, b = blockIdx.y;
    unsigned long long* keys = g_keys + b * NT + seg * SEG;
    bool up = (((seg * SEG) & k) == 0);
    int t = threadIdx.x;
    for (int i = t; i < SEG; i += 128) s[SADDR(i)] = keys[i];
    __syncthreads();
    for (int j = SEG / 2; j >= 16; j >>= 1) {
        for (int i = t; i < SEG; i += 128) {
            int ixj = i ^ j;
            if (ixj > i) {
                unsigned long long a = s[SADDR(i)], c = s[SADDR(ixj)];
                if ((a > c) == up) { s[SADDR(i)] = c; s[SADDR(ixj)] = a; }
            }
        }
        __syncthreads();
    }
    int base = t * 16;
    unsigned long long v[16];
    #pragma unroll
    for (int r = 0; r < 16; r++) v[r] = s[SADDR(base + r)];
    #pragma unroll
    for (int j = 8; j > 0; j >>= 1) {
        #pragma unroll
        for (int r = 0; r < 16; r++) {
            int rr = r ^ j;
            if (rr > r) {
                unsigned long long a = v[r], c = v[rr];
                if ((a > c) == up) { v[r] = c; v[rr] = a; }
            }
        }
    }
    #pragma unroll
    for (int r = 0; r < 16; r++) s[SADDR(base + r)] = v[r];
    __syncthreads();
    for (int i = t; i < SEG; i += 128) keys[i] = s[SADDR(i)];
}

__global__ void k_order() {
    int i = blockIdx.x * blockDim.x + threadIdx.x;
    if (i >= 2 * NT) return;
    int b = i / NT;
    int idx = (int)(g_keys[i] & 0x3FFFULL);
    g_order[i] = idx;
    g_inv[b * NT + idx] = i - b * NT;
}

__global__ void k_ln256(const float* __restrict__ src,
                        const float* __restrict__ w, const float* __restrict__ bias) {
    int r = blockIdx.x, t = threadIdx.x;
    float2 v = *(const float2*)(src + (size_t)r * DM + 2 * t);
    float mean = blockReduceSum(v.x + v.y) * (1.0f / DM);
    float x0 = v.x - mean, x1 = v.y - mean;
    float var = blockReduceSum(x0 * x0 + x1 * x1) * (1.0f / DM);
    float rs = rsqrtf(var + 1e-5f);
    float r0 = x0 * rs * w[2 * t] + bias[2 * t];
    float r1 = x1 * rs * w[2 * t + 1] + bias[2 * t + 1];
    unsigned short h0, l0, h1, l1;
    bfsplit(r0, h0, l0);
    bfsplit(r1, h1, l1);
    g_qnhi[r * (DM / 2) + t] = (unsigned)h0 | ((unsigned)h1 << 16);
    g_qnlo[r * (DM / 2) + t] = (unsigned)l0 | ((unsigned)l1 << 16);
}

__global__ void k_splitW(const float* __restrict__ src, int K, int N, int NP,
                         unsigned* __restrict__ Whi, unsigned* __restrict__ Wlo) {
    int idx = blockIdx.x * blockDim.x + threadIdx.x;
    if (idx >= (K / 2) * NP) return;
    int kp = idx / NP, n = idx - kp * NP;
    float w0 = (n < N) ? src[(size_t)(2 * kp) * N + n] : 0.0f;
    float w1 = (n < N) ? src[(size_t)(2 * kp + 1) * N + n] : 0.0f;
    unsigned short h0, l0, h1, l1;
    bfsplit(w0, h0, l0);
    bfsplit(w1, h1, l1);
    Whi[(size_t)n * (K / 2) + kp] = (unsigned)h0 | ((unsigned)h1 << 16);
    Wlo[(size_t)n * (K / 2) + kp] = (unsigned)l0 | ((unsigned)l1 << 16);
}

// ---------------- bf16x3 tensor-core GEMM ----------------
__device__ __forceinline__ void gemm_load_bf(
    const unsigned* __restrict__ Ahi, const unsigned* __restrict__ Alo, int K2,
    const unsigned* __restrict__ Bhi, const unsigned* __restrict__ Blo,
    int m0, int n0, int kt, unsigned* sAh, unsigned* sAl,
    unsigned* sBh, unsigned* sBl, int tid) {
    int kp0 = kt * 16;
    int r = tid >> 1, cu = (tid & 1) * 8;
    const unsigned* pah = Ahi + (size_t)(m0 + r) * K2 + kp0 + cu;
    const unsigned* pal = Alo + (size_t)(m0 + r) * K2 + kp0 + cu;
    unsigned dah = (unsigned)__cvta_generic_to_shared(sAh + r * WSTR + cu);
    unsigned dal = (unsigned)__cvta_generic_to_shared(sAl + r * WSTR + cu);
    cp16(dah, pah); cp16(dah + 16, pah + 4);
    cp16(dal, pal); cp16(dal + 16, pal + 4);
    int n = tid >> 2, cb = (tid & 3) * 4;
    cp16((unsigned)__cvta_generic_to_shared(sBh + n * WSTR + cb),
         Bhi + (size_t)(n0 + n) * K2 + kp0 + cb);
    cp16((unsigned)__cvta_generic_to_shared(sBl + n * WSTR + cb),
         Blo + (size_t)(n0 + n) * K2 + kp0 + cb);
}

__global__ __launch_bounds__(256) void k_gemm_bf(int M, int N, int K,
        const unsigned* __restrict__ Ahi, const unsigned* __restrict__ Alo,
        const unsigned* __restrict__ Bhi, const unsigned* __restrict__ Blo,
        float* __restrict__ C, int ldc) {
    unsigned* sm = (unsigned*)dynsmem;
    const int ASZ = 128 * WSTR, BSZ = 64 * WSTR;
    const int STG = 2 * ASZ + 2 * BSZ;

    int m0 = blockIdx.y * 128, n0 = blockIdx.x * 64;
    int tid = threadIdx.x;
    int wid = tid >> 5, lane = tid & 31;
    int wm = (wid & 3) * 32, wn = (wid >> 2) * 32;
    int g = lane >> 2, tg = lane & 3;
    int K2 = K >> 1;
    int KT = K / 32;

    float acc[2][4][4];
    #pragma unroll
    for (int a = 0; a < 2; a++)
        #pragma unroll
        for (int b = 0; b < 4; b++)
            #pragma unroll
            for (int c = 0; c < 4; c++) acc[a][b][c] = 0.0f;

    gemm_load_bf(Ahi, Alo, K2, Bhi, Blo, m0, n0, 0,
                 sm, sm + ASZ, sm + 2 * ASZ, sm + 2 * ASZ + BSZ, tid);
    asm volatile("cp.async.commit_group;");

    for (int kt = 0; kt < KT; kt++) {
        int st = kt & 1;
        if (kt + 1 < KT) {
            int ns = st ^ 1;
            unsigned* b0 = sm + ns * STG;
            gemm_load_bf(Ahi, Alo, K2, Bhi, Blo, m0, n0, kt + 1,
                         b0, b0 + ASZ, b0 + 2 * ASZ, b0 + 2 * ASZ + BSZ, tid);
            asm volatile("cp.async.commit_group;");
            asm volatile("cp.async.wait_group 1;");
        } else {
            asm volatile("cp.async.wait_group 0;");
        }
        __syncthreads();
        unsigned* sAhi = sm + st * STG;
        unsigned* sAlo = sAhi + ASZ;
        unsigned* sBhi = sAhi + 2 * ASZ;
        unsigned* sBlo = sBhi + BSZ;
        #pragma unroll
        for (int kk2 = 0; kk2 < 16; kk2 += 8) {
            unsigned ahi[2][4], alo[2][4], bhi[4][2], blo[4][2];
            #pragma unroll
            for (int mi = 0; mi < 2; mi++) {
                int ra = (wm + mi * 16 + g) * WSTR;
                int rb = (wm + mi * 16 + g + 8) * WSTR;
                ahi[mi][0] = sAhi[ra + kk2 + tg];
                ahi[mi][1] = sAhi[rb + kk2 + tg];
                ahi[mi][2] = sAhi[ra + kk2 + 4 + tg];
                ahi[mi][3] = sAhi[rb + kk2 + 4 + tg];
                alo[mi][0] = sAlo[ra + kk2 + tg];
                alo[mi][1] = sAlo[rb + kk2 + tg];
                alo[mi][2] = sAlo[ra + kk2 + 4 + tg];
                alo[mi][3] = sAlo[rb + kk2 + 4 + tg];
            }
            #pragma unroll
            for (int nj = 0; nj < 4; nj++) {
                int rn = (wn + nj * 8 + g) * WSTR;
                bhi[nj][0] = sBhi[rn + kk2 + tg];
                bhi[nj][1] = sBhi[rn + kk2 + 4 + tg];
                blo[nj][0] = sBlo[rn + kk2 + tg];
                blo[nj][1] = sBlo[rn + kk2 + 4 + tg];
            }
            #pragma unroll
            for (int mi = 0; mi < 2; mi++)
                #pragma unroll
                for (int nj = 0; nj < 4; nj++) {
                    mma_bf16(acc[mi][nj], ahi[mi], bhi[nj][0], bhi[nj][1]);
                    mma_bf16(acc[mi][nj], ahi[mi], blo[nj][0], blo[nj][1]);
                    mma_bf16(acc[mi][nj], alo[mi], bhi[nj][0], bhi[nj][1]);
                }
        }
        __syncthreads();
    }
    #pragma unroll
    for (int mi = 0; mi < 2; mi++)
        #pragma unroll
        for (int nj = 0; nj < 4; nj++) {
            int row = m0 + wm + mi * 16 + g;
            int col = n0 + wn + nj * 8 + tg * 2;
            if (col + 1 < N) {
                *(float2*)(C + (size_t)row * ldc + col) =
                    make_float2(acc[mi][nj][0], acc[mi][nj][1]);
                *(float2*)(C + (size_t)(row + 8) * ldc + col) =
                    make_float2(acc[mi][nj][2], acc[mi][nj][3]);
            } else if (col < N) {
                C[(size_t)row * ldc + col] = acc[mi][nj][0];
                C[(size_t)(row + 8) * ldc + col] = acc[mi][nj][2];
            }
        }
}

// ---------------- tiled conv + dt ----------------
__global__ __launch_bounds__(256) void k_conv2(const float* __restrict__ cw,
                                               const float* __restrict__ cb) {
    float* sZ  = dynsmem;
    float* scw = sZ + 67 * CTILE;
    float* scb = scw + CTILE * 4;
    int*   stok = (int*)(scb + CTILE);
    int r0 = blockIdx.x * 64, cc = blockIdx.y * CTILE, b = blockIdx.z;
    int tid = threadIdx.x;
    if (tid < 67) {
        int rr = r0 - 3 + tid;
        stok[tid] = (rr >= 0) ? g_order[b * NT + rr] : -1;
    }
    for (int idx = tid; idx < CTILE * 4; idx += 256)
        scw[idx] = cw[(cc + (idx >> 2)) * KER + (idx & 3)];
    for (int idx = tid; idx < CTILE; idx += 256)
        scb[idx] = cb[cc + idx];
    __syncthreads();
    for (int idx = tid; idx < 67 * CTILE; idx += 256) {
        int row = idx / CTILE, col = idx - row * CTILE;
        int t = stok[row];
        sZ[idx] = (t >= 0) ? g_Z[(size_t)t * DP + DI + cc + col] : 0.0f;
    }
    __syncthreads();
    for (int idx = tid; idx < 64 * CTILE; idx += 256) {
        int row = idx / CTILE, col = idx - row * CTILE;
        float acc = scb[col];
        #pragma unroll
        for (int k = 0; k < KER; k++)
            acc += scw[col * 4 + k] * sZ[(row + k) * CTILE + col];
        float s = acc / (1.0f + __expf(-acc));
        g_XBC[(size_t)(b * NT + r0 + row) * CD + cc + col] = s;
    }
}

__global__ void k_dt(const float* __restrict__ dtb, const float* __restrict__ alog) {
    int i = blockIdx.x * blockDim.x + threadIdx.x;
    if (i >= 2 * NT * NH) return;
    int b = i / (NT * NH);
    int rem = i - b * NT * NH;
    int r = rem / NH, h = rem - r * NH;
    int t = g_order[b * NT + r];
    float x = g_Z[(size_t)t * DP + DI + CD + h] + dtb[h];
    float sp = fmaxf(x, 0.0f) + log1pf(expf(-fabsf(x)));
    float A = -expf(alog[h]);
    g_dt[i] = sp;
    g_a[i] = sp * A;
}

// ---------------- chunked scan ----------------
__global__ __launch_bounds__(256) void k_scan1() {
    int c = blockIdx.x, h = blockIdx.y, b = blockIdx.z;
    __shared__ float sX[CQ * SR], sB[CQ * SR];
    __shared__ float scum[CQ], sw[CQ];
    int r0 = c * CQ, tid = threadIdx.x;
    for (int idx = tid; idx < CQ * 64; idx += 256) {
        int j = idx >> 6, p = idx & 63;
        sX[j * SR + p] = g_XBC[(size_t)(b * NT + r0 + j) * CD + h * HD + p];
        sB[j * SR + p] = g_XBC[(size_t)(b * NT + r0 + j) * CD + DI + p];
    }
    if (tid < CQ) scum[tid] = g_a[(size_t)(b * NT + r0 + tid) * NH + h];
    __syncthreads();
    if (tid < CQ) {
        float x = scum[tid];
        #pragma unroll
        for (int o = 1; o < 32; o <<= 1) {
            float y = __shfl_up_sync(0xffffffffu, x, o);
            if ((tid & 31) >= o) x += y;
        }
        scum[tid] = x;
    }
    __syncthreads();
    if (tid >= 32 && tid < CQ) scum[tid] += scum[31];
    __syncthreads();
    float slast = scum[CQ - 1];
    if (tid < CQ) {
        sw[tid] = __expf(slast - scum[tid]) * g_dt[(size_t)(b * NT + r0 + tid) * NH + h];
        g_cum[((b * NH + h) * NCH + c) * CQ + tid] = scum[tid];
    }
    if (tid == 0) g_cdec[(b * NH + h) * NCH + c] = __expf(slast);
    __syncthreads();
    int p0 = (tid & 15) * 4, s0 = (tid >> 4) * 4;
    unsigned long long acc2[4][2] = {};
    for (int j = 0; j < CQ; j++) {
        float4 xv = *(float4*)&sX[j * SR + p0];
        ulonglong2 b2 = *(const ulonglong2*)&sB[j * SR + s0];
        float w = sw[j];
        float wx[4] = {xv.x * w, xv.y * w, xv.z * w, xv.w * w};
        #pragma unroll
        for (int pi = 0; pi < 4; pi++) {
            unsigned long long w2 = bcast2(wx[pi]);
            fma2(acc2[pi][0], w2, b2.x);
            fma2(acc2[pi][1], w2, b2.y);
        }
    }
    size_t base = ((size_t)((b * NH + h) * NCH + c) * HD) * DS;
    #pragma unroll
    for (int pi = 0; pi < 4; pi++) {
        float2 a01 = unpack2(acc2[pi][0]);
        float2 a23 = unpack2(acc2[pi][1]);
        *(float4*)&g_S[base + (size_t)(p0 + pi) * DS + s0] =
            make_float4(a01.x, a01.y, a23.x, a23.y);
    }
}

__global__ void k_scan2() {
    __shared__ float scd[NCH];
    int bh = blockIdx.x >> 4;
    int e = ((blockIdx.x & 15) << 8) + threadIdx.x;
    if (threadIdx.x < NCH) scd[threadIdx.x] = g_cdec[bh * NCH + threadIdx.x];
    __syncthreads();
    float H = 0.0f;
    for (int c = 0; c < NCH; c++) {
        size_t off = ((size_t)(bh * NCH + c)) * (HD * DS) + e;
        float s = g_S[off];
        g_Hp[off] = H;
        H = scd[c] * H + s;
    }
}

__global__ __launch_bounds__(256) void k_scan3(const float* __restrict__ Dv) {
    int c = blockIdx.x, b = blockIdx.y;
    int r0 = c * CQ, tid = threadIdx.x;
    float* sB  = dynsmem;
    float* sC  = sB  + CQ * SR;
    float* sD0 = sC  + CQ * SR;
    float* sX  = sD0 + CQ * SR;
    float* sH  = sX  + CQ * SR;
    float* sG  = sH  + CQ * SR;
    float* scum = sG + CQ * SR;
    float* sdt  = scum + CQ;
    float* seY  = sdt + CQ;

    for (int idx = tid; idx < CQ * 64; idx += 256) {
        int j = idx >> 6, s = idx & 63;
        sB[j * SR + s] = g_XBC[(size_t)(b * NT + r0 + j) * CD + DI + s];
        sC[j * SR + s] = g_XBC[(size_t)(b * NT + r0 + j) * CD + DI + DS + s];
    }
    __syncthreads();
    int i0 = (tid >> 4) * 4, j0 = (tid & 15) * 4;
    if (j0 <= i0) {
        unsigned long long acc2[4][4] = {};
        for (int sc = 0; sc < 64; sc += 4) {
            ulonglong2 Cr[4], Br[4];
            #pragma unroll
            for (int r = 0; r < 4; r++) Cr[r] = *(const ulonglong2*)&sC[(i0 + r) * SR + sc];
            #pragma unroll
            for (int q = 0; q < 4; q++) Br[q] = *(const ulonglong2*)&sB[(j0 + q) * SR + sc];
            #pragma unroll
            for (int r = 0; r < 4; r++)
                #pragma unroll
                for (int q = 0; q < 4; q++) {
                    fma2(acc2[r][q], Cr[r].x, Br[q].x);
                    fma2(acc2[r][q], Cr[r].y, Br[q].y);
                }
        }
        #pragma unroll
        for (int r = 0; r < 4; r++) {
            float dv[4];
            #pragma unroll
            for (int q = 0; q < 4; q++) {
                float2 p = unpack2(acc2[r][q]);
                dv[q] = p.x + p.y;
            }
            *(float4*)&sD0[(i0 + r) * SR + j0] = make_float4(dv[0], dv[1], dv[2], dv[3]);
        }
    } else {
        #pragma unroll
        for (int r = 0; r < 4; r++)
            *(float4*)&sD0[(i0 + r) * SR + j0] = make_float4(0.f, 0.f, 0.f, 0.f);
    }
    __syncthreads();

    for (int h = 0; h < NH; h++) {
        for (int idx = tid; idx < CQ * 64; idx += 256) {
            int j = idx >> 6, p = idx & 63;
            sX[j * SR + p] = g_XBC[(size_t)(b * NT + r0 + j) * CD + h * HD + p];
            sH[j * SR + p] = g_Hp[((size_t)((b * NH + h) * NCH + c) * HD) * DS + idx];
        }
        if (tid < CQ) {
            float cu = g_cum[((b * NH + h) * NCH + c) * CQ + tid];
            scum[tid] = cu;
            sdt[tid] = g_dt[(size_t)(b * NT + r0 + tid) * NH + h];
            seY[tid] = __expf(cu);
        }
        __syncthreads();
        if (j0 <= i0) {
            #pragma unroll
            for (int r = 0; r < 4; r++) {
                float4 d = *(float4*)&sD0[(i0 + r) * SR + j0];
                float dd[4] = {d.x, d.y, d.z, d.w};
                float gv[4];
                int i = i0 + r;
                float ci = scum[i];
                #pragma unroll
                for (int q = 0; q < 4; q++) {
                    int j = j0 + q;
                    gv[q] = (j <= i) ? __expf(ci - scum[j]) * sdt[j] * dd[q] : 0.0f;
                }
                *(float4*)&sG[(i0 + r) * SR + j0] = make_float4(gv[0], gv[1], gv[2], gv[3]);
            }
        } else {
            #pragma unroll
            for (int r = 0; r < 4; r++)
                *(float4*)&sG[(i0 + r) * SR + j0] = make_float4(0.f, 0.f, 0.f, 0.f);
        }
        __syncthreads();
        int p0 = j0;
        float acc[4][4];
        {
            unsigned long long acc2[4][4] = {};
            for (int sc = 0; sc < 64; sc += 4) {
                ulonglong2 Cr[4], Hc[4];
                #pragma unroll
                for (int r = 0; r < 4; r++) Cr[r] = *(const ulonglong2*)&sC[(i0 + r) * SR + sc];
                #pragma unroll
                for (int q = 0; q < 4; q++) Hc[q] = *(const ulonglong2*)&sH[(p0 + q) * SR + sc];
                #pragma unroll
                for (int r = 0; r < 4; r++)
                    #pragma unroll
                    for (int q = 0; q < 4; q++) {
                        fma2(acc2[r][q], Cr[r].x, Hc[q].x);
                        fma2(acc2[r][q], Cr[r].y, Hc[q].y);
                    }
            }
            #pragma unroll
            for (int r = 0; r < 4; r++) {
                float e = seY[i0 + r];
                #pragma unroll
                for (int q = 0; q < 4; q++) {
                    float2 p = unpack2(acc2[r][q]);
                    acc[r][q] = e * (p.x + p.y);
                }
            }
        }
        unsigned long long accq[4][2];
        #pragma unroll
        for (int r = 0; r < 4; r++) {
            accq[r][0] = packf2(acc[r][0], acc[r][1]);
            accq[r][1] = packf2(acc[r][2], acc[r][3]);
        }
        for (int jc = 0; jc <= i0; jc += 4) {
            float G4[4][4];
            #pragma unroll
            for (int r = 0; r < 4; r++) {
                float4 t = *(float4*)&sG[(i0 + r) * SR + jc];
                G4[r][0] = t.x; G4[r][1] = t.y; G4[r][2] = t.z; G4[r][3] = t.w;
            }
            #pragma unroll
            for (int q = 0; q < 4; q++) {
                ulonglong2 x2 = *(const ulonglong2*)&sX[(jc + q) * SR + p0];
                #pragma unroll
                for (int r = 0; r < 4; r++) {
                    unsigned long long g2 = bcast2(G4[r][q]);
                    fma2(accq[r][0], g2, x2.x);
                    fma2(accq[r][1], g2, x2.y);
                }
            }
        }
        unsigned long long D2 = bcast2(Dv[h]);
        #pragma unroll
        for (int r = 0; r < 4; r++) {
            ulonglong2 xi2 = *(const ulonglong2*)&sX[(i0 + r) * SR + p0];
            fma2(accq[r][0], D2, xi2.x);
            fma2(accq[r][1], D2, xi2.y);
            float2 y01 = unpack2(accq[r][0]);
            float2 y23 = unpack2(accq[r][1]);
            *(float4*)&g_Y[(size_t)(b * NT + r0 + i0 + r) * DI + h * HD + p0] =
                make_float4(y01.x, y01.y, y23.x, y23.y);
        }
        __syncthreads();
    }
}

// ---------------- fused postnorm + combine (token space) ----------------
__global__ void k_pncomb(const float* __restrict__ nw) {
    int t = blockIdx.x, tid = threadIdx.x;
    int r0 = g_inv[t], r1 = g_inv[NT + t];
    int c = 2 * tid;
    float2 y0 = *(const float2*)(g_Y + (size_t)r0 * DI + c);
    float2 y1 = *(const float2*)(g_Y + (size_t)(NT + r1) * DI + c);
    float2 gz = *(const float2*)(g_Z + (size_t)t * DP + c);
    float s0 = gz.x / (1.0f + __expf(-gz.x));
    float s1 = gz.y / (1.0f + __expf(-gz.y));
    float v00 = y0.x * s0, v01 = y0.y * s1;
    float v10 = y1.x * s0, v11 = y1.y * s1;
    float2 ss = blockReduceSum2(v00 * v00 + v01 * v01, v10 * v10 + v11 * v11);
    float rr0 = rsqrtf(ss.x * (1.0f / DI) + 1e-5f);
    float rr1 = rsqrtf(ss.y * (1.0f / DI) + 1e-5f);
    float w0 = nw[c], w1 = nw[c + 1];
    float o0 = 0.5f * w0 * (v00 * rr0 + v10 * rr1);
    float o1 = 0.5f * w1 * (v01 * rr0 + v11 * rr1);
    unsigned short h0, l0, h1, l1;
    bfsplit(o0, h0, l0);
    bfsplit(o1, h1, l1);
    g_combhi[(size_t)t * (DI / 2) + tid] = (unsigned)h0 | ((unsigned)h1 << 16);
    g_comblo[(size_t)t * (DI / 2) + tid] = (unsigned)l0 | ((unsigned)l1 << 16);
}

__global__ void k_final(const float* __restrict__ res,
                        const float* __restrict__ w, const float* __restrict__ bias,
                        float* __restrict__ dout) {
    int r = blockIdx.x, c = threadIdx.x;
    float v = res[(size_t)r * DM + c] + g_O[r * DM + c];
    float mean = blockReduceSum(v) * (1.0f / DM);
    float xc = v - mean;
    float var = blockReduceSum(xc * xc) * (1.0f / DM);
    float result = xc * rsqrtf(var + 1e-5f) * w[c] + bias[c];
    g_q[r * DM + c] = result;
    if (dout) dout[r * DM + c] = result;
}

// ---------------- launcher ----------------
extern "C" void kernel_launch(void* const* d_in, const int* in_sizes, int n_in,
                              void* d_out, int out_size) {
    (void)in_sizes; (void)n_in; (void)out_size;
    const float* query = (const float*)d_in[0];
    const float* pos   = (const float*)d_in[1];
    const float* pre_w = (const float*)d_in[2];
    const float* pre_b = (const float*)d_in[3];
    const float* fin_w = (const float*)d_in[4];
    const float* fin_b = (const float*)d_in[5];

    const int GEMM_SMEM = 2 * (2 * 128 * WSTR + 2 * 64 * WSTR) * 4;
    const int SCAN3_SMEM = (6 * CQ * SR + 3 * CQ) * 4;
    const int CONV_SMEM = (67 * CTILE + CTILE * 4 + CTILE) * 4 + 68 * 4;
    cudaFuncSetAttribute(k_gemm_bf, cudaFuncAttributeMaxDynamicSharedMemorySize, GEMM_SMEM);
    cudaFuncSetAttribute(k_scan3, cudaFuncAttributeMaxDynamicSharedMemorySize, SCAN3_SMEM);
    cudaFuncSetAttribute(k_conv2, cudaFuncAttributeMaxDynamicSharedMemorySize, CONV_SMEM);

    unsigned *p_qnhi, *p_qnlo, *p_combhi, *p_comblo;
    unsigned *p_WIhi, *p_WIlo, *p_WOhi, *p_WOlo;
    float *p_Z, *p_O, *p_q;
    cudaGetSymbolAddress((void**)&p_qnhi, g_qnhi);
    cudaGetSymbolAddress((void**)&p_qnlo, g_qnlo);
    cudaGetSymbolAddress((void**)&p_combhi, g_combhi);
    cudaGetSymbolAddress((void**)&p_comblo, g_comblo);
    cudaGetSymbolAddress((void**)&p_WIhi, g_WIhi);
    cudaGetSymbolAddress((void**)&p_WIlo, g_WIlo);
    cudaGetSymbolAddress((void**)&p_WOhi, g_WOhi);
    cudaGetSymbolAddress((void**)&p_WOlo, g_WOlo);
    cudaGetSymbolAddress((void**)&p_Z, g_Z);
    cudaGetSymbolAddress((void**)&p_O, g_O);
    cudaGetSymbolAddress((void**)&p_q, g_q);

    const int WI_SZ = NPIN * (DM / 2);
    const int WO_SZ = DM * (DI / 2);

    cudaStream_t s1;
    cudaStreamCreateWithFlags(&s1, cudaStreamNonBlocking);
    cudaEvent_t evF, evJ;
    cudaEventCreateWithFlags(&evF, cudaEventDisableTiming);
    cudaEventCreateWithFlags(&evJ, cudaEventDisableTiming);

    const float* Win0  = (const float*)d_in[6];
    const float* Win1  = (const float*)d_in[14];
    const float* Wout0 = (const float*)d_in[13];
    const float* Wout1 = (const float*)d_in[21];

    cudaEventRecord(evF, 0);
    cudaStreamWaitEvent(s1, evF, 0);
    // Branch A (side stream): L0 LN -> split(Win0) -> in-proj GEMM
    k_ln256<<<NT, 128, 0, s1>>>(query, pre_w, pre_b);
    k_splitW<<<((DM / 2) * NPIN + 255) / 256, 256, 0, s1>>>(
        Win0, DM, DP, NPIN, p_WIhi, p_WIlo);
    k_gemm_bf<<<dim3(NPIN / 64, NT / 128), 256, GEMM_SMEM, s1>>>(
        NT, DP, DM, p_qnhi, p_qnlo, p_WIhi, p_WIlo, p_Z, DP);
    cudaEventRecord(evJ, s1);

    // Branch B (origin stream): remaining weight splits + sort chain
    k_splitW<<<((DM / 2) * NPIN + 255) / 256, 256>>>(
        Win1, DM, DP, NPIN, p_WIhi + WI_SZ, p_WIlo + WI_SZ);
    k_splitW<<<((DI / 2) * DM + 255) / 256, 256>>>(
        Wout0, DI, DM, DM, p_WOhi, p_WOlo);
    k_splitW<<<((DI / 2) * DM + 255) / 256, 256>>>(
        Wout1, DI, DM, DM, p_WOhi + WO_SZ, p_WOlo + WO_SZ);
    k_minmax<<<1, 256>>>(pos);
    k_keys<<<(NT + 255) / 256, 256>>>(pos);
    k_sort_init<<<dim3(NT / SEG, 2), 128>>>();
    for (int k = 2 * SEG; k <= NT; k <<= 1) {
        for (int j = k >> 1; j >= SEG; j >>= 1)
            k_sort_gpass<<<dim3(NT / 2 / 256, 2), 256>>>(k, j);
        k_sort_local<<<dim3(NT / SEG, 2), 128>>>(k);
    }
    k_order<<<(2 * NT + 255) / 256, 256>>>();

    cudaStreamWaitEvent(0, evJ, 0);

    for (int L = 0; L < 2; L++) {
        const float* cw   = (const float*)d_in[7 + 8 * L];
        const float* cb   = (const float*)d_in[8 + 8 * L];
        const float* dtb  = (const float*)d_in[9 + 8 * L];
        const float* alog = (const float*)d_in[10 + 8 * L];
        const float* Dv   = (const float*)d_in[11 + 8 * L];
        const float* nw   = (const float*)d_in[12 + 8 * L];
        const float* src  = (L == 0) ? query : p_q;

        if (L == 1) {
            k_ln256<<<NT, 128>>>(src, pre_w, pre_b);
            k_gemm_bf<<<dim3(NPIN / 64, NT / 128), 256, GEMM_SMEM>>>(
                NT, DP, DM, p_qnhi, p_qnlo, p_WIhi + WI_SZ, p_WIlo + WI_SZ, p_Z, DP);
        }
        k_conv2<<<dim3(NT / 64, CD / CTILE, 2), 256, CONV_SMEM>>>(cw, cb);
        k_dt<<<(2 * NT * NH + 255) / 256, 256>>>(dtb, alog);
        k_scan1<<<dim3(NCH, NH, 2), 256>>>();
        k_scan2<<<256, 256>>>();
        k_scan3<<<dim3(NCH, 2), 256, SCAN3_SMEM>>>(Dv);
        k_pncomb<<<NT, 256>>>(nw);
        k_gemm_bf<<<dim3(DM / 64, NT / 128), 256, GEMM_SMEM>>>(
            NT, DM, DI, p_combhi, p_comblo,
            p_WOhi + (size_t)L * WO_SZ, p_WOlo + (size_t)L * WO_SZ, p_O, DM);
        k_final<<<NT, 256>>>(src, fin_w, fin_b, (L == 1) ? (float*)d_out : nullptr);
    }
}

// round 15
// speedup vs baseline: 1.6666x; 1.0127x over previous
#include <cuda_runtime.h>
#include <cuda_bf16.h>
#include <math.h>

#define NT 16384
#define DM 256
#define DI 512
#define DS 64
#define NH 8
#define HD 64
#define CD 640      // CONV_DIM
#define DP 1160     // D_PROJ
#define KER 4
#define NCH 256     // number of chunks
#define CQ 64       // chunk length
#define SR 68       // padded row stride for 64-col smem tiles
#define NPIN 1216   // padded N for in_proj (19*64)
#define WSTR 20     // GEMM smem row stride in uints
#define CTILE 160   // conv col chunk
#define SEG 2048    // sort segment

// ---------------- device scratch ----------------
__device__ float g_q[NT * DM];
__device__ unsigned g_qnhi[NT * (DM / 2)];
__device__ unsigned g_qnlo[NT * (DM / 2)];
__device__ float g_Z[NT * DP];
__device__ float g_XBC[2 * NT * CD];
__device__ float g_dt[2 * NT * NH];
__device__ float g_a[2 * NT * NH];
__device__ float g_cum[2 * NH * NCH * CQ];
__device__ float g_cdec[2 * NH * NCH];
__device__ float g_S[2 * NH * NCH * HD * DS];
__device__ float g_Hp[2 * NH * NCH * HD * DS];
__device__ float g_Y[2 * NT * DI];
__device__ unsigned g_combhi[NT * (DI / 2)];
__device__ unsigned g_comblo[NT * (DI / 2)];
__device__ float g_O[NT * DM];
__device__ unsigned g_WIhi[2 * NPIN * (DM / 2)];
__device__ unsigned g_WIlo[2 * NPIN * (DM / 2)];
__device__ unsigned g_WOhi[2 * DM * (DI / 2)];
__device__ unsigned g_WOlo[2 * DM * (DI / 2)];
__device__ unsigned long long g_keys[2 * NT];
__device__ int g_order[2 * NT];
__device__ int g_inv[2 * NT];
__device__ float g_pmin[3], g_pmax[3];

extern __shared__ float dynsmem[];

// ---------------- helpers ----------------
__device__ __forceinline__ float blockReduceSum(float v) {
    __shared__ float sh[32];
    __shared__ float tot;
    int lane = threadIdx.x & 31, wid = threadIdx.x >> 5;
    #pragma unroll
    for (int o = 16; o > 0; o >>= 1) v += __shfl_xor_sync(0xffffffffu, v, o);
    if (lane == 0) sh[wid] = v;
    __syncthreads();
    int nw = blockDim.x >> 5;
    v = (threadIdx.x < nw) ? sh[threadIdx.x] : 0.0f;
    if (wid == 0) {
        #pragma unroll
        for (int o = 16; o > 0; o >>= 1) v += __shfl_xor_sync(0xffffffffu, v, o);
        if (lane == 0) tot = v;
    }
    __syncthreads();
    return tot;
}

__device__ __forceinline__ float2 blockReduceSum2(float a, float b) {
    __shared__ float sha[32], shb[32];
    __shared__ float2 tot;
    int lane = threadIdx.x & 31, wid = threadIdx.x >> 5;
    #pragma unroll
    for (int o = 16; o > 0; o >>= 1) {
        a += __shfl_xor_sync(0xffffffffu, a, o);
        b += __shfl_xor_sync(0xffffffffu, b, o);
    }
    if (lane == 0) { sha[wid] = a; shb[wid] = b; }
    __syncthreads();
    int nw = blockDim.x >> 5;
    a = (threadIdx.x < nw) ? sha[threadIdx.x] : 0.0f;
    b = (threadIdx.x < nw) ? shb[threadIdx.x] : 0.0f;
    if (wid == 0) {
        #pragma unroll
        for (int o = 16; o > 0; o >>= 1) {
            a += __shfl_xor_sync(0xffffffffu, a, o);
            b += __shfl_xor_sync(0xffffffffu, b, o);
        }
        if (lane == 0) tot = make_float2(a, b);
    }
    __syncthreads();
    return tot;
}

__device__ __forceinline__ unsigned hilbert3(unsigned a0, unsigned a1, unsigned a2) {
    unsigned x0 = a0, x1 = a1, x2 = a2;
    const unsigned M = 1u << 9;
    for (unsigned Q = M; Q > 1; Q >>= 1) {
        unsigned P = Q - 1;
        if (x0 & Q) x0 ^= P;
        {
            unsigned t = (x0 ^ x1) & P;
            if (x1 & Q) { x0 ^= P; } else { x0 ^= t; x1 ^= t; }
        }
        {
            unsigned t = (x0 ^ x2) & P;
            if (x2 & Q) { x0 ^= P; } else { x0 ^= t; x2 ^= t; }
        }
    }
    x1 ^= x0;
    x2 ^= x1;
    unsigned t = 0;
    for (unsigned Q = M; Q > 1; Q >>= 1)
        if (x2 & Q) t ^= (Q - 1);
    x0 ^= t; x1 ^= t; x2 ^= t;
    unsigned code = 0;
    for (int b = 9; b >= 0; b--) {
        code = (code << 1) | ((x0 >> b) & 1);
        code = (code << 1) | ((x1 >> b) & 1);
        code = (code << 1) | ((x2 >> b) & 1);
    }
    return code;
}

__device__ __forceinline__ void bfsplit(float x, unsigned short& hi, unsigned short& lo) {
    __nv_bfloat16 h = __float2bfloat16(x);
    __nv_bfloat16 l = __float2bfloat16(x - __bfloat162float(h));
    hi = *(unsigned short*)&h;
    lo = *(unsigned short*)&l;
}

__device__ __forceinline__ void mma_bf16(float c[4], const unsigned a[4],
                                         unsigned b0, unsigned b1) {
    asm volatile("mma.sync.aligned.m16n8k16.row.col.f32.bf16.bf16.f32 "
        "{%0,%1,%2,%3}, {%4,%5,%6,%7}, {%8,%9}, {%0,%1,%2,%3};"
        : "+f"(c[0]), "+f"(c[1]), "+f"(c[2]), "+f"(c[3])
        : "r"(a[0]), "r"(a[1]), "r"(a[2]), "r"(a[3]), "r"(b0), "r"(b1));
}

__device__ __forceinline__ void cp16(unsigned dst, const void* src) {
    asm volatile("cp.async.cg.shared.global [%0], [%1], 16;" :: "r"(dst), "l"(src));
}

// ---- packed f32x2 FMA ----
__device__ __forceinline__ void fma2(unsigned long long& c, unsigned long long a,
                                     unsigned long long b) {
    asm("fma.rn.f32x2 %0, %1, %2, %0;" : "+l"(c) : "l"(a), "l"(b));
}
__device__ __forceinline__ unsigned long long bcast2(float x) {
    unsigned long long r;
    unsigned u = __float_as_uint(x);
    asm("mov.b64 %0, {%1, %2};" : "=l"(r) : "r"(u), "r"(u));
    return r;
}
__device__ __forceinline__ unsigned long long packf2(float a, float b) {
    unsigned long long r;
    asm("mov.b64 %0, {%1, %2};" : "=l"(r) : "r"(__float_as_uint(a)), "r"(__float_as_uint(b)));
    return r;
}
__device__ __forceinline__ float2 unpack2(unsigned long long v) {
    unsigned lo, hi;
    asm("mov.b64 {%0, %1}, %2;" : "=r"(lo), "=r"(hi) : "l"(v));
    return make_float2(__uint_as_float(lo), __uint_as_float(hi));
}

// ---------------- setup kernels ----------------
__global__ void k_minmax(const float* __restrict__ pos) {
    __shared__ float smn[256][3], smx[256][3];
    float mn[3] = {1e30f, 1e30f, 1e30f}, mx[3] = {-1e30f, -1e30f, -1e30f};
    for (int r = threadIdx.x; r < NT; r += 256) {
        #pragma unroll
        for (int j = 0; j < 3; j++) {
            float v = pos[r * 3 + j];
            mn[j] = fminf(mn[j], v);
            mx[j] = fmaxf(mx[j], v);
        }
    }
    #pragma unroll
    for (int j = 0; j < 3; j++) { smn[threadIdx.x][j] = mn[j]; smx[threadIdx.x][j] = mx[j]; }
    __syncthreads();
    for (int s = 128; s > 0; s >>= 1) {
        if (threadIdx.x < s) {
            #pragma unroll
            for (int j = 0; j < 3; j++) {
                smn[threadIdx.x][j] = fminf(smn[threadIdx.x][j], smn[threadIdx.x + s][j]);
                smx[threadIdx.x][j] = fmaxf(smx[threadIdx.x][j], smx[threadIdx.x + s][j]);
            }
        }
        __syncthreads();
    }
    if (threadIdx.x == 0) {
        #pragma unroll
        for (int j = 0; j < 3; j++) { g_pmin[j] = smn[0][j]; g_pmax[j] = smx[0][j]; }
    }
}

__global__ void k_keys(const float* __restrict__ pos) {
    int idx = blockIdx.x * blockDim.x + threadIdx.x;
    if (idx >= NT) return;
    unsigned g[3];
    #pragma unroll
    for (int j = 0; j < 3; j++) {
        float denom = g_pmax[j] - g_pmin[j] + 1e-6f;
        float v = ((pos[idx * 3 + j] - g_pmin[j]) / denom) * 1023.0f;
        v = fminf(fmaxf(v, 0.0f), 1023.0f);
        g[j] = (unsigned)(int)v;
    }
    unsigned c0 = hilbert3(g[0], g[1], g[2]);
    unsigned c1 = hilbert3(g[1], g[0], g[2]);
    g_keys[idx]      = (((unsigned long long)c0) << 14) | (unsigned long long)idx;
    g_keys[NT + idx] = (((unsigned long long)c1) << 14) | (unsigned long long)idx;
}

#define SADDR(i) ((i) + ((i) >> 4))

__global__ void k_sort_init() {
    __shared__ unsigned long long s[SEG + SEG / 16];
    int seg = blockIdx.x, b = blockIdx.y;
    unsigned long long* keys = g_keys + b * NT + seg * SEG;
    bool upg = ((seg & 1) == 0);
    int t = threadIdx.x;  // 128 threads
    for (int i = t; i < SEG; i += 128) s[SADDR(i)] = keys[i];
    __syncthreads();

    int base = t * 16;
    unsigned long long v[16];
    #pragma unroll
    for (int r = 0; r < 16; r++) v[r] = s[SADDR(base + r)];
    #pragma unroll
    for (int k = 2; k <= 16; k <<= 1) {
        #pragma unroll
        for (int j = k >> 1; j > 0; j >>= 1) {
            #pragma unroll
            for (int r = 0; r < 16; r++) {
                int rr = r ^ j;
                if (rr > r) {
                    bool up = ((((base + r) & k) == 0) == upg);
                    unsigned long long a = v[r], c = v[rr];
                    if ((a > c) == up) { v[r] = c; v[rr] = a; }
                }
            }
        }
    }
    #pragma unroll
    for (int r = 0; r < 16; r++) s[SADDR(base + r)] = v[r];
    __syncthreads();

    for (int k = 32; k <= SEG; k <<= 1) {
        for (int j = k >> 1; j >= 16; j >>= 1) {
            for (int i = t; i < SEG; i += 128) {
                int ixj = i ^ j;
                if (ixj > i) {
                    unsigned long long a = s[SADDR(i)], c = s[SADDR(ixj)];
                    bool up = (((i & k) == 0) == upg);
                    if ((a > c) == up) { s[SADDR(i)] = c; s[SADDR(ixj)] = a; }
                }
            }
            __syncthreads();
        }
        #pragma unroll
        for (int r = 0; r < 16; r++) v[r] = s[SADDR(base + r)];
        bool up = (((base & k) == 0) == upg);
        #pragma unroll
        for (int j = 8; j > 0; j >>= 1) {
            #pragma unroll
            for (int r = 0; r < 16; r++) {
                int rr = r ^ j;
                if (rr > r) {
                    unsigned long long a = v[r], c = v[rr];
                    if ((a > c) == up) { v[r] = c; v[rr] = a; }
                }
            }
        }
        #pragma unroll
        for (int r = 0; r < 16; r++) s[SADDR(base + r)] = v[r];
        __syncthreads();
    }
    for (int i = t; i < SEG; i += 128) keys[i] = s[SADDR(i)];
}

__global__ void k_sort_gpass(int k, int j) {
    int p = blockIdx.x * blockDim.x + threadIdx.x;
    int b = blockIdx.y;
    int low = p & (j - 1);
    int i = ((p & ~(j - 1)) << 1) | low;
    unsigned long long* keys = g_keys + b * NT;
    unsigned long long a = keys[i], c = keys[i + j];
    bool up = ((i & k) == 0);
    if ((a > c) == up) { keys[i] = c; keys[i + j] = a; }
}

__global__ void k_sort_local(int k) {
    __shared__ unsigned long long s[SEG + SEG / 16];
    int seg = blockIdx.x, b = blockIdx.y;
    unsigned long long* keys = g_keys + b * NT + seg * SEG;
    bool up = (((seg * SEG) & k) == 0);
    int t = threadIdx.x;
    for (int i = t; i < SEG; i += 128) s[SADDR(i)] = keys[i];
    __syncthreads();
    for (int j = SEG / 2; j >= 16; j >>= 1) {
        for (int i = t; i < SEG; i += 128) {
            int ixj = i ^ j;
            if (ixj > i) {
                unsigned long long a = s[SADDR(i)], c = s[SADDR(ixj)];
                if ((a > c) == up) { s[SADDR(i)] = c; s[SADDR(ixj)] = a; }
            }
        }
        __syncthreads();
    }
    int base = t * 16;
    unsigned long long v[16];
    #pragma unroll
    for (int r = 0; r < 16; r++) v[r] = s[SADDR(base + r)];
    #pragma unroll
    for (int j = 8; j > 0; j >>= 1) {
        #pragma unroll
        for (int r = 0; r < 16; r++) {
            int rr = r ^ j;
            if (rr > r) {
                unsigned long long a = v[r], c = v[rr];
                if ((a > c) == up) { v[r] = c; v[rr] = a; }
            }
        }
    }
    #pragma unroll
    for (int r = 0; r < 16; r++) s[SADDR(base + r)] = v[r];
    __syncthreads();
    for (int i = t; i < SEG; i += 128) keys[i] = s[SADDR(i)];
}

__global__ void k_order() {
    int i = blockIdx.x * blockDim.x + threadIdx.x;
    if (i >= 2 * NT) return;
    int b = i / NT;
    int idx = (int)(g_keys[i] & 0x3FFFULL);
    g_order[i] = idx;
    g_inv[b * NT + idx] = i - b * NT;
}

__global__ void k_ln256(const float* __restrict__ src,
                        const float* __restrict__ w, const float* __restrict__ bias) {
    int r = blockIdx.x, t = threadIdx.x;
    float2 v = *(const float2*)(src + (size_t)r * DM + 2 * t);
    float mean = blockReduceSum(v.x + v.y) * (1.0f / DM);
    float x0 = v.x - mean, x1 = v.y - mean;
    float var = blockReduceSum(x0 * x0 + x1 * x1) * (1.0f / DM);
    float rs = rsqrtf(var + 1e-5f);
    float r0 = x0 * rs * w[2 * t] + bias[2 * t];
    float r1 = x1 * rs * w[2 * t + 1] + bias[2 * t + 1];
    unsigned short h0, l0, h1, l1;
    bfsplit(r0, h0, l0);
    bfsplit(r1, h1, l1);
    g_qnhi[r * (DM / 2) + t] = (unsigned)h0 | ((unsigned)h1 << 16);
    g_qnlo[r * (DM / 2) + t] = (unsigned)l0 | ((unsigned)l1 << 16);
}

__global__ void k_splitW(const float* __restrict__ src, int K, int N, int NP,
                         unsigned* __restrict__ Whi, unsigned* __restrict__ Wlo) {
    int idx = blockIdx.x * blockDim.x + threadIdx.x;
    if (idx >= (K / 2) * NP) return;
    int kp = idx / NP, n = idx - kp * NP;
    float w0 = (n < N) ? src[(size_t)(2 * kp) * N + n] : 0.0f;
    float w1 = (n < N) ? src[(size_t)(2 * kp + 1) * N + n] : 0.0f;
    unsigned short h0, l0, h1, l1;
    bfsplit(w0, h0, l0);
    bfsplit(w1, h1, l1);
    Whi[(size_t)n * (K / 2) + kp] = (unsigned)h0 | ((unsigned)h1 << 16);
    Wlo[(size_t)n * (K / 2) + kp] = (unsigned)l0 | ((unsigned)l1 << 16);
}

// ---------------- bf16x3 tensor-core GEMM ----------------
__device__ __forceinline__ void gemm_load_bf(
    const unsigned* __restrict__ Ahi, const unsigned* __restrict__ Alo, int K2,
    const unsigned* __restrict__ Bhi, const unsigned* __restrict__ Blo,
    int m0, int n0, int kt, unsigned* sAh, unsigned* sAl,
    unsigned* sBh, unsigned* sBl, int tid) {
    int kp0 = kt * 16;
    int r = tid >> 1, cu = (tid & 1) * 8;
    const unsigned* pah = Ahi + (size_t)(m0 + r) * K2 + kp0 + cu;
    const unsigned* pal = Alo + (size_t)(m0 + r) * K2 + kp0 + cu;
    unsigned dah = (unsigned)__cvta_generic_to_shared(sAh + r * WSTR + cu);
    unsigned dal = (unsigned)__cvta_generic_to_shared(sAl + r * WSTR + cu);
    cp16(dah, pah); cp16(dah + 16, pah + 4);
    cp16(dal, pal); cp16(dal + 16, pal + 4);
    int n = tid >> 2, cb = (tid & 3) * 4;
    cp16((unsigned)__cvta_generic_to_shared(sBh + n * WSTR + cb),
         Bhi + (size_t)(n0 + n) * K2 + kp0 + cb);
    cp16((unsigned)__cvta_generic_to_shared(sBl + n * WSTR + cb),
         Blo + (size_t)(n0 + n) * K2 + kp0 + cb);
}

__global__ __launch_bounds__(256) void k_gemm_bf(int M, int N, int K,
        const unsigned* __restrict__ Ahi, const unsigned* __restrict__ Alo,
        const unsigned* __restrict__ Bhi, const unsigned* __restrict__ Blo,
        float* __restrict__ C, int ldc) {
    unsigned* sm = (unsigned*)dynsmem;
    const int ASZ = 128 * WSTR, BSZ = 64 * WSTR;
    const int STG = 2 * ASZ + 2 * BSZ;

    int m0 = blockIdx.y * 128, n0 = blockIdx.x * 64;
    int tid = threadIdx.x;
    int wid = tid >> 5, lane = tid & 31;
    int wm = (wid & 3) * 32, wn = (wid >> 2) * 32;
    int g = lane >> 2, tg = lane & 3;
    int K2 = K >> 1;
    int KT = K / 32;

    float acc[2][4][4];
    #pragma unroll
    for (int a = 0; a < 2; a++)
        #pragma unroll
        for (int b = 0; b < 4; b++)
            #pragma unroll
            for (int c = 0; c < 4; c++) acc[a][b][c] = 0.0f;

    gemm_load_bf(Ahi, Alo, K2, Bhi, Blo, m0, n0, 0,
                 sm, sm + ASZ, sm + 2 * ASZ, sm + 2 * ASZ + BSZ, tid);
    asm volatile("cp.async.commit_group;");

    for (int kt = 0; kt < KT; kt++) {
        int st = kt & 1;
        if (kt + 1 < KT) {
            int ns = st ^ 1;
            unsigned* b0 = sm + ns * STG;
            gemm_load_bf(Ahi, Alo, K2, Bhi, Blo, m0, n0, kt + 1,
                         b0, b0 + ASZ, b0 + 2 * ASZ, b0 + 2 * ASZ + BSZ, tid);
            asm volatile("cp.async.commit_group;");
            asm volatile("cp.async.wait_group 1;");
        } else {
            asm volatile("cp.async.wait_group 0;");
        }
        __syncthreads();
        unsigned* sAhi = sm + st * STG;
        unsigned* sAlo = sAhi + ASZ;
        unsigned* sBhi = sAhi + 2 * ASZ;
        unsigned* sBlo = sBhi + BSZ;
        #pragma unroll
        for (int kk2 = 0; kk2 < 16; kk2 += 8) {
            unsigned ahi[2][4], alo[2][4], bhi[4][2], blo[4][2];
            #pragma unroll
            for (int mi = 0; mi < 2; mi++) {
                int ra = (wm + mi * 16 + g) * WSTR;
                int rb = (wm + mi * 16 + g + 8) * WSTR;
                ahi[mi][0] = sAhi[ra + kk2 + tg];
                ahi[mi][1] = sAhi[rb + kk2 + tg];
                ahi[mi][2] = sAhi[ra + kk2 + 4 + tg];
                ahi[mi][3] = sAhi[rb + kk2 + 4 + tg];
                alo[mi][0] = sAlo[ra + kk2 + tg];
                alo[mi][1] = sAlo[rb + kk2 + tg];
                alo[mi][2] = sAlo[ra + kk2 + 4 + tg];
                alo[mi][3] = sAlo[rb + kk2 + 4 + tg];
            }
            #pragma unroll
            for (int nj = 0; nj < 4; nj++) {
                int rn = (wn + nj * 8 + g) * WSTR;
                bhi[nj][0] = sBhi[rn + kk2 + tg];
                bhi[nj][1] = sBhi[rn + kk2 + 4 + tg];
                blo[nj][0] = sBlo[rn + kk2 + tg];
                blo[nj][1] = sBlo[rn + kk2 + 4 + tg];
            }
            #pragma unroll
            for (int mi = 0; mi < 2; mi++)
                #pragma unroll
                for (int nj = 0; nj < 4; nj++) {
                    mma_bf16(acc[mi][nj], ahi[mi], bhi[nj][0], bhi[nj][1]);
                    mma_bf16(acc[mi][nj], ahi[mi], blo[nj][0], blo[nj][1]);
                    mma_bf16(acc[mi][nj], alo[mi], bhi[nj][0], bhi[nj][1]);
                }
        }
        __syncthreads();
    }
    #pragma unroll
    for (int mi = 0; mi < 2; mi++)
        #pragma unroll
        for (int nj = 0; nj < 4; nj++) {
            int row = m0 + wm + mi * 16 + g;
            int col = n0 + wn + nj * 8 + tg * 2;
            if (col + 1 < N) {
                *(float2*)(C + (size_t)row * ldc + col) =
                    make_float2(acc[mi][nj][0], acc[mi][nj][1]);
                *(float2*)(C + (size_t)(row + 8) * ldc + col) =
                    make_float2(acc[mi][nj][2], acc[mi][nj][3]);
            } else if (col < N) {
                C[(size_t)row * ldc + col] = acc[mi][nj][0];
                C[(size_t)(row + 8) * ldc + col] = acc[mi][nj][2];
            }
        }
}

// ---------------- tiled conv (+ fused dt on y==0 blocks) ----------------
__global__ __launch_bounds__(256) void k_conv2(const float* __restrict__ cw,
                                               const float* __restrict__ cb,
                                               const float* __restrict__ dtb,
                                               const float* __restrict__ alog) {
    float* sZ  = dynsmem;
    float* scw = sZ + 67 * CTILE;
    float* scb = scw + CTILE * 4;
    int*   stok = (int*)(scb + CTILE);
    int r0 = blockIdx.x * 64, cc = blockIdx.y * CTILE, b = blockIdx.z;
    int tid = threadIdx.x;
    if (tid < 67) {
        int rr = r0 - 3 + tid;
        stok[tid] = (rr >= 0) ? g_order[b * NT + rr] : -1;
    }
    for (int idx = tid; idx < CTILE * 4; idx += 256)
        scw[idx] = cw[(cc + (idx >> 2)) * KER + (idx & 3)];
    for (int idx = tid; idx < CTILE; idx += 256)
        scb[idx] = cb[cc + idx];
    __syncthreads();
    for (int idx = tid; idx < 67 * CTILE; idx += 256) {
        int row = idx / CTILE, col = idx - row * CTILE;
        int t = stok[row];
        sZ[idx] = (t >= 0) ? g_Z[(size_t)t * DP + DI + cc + col] : 0.0f;
    }
    // fused dt/a for this row range (y==0 blocks only; uses stok)
    if (blockIdx.y == 0) {
        for (int idx = tid; idx < 64 * NH; idx += 256) {
            int row = idx >> 3, h = idx & 7;
            int t = stok[row + 3];
            float x = g_Z[(size_t)t * DP + DI + CD + h] + dtb[h];
            float sp = fmaxf(x, 0.0f) + log1pf(expf(-fabsf(x)));
            float A = -expf(alog[h]);
            int gi = (b * NT + r0 + row) * NH + h;
            g_dt[gi] = sp;
            g_a[gi] = sp * A;
        }
    }
    __syncthreads();
    for (int idx = tid; idx < 64 * CTILE; idx += 256) {
        int row = idx / CTILE, col = idx - row * CTILE;
        float acc = scb[col];
        #pragma unroll
        for (int k = 0; k < KER; k++)
            acc += scw[col * 4 + k] * sZ[(row + k) * CTILE + col];
        float s = acc / (1.0f + __expf(-acc));
        g_XBC[(size_t)(b * NT + r0 + row) * CD + cc + col] = s;
    }
}

// ---------------- chunked scan (scan1 loops heads; B loaded once) ----------------
__global__ __launch_bounds__(256) void k_scan1() {
    int c = blockIdx.x, b = blockIdx.y;
    __shared__ float sX[CQ * SR], sB[CQ * SR];
    __shared__ float scum[CQ], sw[CQ];
    int r0 = c * CQ, tid = threadIdx.x;
    for (int idx = tid; idx < CQ * 64; idx += 256) {
        int j = idx >> 6, p = idx & 63;
        sB[j * SR + p] = g_XBC[(size_t)(b * NT + r0 + j) * CD + DI + p];
    }
    int p0 = (tid & 15) * 4, s0 = (tid >> 4) * 4;
    for (int h = 0; h < NH; h++) {
        __syncthreads();  // protect sX/scum/sw from previous iteration (and cover sB load)
        for (int idx = tid; idx < CQ * 64; idx += 256) {
            int j = idx >> 6, p = idx & 63;
            sX[j * SR + p] = g_XBC[(size_t)(b * NT + r0 + j) * CD + h * HD + p];
        }
        if (tid < CQ) scum[tid] = g_a[(size_t)(b * NT + r0 + tid) * NH + h];
        __syncthreads();
        if (tid < CQ) {
            float x = scum[tid];
            #pragma unroll
            for (int o = 1; o < 32; o <<= 1) {
                float y = __shfl_up_sync(0xffffffffu, x, o);
                if ((tid & 31) >= o) x += y;
            }
            scum[tid] = x;
        }
        __syncthreads();
        if (tid >= 32 && tid < CQ) scum[tid] += scum[31];
        __syncthreads();
        float slast = scum[CQ - 1];
        if (tid < CQ) {
            sw[tid] = __expf(slast - scum[tid]) * g_dt[(size_t)(b * NT + r0 + tid) * NH + h];
            g_cum[((b * NH + h) * NCH + c) * CQ + tid] = scum[tid];
        }
        if (tid == 0) g_cdec[(b * NH + h) * NCH + c] = __expf(slast);
        __syncthreads();
        unsigned long long acc2[4][2] = {};
        for (int j = 0; j < CQ; j++) {
            float4 xv = *(float4*)&sX[j * SR + p0];
            ulonglong2 b2 = *(const ulonglong2*)&sB[j * SR + s0];
            float w = sw[j];
            float wx[4] = {xv.x * w, xv.y * w, xv.z * w, xv.w * w};
            #pragma unroll
            for (int pi = 0; pi < 4; pi++) {
                unsigned long long w2 = bcast2(wx[pi]);
                fma2(acc2[pi][0], w2, b2.x);
                fma2(acc2[pi][1], w2, b2.y);
            }
        }
        size_t base = ((size_t)((b * NH + h) * NCH + c) * HD) * DS;
        #pragma unroll
        for (int pi = 0; pi < 4; pi++) {
            float2 a01 = unpack2(acc2[pi][0]);
            float2 a23 = unpack2(acc2[pi][1]);
            *(float4*)&g_S[base + (size_t)(p0 + pi) * DS + s0] =
                make_float4(a01.x, a01.y, a23.x, a23.y);
        }
    }
}

__global__ void k_scan2() {
    __shared__ float scd[NCH];
    int bh = blockIdx.x >> 4;
    int e = ((blockIdx.x & 15) << 8) + threadIdx.x;
    if (threadIdx.x < NCH) scd[threadIdx.x] = g_cdec[bh * NCH + threadIdx.x];
    __syncthreads();
    float H = 0.0f;
    for (int c = 0; c < NCH; c++) {
        size_t off = ((size_t)(bh * NCH + c)) * (HD * DS) + e;
        float s = g_S[off];
        g_Hp[off] = H;
        H = scd[c] * H + s;
    }
}

__global__ __launch_bounds__(256) void k_scan3(const float* __restrict__ Dv) {
    int c = blockIdx.x, b = blockIdx.y;
    int r0 = c * CQ, tid = threadIdx.x;
    float* sB  = dynsmem;
    float* sC  = sB  + CQ * SR;
    float* sD0 = sC  + CQ * SR;
    float* sX  = sD0 + CQ * SR;
    float* sH  = sX  + CQ * SR;
    float* sG  = sH  + CQ * SR;
    float* scum = sG + CQ * SR;
    float* sdt  = scum + CQ;
    float* seY  = sdt + CQ;

    for (int idx = tid; idx < CQ * 64; idx += 256) {
        int j = idx >> 6, s = idx & 63;
        sB[j * SR + s] = g_XBC[(size_t)(b * NT + r0 + j) * CD + DI + s];
        sC[j * SR + s] = g_XBC[(size_t)(b * NT + r0 + j) * CD + DI + DS + s];
    }
    __syncthreads();
    int i0 = (tid >> 4) * 4, j0 = (tid & 15) * 4;
    if (j0 <= i0) {
        unsigned long long acc2[4][4] = {};
        for (int sc = 0; sc < 64; sc += 4) {
            ulonglong2 Cr[4], Br[4];
            #pragma unroll
            for (int r = 0; r < 4; r++) Cr[r] = *(const ulonglong2*)&sC[(i0 + r) * SR + sc];
            #pragma unroll
            for (int q = 0; q < 4; q++) Br[q] = *(const ulonglong2*)&sB[(j0 + q) * SR + sc];
            #pragma unroll
            for (int r = 0; r < 4; r++)
                #pragma unroll
                for (int q = 0; q < 4; q++) {
                    fma2(acc2[r][q], Cr[r].x, Br[q].x);
                    fma2(acc2[r][q], Cr[r].y, Br[q].y);
                }
        }
        #pragma unroll
        for (int r = 0; r < 4; r++) {
            float dv[4];
            #pragma unroll
            for (int q = 0; q < 4; q++) {
                float2 p = unpack2(acc2[r][q]);
                dv[q] = p.x + p.y;
            }
            *(float4*)&sD0[(i0 + r) * SR + j0] = make_float4(dv[0], dv[1], dv[2], dv[3]);
        }
    } else {
        #pragma unroll
        for (int r = 0; r < 4; r++)
            *(float4*)&sD0[(i0 + r) * SR + j0] = make_float4(0.f, 0.f, 0.f, 0.f);
    }
    __syncthreads();

    for (int h = 0; h < NH; h++) {
        for (int idx = tid; idx < CQ * 64; idx += 256) {
            int j = idx >> 6, p = idx & 63;
            sX[j * SR + p] = g_XBC[(size_t)(b * NT + r0 + j) * CD + h * HD + p];
            sH[j * SR + p] = g_Hp[((size_t)((b * NH + h) * NCH + c) * HD) * DS + idx];
        }
        if (tid < CQ) {
            float cu = g_cum[((b * NH + h) * NCH + c) * CQ + tid];
            scum[tid] = cu;
            sdt[tid] = g_dt[(size_t)(b * NT + r0 + tid) * NH + h];
            seY[tid] = __expf(cu);
        }
        __syncthreads();
        if (j0 <= i0) {
            #pragma unroll
            for (int r = 0; r < 4; r++) {
                float4 d = *(float4*)&sD0[(i0 + r) * SR + j0];
                float dd[4] = {d.x, d.y, d.z, d.w};
                float gv[4];
                int i = i0 + r;
                float ci = scum[i];
                #pragma unroll
                for (int q = 0; q < 4; q++) {
                    int j = j0 + q;
                    gv[q] = (j <= i) ? __expf(ci - scum[j]) * sdt[j] * dd[q] : 0.0f;
                }
                *(float4*)&sG[(i0 + r) * SR + j0] = make_float4(gv[0], gv[1], gv[2], gv[3]);
            }
        } else {
            #pragma unroll
            for (int r = 0; r < 4; r++)
                *(float4*)&sG[(i0 + r) * SR + j0] = make_float4(0.f, 0.f, 0.f, 0.f);
        }
        __syncthreads();
        int p0 = j0;
        float acc[4][4];
        {
            unsigned long long acc2[4][4] = {};
            for (int sc = 0; sc < 64; sc += 4) {
                ulonglong2 Cr[4], Hc[4];
                #pragma unroll
                for (int r = 0; r < 4; r++) Cr[r] = *(const ulonglong2*)&sC[(i0 + r) * SR + sc];
                #pragma unroll
                for (int q = 0; q < 4; q++) Hc[q] = *(const ulonglong2*)&sH[(p0 + q) * SR + sc];
                #pragma unroll
                for (int r = 0; r < 4; r++)
                    #pragma unroll
                    for (int q = 0; q < 4; q++) {
                        fma2(acc2[r][q], Cr[r].x, Hc[q].x);
                        fma2(acc2[r][q], Cr[r].y, Hc[q].y);
                    }
            }
            #pragma unroll
            for (int r = 0; r < 4; r++) {
                float e = seY[i0 + r];
                #pragma unroll
                for (int q = 0; q < 4; q++) {
                    float2 p = unpack2(acc2[r][q]);
                    acc[r][q] = e * (p.x + p.y);
                }
            }
        }
        unsigned long long accq[4][2];
        #pragma unroll
        for (int r = 0; r < 4; r++) {
            accq[r][0] = packf2(acc[r][0], acc[r][1]);
            accq[r][1] = packf2(acc[r][2], acc[r][3]);
        }
        for (int jc = 0; jc <= i0; jc += 4) {
            float G4[4][4];
            #pragma unroll
            for (int r = 0; r < 4; r++) {
                float4 t = *(float4*)&sG[(i0 + r) * SR + jc];
                G4[r][0] = t.x; G4[r][1] = t.y; G4[r][2] = t.z; G4[r][3] = t.w;
            }
            #pragma unroll
            for (int q = 0; q < 4; q++) {
                ulonglong2 x2 = *(const ulonglong2*)&sX[(jc + q) * SR + p0];
                #pragma unroll
                for (int r = 0; r < 4; r++) {
                    unsigned long long g2 = bcast2(G4[r][q]);
                    fma2(accq[r][0], g2, x2.x);
                    fma2(accq[r][1], g2, x2.y);
                }
            }
        }
        unsigned long long D2 = bcast2(Dv[h]);
        #pragma unroll
        for (int r = 0; r < 4; r++) {
            ulonglong2 xi2 = *(const ulonglong2*)&sX[(i0 + r) * SR + p0];
            fma2(accq[r][0], D2, xi2.x);
            fma2(accq[r][1], D2, xi2.y);
            float2 y01 = unpack2(accq[r][0]);
            float2 y23 = unpack2(accq[r][1]);
            *(float4*)&g_Y[(size_t)(b * NT + r0 + i0 + r) * DI + h * HD + p0] =
                make_float4(y01.x, y01.y, y23.x, y23.y);
        }
        __syncthreads();
    }
}

// ---------------- fused postnorm + combine ----------------
__global__ void k_pncomb(const float* __restrict__ nw) {
    int t = blockIdx.x, tid = threadIdx.x;
    int r0 = g_inv[t], r1 = g_inv[NT + t];
    int c = 2 * tid;
    float2 y0 = *(const float2*)(g_Y + (size_t)r0 * DI + c);
    float2 y1 = *(const float2*)(g_Y + (size_t)(NT + r1) * DI + c);
    float2 gz = *(const float2*)(g_Z + (size_t)t * DP + c);
    float s0 = gz.x / (1.0f + __expf(-gz.x));
    float s1 = gz.y / (1.0f + __expf(-gz.y));
    float v00 = y0.x * s0, v01 = y0.y * s1;
    float v10 = y1.x * s0, v11 = y1.y * s1;
    float2 ss = blockReduceSum2(v00 * v00 + v01 * v01, v10 * v10 + v11 * v11);
    float rr0 = rsqrtf(ss.x * (1.0f / DI) + 1e-5f);
    float rr1 = rsqrtf(ss.y * (1.0f / DI) + 1e-5f);
    float w0 = nw[c], w1 = nw[c + 1];
    float o0 = 0.5f * w0 * (v00 * rr0 + v10 * rr1);
    float o1 = 0.5f * w1 * (v01 * rr0 + v11 * rr1);
    unsigned short h0, l0, h1, l1;
    bfsplit(o0, h0, l0);
    bfsplit(o1, h1, l1);
    g_combhi[(size_t)t * (DI / 2) + tid] = (unsigned)h0 | ((unsigned)h1 << 16);
    g_comblo[(size_t)t * (DI / 2) + tid] = (unsigned)l0 | ((unsigned)l1 << 16);
}

__global__ void k_final(const float* __restrict__ res,
                        const float* __restrict__ w, const float* __restrict__ bias,
                        float* __restrict__ dout) {
    int r = blockIdx.x, c = threadIdx.x;
    float v = res[(size_t)r * DM + c] + g_O[r * DM + c];
    float mean = blockReduceSum(v) * (1.0f / DM);
    float xc = v - mean;
    float var = blockReduceSum(xc * xc) * (1.0f / DM);
    float result = xc * rsqrtf(var + 1e-5f) * w[c] + bias[c];
    g_q[r * DM + c] = result;
    if (dout) dout[r * DM + c] = result;
}

// ---------------- launcher ----------------
extern "C" void kernel_launch(void* const* d_in, const int* in_sizes, int n_in,
                              void* d_out, int out_size) {
    (void)in_sizes; (void)n_in; (void)out_size;
    const float* query = (const float*)d_in[0];
    const float* pos   = (const float*)d_in[1];
    const float* pre_w = (const float*)d_in[2];
    const float* pre_b = (const float*)d_in[3];
    const float* fin_w = (const float*)d_in[4];
    const float* fin_b = (const float*)d_in[5];

    const int GEMM_SMEM = 2 * (2 * 128 * WSTR + 2 * 64 * WSTR) * 4;
    const int SCAN3_SMEM = (6 * CQ * SR + 3 * CQ) * 4;
    const int CONV_SMEM = (67 * CTILE + CTILE * 4 + CTILE) * 4 + 68 * 4;
    cudaFuncSetAttribute(k_gemm_bf, cudaFuncAttributeMaxDynamicSharedMemorySize, GEMM_SMEM);
    cudaFuncSetAttribute(k_scan3, cudaFuncAttributeMaxDynamicSharedMemorySize, SCAN3_SMEM);
    cudaFuncSetAttribute(k_conv2, cudaFuncAttributeMaxDynamicSharedMemorySize, CONV_SMEM);

    unsigned *p_qnhi, *p_qnlo, *p_combhi, *p_comblo;
    unsigned *p_WIhi, *p_WIlo, *p_WOhi, *p_WOlo;
    float *p_Z, *p_O, *p_q;
    cudaGetSymbolAddress((void**)&p_qnhi, g_qnhi);
    cudaGetSymbolAddress((void**)&p_qnlo, g_qnlo);
    cudaGetSymbolAddress((void**)&p_combhi, g_combhi);
    cudaGetSymbolAddress((void**)&p_comblo, g_comblo);
    cudaGetSymbolAddress((void**)&p_WIhi, g_WIhi);
    cudaGetSymbolAddress((void**)&p_WIlo, g_WIlo);
    cudaGetSymbolAddress((void**)&p_WOhi, g_WOhi);
    cudaGetSymbolAddress((void**)&p_WOlo, g_WOlo);
    cudaGetSymbolAddress((void**)&p_Z, g_Z);
    cudaGetSymbolAddress((void**)&p_O, g_O);
    cudaGetSymbolAddress((void**)&p_q, g_q);

    const int WI_SZ = NPIN * (DM / 2);
    const int WO_SZ = DM * (DI / 2);

    cudaStream_t s1;
    cudaStreamCreateWithFlags(&s1, cudaStreamNonBlocking);
    cudaEvent_t evF, evJ;
    cudaEventCreateWithFlags(&evF, cudaEventDisableTiming);
    cudaEventCreateWithFlags(&evJ, cudaEventDisableTiming);

    const float* Win0  = (const float*)d_in[6];
    const float* Win1  = (const float*)d_in[14];
    const float* Wout0 = (const float*)d_in[13];
    const float* Wout1 = (const float*)d_in[21];

    cudaEventRecord(evF, 0);
    cudaStreamWaitEvent(s1, evF, 0);
    k_ln256<<<NT, 128, 0, s1>>>(query, pre_w, pre_b);
    k_splitW<<<((DM / 2) * NPIN + 255) / 256, 256, 0, s1>>>(
        Win0, DM, DP, NPIN, p_WIhi, p_WIlo);
    k_gemm_bf<<<dim3(NPIN / 64, NT / 128), 256, GEMM_SMEM, s1>>>(
        NT, DP, DM, p_qnhi, p_qnlo, p_WIhi, p_WIlo, p_Z, DP);
    cudaEventRecord(evJ, s1);

    k_splitW<<<((DM / 2) * NPIN + 255) / 256, 256>>>(
        Win1, DM, DP, NPIN, p_WIhi + WI_SZ, p_WIlo + WI_SZ);
    k_splitW<<<((DI / 2) * DM + 255) / 256, 256>>>(
        Wout0, DI, DM, DM, p_WOhi, p_WOlo);
    k_splitW<<<((DI / 2) * DM + 255) / 256, 256>>>(
        Wout1, DI, DM, DM, p_WOhi + WO_SZ, p_WOlo + WO_SZ);
    k_minmax<<<1, 256>>>(pos);
    k_keys<<<(NT + 255) / 256, 256>>>(pos);
    k_sort_init<<<dim3(NT / SEG, 2), 128>>>();
    for (int k = 2 * SEG; k <= NT; k <<= 1) {
        for (int j = k >> 1; j >= SEG; j >>= 1)
            k_sort_gpass<<<dim3(NT / 2 / 256, 2), 256>>>(k, j);
        k_sort_local<<<dim3(NT / SEG, 2), 128>>>(k);
    }
    k_order<<<(2 * NT + 255) / 256, 256>>>();

    cudaStreamWaitEvent(0, evJ, 0);

    for (int L = 0; L < 2; L++) {
        const float* cw   = (const float*)d_in[7 + 8 * L];
        const float* cb   = (const float*)d_in[8 + 8 * L];
        const float* dtb  = (const float*)d_in[9 + 8 * L];
        const float* alog = (const float*)d_in[10 + 8 * L];
        const float* Dv   = (const float*)d_in[11 + 8 * L];
        const float* nw   = (const float*)d_in[12 + 8 * L];
        const float* src  = (L == 0) ? query : p_q;

        if (L == 1) {
            k_ln256<<<NT, 128>>>(src, pre_w, pre_b);
            k_gemm_bf<<<dim3(NPIN / 64, NT / 128), 256, GEMM_SMEM>>>(
                NT, DP, DM, p_qnhi, p_qnlo, p_WIhi + WI_SZ, p_WIlo + WI_SZ, p_Z, DP);
        }
        k_conv2<<<dim3(NT / 64, CD / CTILE, 2), 256, CONV_SMEM>>>(cw, cb, dtb, alog);
        k_scan1<<<dim3(NCH, 2), 256>>>();
        k_scan2<<<256, 256>>>();
        k_scan3<<<dim3(NCH, 2), 256, SCAN3_SMEM>>>(Dv);
        k_pncomb<<<NT, 256>>>(nw);
        k_gemm_bf<<<dim3(DM / 64, NT / 128), 256, GEMM_SMEM>>>(
            NT, DM, DI, p_combhi, p_comblo,
            p_WOhi + (size_t)L * WO_SZ, p_WOlo + (size_t)L * WO_SZ, p_O, DM);
        k_final<<<NT, 256>>>(src, fin_w, fin_b, (L == 1) ? (float*)d_out : nullptr);
    }
}

// round 16
// speedup vs baseline: 1.6823x; 1.0094x over previous
#include <cuda_runtime.h>
#include <cuda_bf16.h>
#include <math.h>

#define NT 16384
#define DM 256
#define DI 512
#define DS 64
#define NH 8
#define HD 64
#define CD 640      // CONV_DIM
#define DP 1160     // D_PROJ
#define KER 4
#define NCH 256     // number of chunks
#define CQ 64       // chunk length
#define SR 68       // padded row stride for 64-col smem tiles
#define NPIN 1216   // padded N for in_proj (19*64)
#define WSTR 20     // GEMM smem row stride in uints
#define CTILE 160   // conv col chunk
#define SEG 2048    // sort segment

// ---------------- device scratch ----------------
__device__ float g_q[NT * DM];
__device__ unsigned g_qnhi[NT * (DM / 2)];
__device__ unsigned g_qnlo[NT * (DM / 2)];
__device__ float g_Z[NT * DP];
__device__ float g_XBC[2 * NT * CD];
__device__ float g_dt[2 * NT * NH];
__device__ float g_a[2 * NT * NH];
__device__ float g_cum[2 * NH * NCH * CQ];
__device__ float g_cdec[2 * NH * NCH];
__device__ float g_S[2 * NH * NCH * HD * DS];
__device__ float g_Hp[2 * NH * NCH * HD * DS];
__device__ float g_Y[2 * NT * DI];
__device__ unsigned g_combhi[NT * (DI / 2)];
__device__ unsigned g_comblo[NT * (DI / 2)];
__device__ float g_O[NT * DM];
__device__ unsigned g_WIhi[2 * NPIN * (DM / 2)];
__device__ unsigned g_WIlo[2 * NPIN * (DM / 2)];
__device__ unsigned g_WOhi[2 * DM * (DI / 2)];
__device__ unsigned g_WOlo[2 * DM * (DI / 2)];
__device__ unsigned long long g_keys[2 * NT];
__device__ int g_order[2 * NT];
__device__ int g_inv[2 * NT];
__device__ float g_pmin[3], g_pmax[3];

extern __shared__ float dynsmem[];

// ---------------- helpers ----------------
__device__ __forceinline__ float blockReduceSum(float v) {
    __shared__ float sh[32];
    __shared__ float tot;
    int lane = threadIdx.x & 31, wid = threadIdx.x >> 5;
    #pragma unroll
    for (int o = 16; o > 0; o >>= 1) v += __shfl_xor_sync(0xffffffffu, v, o);
    if (lane == 0) sh[wid] = v;
    __syncthreads();
    int nw = blockDim.x >> 5;
    v = (threadIdx.x < nw) ? sh[threadIdx.x] : 0.0f;
    if (wid == 0) {
        #pragma unroll
        for (int o = 16; o > 0; o >>= 1) v += __shfl_xor_sync(0xffffffffu, v, o);
        if (lane == 0) tot = v;
    }
    __syncthreads();
    return tot;
}

__device__ __forceinline__ float2 blockReduceSum2(float a, float b) {
    __shared__ float sha[32], shb[32];
    __shared__ float2 tot;
    int lane = threadIdx.x & 31, wid = threadIdx.x >> 5;
    #pragma unroll
    for (int o = 16; o > 0; o >>= 1) {
        a += __shfl_xor_sync(0xffffffffu, a, o);
        b += __shfl_xor_sync(0xffffffffu, b, o);
    }
    if (lane == 0) { sha[wid] = a; shb[wid] = b; }
    __syncthreads();
    int nw = blockDim.x >> 5;
    a = (threadIdx.x < nw) ? sha[threadIdx.x] : 0.0f;
    b = (threadIdx.x < nw) ? shb[threadIdx.x] : 0.0f;
    if (wid == 0) {
        #pragma unroll
        for (int o = 16; o > 0; o >>= 1) {
            a += __shfl_xor_sync(0xffffffffu, a, o);
            b += __shfl_xor_sync(0xffffffffu, b, o);
        }
        if (lane == 0) tot = make_float2(a, b);
    }
    __syncthreads();
    return tot;
}

__device__ __forceinline__ float warpReduceSum(float v) {
    #pragma unroll
    for (int o = 16; o > 0; o >>= 1) v += __shfl_xor_sync(0xffffffffu, v, o);
    return v;
}

__device__ __forceinline__ unsigned hilbert3(unsigned a0, unsigned a1, unsigned a2) {
    unsigned x0 = a0, x1 = a1, x2 = a2;
    const unsigned M = 1u << 9;
    for (unsigned Q = M; Q > 1; Q >>= 1) {
        unsigned P = Q - 1;
        if (x0 & Q) x0 ^= P;
        {
            unsigned t = (x0 ^ x1) & P;
            if (x1 & Q) { x0 ^= P; } else { x0 ^= t; x1 ^= t; }
        }
        {
            unsigned t = (x0 ^ x2) & P;
            if (x2 & Q) { x0 ^= P; } else { x0 ^= t; x2 ^= t; }
        }
    }
    x1 ^= x0;
    x2 ^= x1;
    unsigned t = 0;
    for (unsigned Q = M; Q > 1; Q >>= 1)
        if (x2 & Q) t ^= (Q - 1);
    x0 ^= t; x1 ^= t; x2 ^= t;
    unsigned code = 0;
    for (int b = 9; b >= 0; b--) {
        code = (code << 1) | ((x0 >> b) & 1);
        code = (code << 1) | ((x1 >> b) & 1);
        code = (code << 1) | ((x2 >> b) & 1);
    }
    return code;
}

__device__ __forceinline__ void bfsplit(float x, unsigned short& hi, unsigned short& lo) {
    __nv_bfloat16 h = __float2bfloat16(x);
    __nv_bfloat16 l = __float2bfloat16(x - __bfloat162float(h));
    hi = *(unsigned short*)&h;
    lo = *(unsigned short*)&l;
}

__device__ __forceinline__ void mma_bf16(float c[4], const unsigned a[4],
                                         unsigned b0, unsigned b1) {
    asm volatile("mma.sync.aligned.m16n8k16.row.col.f32.bf16.bf16.f32 "
        "{%0,%1,%2,%3}, {%4,%5,%6,%7}, {%8,%9}, {%0,%1,%2,%3};"
        : "+f"(c[0]), "+f"(c[1]), "+f"(c[2]), "+f"(c[3])
        : "r"(a[0]), "r"(a[1]), "r"(a[2]), "r"(a[3]), "r"(b0), "r"(b1));
}

__device__ __forceinline__ void cp16(unsigned dst, const void* src) {
    asm volatile("cp.async.cg.shared.global [%0], [%1], 16;" :: "r"(dst), "l"(src));
}

// ---- packed f32x2 FMA ----
__device__ __forceinline__ void fma2(unsigned long long& c, unsigned long long a,
                                     unsigned long long b) {
    asm("fma.rn.f32x2 %0, %1, %2, %0;" : "+l"(c) : "l"(a), "l"(b));
}
__device__ __forceinline__ unsigned long long bcast2(float x) {
    unsigned long long r;
    unsigned u = __float_as_uint(x);
    asm("mov.b64 %0, {%1, %2};" : "=l"(r) : "r"(u), "r"(u));
    return r;
}
__device__ __forceinline__ unsigned long long packf2(float a, float b) {
    unsigned long long r;
    asm("mov.b64 %0, {%1, %2};" : "=l"(r) : "r"(__float_as_uint(a)), "r"(__float_as_uint(b)));
    return r;
}
__device__ __forceinline__ float2 unpack2(unsigned long long v) {
    unsigned lo, hi;
    asm("mov.b64 {%0, %1}, %2;" : "=r"(lo), "=r"(hi) : "l"(v));
    return make_float2(__uint_as_float(lo), __uint_as_float(hi));
}

// ---------------- setup kernels ----------------
__global__ void k_minmax(const float* __restrict__ pos) {
    __shared__ float smn[256][3], smx[256][3];
    float mn[3] = {1e30f, 1e30f, 1e30f}, mx[3] = {-1e30f, -1e30f, -1e30f};
    for (int r = threadIdx.x; r < NT; r += 256) {
        #pragma unroll
        for (int j = 0; j < 3; j++) {
            float v = pos[r * 3 + j];
            mn[j] = fminf(mn[j], v);
            mx[j] = fmaxf(mx[j], v);
        }
    }
    #pragma unroll
    for (int j = 0; j < 3; j++) { smn[threadIdx.x][j] = mn[j]; smx[threadIdx.x][j] = mx[j]; }
    __syncthreads();
    for (int s = 128; s > 0; s >>= 1) {
        if (threadIdx.x < s) {
            #pragma unroll
            for (int j = 0; j < 3; j++) {
                smn[threadIdx.x][j] = fminf(smn[threadIdx.x][j], smn[threadIdx.x + s][j]);
                smx[threadIdx.x][j] = fmaxf(smx[threadIdx.x][j], smx[threadIdx.x + s][j]);
            }
        }
        __syncthreads();
    }
    if (threadIdx.x == 0) {
        #pragma unroll
        for (int j = 0; j < 3; j++) { g_pmin[j] = smn[0][j]; g_pmax[j] = smx[0][j]; }
    }
}

__global__ void k_keys(const float* __restrict__ pos) {
    int idx = blockIdx.x * blockDim.x + threadIdx.x;
    if (idx >= NT) return;
    unsigned g[3];
    #pragma unroll
    for (int j = 0; j < 3; j++) {
        float denom = g_pmax[j] - g_pmin[j] + 1e-6f;
        float v = ((pos[idx * 3 + j] - g_pmin[j]) / denom) * 1023.0f;
        v = fminf(fmaxf(v, 0.0f), 1023.0f);
        g[j] = (unsigned)(int)v;
    }
    unsigned c0 = hilbert3(g[0], g[1], g[2]);
    unsigned c1 = hilbert3(g[1], g[0], g[2]);
    g_keys[idx]      = (((unsigned long long)c0) << 14) | (unsigned long long)idx;
    g_keys[NT + idx] = (((unsigned long long)c1) << 14) | (unsigned long long)idx;
}

#define SADDR(i) ((i) + ((i) >> 4))

__global__ void k_sort_init() {
    __shared__ unsigned long long s[SEG + SEG / 16];
    int seg = blockIdx.x, b = blockIdx.y;
    unsigned long long* keys = g_keys + b * NT + seg * SEG;
    bool upg = ((seg & 1) == 0);
    int t = threadIdx.x;  // 128 threads
    for (int i = t; i < SEG; i += 128) s[SADDR(i)] = keys[i];
    __syncthreads();

    int base = t * 16;
    unsigned long long v[16];
    #pragma unroll
    for (int r = 0; r < 16; r++) v[r] = s[SADDR(base + r)];
    #pragma unroll
    for (int k = 2; k <= 16; k <<= 1) {
        #pragma unroll
        for (int j = k >> 1; j > 0; j >>= 1) {
            #pragma unroll
            for (int r = 0; r < 16; r++) {
                int rr = r ^ j;
                if (rr > r) {
                    bool up = ((((base + r) & k) == 0) == upg);
                    unsigned long long a = v[r], c = v[rr];
                    if ((a > c) == up) { v[r] = c; v[rr] = a; }
                }
            }
        }
    }
    #pragma unroll
    for (int r = 0; r < 16; r++) s[SADDR(base + r)] = v[r];
    __syncthreads();

    for (int k = 32; k <= SEG; k <<= 1) {
        for (int j = k >> 1; j >= 16; j >>= 1) {
            for (int i = t; i < SEG; i += 128) {
                int ixj = i ^ j;
                if (ixj > i) {
                    unsigned long long a = s[SADDR(i)], c = s[SADDR(ixj)];
                    bool up = (((i & k) == 0) == upg);
                    if ((a > c) == up) { s[SADDR(i)] = c; s[SADDR(ixj)] = a; }
                }
            }
            __syncthreads();
        }
        #pragma unroll
        for (int r = 0; r < 16; r++) v[r] = s[SADDR(base + r)];
        bool up = (((base & k) == 0) == upg);
        #pragma unroll
        for (int j = 8; j > 0; j >>= 1) {
            #pragma unroll
            for (int r = 0; r < 16; r++) {
                int rr = r ^ j;
                if (rr > r) {
                    unsigned long long a = v[r], c = v[rr];
                    if ((a > c) == up) { v[r] = c; v[rr] = a; }
                }
            }
        }
        #pragma unroll
        for (int r = 0; r < 16; r++) s[SADDR(base + r)] = v[r];
        __syncthreads();
    }
    for (int i = t; i < SEG; i += 128) keys[i] = s[SADDR(i)];
}

__global__ void k_sort_gpass(int k, int j) {
    int p = blockIdx.x * blockDim.x + threadIdx.x;
    int b = blockIdx.y;
    int low = p & (j - 1);
    int i = ((p & ~(j - 1)) << 1) | low;
    unsigned long long* keys = g_keys + b * NT;
    unsigned long long a = keys[i], c = keys[i + j];
    bool up = ((i & k) == 0);
    if ((a > c) == up) { keys[i] = c; keys[i + j] = a; }
}

__global__ void k_sort_local(int k) {
    __shared__ unsigned long long s[SEG + SEG / 16];
    int seg = blockIdx.x, b = blockIdx.y;
    unsigned long long* keys = g_keys + b * NT + seg * SEG;
    bool up = (((seg * SEG) & k) == 0);
    int t = threadIdx.x;
    for (int i = t; i < SEG; i += 128) s[SADDR(i)] = keys[i];
    __syncthreads();
    for (int j = SEG / 2; j >= 16; j >>= 1) {
        for (int i = t; i < SEG; i += 128) {
            int ixj = i ^ j;
            if (ixj > i) {
                unsigned long long a = s[SADDR(i)], c = s[SADDR(ixj)];
                if ((a > c) == up) { s[SADDR(i)] = c; s[SADDR(ixj)] = a; }
            }
        }
        __syncthreads();
    }
    int base = t * 16;
    unsigned long long v[16];
    #pragma unroll
    for (int r = 0; r < 16; r++) v[r] = s[SADDR(base + r)];
    #pragma unroll
    for (int j = 8; j > 0; j >>= 1) {
        #pragma unroll
        for (int r = 0; r < 16; r++) {
            int rr = r ^ j;
            if (rr > r) {
                unsigned long long a = v[r], c = v[rr];
                if ((a > c) == up) { v[r] = c; v[rr] = a; }
            }
        }
    }
    #pragma unroll
    for (int r = 0; r < 16; r++) s[SADDR(base + r)] = v[r];
    __syncthreads();
    for (int i = t; i < SEG; i += 128) keys[i] = s[SADDR(i)];
}

__global__ void k_order() {
    int i = blockIdx.x * blockDim.x + threadIdx.x;
    if (i >= 2 * NT) return;
    int b = i / NT;
    int idx = (int)(g_keys[i] & 0x3FFFULL);
    g_order[i] = idx;
    g_inv[b * NT + idx] = i - b * NT;
}

// standalone LN (L0 prologue only)
__global__ void k_ln256(const float* __restrict__ src,
                        const float* __restrict__ w, const float* __restrict__ bias) {
    int r = blockIdx.x, t = threadIdx.x;
    float2 v = *(const float2*)(src + (size_t)r * DM + 2 * t);
    float mean = blockReduceSum(v.x + v.y) * (1.0f / DM);
    float x0 = v.x - mean, x1 = v.y - mean;
    float var = blockReduceSum(x0 * x0 + x1 * x1) * (1.0f / DM);
    float rs = rsqrtf(var + 1e-5f);
    float r0 = x0 * rs * w[2 * t] + bias[2 * t];
    float r1 = x1 * rs * w[2 * t + 1] + bias[2 * t + 1];
    unsigned short h0, l0, h1, l1;
    bfsplit(r0, h0, l0);
    bfsplit(r1, h1, l1);
    g_qnhi[r * (DM / 2) + t] = (unsigned)h0 | ((unsigned)h1 << 16);
    g_qnlo[r * (DM / 2) + t] = (unsigned)l0 | ((unsigned)l1 << 16);
}

// fused: residual + final-LN -> g_q (+dout), then pre-LN -> packed qn (if emitqn)
// warp per row: 8 rows/block, 8 cols per lane, shfl-only reduces
__global__ __launch_bounds__(256) void k_fln(const float* __restrict__ res,
        const float* __restrict__ w, const float* __restrict__ bias,
        const float* __restrict__ pw, const float* __restrict__ pb,
        float* __restrict__ dout, int emitqn) {
    int wid = threadIdx.x >> 5, lane = threadIdx.x & 31;
    int r = blockIdx.x * 8 + wid;
    int c0 = lane * 8;
    float v[8];
    {
        float4 a0 = *(const float4*)(res + (size_t)r * DM + c0);
        float4 a1 = *(const float4*)(res + (size_t)r * DM + c0 + 4);
        float4 b0 = *(const float4*)(g_O + (size_t)r * DM + c0);
        float4 b1 = *(const float4*)(g_O + (size_t)r * DM + c0 + 4);
        v[0] = a0.x + b0.x; v[1] = a0.y + b0.y; v[2] = a0.z + b0.z; v[3] = a0.w + b0.w;
        v[4] = a1.x + b1.x; v[5] = a1.y + b1.y; v[6] = a1.z + b1.z; v[7] = a1.w + b1.w;
    }
    float s = 0.0f;
    #pragma unroll
    for (int i = 0; i < 8; i++) s += v[i];
    float mean = warpReduceSum(s) * (1.0f / DM);
    float sq = 0.0f;
    #pragma unroll
    for (int i = 0; i < 8; i++) { v[i] -= mean; sq += v[i] * v[i]; }
    float rs = rsqrtf(warpReduceSum(sq) * (1.0f / DM) + 1e-5f);
    float resu[8];
    #pragma unroll
    for (int i = 0; i < 8; i++) resu[i] = v[i] * rs * w[c0 + i] + bias[c0 + i];
    #pragma unroll
    for (int i = 0; i < 8; i += 4)
        *(float4*)(g_q + (size_t)r * DM + c0 + i) =
            make_float4(resu[i], resu[i + 1], resu[i + 2], resu[i + 3]);
    if (dout) {
        #pragma unroll
        for (int i = 0; i < 8; i += 4)
            *(float4*)(dout + (size_t)r * DM + c0 + i) =
                make_float4(resu[i], resu[i + 1], resu[i + 2], resu[i + 3]);
    }
    if (emitqn) {
        float s2 = 0.0f;
        #pragma unroll
        for (int i = 0; i < 8; i++) s2 += resu[i];
        float mean2 = warpReduceSum(s2) * (1.0f / DM);
        float sq2 = 0.0f;
        float x2[8];
        #pragma unroll
        for (int i = 0; i < 8; i++) { x2[i] = resu[i] - mean2; sq2 += x2[i] * x2[i]; }
        float rs2 = rsqrtf(warpReduceSum(sq2) * (1.0f / DM) + 1e-5f);
        #pragma unroll
        for (int i = 0; i < 8; i += 2) {
            float q0 = x2[i] * rs2 * pw[c0 + i] + pb[c0 + i];
            float q1 = x2[i + 1] * rs2 * pw[c0 + i + 1] + pb[c0 + i + 1];
            unsigned short h0, l0, h1, l1;
            bfsplit(q0, h0, l0);
            bfsplit(q1, h1, l1);
            g_qnhi[r * (DM / 2) + (c0 + i) / 2] = (unsigned)h0 | ((unsigned)h1 << 16);
            g_qnlo[r * (DM / 2) + (c0 + i) / 2] = (unsigned)l0 | ((unsigned)l1 << 16);
        }
    }
}

__global__ void k_splitW(const float* __restrict__ src, int K, int N, int NP,
                         unsigned* __restrict__ Whi, unsigned* __restrict__ Wlo) {
    int idx = blockIdx.x * blockDim.x + threadIdx.x;
    if (idx >= (K / 2) * NP) return;
    int kp = idx / NP, n = idx - kp * NP;
    float w0 = (n < N) ? src[(size_t)(2 * kp) * N + n] : 0.0f;
    float w1 = (n < N) ? src[(size_t)(2 * kp + 1) * N + n] : 0.0f;
    unsigned short h0, l0, h1, l1;
    bfsplit(w0, h0, l0);
    bfsplit(w1, h1, l1);
    Whi[(size_t)n * (K / 2) + kp] = (unsigned)h0 | ((unsigned)h1 << 16);
    Wlo[(size_t)n * (K / 2) + kp] = (unsigned)l0 | ((unsigned)l1 << 16);
}

// ---------------- bf16x3 tensor-core GEMM ----------------
__device__ __forceinline__ void gemm_load_bf(
    const unsigned* __restrict__ Ahi, const unsigned* __restrict__ Alo, int K2,
    const unsigned* __restrict__ Bhi, const unsigned* __restrict__ Blo,
    int m0, int n0, int kt, unsigned* sAh, unsigned* sAl,
    unsigned* sBh, unsigned* sBl, int tid) {
    int kp0 = kt * 16;
    int r = tid >> 1, cu = (tid & 1) * 8;
    const unsigned* pah = Ahi + (size_t)(m0 + r) * K2 + kp0 + cu;
    const unsigned* pal = Alo + (size_t)(m0 + r) * K2 + kp0 + cu;
    unsigned dah = (unsigned)__cvta_generic_to_shared(sAh + r * WSTR + cu);
    unsigned dal = (unsigned)__cvta_generic_to_shared(sAl + r * WSTR + cu);
    cp16(dah, pah); cp16(dah + 16, pah + 4);
    cp16(dal, pal); cp16(dal + 16, pal + 4);
    int n = tid >> 2, cb = (tid & 3) * 4;
    cp16((unsigned)__cvta_generic_to_shared(sBh + n * WSTR + cb),
         Bhi + (size_t)(n0 + n) * K2 + kp0 + cb);
    cp16((unsigned)__cvta_generic_to_shared(sBl + n * WSTR + cb),
         Blo + (size_t)(n0 + n) * K2 + kp0 + cb);
}

__global__ __launch_bounds__(256) void k_gemm_bf(int M, int N, int K,
        const unsigned* __restrict__ Ahi, const unsigned* __restrict__ Alo,
        const unsigned* __restrict__ Bhi, const unsigned* __restrict__ Blo,
        float* __restrict__ C, int ldc) {
    unsigned* sm = (unsigned*)dynsmem;
    const int ASZ = 128 * WSTR, BSZ = 64 * WSTR;
    const int STG = 2 * ASZ + 2 * BSZ;

    int m0 = blockIdx.y * 128, n0 = blockIdx.x * 64;
    int tid = threadIdx.x;
    int wid = tid >> 5, lane = tid & 31;
    int wm = (wid & 3) * 32, wn = (wid >> 2) * 32;
    int g = lane >> 2, tg = lane & 3;
    int K2 = K >> 1;
    int KT = K / 32;

    float acc[2][4][4];
    #pragma unroll
    for (int a = 0; a < 2; a++)
        #pragma unroll
        for (int b = 0; b < 4; b++)
            #pragma unroll
            for (int c = 0; c < 4; c++) acc[a][b][c] = 0.0f;

    gemm_load_bf(Ahi, Alo, K2, Bhi, Blo, m0, n0, 0,
                 sm, sm + ASZ, sm + 2 * ASZ, sm + 2 * ASZ + BSZ, tid);
    asm volatile("cp.async.commit_group;");

    for (int kt = 0; kt < KT; kt++) {
        int st = kt & 1;
        if (kt + 1 < KT) {
            int ns = st ^ 1;
            unsigned* b0 = sm + ns * STG;
            gemm_load_bf(Ahi, Alo, K2, Bhi, Blo, m0, n0, kt + 1,
                         b0, b0 + ASZ, b0 + 2 * ASZ, b0 + 2 * ASZ + BSZ, tid);
            asm volatile("cp.async.commit_group;");
            asm volatile("cp.async.wait_group 1;");
        } else {
            asm volatile("cp.async.wait_group 0;");
        }
        __syncthreads();
        unsigned* sAhi = sm + st * STG;
        unsigned* sAlo = sAhi + ASZ;
        unsigned* sBhi = sAhi + 2 * ASZ;
        unsigned* sBlo = sBhi + BSZ;
        #pragma unroll
        for (int kk2 = 0; kk2 < 16; kk2 += 8) {
            unsigned ahi[2][4], alo[2][4], bhi[4][2], blo[4][2];
            #pragma unroll
            for (int mi = 0; mi < 2; mi++) {
                int ra = (wm + mi * 16 + g) * WSTR;
                int rb = (wm + mi * 16 + g + 8) * WSTR;
                ahi[mi][0] = sAhi[ra + kk2 + tg];
                ahi[mi][1] = sAhi[rb + kk2 + tg];
                ahi[mi][2] = sAhi[ra + kk2 + 4 + tg];
                ahi[mi][3] = sAhi[rb + kk2 + 4 + tg];
                alo[mi][0] = sAlo[ra + kk2 + tg];
                alo[mi][1] = sAlo[rb + kk2 + tg];
                alo[mi][2] = sAlo[ra + kk2 + 4 + tg];
                alo[mi][3] = sAlo[rb + kk2 + 4 + tg];
            }
            #pragma unroll
            for (int nj = 0; nj < 4; nj++) {
                int rn = (wn + nj * 8 + g) * WSTR;
                bhi[nj][0] = sBhi[rn + kk2 + tg];
                bhi[nj][1] = sBhi[rn + kk2 + 4 + tg];
                blo[nj][0] = sBlo[rn + kk2 + tg];
                blo[nj][1] = sBlo[rn + kk2 + 4 + tg];
            }
            #pragma unroll
            for (int mi = 0; mi < 2; mi++)
                #pragma unroll
                for (int nj = 0; nj < 4; nj++) {
                    mma_bf16(acc[mi][nj], ahi[mi], bhi[nj][0], bhi[nj][1]);
                    mma_bf16(acc[mi][nj], ahi[mi], blo[nj][0], blo[nj][1]);
                    mma_bf16(acc[mi][nj], alo[mi], bhi[nj][0], bhi[nj][1]);
                }
        }
        __syncthreads();
    }
    #pragma unroll
    for (int mi = 0; mi < 2; mi++)
        #pragma unroll
        for (int nj = 0; nj < 4; nj++) {
            int row = m0 + wm + mi * 16 + g;
            int col = n0 + wn + nj * 8 + tg * 2;
            if (col + 1 < N) {
                *(float2*)(C + (size_t)row * ldc + col) =
                    make_float2(acc[mi][nj][0], acc[mi][nj][1]);
                *(float2*)(C + (size_t)(row + 8) * ldc + col) =
                    make_float2(acc[mi][nj][2], acc[mi][nj][3]);
            } else if (col < N) {
                C[(size_t)row * ldc + col] = acc[mi][nj][0];
                C[(size_t)(row + 8) * ldc + col] = acc[mi][nj][2];
            }
        }
}

// ---------------- tiled conv (+ fused dt on y==0 blocks) ----------------
__global__ __launch_bounds__(256) void k_conv2(const float* __restrict__ cw,
                                               const float* __restrict__ cb,
                                               const float* __restrict__ dtb,
                                               const float* __restrict__ alog) {
    float* sZ  = dynsmem;
    float* scw = sZ + 67 * CTILE;
    float* scb = scw + CTILE * 4;
    int*   stok = (int*)(scb + CTILE);
    int r0 = blockIdx.x * 64, cc = blockIdx.y * CTILE, b = blockIdx.z;
    int tid = threadIdx.x;
    if (tid < 67) {
        int rr = r0 - 3 + tid;
        stok[tid] = (rr >= 0) ? g_order[b * NT + rr] : -1;
    }
    for (int idx = tid; idx < CTILE * 4; idx += 256)
        scw[idx] = cw[(cc + (idx >> 2)) * KER + (idx & 3)];
    for (int idx = tid; idx < CTILE; idx += 256)
        scb[idx] = cb[cc + idx];
    __syncthreads();
    for (int idx = tid; idx < 67 * CTILE; idx += 256) {
        int row = idx / CTILE, col = idx - row * CTILE;
        int t = stok[row];
        sZ[idx] = (t >= 0) ? g_Z[(size_t)t * DP + DI + cc + col] : 0.0f;
    }
    if (blockIdx.y == 0) {
        for (int idx = tid; idx < 64 * NH; idx += 256) {
            int row = idx >> 3, h = idx & 7;
            int t = stok[row + 3];
            float x = g_Z[(size_t)t * DP + DI + CD + h] + dtb[h];
            float sp = fmaxf(x, 0.0f) + log1pf(expf(-fabsf(x)));
            float A = -expf(alog[h]);
            int gi = (b * NT + r0 + row) * NH + h;
            g_dt[gi] = sp;
            g_a[gi] = sp * A;
        }
    }
    __syncthreads();
    for (int idx = tid; idx < 64 * CTILE; idx += 256) {
        int row = idx / CTILE, col = idx - row * CTILE;
        float acc = scb[col];
        #pragma unroll
        for (int k = 0; k < KER; k++)
            acc += scw[col * 4 + k] * sZ[(row + k) * CTILE + col];
        float s = acc / (1.0f + __expf(-acc));
        g_XBC[(size_t)(b * NT + r0 + row) * CD + cc + col] = s;
    }
}

// ---------------- chunked scan ----------------
__global__ __launch_bounds__(256) void k_scan1() {
    int c = blockIdx.x, b = blockIdx.y;
    __shared__ float sX[CQ * SR], sB[CQ * SR];
    __shared__ float scum[CQ], sw[CQ];
    int r0 = c * CQ, tid = threadIdx.x;
    for (int idx = tid; idx < CQ * 64; idx += 256) {
        int j = idx >> 6, p = idx & 63;
        sB[j * SR + p] = g_XBC[(size_t)(b * NT + r0 + j) * CD + DI + p];
    }
    int p0 = (tid & 15) * 4, s0 = (tid >> 4) * 4;
    for (int h = 0; h < NH; h++) {
        __syncthreads();
        for (int idx = tid; idx < CQ * 64; idx += 256) {
            int j = idx >> 6, p = idx & 63;
            sX[j * SR + p] = g_XBC[(size_t)(b * NT + r0 + j) * CD + h * HD + p];
        }
        if (tid < CQ) scum[tid] = g_a[(size_t)(b * NT + r0 + tid) * NH + h];
        __syncthreads();
        if (tid < CQ) {
            float x = scum[tid];
            #pragma unroll
            for (int o = 1; o < 32; o <<= 1) {
                float y = __shfl_up_sync(0xffffffffu, x, o);
                if ((tid & 31) >= o) x += y;
            }
            scum[tid] = x;
        }
        __syncthreads();
        if (tid >= 32 && tid < CQ) scum[tid] += scum[31];
        __syncthreads();
        float slast = scum[CQ - 1];
        if (tid < CQ) {
            sw[tid] = __expf(slast - scum[tid]) * g_dt[(size_t)(b * NT + r0 + tid) * NH + h];
            g_cum[((b * NH + h) * NCH + c) * CQ + tid] = scum[tid];
        }
        if (tid == 0) g_cdec[(b * NH + h) * NCH + c] = __expf(slast);
        __syncthreads();
        unsigned long long acc2[4][2] = {};
        for (int j = 0; j < CQ; j++) {
            float4 xv = *(float4*)&sX[j * SR + p0];
            ulonglong2 b2 = *(const ulonglong2*)&sB[j * SR + s0];
            float w = sw[j];
            float wx[4] = {xv.x * w, xv.y * w, xv.z * w, xv.w * w};
            #pragma unroll
            for (int pi = 0; pi < 4; pi++) {
                unsigned long long w2 = bcast2(wx[pi]);
                fma2(acc2[pi][0], w2, b2.x);
                fma2(acc2[pi][1], w2, b2.y);
            }
        }
        size_t base = ((size_t)((b * NH + h) * NCH + c) * HD) * DS;
        #pragma unroll
        for (int pi = 0; pi < 4; pi++) {
            float2 a01 = unpack2(acc2[pi][0]);
            float2 a23 = unpack2(acc2[pi][1]);
            *(float4*)&g_S[base + (size_t)(p0 + pi) * DS + s0] =
                make_float4(a01.x, a01.y, a23.x, a23.y);
        }
    }
}

__global__ void k_scan2() {
    __shared__ float scd[NCH];
    int bh = blockIdx.x >> 4;
    int e = ((blockIdx.x & 15) << 8) + threadIdx.x;
    if (threadIdx.x < NCH) scd[threadIdx.x] = g_cdec[bh * NCH + threadIdx.x];
    __syncthreads();
    float H = 0.0f;
    for (int c = 0; c < NCH; c++) {
        size_t off = ((size_t)(bh * NCH + c)) * (HD * DS) + e;
        float s = g_S[off];
        g_Hp[off] = H;
        H = scd[c] * H + s;
    }
}

__global__ __launch_bounds__(256) void k_scan3(const float* __restrict__ Dv) {
    int c = blockIdx.x, b = blockIdx.y;
    int r0 = c * CQ, tid = threadIdx.x;
    float* sB  = dynsmem;
    float* sC  = sB  + CQ * SR;
    float* sD0 = sC  + CQ * SR;
    float* sX  = sD0 + CQ * SR;
    float* sH  = sX  + CQ * SR;
    float* sG  = sH  + CQ * SR;
    float* scum = sG + CQ * SR;
    float* sdt  = scum + CQ;
    float* seY  = sdt + CQ;

    for (int idx = tid; idx < CQ * 64; idx += 256) {
        int j = idx >> 6, s = idx & 63;
        sB[j * SR + s] = g_XBC[(size_t)(b * NT + r0 + j) * CD + DI + s];
        sC[j * SR + s] = g_XBC[(size_t)(b * NT + r0 + j) * CD + DI + DS + s];
    }
    __syncthreads();
    int i0 = (tid >> 4) * 4, j0 = (tid & 15) * 4;
    if (j0 <= i0) {
        unsigned long long acc2[4][4] = {};
        for (int sc = 0; sc < 64; sc += 4) {
            ulonglong2 Cr[4], Br[4];
            #pragma unroll
            for (int r = 0; r < 4; r++) Cr[r] = *(const ulonglong2*)&sC[(i0 + r) * SR + sc];
            #pragma unroll
            for (int q = 0; q < 4; q++) Br[q] = *(const ulonglong2*)&sB[(j0 + q) * SR + sc];
            #pragma unroll
            for (int r = 0; r < 4; r++)
                #pragma unroll
                for (int q = 0; q < 4; q++) {
                    fma2(acc2[r][q], Cr[r].x, Br[q].x);
                    fma2(acc2[r][q], Cr[r].y, Br[q].y);
                }
        }
        #pragma unroll
        for (int r = 0; r < 4; r++) {
            float dv[4];
            #pragma unroll
            for (int q = 0; q < 4; q++) {
                float2 p = unpack2(acc2[r][q]);
                dv[q] = p.x + p.y;
            }
            *(float4*)&sD0[(i0 + r) * SR + j0] = make_float4(dv[0], dv[1], dv[2], dv[3]);
        }
    } else {
        #pragma unroll
        for (int r = 0; r < 4; r++)
            *(float4*)&sD0[(i0 + r) * SR + j0] = make_float4(0.f, 0.f, 0.f, 0.f);
    }
    __syncthreads();

    for (int h = 0; h < NH; h++) {
        for (int idx = tid; idx < CQ * 64; idx += 256) {
            int j = idx >> 6, p = idx & 63;
            sX[j * SR + p] = g_XBC[(size_t)(b * NT + r0 + j) * CD + h * HD + p];
            sH[j * SR + p] = g_Hp[((size_t)((b * NH + h) * NCH + c) * HD) * DS + idx];
        }
        if (tid < CQ) {
            float cu = g_cum[((b * NH + h) * NCH + c) * CQ + tid];
            scum[tid] = cu;
            sdt[tid] = g_dt[(size_t)(b * NT + r0 + tid) * NH + h];
            seY[tid] = __expf(cu);
        }
        __syncthreads();
        if (j0 <= i0) {
            #pragma unroll
            for (int r = 0; r < 4; r++) {
                float4 d = *(float4*)&sD0[(i0 + r) * SR + j0];
                float dd[4] = {d.x, d.y, d.z, d.w};
                float gv[4];
                int i = i0 + r;
                float ci = scum[i];
                #pragma unroll
                for (int q = 0; q < 4; q++) {
                    int j = j0 + q;
                    gv[q] = (j <= i) ? __expf(ci - scum[j]) * sdt[j] * dd[q] : 0.0f;
                }
                *(float4*)&sG[(i0 + r) * SR + j0] = make_float4(gv[0], gv[1], gv[2], gv[3]);
            }
        } else {
            #pragma unroll
            for (int r = 0; r < 4; r++)
                *(float4*)&sG[(i0 + r) * SR + j0] = make_float4(0.f, 0.f, 0.f, 0.f);
        }
        __syncthreads();
        int p0 = j0;
        float acc[4][4];
        {
            unsigned long long acc2[4][4] = {};
            for (int sc = 0; sc < 64; sc += 4) {
                ulonglong2 Cr[4], Hc[4];
                #pragma unroll
                for (int r = 0; r < 4; r++) Cr[r] = *(const ulonglong2*)&sC[(i0 + r) * SR + sc];
                #pragma unroll
                for (int q = 0; q < 4; q++) Hc[q] = *(const ulonglong2*)&sH[(p0 + q) * SR + sc];
                #pragma unroll
                for (int r = 0; r < 4; r++)
                    #pragma unroll
                    for (int q = 0; q < 4; q++) {
                        fma2(acc2[r][q], Cr[r].x, Hc[q].x);
                        fma2(acc2[r][q], Cr[r].y, Hc[q].y);
                    }
            }
            #pragma unroll
            for (int r = 0; r < 4; r++) {
                float e = seY[i0 + r];
                #pragma unroll
                for (int q = 0; q < 4; q++) {
                    float2 p = unpack2(acc2[r][q]);
                    acc[r][q] = e * (p.x + p.y);
                }
            }
        }
        unsigned long long accq[4][2];
        #pragma unroll
        for (int r = 0; r < 4; r++) {
            accq[r][0] = packf2(acc[r][0], acc[r][1]);
            accq[r][1] = packf2(acc[r][2], acc[r][3]);
        }
        for (int jc = 0; jc <= i0; jc += 4) {
            float G4[4][4];
            #pragma unroll
            for (int r = 0; r < 4; r++) {
                float4 t = *(float4*)&sG[(i0 + r) * SR + jc];
                G4[r][0] = t.x; G4[r][1] = t.y; G4[r][2] = t.z; G4[r][3] = t.w;
            }
            #pragma unroll
            for (int q = 0; q < 4; q++) {
                ulonglong2 x2 = *(const ulonglong2*)&sX[(jc + q) * SR + p0];
                #pragma unroll
                for (int r = 0; r < 4; r++) {
                    unsigned long long g2 = bcast2(G4[r][q]);
                    fma2(accq[r][0], g2, x2.x);
                    fma2(accq[r][1], g2, x2.y);
                }
            }
        }
        unsigned long long D2 = bcast2(Dv[h]);
        #pragma unroll
        for (int r = 0; r < 4; r++) {
            ulonglong2 xi2 = *(const ulonglong2*)&sX[(i0 + r) * SR + p0];
            fma2(accq[r][0], D2, xi2.x);
            fma2(accq[r][1], D2, xi2.y);
            float2 y01 = unpack2(accq[r][0]);
            float2 y23 = unpack2(accq[r][1]);
            *(float4*)&g_Y[(size_t)(b * NT + r0 + i0 + r) * DI + h * HD + p0] =
                make_float4(y01.x, y01.y, y23.x, y23.y);
        }
        __syncthreads();
    }
}

// ---------------- fused postnorm + combine ----------------
__global__ void k_pncomb(const float* __restrict__ nw) {
    int t = blockIdx.x, tid = threadIdx.x;
    int r0 = g_inv[t], r1 = g_inv[NT + t];
    int c = 2 * tid;
    float2 y0 = *(const float2*)(g_Y + (size_t)r0 * DI + c);
    float2 y1 = *(const float2*)(g_Y + (size_t)(NT + r1) * DI + c);
    float2 gz = *(const float2*)(g_Z + (size_t)t * DP + c);
    float s0 = gz.x / (1.0f + __expf(-gz.x));
    float s1 = gz.y / (1.0f + __expf(-gz.y));
    float v00 = y0.x * s0, v01 = y0.y * s1;
    float v10 = y1.x * s0, v11 = y1.y * s1;
    float2 ss = blockReduceSum2(v00 * v00 + v01 * v01, v10 * v10 + v11 * v11);
    float rr0 = rsqrtf(ss.x * (1.0f / DI) + 1e-5f);
    float rr1 = rsqrtf(ss.y * (1.0f / DI) + 1e-5f);
    float w0 = nw[c], w1 = nw[c + 1];
    float o0 = 0.5f * w0 * (v00 * rr0 + v10 * rr1);
    float o1 = 0.5f * w1 * (v01 * rr0 + v11 * rr1);
    unsigned short h0, l0, h1, l1;
    bfsplit(o0, h0, l0);
    bfsplit(o1, h1, l1);
    g_combhi[(size_t)t * (DI / 2) + tid] = (unsigned)h0 | ((unsigned)h1 << 16);
    g_comblo[(size_t)t * (DI / 2) + tid] = (unsigned)l0 | ((unsigned)l1 << 16);
}

// ---------------- launcher ----------------
extern "C" void kernel_launch(void* const* d_in, const int* in_sizes, int n_in,
                              void* d_out, int out_size) {
    (void)in_sizes; (void)n_in; (void)out_size;
    const float* query = (const float*)d_in[0];
    const float* pos   = (const float*)d_in[1];
    const float* pre_w = (const float*)d_in[2];
    const float* pre_b = (const float*)d_in[3];
    const float* fin_w = (const float*)d_in[4];
    const float* fin_b = (const float*)d_in[5];

    const int GEMM_SMEM = 2 * (2 * 128 * WSTR + 2 * 64 * WSTR) * 4;
    const int SCAN3_SMEM = (6 * CQ * SR + 3 * CQ) * 4;
    const int CONV_SMEM = (67 * CTILE + CTILE * 4 + CTILE) * 4 + 68 * 4;
    cudaFuncSetAttribute(k_gemm_bf, cudaFuncAttributeMaxDynamicSharedMemorySize, GEMM_SMEM);
    cudaFuncSetAttribute(k_scan3, cudaFuncAttributeMaxDynamicSharedMemorySize, SCAN3_SMEM);
    cudaFuncSetAttribute(k_conv2, cudaFuncAttributeMaxDynamicSharedMemorySize, CONV_SMEM);

    unsigned *p_qnhi, *p_qnlo, *p_combhi, *p_comblo;
    unsigned *p_WIhi, *p_WIlo, *p_WOhi, *p_WOlo;
    float *p_Z, *p_O, *p_q;
    cudaGetSymbolAddress((void**)&p_qnhi, g_qnhi);
    cudaGetSymbolAddress((void**)&p_qnlo, g_qnlo);
    cudaGetSymbolAddress((void**)&p_combhi, g_combhi);
    cudaGetSymbolAddress((void**)&p_comblo, g_comblo);
    cudaGetSymbolAddress((void**)&p_WIhi, g_WIhi);
    cudaGetSymbolAddress((void**)&p_WIlo, g_WIlo);
    cudaGetSymbolAddress((void**)&p_WOhi, g_WOhi);
    cudaGetSymbolAddress((void**)&p_WOlo, g_WOlo);
    cudaGetSymbolAddress((void**)&p_Z, g_Z);
    cudaGetSymbolAddress((void**)&p_O, g_O);
    cudaGetSymbolAddress((void**)&p_q, g_q);

    const int WI_SZ = NPIN * (DM / 2);
    const int WO_SZ = DM * (DI / 2);

    cudaStream_t s1;
    cudaStreamCreateWithFlags(&s1, cudaStreamNonBlocking);
    cudaEvent_t evF, evJ;
    cudaEventCreateWithFlags(&evF, cudaEventDisableTiming);
    cudaEventCreateWithFlags(&evJ, cudaEventDisableTiming);

    const float* Win0  = (const float*)d_in[6];
    const float* Win1  = (const float*)d_in[14];
    const float* Wout0 = (const float*)d_in[13];
    const float* Wout1 = (const float*)d_in[21];

    cudaEventRecord(evF, 0);
    cudaStreamWaitEvent(s1, evF, 0);
    k_ln256<<<NT, 128, 0, s1>>>(query, pre_w, pre_b);
    k_splitW<<<((DM / 2) * NPIN + 255) / 256, 256, 0, s1>>>(
        Win0, DM, DP, NPIN, p_WIhi, p_WIlo);
    k_gemm_bf<<<dim3(NPIN / 64, NT / 128), 256, GEMM_SMEM, s1>>>(
        NT, DP, DM, p_qnhi, p_qnlo, p_WIhi, p_WIlo, p_Z, DP);
    cudaEventRecord(evJ, s1);

    k_splitW<<<((DM / 2) * NPIN + 255) / 256, 256>>>(
        Win1, DM, DP, NPIN, p_WIhi + WI_SZ, p_WIlo + WI_SZ);
    k_splitW<<<((DI / 2) * DM + 255) / 256, 256>>>(
        Wout0, DI, DM, DM, p_WOhi, p_WOlo);
    k_splitW<<<((DI / 2) * DM + 255) / 256, 256>>>(
        Wout1, DI, DM, DM, p_WOhi + WO_SZ, p_WOlo + WO_SZ);
    k_minmax<<<1, 256>>>(pos);
    k_keys<<<(NT + 255) / 256, 256>>>(pos);
    k_sort_init<<<dim3(NT / SEG, 2), 128>>>();
    for (int k = 2 * SEG; k <= NT; k <<= 1) {
        for (int j = k >> 1; j >= SEG; j >>= 1)
            k_sort_gpass<<<dim3(NT / 2 / 256, 2), 256>>>(k, j);
        k_sort_local<<<dim3(NT / SEG, 2), 128>>>(k);
    }
    k_order<<<(2 * NT + 255) / 256, 256>>>();

    cudaStreamWaitEvent(0, evJ, 0);

    for (int L = 0; L < 2; L++) {
        const float* cw   = (const float*)d_in[7 + 8 * L];
        const float* cb   = (const float*)d_in[8 + 8 * L];
        const float* dtb  = (const float*)d_in[9 + 8 * L];
        const float* alog = (const float*)d_in[10 + 8 * L];
        const float* Dv   = (const float*)d_in[11 + 8 * L];
        const float* nw   = (const float*)d_in[12 + 8 * L];
        const float* src  = (L == 0) ? query : p_q;

        if (L == 1) {
            k_gemm_bf<<<dim3(NPIN / 64, NT / 128), 256, GEMM_SMEM>>>(
                NT, DP, DM, p_qnhi, p_qnlo, p_WIhi + WI_SZ, p_WIlo + WI_SZ, p_Z, DP);
        }
        k_conv2<<<dim3(NT / 64, CD / CTILE, 2), 256, CONV_SMEM>>>(cw, cb, dtb, alog);
        k_scan1<<<dim3(NCH, 2), 256>>>();
        k_scan2<<<256, 256>>>();
        k_scan3<<<dim3(NCH, 2), 256, SCAN3_SMEM>>>(Dv);
        k_pncomb<<<NT, 256>>>(nw);
        k_gemm_bf<<<dim3(DM / 64, NT / 128), 256, GEMM_SMEM>>>(
            NT, DM, DI, p_combhi, p_comblo,
            p_WOhi + (size_t)L * WO_SZ, p_WOlo + (size_t)L * WO_SZ, p_O, DM);
        // fused final-LN + (for L0) next-layer pre-LN
        k_fln<<<NT / 8, 256>>>(src, fin_w, fin_b, pre_w, pre_b,
                               (L == 1) ? (float*)d_out : nullptr, (L == 0) ? 1 : 0);
    }
}

// round 17
// speedup vs baseline: 1.7351x; 1.0314x over previous
#include <cuda_runtime.h>
#include <cuda_bf16.h>
#include <math.h>

#define NT 16384
#define DM 256
#define DI 512
#define DS 64
#define NH 8
#define HD 64
#define CD 640      // CONV_DIM
#define DP 1160     // D_PROJ
#define KER 4
#define NCH 256     // number of chunks
#define CQ 64       // chunk length
#define SR 68       // padded row stride for 64-col smem tiles
#define NPIN 1216   // padded N for in_proj (19*64)
#define WSTR 20     // GEMM smem row stride in uints
#define CTILE 160   // conv col chunk
#define SEG 2048    // sort segment

// ---------------- device scratch ----------------
__device__ float g_q[NT * DM];
__device__ unsigned g_qnhi[NT * (DM / 2)];
__device__ unsigned g_qnlo[NT * (DM / 2)];
__device__ float g_Z[NT * DP];
__device__ float g_XBC[2 * NT * CD];
__device__ float g_dt[2 * NT * NH];
__device__ float g_a[2 * NT * NH];
__device__ float g_cum[2 * NH * NCH * CQ];
__device__ float g_cdec[2 * NH * NCH];
__device__ float g_S[2 * NH * NCH * HD * DS];
__device__ float g_Hp[2 * NH * NCH * HD * DS];
__device__ float g_Y[2 * NT * DI];
__device__ unsigned g_combhi[NT * (DI / 2)];
__device__ unsigned g_comblo[NT * (DI / 2)];
__device__ float g_O[NT * DM];
__device__ unsigned g_WIhi[2 * NPIN * (DM / 2)];
__device__ unsigned g_WIlo[2 * NPIN * (DM / 2)];
__device__ unsigned g_WOhi[2 * DM * (DI / 2)];
__device__ unsigned g_WOlo[2 * DM * (DI / 2)];
__device__ unsigned long long g_keys[2 * NT];
__device__ int g_order[2 * NT];
__device__ int g_inv[2 * NT];
__device__ float g_pmin[3], g_pmax[3];

extern __shared__ float dynsmem[];

// ---------------- helpers ----------------
__device__ __forceinline__ float blockReduceSum(float v) {
    __shared__ float sh[32];
    __shared__ float tot;
    int lane = threadIdx.x & 31, wid = threadIdx.x >> 5;
    #pragma unroll
    for (int o = 16; o > 0; o >>= 1) v += __shfl_xor_sync(0xffffffffu, v, o);
    if (lane == 0) sh[wid] = v;
    __syncthreads();
    int nw = blockDim.x >> 5;
    v = (threadIdx.x < nw) ? sh[threadIdx.x] : 0.0f;
    if (wid == 0) {
        #pragma unroll
        for (int o = 16; o > 0; o >>= 1) v += __shfl_xor_sync(0xffffffffu, v, o);
        if (lane == 0) tot = v;
    }
    __syncthreads();
    return tot;
}

__device__ __forceinline__ float warpReduceSum(float v) {
    #pragma unroll
    for (int o = 16; o > 0; o >>= 1) v += __shfl_xor_sync(0xffffffffu, v, o);
    return v;
}

__device__ __forceinline__ unsigned hilbert3(unsigned a0, unsigned a1, unsigned a2) {
    unsigned x0 = a0, x1 = a1, x2 = a2;
    const unsigned M = 1u << 9;
    for (unsigned Q = M; Q > 1; Q >>= 1) {
        unsigned P = Q - 1;
        if (x0 & Q) x0 ^= P;
        {
            unsigned t = (x0 ^ x1) & P;
            if (x1 & Q) { x0 ^= P; } else { x0 ^= t; x1 ^= t; }
        }
        {
            unsigned t = (x0 ^ x2) & P;
            if (x2 & Q) { x0 ^= P; } else { x0 ^= t; x2 ^= t; }
        }
    }
    x1 ^= x0;
    x2 ^= x1;
    unsigned t = 0;
    for (unsigned Q = M; Q > 1; Q >>= 1)
        if (x2 & Q) t ^= (Q - 1);
    x0 ^= t; x1 ^= t; x2 ^= t;
    unsigned code = 0;
    for (int b = 9; b >= 0; b--) {
        code = (code << 1) | ((x0 >> b) & 1);
        code = (code << 1) | ((x1 >> b) & 1);
        code = (code << 1) | ((x2 >> b) & 1);
    }
    return code;
}

__device__ __forceinline__ void bfsplit(float x, unsigned short& hi, unsigned short& lo) {
    __nv_bfloat16 h = __float2bfloat16(x);
    __nv_bfloat16 l = __float2bfloat16(x - __bfloat162float(h));
    hi = *(unsigned short*)&h;
    lo = *(unsigned short*)&l;
}

__device__ __forceinline__ void mma_bf16(float c[4], const unsigned a[4],
                                         unsigned b0, unsigned b1) {
    asm volatile("mma.sync.aligned.m16n8k16.row.col.f32.bf16.bf16.f32 "
        "{%0,%1,%2,%3}, {%4,%5,%6,%7}, {%8,%9}, {%0,%1,%2,%3};"
        : "+f"(c[0]), "+f"(c[1]), "+f"(c[2]), "+f"(c[3])
        : "r"(a[0]), "r"(a[1]), "r"(a[2]), "r"(a[3]), "r"(b0), "r"(b1));
}

__device__ __forceinline__ void cp16(unsigned dst, const void* src) {
    asm volatile("cp.async.cg.shared.global [%0], [%1], 16;" :: "r"(dst), "l"(src));
}

// ---- packed f32x2 FMA ----
__device__ __forceinline__ void fma2(unsigned long long& c, unsigned long long a,
                                     unsigned long long b) {
    asm("fma.rn.f32x2 %0, %1, %2, %0;" : "+l"(c) : "l"(a), "l"(b));
}
__device__ __forceinline__ unsigned long long bcast2(float x) {
    unsigned long long r;
    unsigned u = __float_as_uint(x);
    asm("mov.b64 %0, {%1, %2};" : "=l"(r) : "r"(u), "r"(u));
    return r;
}
__device__ __forceinline__ unsigned long long packf2(float a, float b) {
    unsigned long long r;
    asm("mov.b64 %0, {%1, %2};" : "=l"(r) : "r"(__float_as_uint(a)), "r"(__float_as_uint(b)));
    return r;
}
__device__ __forceinline__ float2 unpack2(unsigned long long v) {
    unsigned lo, hi;
    asm("mov.b64 {%0, %1}, %2;" : "=r"(lo), "=r"(hi) : "l"(v));
    return make_float2(__uint_as_float(lo), __uint_as_float(hi));
}

// ---------------- setup kernels ----------------
__global__ void k_minmax(const float* __restrict__ pos) {
    __shared__ float smn[256][3], smx[256][3];
    float mn[3] = {1e30f, 1e30f, 1e30f}, mx[3] = {-1e30f, -1e30f, -1e30f};
    for (int r = threadIdx.x; r < NT; r += 256) {
        #pragma unroll
        for (int j = 0; j < 3; j++) {
            float v = pos[r * 3 + j];
            mn[j] = fminf(mn[j], v);
            mx[j] = fmaxf(mx[j], v);
        }
    }
    #pragma unroll
    for (int j = 0; j < 3; j++) { smn[threadIdx.x][j] = mn[j]; smx[threadIdx.x][j] = mx[j]; }
    __syncthreads();
    for (int s = 128; s > 0; s >>= 1) {
        if (threadIdx.x < s) {
            #pragma unroll
            for (int j = 0; j < 3; j++) {
                smn[threadIdx.x][j] = fminf(smn[threadIdx.x][j], smn[threadIdx.x + s][j]);
                smx[threadIdx.x][j] = fmaxf(smx[threadIdx.x][j], smx[threadIdx.x + s][j]);
            }
        }
        __syncthreads();
    }
    if (threadIdx.x == 0) {
        #pragma unroll
        for (int j = 0; j < 3; j++) { g_pmin[j] = smn[0][j]; g_pmax[j] = smx[0][j]; }
    }
}

__global__ void k_keys(const float* __restrict__ pos) {
    int idx = blockIdx.x * blockDim.x + threadIdx.x;
    if (idx >= NT) return;
    unsigned g[3];
    #pragma unroll
    for (int j = 0; j < 3; j++) {
        float denom = g_pmax[j] - g_pmin[j] + 1e-6f;
        float v = ((pos[idx * 3 + j] - g_pmin[j]) / denom) * 1023.0f;
        v = fminf(fmaxf(v, 0.0f), 1023.0f);
        g[j] = (unsigned)(int)v;
    }
    unsigned c0 = hilbert3(g[0], g[1], g[2]);
    unsigned c1 = hilbert3(g[1], g[0], g[2]);
    g_keys[idx]      = (((unsigned long long)c0) << 14) | (unsigned long long)idx;
    g_keys[NT + idx] = (((unsigned long long)c1) << 14) | (unsigned long long)idx;
}

#define SADDR(i) ((i) + ((i) >> 4))

__global__ void k_sort_init() {
    __shared__ unsigned long long s[SEG + SEG / 16];
    int seg = blockIdx.x, b = blockIdx.y;
    unsigned long long* keys = g_keys + b * NT + seg * SEG;
    bool upg = ((seg & 1) == 0);
    int t = threadIdx.x;  // 128 threads
    for (int i = t; i < SEG; i += 128) s[SADDR(i)] = keys[i];
    __syncthreads();

    int base = t * 16;
    unsigned long long v[16];
    #pragma unroll
    for (int r = 0; r < 16; r++) v[r] = s[SADDR(base + r)];
    #pragma unroll
    for (int k = 2; k <= 16; k <<= 1) {
        #pragma unroll
        for (int j = k >> 1; j > 0; j >>= 1) {
            #pragma unroll
            for (int r = 0; r < 16; r++) {
                int rr = r ^ j;
                if (rr > r) {
                    bool up = ((((base + r) & k) == 0) == upg);
                    unsigned long long a = v[r], c = v[rr];
                    if ((a > c) == up) { v[r] = c; v[rr] = a; }
                }
            }
        }
    }
    #pragma unroll
    for (int r = 0; r < 16; r++) s[SADDR(base + r)] = v[r];
    __syncthreads();

    for (int k = 32; k <= SEG; k <<= 1) {
        for (int j = k >> 1; j >= 16; j >>= 1) {
            for (int i = t; i < SEG; i += 128) {
                int ixj = i ^ j;
                if (ixj > i) {
                    unsigned long long a = s[SADDR(i)], c = s[SADDR(ixj)];
                    bool up = (((i & k) == 0) == upg);
                    if ((a > c) == up) { s[SADDR(i)] = c; s[SADDR(ixj)] = a; }
                }
            }
            __syncthreads();
        }
        #pragma unroll
        for (int r = 0; r < 16; r++) v[r] = s[SADDR(base + r)];
        bool up = (((base & k) == 0) == upg);
        #pragma unroll
        for (int j = 8; j > 0; j >>= 1) {
            #pragma unroll
            for (int r = 0; r < 16; r++) {
                int rr = r ^ j;
                if (rr > r) {
                    unsigned long long a = v[r], c = v[rr];
                    if ((a > c) == up) { v[r] = c; v[rr] = a; }
                }
            }
        }
        #pragma unroll
        for (int r = 0; r < 16; r++) s[SADDR(base + r)] = v[r];
        __syncthreads();
    }
    for (int i = t; i < SEG; i += 128) keys[i] = s[SADDR(i)];
}

__global__ void k_sort_gpass(int k, int j) {
    int p = blockIdx.x * blockDim.x + threadIdx.x;
    int b = blockIdx.y;
    int low = p & (j - 1);
    int i = ((p & ~(j - 1)) << 1) | low;
    unsigned long long* keys = g_keys + b * NT;
    unsigned long long a = keys[i], c = keys[i + j];
    bool up = ((i & k) == 0);
    if ((a > c) == up) { keys[i] = c; keys[i + j] = a; }
}

__global__ void k_sort_local(int k) {
    __shared__ unsigned long long s[SEG + SEG / 16];
    int seg = blockIdx.x, b = blockIdx.y;
    unsigned long long* keys = g_keys + b * NT + seg * SEG;
    bool up = (((seg * SEG) & k) == 0);
    int t = threadIdx.x;
    for (int i = t; i < SEG; i += 128) s[SADDR(i)] = keys[i];
    __syncthreads();
    for (int j = SEG / 2; j >= 16; j >>= 1) {
        for (int i = t; i < SEG; i += 128) {
            int ixj = i ^ j;
            if (ixj > i) {
                unsigned long long a = s[SADDR(i)], c = s[SADDR(ixj)];
                if ((a > c) == up) { s[SADDR(i)] = c; s[SADDR(ixj)] = a; }
            }
        }
        __syncthreads();
    }
    int base = t * 16;
    unsigned long long v[16];
    #pragma unroll
    for (int r = 0; r < 16; r++) v[r] = s[SADDR(base + r)];
    #pragma unroll
    for (int j = 8; j > 0; j >>= 1) {
        #pragma unroll
        for (int r = 0; r < 16; r++) {
            int rr = r ^ j;
            if (rr > r) {
                unsigned long long a = v[r], c = v[rr];
                if ((a > c) == up) { v[r] = c; v[rr] = a; }
            }
        }
    }
    #pragma unroll
    for (int r = 0; r < 16; r++) s[SADDR(base + r)] = v[r];
    __syncthreads();
    for (int i = t; i < SEG; i += 128) keys[i] = s[SADDR(i)];
}

__global__ void k_order() {
    int i = blockIdx.x * blockDim.x + threadIdx.x;
    if (i >= 2 * NT) return;
    int b = i / NT;
    int idx = (int)(g_keys[i] & 0x3FFFULL);
    g_order[i] = idx;
    g_inv[b * NT + idx] = i - b * NT;
}

// standalone LN (L0 prologue only)
__global__ void k_ln256(const float* __restrict__ src,
                        const float* __restrict__ w, const float* __restrict__ bias) {
    int r = blockIdx.x, t = threadIdx.x;
    float2 v = *(const float2*)(src + (size_t)r * DM + 2 * t);
    float mean = blockReduceSum(v.x + v.y) * (1.0f / DM);
    float x0 = v.x - mean, x1 = v.y - mean;
    float var = blockReduceSum(x0 * x0 + x1 * x1) * (1.0f / DM);
    float rs = rsqrtf(var + 1e-5f);
    float r0 = x0 * rs * w[2 * t] + bias[2 * t];
    float r1 = x1 * rs * w[2 * t + 1] + bias[2 * t + 1];
    unsigned short h0, l0, h1, l1;
    bfsplit(r0, h0, l0);
    bfsplit(r1, h1, l1);
    g_qnhi[r * (DM / 2) + t] = (unsigned)h0 | ((unsigned)h1 << 16);
    g_qnlo[r * (DM / 2) + t] = (unsigned)l0 | ((unsigned)l1 << 16);
}

// fused final-LN (+ optional next pre-LN), warp per row
__global__ __launch_bounds__(256) void k_fln(const float* __restrict__ res,
        const float* __restrict__ w, const float* __restrict__ bias,
        const float* __restrict__ pw, const float* __restrict__ pb,
        float* __restrict__ dout, int emitqn) {
    int wid = threadIdx.x >> 5, lane = threadIdx.x & 31;
    int r = blockIdx.x * 8 + wid;
    int c0 = lane * 8;
    float v[8];
    {
        float4 a0 = *(const float4*)(res + (size_t)r * DM + c0);
        float4 a1 = *(const float4*)(res + (size_t)r * DM + c0 + 4);
        float4 b0 = *(const float4*)(g_O + (size_t)r * DM + c0);
        float4 b1 = *(const float4*)(g_O + (size_t)r * DM + c0 + 4);
        v[0] = a0.x + b0.x; v[1] = a0.y + b0.y; v[2] = a0.z + b0.z; v[3] = a0.w + b0.w;
        v[4] = a1.x + b1.x; v[5] = a1.y + b1.y; v[6] = a1.z + b1.z; v[7] = a1.w + b1.w;
    }
    float s = 0.0f;
    #pragma unroll
    for (int i = 0; i < 8; i++) s += v[i];
    float mean = warpReduceSum(s) * (1.0f / DM);
    float sq = 0.0f;
    #pragma unroll
    for (int i = 0; i < 8; i++) { v[i] -= mean; sq += v[i] * v[i]; }
    float rs = rsqrtf(warpReduceSum(sq) * (1.0f / DM) + 1e-5f);
    float resu[8];
    #pragma unroll
    for (int i = 0; i < 8; i++) resu[i] = v[i] * rs * w[c0 + i] + bias[c0 + i];
    #pragma unroll
    for (int i = 0; i < 8; i += 4)
        *(float4*)(g_q + (size_t)r * DM + c0 + i) =
            make_float4(resu[i], resu[i + 1], resu[i + 2], resu[i + 3]);
    if (dout) {
        #pragma unroll
        for (int i = 0; i < 8; i += 4)
            *(float4*)(dout + (size_t)r * DM + c0 + i) =
                make_float4(resu[i], resu[i + 1], resu[i + 2], resu[i + 3]);
    }
    if (emitqn) {
        float s2 = 0.0f;
        #pragma unroll
        for (int i = 0; i < 8; i++) s2 += resu[i];
        float mean2 = warpReduceSum(s2) * (1.0f / DM);
        float sq2 = 0.0f;
        float x2[8];
        #pragma unroll
        for (int i = 0; i < 8; i++) { x2[i] = resu[i] - mean2; sq2 += x2[i] * x2[i]; }
        float rs2 = rsqrtf(warpReduceSum(sq2) * (1.0f / DM) + 1e-5f);
        #pragma unroll
        for (int i = 0; i < 8; i += 2) {
            float q0 = x2[i] * rs2 * pw[c0 + i] + pb[c0 + i];
            float q1 = x2[i + 1] * rs2 * pw[c0 + i + 1] + pb[c0 + i + 1];
            unsigned short h0, l0, h1, l1;
            bfsplit(q0, h0, l0);
            bfsplit(q1, h1, l1);
            g_qnhi[r * (DM / 2) + (c0 + i) / 2] = (unsigned)h0 | ((unsigned)h1 << 16);
            g_qnlo[r * (DM / 2) + (c0 + i) / 2] = (unsigned)l0 | ((unsigned)l1 << 16);
        }
    }
}

__global__ void k_splitW(const float* __restrict__ src, int K, int N, int NP,
                         unsigned* __restrict__ Whi, unsigned* __restrict__ Wlo) {
    int idx = blockIdx.x * blockDim.x + threadIdx.x;
    if (idx >= (K / 2) * NP) return;
    int kp = idx / NP, n = idx - kp * NP;
    float w0 = (n < N) ? src[(size_t)(2 * kp) * N + n] : 0.0f;
    float w1 = (n < N) ? src[(size_t)(2 * kp + 1) * N + n] : 0.0f;
    unsigned short h0, l0, h1, l1;
    bfsplit(w0, h0, l0);
    bfsplit(w1, h1, l1);
    Whi[(size_t)n * (K / 2) + kp] = (unsigned)h0 | ((unsigned)h1 << 16);
    Wlo[(size_t)n * (K / 2) + kp] = (unsigned)l0 | ((unsigned)l1 << 16);
}

// ---------------- bf16x3 tensor-core GEMM ----------------
__device__ __forceinline__ void gemm_load_bf(
    const unsigned* __restrict__ Ahi, const unsigned* __restrict__ Alo, int K2,
    const unsigned* __restrict__ Bhi, const unsigned* __restrict__ Blo,
    int m0, int n0, int kt, unsigned* sAh, unsigned* sAl,
    unsigned* sBh, unsigned* sBl, int tid) {
    int kp0 = kt * 16;
    int r = tid >> 1, cu = (tid & 1) * 8;
    const unsigned* pah = Ahi + (size_t)(m0 + r) * K2 + kp0 + cu;
    const unsigned* pal = Alo + (size_t)(m0 + r) * K2 + kp0 + cu;
    unsigned dah = (unsigned)__cvta_generic_to_shared(sAh + r * WSTR + cu);
    unsigned dal = (unsigned)__cvta_generic_to_shared(sAl + r * WSTR + cu);
    cp16(dah, pah); cp16(dah + 16, pah + 4);
    cp16(dal, pal); cp16(dal + 16, pal + 4);
    int n = tid >> 2, cb = (tid & 3) * 4;
    cp16((unsigned)__cvta_generic_to_shared(sBh + n * WSTR + cb),
         Bhi + (size_t)(n0 + n) * K2 + kp0 + cb);
    cp16((unsigned)__cvta_generic_to_shared(sBl + n * WSTR + cb),
         Blo + (size_t)(n0 + n) * K2 + kp0 + cb);
}

__global__ __launch_bounds__(256) void k_gemm_bf(int M, int N, int K,
        const unsigned* __restrict__ Ahi, const unsigned* __restrict__ Alo,
        const unsigned* __restrict__ Bhi, const unsigned* __restrict__ Blo,
        float* __restrict__ C, int ldc) {
    unsigned* sm = (unsigned*)dynsmem;
    const int ASZ = 128 * WSTR, BSZ = 64 * WSTR;
    const int STG = 2 * ASZ + 2 * BSZ;

    int m0 = blockIdx.y * 128, n0 = blockIdx.x * 64;
    int tid = threadIdx.x;
    int wid = tid >> 5, lane = tid & 31;
    int wm = (wid & 3) * 32, wn = (wid >> 2) * 32;
    int g = lane >> 2, tg = lane & 3;
    int K2 = K >> 1;
    int KT = K / 32;

    float acc[2][4][4];
    #pragma unroll
    for (int a = 0; a < 2; a++)
        #pragma unroll
        for (int b = 0; b < 4; b++)
            #pragma unroll
            for (int c = 0; c < 4; c++) acc[a][b][c] = 0.0f;

    gemm_load_bf(Ahi, Alo, K2, Bhi, Blo, m0, n0, 0,
                 sm, sm + ASZ, sm + 2 * ASZ, sm + 2 * ASZ + BSZ, tid);
    asm volatile("cp.async.commit_group;");

    for (int kt = 0; kt < KT; kt++) {
        int st = kt & 1;
        if (kt + 1 < KT) {
            int ns = st ^ 1;
            unsigned* b0 = sm + ns * STG;
            gemm_load_bf(Ahi, Alo, K2, Bhi, Blo, m0, n0, kt + 1,
                         b0, b0 + ASZ, b0 + 2 * ASZ, b0 + 2 * ASZ + BSZ, tid);
            asm volatile("cp.async.commit_group;");
            asm volatile("cp.async.wait_group 1;");
        } else {
            asm volatile("cp.async.wait_group 0;");
        }
        __syncthreads();
        unsigned* sAhi = sm + st * STG;
        unsigned* sAlo = sAhi + ASZ;
        unsigned* sBhi = sAhi + 2 * ASZ;
        unsigned* sBlo = sBhi + BSZ;
        #pragma unroll
        for (int kk2 = 0; kk2 < 16; kk2 += 8) {
            unsigned ahi[2][4], alo[2][4], bhi[4][2], blo[4][2];
            #pragma unroll
            for (int mi = 0; mi < 2; mi++) {
                int ra = (wm + mi * 16 + g) * WSTR;
                int rb = (wm + mi * 16 + g + 8) * WSTR;
                ahi[mi][0] = sAhi[ra + kk2 + tg];
                ahi[mi][1] = sAhi[rb + kk2 + tg];
                ahi[mi][2] = sAhi[ra + kk2 + 4 + tg];
                ahi[mi][3] = sAhi[rb + kk2 + 4 + tg];
                alo[mi][0] = sAlo[ra + kk2 + tg];
                alo[mi][1] = sAlo[rb + kk2 + tg];
                alo[mi][2] = sAlo[ra + kk2 + 4 + tg];
                alo[mi][3] = sAlo[rb + kk2 + 4 + tg];
            }
            #pragma unroll
            for (int nj = 0; nj < 4; nj++) {
                int rn = (wn + nj * 8 + g) * WSTR;
                bhi[nj][0] = sBhi[rn + kk2 + tg];
                bhi[nj][1] = sBhi[rn + kk2 + 4 + tg];
                blo[nj][0] = sBlo[rn + kk2 + tg];
                blo[nj][1] = sBlo[rn + kk2 + 4 + tg];
            }
            #pragma unroll
            for (int mi = 0; mi < 2; mi++)
                #pragma unroll
                for (int nj = 0; nj < 4; nj++) {
                    mma_bf16(acc[mi][nj], ahi[mi], bhi[nj][0], bhi[nj][1]);
                    mma_bf16(acc[mi][nj], ahi[mi], blo[nj][0], blo[nj][1]);
                    mma_bf16(acc[mi][nj], alo[mi], bhi[nj][0], bhi[nj][1]);
                }
        }
        __syncthreads();
    }
    #pragma unroll
    for (int mi = 0; mi < 2; mi++)
        #pragma unroll
        for (int nj = 0; nj < 4; nj++) {
            int row = m0 + wm + mi * 16 + g;
            int col = n0 + wn + nj * 8 + tg * 2;
            if (col + 1 < N) {
                *(float2*)(C + (size_t)row * ldc + col) =
                    make_float2(acc[mi][nj][0], acc[mi][nj][1]);
                *(float2*)(C + (size_t)(row + 8) * ldc + col) =
                    make_float2(acc[mi][nj][2], acc[mi][nj][3]);
            } else if (col < N) {
                C[(size_t)row * ldc + col] = acc[mi][nj][0];
                C[(size_t)(row + 8) * ldc + col] = acc[mi][nj][2];
            }
        }
}

// ---------------- tiled conv (+ fused dt on y==0 blocks) ----------------
__global__ __launch_bounds__(256) void k_conv2(const float* __restrict__ cw,
                                               const float* __restrict__ cb,
                                               const float* __restrict__ dtb,
                                               const float* __restrict__ alog) {
    float* sZ  = dynsmem;
    float* scw = sZ + 67 * CTILE;
    float* scb = scw + CTILE * 4;
    int*   stok = (int*)(scb + CTILE);
    int r0 = blockIdx.x * 64, cc = blockIdx.y * CTILE, b = blockIdx.z;
    int tid = threadIdx.x;
    if (tid < 67) {
        int rr = r0 - 3 + tid;
        stok[tid] = (rr >= 0) ? g_order[b * NT + rr] : -1;
    }
    for (int idx = tid; idx < CTILE * 4; idx += 256)
        scw[idx] = cw[(cc + (idx >> 2)) * KER + (idx & 3)];
    for (int idx = tid; idx < CTILE; idx += 256)
        scb[idx] = cb[cc + idx];
    __syncthreads();
    for (int idx = tid; idx < 67 * CTILE; idx += 256) {
        int row = idx / CTILE, col = idx - row * CTILE;
        int t = stok[row];
        sZ[idx] = (t >= 0) ? g_Z[(size_t)t * DP + DI + cc + col] : 0.0f;
    }
    if (blockIdx.y == 0) {
        for (int idx = tid; idx < 64 * NH; idx += 256) {
            int row = idx >> 3, h = idx & 7;
            int t = stok[row + 3];
            float x = g_Z[(size_t)t * DP + DI + CD + h] + dtb[h];
            float sp = fmaxf(x, 0.0f) + log1pf(expf(-fabsf(x)));
            float A = -expf(alog[h]);
            int gi = (b * NT + r0 + row) * NH + h;
            g_dt[gi] = sp;
            g_a[gi] = sp * A;
        }
    }
    __syncthreads();
    for (int idx = tid; idx < 64 * CTILE; idx += 256) {
        int row = idx / CTILE, col = idx - row * CTILE;
        float acc = scb[col];
        #pragma unroll
        for (int k = 0; k < KER; k++)
            acc += scw[col * 4 + k] * sZ[(row + k) * CTILE + col];
        float s = acc / (1.0f + __expf(-acc));
        g_XBC[(size_t)(b * NT + r0 + row) * CD + cc + col] = s;
    }
}

// ---------------- chunked scan ----------------
__global__ __launch_bounds__(256) void k_scan1() {
    int c = blockIdx.x, b = blockIdx.y;
    __shared__ float sX[CQ * SR], sB[CQ * SR];
    __shared__ float scum[CQ], sw[CQ];
    int r0 = c * CQ, tid = threadIdx.x;
    for (int idx = tid; idx < CQ * 64; idx += 256) {
        int j = idx >> 6, p = idx & 63;
        sB[j * SR + p] = g_XBC[(size_t)(b * NT + r0 + j) * CD + DI + p];
    }
    int p0 = (tid & 15) * 4, s0 = (tid >> 4) * 4;
    for (int h = 0; h < NH; h++) {
        __syncthreads();
        for (int idx = tid; idx < CQ * 64; idx += 256) {
            int j = idx >> 6, p = idx & 63;
            sX[j * SR + p] = g_XBC[(size_t)(b * NT + r0 + j) * CD + h * HD + p];
        }
        if (tid < CQ) scum[tid] = g_a[(size_t)(b * NT + r0 + tid) * NH + h];
        __syncthreads();
        if (tid < CQ) {
            float x = scum[tid];
            #pragma unroll
            for (int o = 1; o < 32; o <<= 1) {
                float y = __shfl_up_sync(0xffffffffu, x, o);
                if ((tid & 31) >= o) x += y;
            }
            scum[tid] = x;
        }
        __syncthreads();
        if (tid >= 32 && tid < CQ) scum[tid] += scum[31];
        __syncthreads();
        float slast = scum[CQ - 1];
        if (tid < CQ) {
            sw[tid] = __expf(slast - scum[tid]) * g_dt[(size_t)(b * NT + r0 + tid) * NH + h];
            g_cum[((b * NH + h) * NCH + c) * CQ + tid] = scum[tid];
        }
        if (tid == 0) g_cdec[(b * NH + h) * NCH + c] = __expf(slast);
        __syncthreads();
        unsigned long long acc2[4][2] = {};
        for (int j = 0; j < CQ; j++) {
            float4 xv = *(float4*)&sX[j * SR + p0];
            ulonglong2 b2 = *(const ulonglong2*)&sB[j * SR + s0];
            float w = sw[j];
            float wx[4] = {xv.x * w, xv.y * w, xv.z * w, xv.w * w};
            #pragma unroll
            for (int pi = 0; pi < 4; pi++) {
                unsigned long long w2 = bcast2(wx[pi]);
                fma2(acc2[pi][0], w2, b2.x);
                fma2(acc2[pi][1], w2, b2.y);
            }
        }
        size_t base = ((size_t)((b * NH + h) * NCH + c) * HD) * DS;
        #pragma unroll
        for (int pi = 0; pi < 4; pi++) {
            float2 a01 = unpack2(acc2[pi][0]);
            float2 a23 = unpack2(acc2[pi][1]);
            *(float4*)&g_S[base + (size_t)(p0 + pi) * DS + s0] =
                make_float4(a01.x, a01.y, a23.x, a23.y);
        }
    }
}

// inter-chunk recurrence with explicit 4-deep load prefetch
__global__ void k_scan2() {
    __shared__ float scd[NCH];
    int bh = blockIdx.x >> 4;
    int e = ((blockIdx.x & 15) << 8) + threadIdx.x;
    if (threadIdx.x < NCH) scd[threadIdx.x] = g_cdec[bh * NCH + threadIdx.x];
    __syncthreads();
    const size_t stride = HD * DS;
    size_t off = (size_t)bh * NCH * stride + e;
    float H = 0.0f;
    float pre[4];
    #pragma unroll
    for (int i = 0; i < 4; i++) pre[i] = g_S[off + (size_t)i * stride];
    for (int c = 0; c < NCH; c += 4) {
        float cur[4];
        #pragma unroll
        for (int i = 0; i < 4; i++) cur[i] = pre[i];
        if (c + 4 < NCH) {
            #pragma unroll
            for (int i = 0; i < 4; i++) pre[i] = g_S[off + (size_t)(i + 4) * stride];
        }
        #pragma unroll
        for (int i = 0; i < 4; i++) {
            g_Hp[off] = H;
            H = scd[c + i] * H + cur[i];
            off += stride;
        }
    }
}

__global__ __launch_bounds__(256) void k_scan3(const float* __restrict__ Dv) {
    int c = blockIdx.x, b = blockIdx.y;
    int r0 = c * CQ, tid = threadIdx.x;
    float* sB  = dynsmem;
    float* sC  = sB  + CQ * SR;
    float* sD0 = sC  + CQ * SR;
    float* sX  = sD0 + CQ * SR;
    float* sH  = sX  + CQ * SR;
    float* sG  = sH  + CQ * SR;
    float* scum = sG + CQ * SR;
    float* sdt  = scum + CQ;
    float* seY  = sdt + CQ;

    for (int idx = tid; idx < CQ * 64; idx += 256) {
        int j = idx >> 6, s = idx & 63;
        sB[j * SR + s] = g_XBC[(size_t)(b * NT + r0 + j) * CD + DI + s];
        sC[j * SR + s] = g_XBC[(size_t)(b * NT + r0 + j) * CD + DI + DS + s];
    }
    __syncthreads();
    int i0 = (tid >> 4) * 4, j0 = (tid & 15) * 4;
    if (j0 <= i0) {
        unsigned long long acc2[4][4] = {};
        for (int sc = 0; sc < 64; sc += 4) {
            ulonglong2 Cr[4], Br[4];
            #pragma unroll
            for (int r = 0; r < 4; r++) Cr[r] = *(const ulonglong2*)&sC[(i0 + r) * SR + sc];
            #pragma unroll
            for (int q = 0; q < 4; q++) Br[q] = *(const ulonglong2*)&sB[(j0 + q) * SR + sc];
            #pragma unroll
            for (int r = 0; r < 4; r++)
                #pragma unroll
                for (int q = 0; q < 4; q++) {
                    fma2(acc2[r][q], Cr[r].x, Br[q].x);
                    fma2(acc2[r][q], Cr[r].y, Br[q].y);
                }
        }
        #pragma unroll
        for (int r = 0; r < 4; r++) {
            float dv[4];
            #pragma unroll
            for (int q = 0; q < 4; q++) {
                float2 p = unpack2(acc2[r][q]);
                dv[q] = p.x + p.y;
            }
            *(float4*)&sD0[(i0 + r) * SR + j0] = make_float4(dv[0], dv[1], dv[2], dv[3]);
        }
    } else {
        #pragma unroll
        for (int r = 0; r < 4; r++)
            *(float4*)&sD0[(i0 + r) * SR + j0] = make_float4(0.f, 0.f, 0.f, 0.f);
    }
    __syncthreads();

    for (int h = 0; h < NH; h++) {
        for (int idx = tid; idx < CQ * 64; idx += 256) {
            int j = idx >> 6, p = idx & 63;
            sX[j * SR + p] = g_XBC[(size_t)(b * NT + r0 + j) * CD + h * HD + p];
            sH[j * SR + p] = g_Hp[((size_t)((b * NH + h) * NCH + c) * HD) * DS + idx];
        }
        if (tid < CQ) {
            float cu = g_cum[((b * NH + h) * NCH + c) * CQ + tid];
            scum[tid] = cu;
            sdt[tid] = g_dt[(size_t)(b * NT + r0 + tid) * NH + h];
            seY[tid] = __expf(cu);
        }
        __syncthreads();
        if (j0 <= i0) {
            #pragma unroll
            for (int r = 0; r < 4; r++) {
                float4 d = *(float4*)&sD0[(i0 + r) * SR + j0];
                float dd[4] = {d.x, d.y, d.z, d.w};
                float gv[4];
                int i = i0 + r;
                float ci = scum[i];
                #pragma unroll
                for (int q = 0; q < 4; q++) {
                    int j = j0 + q;
                    gv[q] = (j <= i) ? __expf(ci - scum[j]) * sdt[j] * dd[q] : 0.0f;
                }
                *(float4*)&sG[(i0 + r) * SR + j0] = make_float4(gv[0], gv[1], gv[2], gv[3]);
            }
        } else {
            #pragma unroll
            for (int r = 0; r < 4; r++)
                *(float4*)&sG[(i0 + r) * SR + j0] = make_float4(0.f, 0.f, 0.f, 0.f);
        }
        __syncthreads();
        int p0 = j0;
        float acc[4][4];
        {
            unsigned long long acc2[4][4] = {};
            for (int sc = 0; sc < 64; sc += 4) {
                ulonglong2 Cr[4], Hc[4];
                #pragma unroll
                for (int r = 0; r < 4; r++) Cr[r] = *(const ulonglong2*)&sC[(i0 + r) * SR + sc];
                #pragma unroll
                for (int q = 0; q < 4; q++) Hc[q] = *(const ulonglong2*)&sH[(p0 + q) * SR + sc];
                #pragma unroll
                for (int r = 0; r < 4; r++)
                    #pragma unroll
                    for (int q = 0; q < 4; q++) {
                        fma2(acc2[r][q], Cr[r].x, Hc[q].x);
                        fma2(acc2[r][q], Cr[r].y, Hc[q].y);
                    }
            }
            #pragma unroll
            for (int r = 0; r < 4; r++) {
                float e = seY[i0 + r];
                #pragma unroll
                for (int q = 0; q < 4; q++) {
                    float2 p = unpack2(acc2[r][q]);
                    acc[r][q] = e * (p.x + p.y);
                }
            }
        }
        unsigned long long accq[4][2];
        #pragma unroll
        for (int r = 0; r < 4; r++) {
            accq[r][0] = packf2(acc[r][0], acc[r][1]);
            accq[r][1] = packf2(acc[r][2], acc[r][3]);
        }
        for (int jc = 0; jc <= i0; jc += 4) {
            float G4[4][4];
            #pragma unroll
            for (int r = 0; r < 4; r++) {
                float4 t = *(float4*)&sG[(i0 + r) * SR + jc];
                G4[r][0] = t.x; G4[r][1] = t.y; G4[r][2] = t.z; G4[r][3] = t.w;
            }
            #pragma unroll
            for (int q = 0; q < 4; q++) {
                ulonglong2 x2 = *(const ulonglong2*)&sX[(jc + q) * SR + p0];
                #pragma unroll
                for (int r = 0; r < 4; r++) {
                    unsigned long long g2 = bcast2(G4[r][q]);
                    fma2(accq[r][0], g2, x2.x);
                    fma2(accq[r][1], g2, x2.y);
                }
            }
        }
        unsigned long long D2 = bcast2(Dv[h]);
        #pragma unroll
        for (int r = 0; r < 4; r++) {
            ulonglong2 xi2 = *(const ulonglong2*)&sX[(i0 + r) * SR + p0];
            fma2(accq[r][0], D2, xi2.x);
            fma2(accq[r][1], D2, xi2.y);
            float2 y01 = unpack2(accq[r][0]);
            float2 y23 = unpack2(accq[r][1]);
            *(float4*)&g_Y[(size_t)(b * NT + r0 + i0 + r) * DI + h * HD + p0] =
                make_float4(y01.x, y01.y, y23.x, y23.y);
        }
        __syncthreads();
    }
}

// ---------------- fused postnorm + combine (warp per token) ----------------
__global__ __launch_bounds__(256) void k_pncomb(const float* __restrict__ nw) {
    int w = threadIdx.x >> 5, lane = threadIdx.x & 31;
    int t = blockIdx.x * 8 + w;
    int r0 = g_inv[t], r1 = g_inv[NT + t];
    int c0 = lane * 16;
    float v0[16], v1[16];
    float sq0 = 0.0f, sq1 = 0.0f;
    #pragma unroll
    for (int i = 0; i < 16; i += 4) {
        float4 a = *(const float4*)(g_Y + (size_t)r0 * DI + c0 + i);
        float4 bq = *(const float4*)(g_Y + (size_t)(NT + r1) * DI + c0 + i);
        float4 gz = *(const float4*)(g_Z + (size_t)t * DP + c0 + i);
        float s;
        s = gz.x / (1.0f + __expf(-gz.x)); v0[i]   = a.x * s; v1[i]   = bq.x * s;
        s = gz.y / (1.0f + __expf(-gz.y)); v0[i+1] = a.y * s; v1[i+1] = bq.y * s;
        s = gz.z / (1.0f + __expf(-gz.z)); v0[i+2] = a.z * s; v1[i+2] = bq.z * s;
        s = gz.w / (1.0f + __expf(-gz.w)); v0[i+3] = a.w * s; v1[i+3] = bq.w * s;
        #pragma unroll
        for (int k = 0; k < 4; k++) {
            sq0 += v0[i+k] * v0[i+k];
            sq1 += v1[i+k] * v1[i+k];
        }
    }
    float rr0 = rsqrtf(warpReduceSum(sq0) * (1.0f / DI) + 1e-5f);
    float rr1 = rsqrtf(warpReduceSum(sq1) * (1.0f / DI) + 1e-5f);
    unsigned hi8[8], lo8[8];
    #pragma unroll
    for (int i = 0; i < 16; i += 2) {
        float o0 = 0.5f * nw[c0 + i]     * (v0[i]     * rr0 + v1[i]     * rr1);
        float o1 = 0.5f * nw[c0 + i + 1] * (v0[i + 1] * rr0 + v1[i + 1] * rr1);
        unsigned short h0, l0, h1, l1;
        bfsplit(o0, h0, l0);
        bfsplit(o1, h1, l1);
        hi8[i / 2] = (unsigned)h0 | ((unsigned)h1 << 16);
        lo8[i / 2] = (unsigned)l0 | ((unsigned)l1 << 16);
    }
    size_t ob = (size_t)t * (DI / 2) + c0 / 2;
    *(uint4*)(g_combhi + ob)     = make_uint4(hi8[0], hi8[1], hi8[2], hi8[3]);
    *(uint4*)(g_combhi + ob + 4) = make_uint4(hi8[4], hi8[5], hi8[6], hi8[7]);
    *(uint4*)(g_comblo + ob)     = make_uint4(lo8[0], lo8[1], lo8[2], lo8[3]);
    *(uint4*)(g_comblo + ob + 4) = make_uint4(lo8[4], lo8[5], lo8[6], lo8[7]);
}

// ---------------- launcher ----------------
extern "C" void kernel_launch(void* const* d_in, const int* in_sizes, int n_in,
                              void* d_out, int out_size) {
    (void)in_sizes; (void)n_in; (void)out_size;
    const float* query = (const float*)d_in[0];
    const float* pos   = (const float*)d_in[1];
    const float* pre_w = (const float*)d_in[2];
    const float* pre_b = (const float*)d_in[3];
    const float* fin_w = (const float*)d_in[4];
    const float* fin_b = (const float*)d_in[5];

    const int GEMM_SMEM = 2 * (2 * 128 * WSTR + 2 * 64 * WSTR) * 4;
    const int SCAN3_SMEM = (6 * CQ * SR + 3 * CQ) * 4;
    const int CONV_SMEM = (67 * CTILE + CTILE * 4 + CTILE) * 4 + 68 * 4;
    cudaFuncSetAttribute(k_gemm_bf, cudaFuncAttributeMaxDynamicSharedMemorySize, GEMM_SMEM);
    cudaFuncSetAttribute(k_scan3, cudaFuncAttributeMaxDynamicSharedMemorySize, SCAN3_SMEM);
    cudaFuncSetAttribute(k_conv2, cudaFuncAttributeMaxDynamicSharedMemorySize, CONV_SMEM);

    unsigned *p_qnhi, *p_qnlo, *p_combhi, *p_comblo;
    unsigned *p_WIhi, *p_WIlo, *p_WOhi, *p_WOlo;
    float *p_Z, *p_O, *p_q;
    cudaGetSymbolAddress((void**)&p_qnhi, g_qnhi);
    cudaGetSymbolAddress((void**)&p_qnlo, g_qnlo);
    cudaGetSymbolAddress((void**)&p_combhi, g_combhi);
    cudaGetSymbolAddress((void**)&p_comblo, g_comblo);
    cudaGetSymbolAddress((void**)&p_WIhi, g_WIhi);
    cudaGetSymbolAddress((void**)&p_WIlo, g_WIlo);
    cudaGetSymbolAddress((void**)&p_WOhi, g_WOhi);
    cudaGetSymbolAddress((void**)&p_WOlo, g_WOlo);
    cudaGetSymbolAddress((void**)&p_Z, g_Z);
    cudaGetSymbolAddress((void**)&p_O, g_O);
    cudaGetSymbolAddress((void**)&p_q, g_q);

    const int WI_SZ = NPIN * (DM / 2);
    const int WO_SZ = DM * (DI / 2);

    cudaStream_t s1;
    cudaStreamCreateWithFlags(&s1, cudaStreamNonBlocking);
    cudaEvent_t evF, evJ;
    cudaEventCreateWithFlags(&evF, cudaEventDisableTiming);
    cudaEventCreateWithFlags(&evJ, cudaEventDisableTiming);

    const float* Win0  = (const float*)d_in[6];
    const float* Win1  = (const float*)d_in[14];
    const float* Wout0 = (const float*)d_in[13];
    const float* Wout1 = (const float*)d_in[21];

    cudaEventRecord(evF, 0);
    cudaStreamWaitEvent(s1, evF, 0);
    k_ln256<<<NT, 128, 0, s1>>>(query, pre_w, pre_b);
    k_splitW<<<((DM / 2) * NPIN + 255) / 256, 256, 0, s1>>>(
        Win0, DM, DP, NPIN, p_WIhi, p_WIlo);
    k_gemm_bf<<<dim3(NPIN / 64, NT / 128), 256, GEMM_SMEM, s1>>>(
        NT, DP, DM, p_qnhi, p_qnlo, p_WIhi, p_WIlo, p_Z, DP);
    cudaEventRecord(evJ, s1);

    k_splitW<<<((DM / 2) * NPIN + 255) / 256, 256>>>(
        Win1, DM, DP, NPIN, p_WIhi + WI_SZ, p_WIlo + WI_SZ);
    k_splitW<<<((DI / 2) * DM + 255) / 256, 256>>>(
        Wout0, DI, DM, DM, p_WOhi, p_WOlo);
    k_splitW<<<((DI / 2) * DM + 255) / 256, 256>>>(
        Wout1, DI, DM, DM, p_WOhi + WO_SZ, p_WOlo + WO_SZ);
    k_minmax<<<1, 256>>>(pos);
    k_keys<<<(NT + 255) / 256, 256>>>(pos);
    k_sort_init<<<dim3(NT / SEG, 2), 128>>>();
    for (int k = 2 * SEG; k <= NT; k <<= 1) {
        for (int j = k >> 1; j >= SEG; j >>= 1)
            k_sort_gpass<<<dim3(NT / 2 / 256, 2), 256>>>(k, j);
        k_sort_local<<<dim3(NT / SEG, 2), 128>>>(k);
    }
    k_order<<<(2 * NT + 255) / 256, 256>>>();

    cudaStreamWaitEvent(0, evJ, 0);

    for (int L = 0; L < 2; L++) {
        const float* cw   = (const float*)d_in[7 + 8 * L];
        const float* cb   = (const float*)d_in[8 + 8 * L];
        const float* dtb  = (const float*)d_in[9 + 8 * L];
        const float* alog = (const float*)d_in[10 + 8 * L];
        const float* Dv   = (const float*)d_in[11 + 8 * L];
        const float* nw   = (const float*)d_in[12 + 8 * L];
        const float* src  = (L == 0) ? query : p_q;

        if (L == 1) {
            k_gemm_bf<<<dim3(NPIN / 64, NT / 128), 256, GEMM_SMEM>>>(
                NT, DP, DM, p_qnhi, p_qnlo, p_WIhi + WI_SZ, p_WIlo + WI_SZ, p_Z, DP);
        }
        k_conv2<<<dim3(NT / 64, CD / CTILE, 2), 256, CONV_SMEM>>>(cw, cb, dtb, alog);
        k_scan1<<<dim3(NCH, 2), 256>>>();
        k_scan2<<<256, 256>>>();
        k_scan3<<<dim3(NCH, 2), 256, SCAN3_SMEM>>>(Dv);
        k_pncomb<<<NT / 8, 256>>>(nw);
        k_gemm_bf<<<dim3(DM / 64, NT / 128), 256, GEMM_SMEM>>>(
            NT, DM, DI, p_combhi, p_comblo,
            p_WOhi + (size_t)L * WO_SZ, p_WOlo + (size_t)L * WO_SZ, p_O, DM);
        k_fln<<<NT / 8, 256>>>(src, fin_w, fin_b, pre_w, pre_b,
                               (L == 1) ? (float*)d_out : nullptr, (L == 0) ? 1 : 0);
    }
}